// round 6
// baseline (speedup 1.0000x reference)
#include <cuda_runtime.h>
#include <math.h>
#include <stdint.h>

// ---------------- model constants ----------------
#define BATCH 16
#define LSEQ  1000
#define DMODEL 512
#define NH    8
#define DHD   64
#define NPAD  1024
#define PADL  24
#define ML    256
#define LMR   4
#define FFD   2048
#define DEPTH 6
#define KC    33
#define QSCALE 0.125f
#define BH (BATCH*NH)

// ---------------- scratch ----------------
__device__ float g_h   [BATCH*LSEQ*DMODEL];
__device__ float g_x   [BATCH*NPAD*DMODEL];
__device__ float g_q   [BH*NPAD*DHD];
__device__ float g_k   [BH*NPAD*DHD];
__device__ float g_v   [BH*NPAD*DHD];
__device__ float g_ql  [BH*ML*DHD];
__device__ float g_kl  [BH*ML*DHD];
__device__ float g_a1  [BH*NPAD*ML];
__device__ float g_a3  [BH*ML*NPAD];
__device__ float g_a2  [BH*ML*ML];
__device__ float g_zb  [BH*ML*ML];
__device__ float g_zb2 [BH*ML*ML];
__device__ float g_pb  [BH*ML*ML];
__device__ float g_tb  [BH*ML*ML];
__device__ float g_tb2 [BH*ML*ML];
__device__ float g_kvb [BH*ML*DHD];
__device__ float g_a1z [BH*NPAD*ML];
__device__ float g_ao  [BH*NPAD*DHD];
__device__ float g_y   [BATCH*NPAD*DMODEL];
__device__ float g_x2  [BATCH*LSEQ*DMODEL];
__device__ float g_ff  [BATCH*LSEQ*FFD];
__device__ int   g_red [2];

// ---------------- reductions ----------------
__device__ __forceinline__ float warpSum(float v){
    #pragma unroll
    for (int o=16;o;o>>=1) v += __shfl_xor_sync(0xffffffffu, v, o);
    return v;
}
__device__ __forceinline__ float warpMax(float v){
    #pragma unroll
    for (int o=16;o;o>>=1) v = fmaxf(v, __shfl_xor_sync(0xffffffffu, v, o));
    return v;
}
__device__ __forceinline__ float blockSumN(float v, float* sh, int nw){
    int w = threadIdx.x>>5, l = threadIdx.x&31;
    v = warpSum(v);
    if (l==0) sh[w] = v;
    __syncthreads();
    if (w==0){
        float x = (l < nw) ? sh[l] : 0.f;
        x = warpSum(x);
        if (l==0) sh[0] = x;
    }
    __syncthreads();
    float r = sh[0];
    __syncthreads();
    return r;
}
__device__ __forceinline__ float blockMaxN(float v, float* sh, int nw){
    int w = threadIdx.x>>5, l = threadIdx.x&31;
    v = warpMax(v);
    if (l==0) sh[w] = v;
    __syncthreads();
    if (w==0){
        float x = (l < nw) ? sh[l] : -3.4e38f;
        x = warpMax(x);
        if (l==0) sh[0] = x;
    }
    __syncthreads();
    float r = sh[0];
    __syncthreads();
    return r;
}

// ---------------- mma / cp.async helpers ----------------
__device__ __forceinline__ void mma_tf32(float c[4],
    unsigned a0, unsigned a1, unsigned a2, unsigned a3,
    unsigned b0, unsigned b1)
{
    asm volatile(
        "mma.sync.aligned.m16n8k8.row.col.f32.tf32.tf32.f32 "
        "{%0,%1,%2,%3}, {%4,%5,%6,%7}, {%8,%9}, {%0,%1,%2,%3};"
        : "+f"(c[0]), "+f"(c[1]), "+f"(c[2]), "+f"(c[3])
        : "r"(a0), "r"(a1), "r"(a2), "r"(a3), "r"(b0), "r"(b1));
}
__device__ __forceinline__ void cp16(unsigned saddr, const void* gptr){
    asm volatile("cp.async.cg.shared.global [%0], [%1], 16;\n"
                 :: "r"(saddr), "l"(gptr));
}
__device__ __forceinline__ void cp_commit(){
    asm volatile("cp.async.commit_group;\n");
}
template<int N>
__device__ __forceinline__ void cp_wait(){
    asm volatile("cp.async.wait_group %0;\n" :: "n"(N));
}

// epilogue: writes 2 consecutive cols at (r, cc)
// EPI 0: C = alpha*val         EPI 2: C = gelu(val+bias)
// EPI 3: C += val+bias         EPI 4: pad-sliced residual add into h
// EPI 5: C = alpha*I - val     EPI 6: C = val ; C2 = alpha*I - val
// EPI 7: fused qkv split: C=q(*QSCALE), C2=k, C3=v in (b,h,n,d) layout
template<int EPI>
__device__ __forceinline__ void store2(
    float* __restrict__ C, float* __restrict__ C2, float* __restrict__ C3,
    int ldc, int r, int cc, float v0, float v1,
    float alpha, const float* __restrict__ bias)
{
    if (EPI==0){
        float2 o = {alpha*v0, alpha*v1};
        *(float2*)&C[(long long)r*ldc + cc] = o;
    } else if (EPI==2){
        float x0 = v0 + bias[cc], x1 = v1 + bias[cc+1];
        float2 o;
        o.x = 0.5f*x0*(1.f+erff(x0*0.70710678118654752f));
        o.y = 0.5f*x1*(1.f+erff(x1*0.70710678118654752f));
        *(float2*)&C[(long long)r*ldc + cc] = o;
    } else if (EPI==3){
        float2 o = *(float2*)&C[(long long)r*ldc + cc];
        o.x += v0 + bias[cc];
        o.y += v1 + bias[cc+1];
        *(float2*)&C[(long long)r*ldc + cc] = o;
    } else if (EPI==4){
        int bb = r / NPAD, nl = r % NPAD;
        if (nl >= PADL){
            long long orow = (long long)bb*LSEQ + (nl - PADL);
            float2 o = *(float2*)&C[orow*ldc + cc];
            o.x += v0 + bias[cc];
            o.y += v1 + bias[cc+1];
            *(float2*)&C[orow*ldc + cc] = o;
        }
    } else if (EPI==5){
        float2 o = {(r==cc ? alpha : 0.f) - v0, (r==cc+1 ? alpha : 0.f) - v1};
        *(float2*)&C[(long long)r*ldc + cc] = o;
    } else if (EPI==6){
        float2 o = {v0, v1};
        *(float2*)&C[(long long)r*ldc + cc] = o;
        float2 o2 = {(r==cc ? alpha : 0.f) - v0, (r==cc+1 ? alpha : 0.f) - v1};
        *(float2*)&C2[(long long)r*ldc + cc] = o2;
    } else if (EPI==7){
        int b = r >> 10, n = r & 1023;
        int which = cc >> 9;
        int hd = cc & 511;
        long long idx = ((((long long)b*NH + (hd>>6))*NPAD) + n)*DHD + (hd&63);
        float2 o;
        if (which==0){ o.x = v0*QSCALE; o.y = v1*QSCALE; *(float2*)&C[idx] = o; }
        else if (which==1){ o.x = v0; o.y = v1; *(float2*)&C2[idx] = o; }
        else { o.x = v0; o.y = v1; *(float2*)&C3[idx] = o; }
    }
}

// ===== TF32 tensor GEMM v4: CTA 128x128, warp 64x32, 4-stage cp.async =====
// TB=0: B is KxN rm.  TB=1: B is NxK rm (C = A @ B^T).
// Requires M%128==0, N%128==0, K%16==0.
#define AS_STRIDE 20
#define AS_ST     (128*AS_STRIDE)      // 2560 words
#define BS0_STRIDE 132
#define BS1_STRIDE 20
#define BS_ST     (128*BS1_STRIDE)     // 2560 words (>= 16*132=2112)
#define NSTAGE 4
#define SMEM_TC_BYTES (NSTAGE*(AS_ST + BS_ST)*4)   // 81920

template<int TB, int EPI>
__global__ void __launch_bounds__(256,2) gemm_tc_kernel(
    int Ki,
    const float* __restrict__ A, int lda, long long sA,
    const float* __restrict__ Bm, int ldb, long long sB,
    float* __restrict__ C, int ldc, long long sC,
    float alpha, const float* __restrict__ bias,
    float* __restrict__ C2, float* __restrict__ C3)
{
    extern __shared__ unsigned sm[];
    unsigned* As = sm;
    unsigned* Bs = sm + NSTAGE*AS_ST;
    const unsigned As_base = (unsigned)__cvta_generic_to_shared(As);
    const unsigned Bs_base = (unsigned)__cvta_generic_to_shared(Bs);

    const int bz = blockIdx.z;
    A  += (long long)bz*sA;
    Bm += (long long)bz*sB;
    C  += (long long)bz*sC;
    if (EPI==6) C2 += (long long)bz*sC;

    const int row0 = blockIdx.y*128;
    const int col0 = blockIdx.x*128;
    const int tid = threadIdx.x;
    const int warp = tid>>5, lane = tid&31;
    const int wm = warp & 1, wn = warp >> 1;   // 2x4 warp grid, warp tile 64x32
    const int g = lane>>2, qc = lane&3;

    // staging maps (2 cp16 per array per thread)
    const int a_r  = tid>>1;
    const int a_c2 = (tid&1)<<1;               // float4-chunk pair base (0 or 2)
    const int b0_k = tid>>4;
    const int b0_n = (tid&15)<<3;

    auto issue = [&](int kt, int st){
        unsigned abase = As_base + (unsigned)(st*AS_ST)*4u;
        #pragma unroll
        for (int i=0;i<2;i++)
            cp16(abase + (unsigned)(a_r*AS_STRIDE + (a_c2+i)*4)*4u,
                 A + (long long)(row0 + a_r)*lda + kt + (a_c2+i)*4);
        unsigned bbase = Bs_base + (unsigned)(st*BS_ST)*4u;
        if (TB==0){
            #pragma unroll
            for (int i=0;i<2;i++)
                cp16(bbase + (unsigned)(b0_k*BS0_STRIDE + b0_n + i*4)*4u,
                     Bm + (long long)(kt + b0_k)*ldb + col0 + b0_n + i*4);
        } else {
            #pragma unroll
            for (int i=0;i<2;i++)
                cp16(bbase + (unsigned)(a_r*BS1_STRIDE + (a_c2+i)*4)*4u,
                     Bm + (long long)(col0 + a_r)*ldb + kt + (a_c2+i)*4);
        }
    };

    float acc[4][4][4];
    #pragma unroll
    for (int mt=0;mt<4;mt++)
        #pragma unroll
        for (int nt=0;nt<4;nt++)
            #pragma unroll
            for (int i=0;i<4;i++) acc[mt][nt][i]=0.f;

    const int nk = Ki >> 4;
    issue(0, 0);  cp_commit();
    issue(16, 1); cp_commit();
    issue(32, 2); cp_commit();

    const int a_frag_off  = (wm*64 + g)*AS_STRIDE + qc;
    const int b0_frag_off = qc*BS0_STRIDE + wn*32 + g;
    const int b1_frag_off = (wn*32 + g)*BS1_STRIDE + qc;

    for (int t = 0; t < nk; ++t){
        cp_wait<2>();
        __syncthreads();
        const int rb = t & (NSTAGE-1);
        if (t+3 < nk) issue((t+3)<<4, (t+3)&(NSTAGE-1));
        cp_commit();

        #pragma unroll
        for (int grp=0; grp<2; grp++){
            const int koff = grp*8;
            unsigned af[4][4], bf[4][2];
            const unsigned* Ab = As + rb*AS_ST + a_frag_off + koff;
            #pragma unroll
            for (int mt=0;mt<4;mt++){
                const unsigned* p = Ab + (mt*16)*AS_STRIDE;
                af[mt][0] = p[0];
                af[mt][1] = p[8*AS_STRIDE];
                af[mt][2] = p[4];
                af[mt][3] = p[8*AS_STRIDE+4];
            }
            if (TB==0){
                const unsigned* Bb = Bs + rb*BS_ST + b0_frag_off + koff*BS0_STRIDE;
                #pragma unroll
                for (int nt=0;nt<4;nt++){
                    bf[nt][0] = Bb[nt*8];
                    bf[nt][1] = Bb[4*BS0_STRIDE + nt*8];
                }
            } else {
                const unsigned* Bb = Bs + rb*BS_ST + b1_frag_off + koff;
                #pragma unroll
                for (int nt=0;nt<4;nt++){
                    bf[nt][0] = Bb[nt*8*BS1_STRIDE];
                    bf[nt][1] = Bb[nt*8*BS1_STRIDE + 4];
                }
            }
            #pragma unroll
            for (int mt=0;mt<4;mt++)
                #pragma unroll
                for (int nt=0;nt<4;nt++)
                    mma_tf32(acc[mt][nt], af[mt][0],af[mt][1],af[mt][2],af[mt][3],
                             bf[nt][0],bf[nt][1]);
        }
    }

    // epilogue
    #pragma unroll
    for (int mt=0;mt<4;mt++){
        int r = row0 + wm*64 + mt*16 + g;
        #pragma unroll
        for (int nt=0;nt<4;nt++){
            int cc = col0 + wn*32 + nt*8 + 2*qc;
            store2<EPI>(C, C2, C3, ldc, r,   cc, acc[mt][nt][0], acc[mt][nt][1], alpha, bias);
            store2<EPI>(C, C2, C3, ldc, r+8, cc, acc[mt][nt][2], acc[mt][nt][3], alpha, bias);
        }
    }
}

// ---------------- generic 64x64 tiled SIMT GEMM (small-N fallback) --------
template<int TB, int EPI>
__global__ void __launch_bounds__(256) gemm_kernel(
    int Ki,
    const float* __restrict__ A, int lda, long long sA,
    const float* __restrict__ Bm, int ldb, long long sB,
    float* __restrict__ C, int ldc, long long sC,
    float alpha, const float* __restrict__ bias)
{
    const int bz = blockIdx.z;
    A  += (long long)bz * sA;
    Bm += (long long)bz * sB;
    C  += (long long)bz * sC;
    const int row0 = blockIdx.y * 64;
    const int col0 = blockIdx.x * 64;
    __shared__ float As[16][68];
    __shared__ float Bs[16][68];
    const int tid = threadIdx.x;
    const int ty = tid >> 4, tx = tid & 15;
    const int ar = tid >> 2, akq = (tid & 3) << 2;

    float acc[4][4];
    #pragma unroll
    for (int i=0;i<4;i++)
        #pragma unroll
        for (int j=0;j<4;j++) acc[i][j]=0.f;

    for (int k0 = 0; k0 < Ki; k0 += 16) {
        float4 av = *(const float4*)(A + (long long)(row0+ar)*lda + k0 + akq);
        As[akq+0][ar]=av.x; As[akq+1][ar]=av.y; As[akq+2][ar]=av.z; As[akq+3][ar]=av.w;
        if (TB==0) {
            int bkk = tid >> 4, bc = (tid & 15) << 2;
            float4 bv = *(const float4*)(Bm + (long long)(k0+bkk)*ldb + col0 + bc);
            Bs[bkk][bc+0]=bv.x; Bs[bkk][bc+1]=bv.y; Bs[bkk][bc+2]=bv.z; Bs[bkk][bc+3]=bv.w;
        } else {
            int bc = tid >> 2, bkq = (tid & 3) << 2;
            float4 bv = *(const float4*)(Bm + (long long)(col0+bc)*ldb + k0 + bkq);
            Bs[bkq+0][bc]=bv.x; Bs[bkq+1][bc]=bv.y; Bs[bkq+2][bc]=bv.z; Bs[bkq+3][bc]=bv.w;
        }
        __syncthreads();
        #pragma unroll
        for (int kk=0;kk<16;kk++){
            float a[4], b[4];
            #pragma unroll
            for (int i=0;i<4;i++) a[i]=As[kk][ty+16*i];
            #pragma unroll
            for (int j=0;j<4;j++) b[j]=Bs[kk][tx+16*j];
            #pragma unroll
            for (int i=0;i<4;i++)
                #pragma unroll
                for (int j=0;j<4;j++)
                    acc[i][j] = fmaf(a[i], b[j], acc[i][j]);
        }
        __syncthreads();
    }

    #pragma unroll
    for (int i=0;i<4;i++){
        int r = row0 + ty + 16*i;
        #pragma unroll
        for (int j=0;j<4;j++){
            int c = col0 + tx + 16*j;
            float val = alpha * acc[i][j];
            if (EPI==0) {
                C[(long long)r*ldc + c] = val;
            } else if (EPI==2) {
                float xg = val + bias[c];
                C[(long long)r*ldc + c] = 0.5f*xg*(1.f+erff(xg*0.70710678118654752f));
            } else if (EPI==3) {
                C[(long long)r*ldc + c] += val + bias[c];
            } else if (EPI==4) {
                int bb = r / NPAD, nl = r % NPAD;
                if (nl >= PADL)
                    C[((long long)bb*LSEQ + (nl-PADL))*ldc + c] += val + bias[c];
            }
        }
    }
}

// ---------------- elementwise / small kernels ----------------
__global__ void embed_kernel(const int* __restrict__ x,
                             const float* __restrict__ emb,
                             const float* __restrict__ pos){
    long long idx = (long long)blockIdx.x*blockDim.x + threadIdx.x;
    if (idx >= (long long)BATCH*LSEQ*DMODEL) return;
    int d = (int)(idx % DMODEL);
    long long bl = idx / DMODEL;
    int l = (int)(bl % LSEQ);
    int tok = x[bl];
    g_h[idx] = emb[(long long)tok*DMODEL + d] + pos[(long long)l*DMODEL + d];
}

__global__ void zero_pad_kernel(){
    int idx = blockIdx.x*blockDim.x + threadIdx.x;
    if (idx >= BATCH*PADL*DMODEL) return;
    int d  = idx % DMODEL;
    int bp = idx / DMODEL;
    int b  = bp / PADL, p = bp % PADL;
    g_x[((long long)b*NPAD + p)*DMODEL + d] = 0.f;
}

__global__ void ln_kernel(const float* __restrict__ in, float* __restrict__ out,
                          const float* __restrict__ gm, const float* __restrict__ bt,
                          int padmode){
    __shared__ float sh[8];
    int r = blockIdx.x;
    int t = threadIdx.x;
    const float* p = in + (long long)r*DMODEL;
    float a  = p[t];
    float b2 = p[t+256];
    float s  = blockSumN(a+b2, sh, 8);
    float mu = s * (1.f/512.f);
    float da = a - mu, db = b2 - mu;
    float v  = blockSumN(da*da + db*db, sh, 8) * (1.f/512.f);
    float rstd = rsqrtf(v + 1e-5f);
    long long orow = padmode ? ((long long)(r/LSEQ)*NPAD + PADL + (r%LSEQ)) : (long long)r;
    float* q = out + orow*DMODEL;
    q[t]     = da*rstd*gm[t]     + bt[t];
    q[t+256] = db*rstd*gm[t+256] + bt[t+256];
}

__global__ void landmark_kernel(){
    long long idx = (long long)blockIdx.x*blockDim.x + threadIdx.x;
    if (idx >= (long long)BH*ML*DHD) return;
    int d = (int)(idx & 63);
    long long r = idx >> 6;
    int m  = (int)(r % ML);
    int bh = (int)(r / ML);
    long long base = ((long long)bh*NPAD + (long long)m*LMR)*DHD + d;
    float sq = 0.f, sk = 0.f;
    #pragma unroll
    for (int j=0;j<LMR;j++){ sq += g_q[base + (long long)j*DHD]; sk += g_k[base + (long long)j*DHD]; }
    g_ql[idx] = sq * 0.25f;
    g_kl[idx] = sk * 0.25f;
}

__global__ void softmax_kernel(float* __restrict__ X, int cols){
    __shared__ float sh[4];
    long long row = blockIdx.x;
    float* p = X + row*(long long)cols;
    int t = threadIdx.x;
    int cnt = cols >> 7;
    float v[8];
    float mx = -3.4e38f;
    #pragma unroll
    for (int i=0;i<8;i++) if (i<cnt){ v[i]=p[t + (i<<7)]; mx = fmaxf(mx, v[i]); }
    mx = blockMaxN(mx, sh, 4);
    float s = 0.f;
    #pragma unroll
    for (int i=0;i<8;i++) if (i<cnt){ v[i]=expf(v[i]-mx); s += v[i]; }
    s = blockSumN(s, sh, 4);
    float inv = 1.f/s;
    #pragma unroll
    for (int i=0;i<8;i++) if (i<cnt) p[t + (i<<7)] = v[i]*inv;
}

__global__ void red_init_kernel(){ g_red[0]=0; g_red[1]=0; }

__global__ void colsum_kernel(){
    int idx = blockIdx.x*blockDim.x + threadIdx.x;
    if (idx >= BH*ML) return;
    int c  = idx % ML;
    int bz = idx / ML;
    const float* p = g_a2 + (long long)bz*ML*ML + c;
    float s = 0.f;
    for (int r2=0;r2<ML;r2++) s += fabsf(p[(long long)r2*ML]);
    atomicMax(&g_red[0], __float_as_int(s));
}
__global__ void rowsum_kernel(){
    int idx = blockIdx.x*blockDim.x + threadIdx.x;
    if (idx >= BH*ML) return;
    int r2 = idx % ML;
    int bz = idx / ML;
    const float* p = g_a2 + (long long)bz*ML*ML + (long long)r2*ML;
    float s = 0.f;
    for (int c=0;c<ML;c++) s += fabsf(p[c]);
    atomicMax(&g_red[1], __float_as_int(s));
}
__global__ void zinit_kernel(){
    long long idx = (long long)blockIdx.x*blockDim.x + threadIdx.x;
    if (idx >= (long long)BH*ML*ML) return;
    int j = (int)(idx % ML);
    long long r = idx / ML;
    int i  = (int)(r % ML);
    int bz = (int)(r / ML);
    float c = __int_as_float(g_red[0]) * __int_as_float(g_red[1]);
    g_zb[idx] = g_a2[((long long)bz*ML + j)*ML + i] / c;
}

__global__ void combine_kernel(const float* __restrict__ cw){
    long long idx = (long long)blockIdx.x*blockDim.x + threadIdx.x;
    if (idx >= (long long)BH*NPAD*DHD) return;
    int d = (int)(idx & 63);
    long long r = idx >> 6;
    int n  = (int)(r % NPAD);
    int bh = (int)(r / NPAD);
    int h  = bh % NH, b = bh / NH;
    float s = g_ao[idx];
    const float* w  = cw + h*KC;
    const float* vp = g_v + ((long long)bh*NPAD)*DHD + d;
    int k0 = (16-n > 0) ? (16-n) : 0;
    int k1 = (NPAD+16-n < KC) ? (NPAD+16-n) : KC;
    for (int kk=k0; kk<k1; kk++)
        s = fmaf(vp[(long long)(n+kk-16)*DHD], w[kk], s);
    g_y[((long long)b*NPAD + n)*DMODEL + h*DHD + d] = s;
}

__global__ void final_kernel(const float* __restrict__ fw,
                             const float* __restrict__ fb,
                             float* __restrict__ out){
    __shared__ float sh[8];
    int b = blockIdx.x;
    int t = threadIdx.x;
    const float* hp = g_h + (long long)b*LSEQ*DMODEL;
    float s = 0.f;
    for (long long i=t; i<(long long)LSEQ*DMODEL; i+=256)
        s = fmaf(hp[i], fw[i], s);
    s = blockSumN(s, sh, 8);
    if (t==0) out[b] = s + fb[0];
}

// ---------------- host-side GEMM dispatch ----------------
static void run_gemm(int tb, int epi, int Mi, int Ni, int Ki,
                     const float* A, int lda, long long sA,
                     const float* Bm, int ldb, long long sB,
                     float* C, int ldc, long long sC,
                     int batch, float alpha, const float* bias,
                     float* C2 = nullptr, float* C3 = nullptr)
{
    if ((Mi % 128) == 0 && (Ni % 128) == 0 && (Ki % 16) == 0) {
        dim3 g(Ni/128, Mi/128, batch), t(256);
        size_t sh = SMEM_TC_BYTES;
        if (tb == 0) {
            switch (epi) {
                case 0: gemm_tc_kernel<0,0><<<g,t,sh>>>(Ki,A,lda,sA,Bm,ldb,sB,C,ldc,sC,alpha,bias,C2,C3); break;
                case 2: gemm_tc_kernel<0,2><<<g,t,sh>>>(Ki,A,lda,sA,Bm,ldb,sB,C,ldc,sC,alpha,bias,C2,C3); break;
                case 3: gemm_tc_kernel<0,3><<<g,t,sh>>>(Ki,A,lda,sA,Bm,ldb,sB,C,ldc,sC,alpha,bias,C2,C3); break;
                case 4: gemm_tc_kernel<0,4><<<g,t,sh>>>(Ki,A,lda,sA,Bm,ldb,sB,C,ldc,sC,alpha,bias,C2,C3); break;
                case 5: gemm_tc_kernel<0,5><<<g,t,sh>>>(Ki,A,lda,sA,Bm,ldb,sB,C,ldc,sC,alpha,bias,C2,C3); break;
                case 6: gemm_tc_kernel<0,6><<<g,t,sh>>>(Ki,A,lda,sA,Bm,ldb,sB,C,ldc,sC,alpha,bias,C2,C3); break;
                case 7: gemm_tc_kernel<0,7><<<g,t,sh>>>(Ki,A,lda,sA,Bm,ldb,sB,C,ldc,sC,alpha,bias,C2,C3); break;
            }
        } else {
            gemm_tc_kernel<1,0><<<g,t,sh>>>(Ki,A,lda,sA,Bm,ldb,sB,C,ldc,sC,alpha,bias,C2,C3);
        }
        return;
    }
    dim3 g(Ni/64, Mi/64, batch), t(256);
    if (tb==0){
        if      (epi==0) gemm_kernel<0,0><<<g,t>>>(Ki,A,lda,sA,Bm,ldb,sB,C,ldc,sC,alpha,bias);
        else if (epi==2) gemm_kernel<0,2><<<g,t>>>(Ki,A,lda,sA,Bm,ldb,sB,C,ldc,sC,alpha,bias);
        else if (epi==3) gemm_kernel<0,3><<<g,t>>>(Ki,A,lda,sA,Bm,ldb,sB,C,ldc,sC,alpha,bias);
        else             gemm_kernel<0,4><<<g,t>>>(Ki,A,lda,sA,Bm,ldb,sB,C,ldc,sC,alpha,bias);
    } else {
        gemm_kernel<1,0><<<g,t>>>(Ki,A,lda,sA,Bm,ldb,sB,C,ldc,sC,alpha,bias);
    }
}

static void setup_tc_attrs(){
    cudaFuncSetAttribute(gemm_tc_kernel<0,0>, cudaFuncAttributeMaxDynamicSharedMemorySize, SMEM_TC_BYTES);
    cudaFuncSetAttribute(gemm_tc_kernel<0,2>, cudaFuncAttributeMaxDynamicSharedMemorySize, SMEM_TC_BYTES);
    cudaFuncSetAttribute(gemm_tc_kernel<0,3>, cudaFuncAttributeMaxDynamicSharedMemorySize, SMEM_TC_BYTES);
    cudaFuncSetAttribute(gemm_tc_kernel<0,4>, cudaFuncAttributeMaxDynamicSharedMemorySize, SMEM_TC_BYTES);
    cudaFuncSetAttribute(gemm_tc_kernel<0,5>, cudaFuncAttributeMaxDynamicSharedMemorySize, SMEM_TC_BYTES);
    cudaFuncSetAttribute(gemm_tc_kernel<0,6>, cudaFuncAttributeMaxDynamicSharedMemorySize, SMEM_TC_BYTES);
    cudaFuncSetAttribute(gemm_tc_kernel<0,7>, cudaFuncAttributeMaxDynamicSharedMemorySize, SMEM_TC_BYTES);
    cudaFuncSetAttribute(gemm_tc_kernel<1,0>, cudaFuncAttributeMaxDynamicSharedMemorySize, SMEM_TC_BYTES);
}

extern "C" void kernel_launch(void* const* d_in, const int* in_sizes, int n_in,
                              void* d_out, int out_size)
{
    (void)in_sizes; (void)n_in; (void)out_size;
    const int*   x       = (const int*)  d_in[0];
    const float* enc_emb = (const float*)d_in[1];
    const float* pos_emb = (const float*)d_in[2];
    const float* ln1_s   = (const float*)d_in[3];
    const float* ln1_b   = (const float*)d_in[4];
    const float* qkv_w   = (const float*)d_in[5];
    const float* aout_w  = (const float*)d_in[6];
    const float* aout_b  = (const float*)d_in[7];
    const float* conv_k  = (const float*)d_in[8];
    const float* ln2_s   = (const float*)d_in[9];
    const float* ln2_b   = (const float*)d_in[10];
    const float* ff_w1   = (const float*)d_in[11];
    const float* ff_b1   = (const float*)d_in[12];
    const float* ff_w2   = (const float*)d_in[13];
    const float* ff_b2   = (const float*)d_in[14];
    const float* fin_w   = (const float*)d_in[15];
    const float* fin_b   = (const float*)d_in[16];
    float* out = (float*)d_out;

    setup_tc_attrs();

    float *p_h,*p_x,*p_q,*p_k,*p_v,*p_ql,*p_kl,*p_a1,*p_a3,*p_a2;
    float *p_z,*p_z2,*p_p,*p_t,*p_t2,*p_kv,*p_a1z,*p_ao,*p_y,*p_x2,*p_ff;
    cudaGetSymbolAddress((void**)&p_h,  g_h);
    cudaGetSymbolAddress((void**)&p_x,  g_x);
    cudaGetSymbolAddress((void**)&p_q,  g_q);
    cudaGetSymbolAddress((void**)&p_k,  g_k);
    cudaGetSymbolAddress((void**)&p_v,  g_v);
    cudaGetSymbolAddress((void**)&p_ql, g_ql);
    cudaGetSymbolAddress((void**)&p_kl, g_kl);
    cudaGetSymbolAddress((void**)&p_a1, g_a1);
    cudaGetSymbolAddress((void**)&p_a3, g_a3);
    cudaGetSymbolAddress((void**)&p_a2, g_a2);
    cudaGetSymbolAddress((void**)&p_z,  g_zb);
    cudaGetSymbolAddress((void**)&p_z2, g_zb2);
    cudaGetSymbolAddress((void**)&p_p,  g_pb);
    cudaGetSymbolAddress((void**)&p_t,  g_tb);
    cudaGetSymbolAddress((void**)&p_t2, g_tb2);
    cudaGetSymbolAddress((void**)&p_kv, g_kvb);
    cudaGetSymbolAddress((void**)&p_a1z,g_a1z);
    cudaGetSymbolAddress((void**)&p_ao, g_ao);
    cudaGetSymbolAddress((void**)&p_y,  g_y);
    cudaGetSymbolAddress((void**)&p_x2, g_x2);
    cudaGetSymbolAddress((void**)&p_ff, g_ff);

    const long long MM  = (long long)ML*ML;
    const long long NM  = (long long)NPAD*ML;
    const long long ND  = (long long)NPAD*DHD;
    const long long MD  = (long long)ML*DHD;

    {
        long long tot = (long long)BATCH*LSEQ*DMODEL;
        embed_kernel<<<(unsigned)((tot+255)/256),256>>>(x, enc_emb, pos_emb);
        int tot2 = BATCH*PADL*DMODEL;
        zero_pad_kernel<<<(tot2+255)/256,256>>>();
    }

    for (int lay=0; lay<DEPTH; lay++){
        ln_kernel<<<BATCH*LSEQ,256>>>(p_h, p_x, ln1_s+(long long)lay*DMODEL, ln1_b+(long long)lay*DMODEL, 1);
        // QKV [tensor, fused split into q/k/v]
        run_gemm(0,7, BATCH*NPAD, 3*DMODEL, DMODEL,
                 p_x, DMODEL, 0,
                 qkv_w + (long long)lay*DMODEL*3*DMODEL, 3*DMODEL, 0,
                 p_q, 3*DMODEL, 0, 1, 1.f, nullptr, p_k, p_v);
        {
            long long tot2 = (long long)BH*ML*DHD;
            landmark_kernel<<<(unsigned)((tot2+255)/256),256>>>();
        }
        // attn1 = softmax(q @ kl^T)  [tensor TB=1]
        run_gemm(1,0, NPAD, ML, DHD, p_q, DHD, ND, p_kl, DHD, MD, p_a1, ML, NM, BH, 1.f, nullptr);
        softmax_kernel<<<BH*NPAD,128>>>(p_a1, ML);
        // attn2 = softmax(ql @ kl^T)  [tensor TB=1]
        run_gemm(1,0, ML, ML, DHD, p_ql, DHD, MD, p_kl, DHD, MD, p_a2, ML, MM, BH, 1.f, nullptr);
        softmax_kernel<<<BH*ML,128>>>(p_a2, ML);
        // attn3 = softmax(ql @ k^T)  [tensor TB=1]
        run_gemm(1,0, ML, NPAD, DHD, p_ql, DHD, MD, p_k, DHD, ND, p_a3, NPAD, (long long)ML*NPAD, BH, 1.f, nullptr);
        softmax_kernel<<<BH*ML,128>>>(p_a3, NPAD);

        // ---- pinv (tensor, fused aI-X epilogues) ----
        red_init_kernel<<<1,1>>>();
        colsum_kernel<<<(BH*ML+255)/256,256>>>();
        rowsum_kernel<<<(BH*ML+255)/256,256>>>();
        {
            long long tot = (long long)BH*ML*ML;
            unsigned g = (unsigned)((tot+255)/256);
            zinit_kernel<<<g,256>>>();
        }
        float* zc = p_z; float* zn = p_z2;
        for (int it=0; it<6; it++){
            run_gemm(0,6, ML, ML, ML, p_a2, ML, MM, zc, ML, MM, p_p, ML, MM, BH, 7.f, nullptr, p_t);
            run_gemm(0,5, ML, ML, ML, p_p, ML, MM, p_t, ML, MM, p_t2, ML, MM, BH, 15.f, nullptr);
            run_gemm(0,5, ML, ML, ML, p_p, ML, MM, p_t2, ML, MM, p_t, ML, MM, BH, 13.f, nullptr);
            run_gemm(0,0, ML, ML, ML, zc, ML, MM, p_t, ML, MM, zn, ML, MM, BH, 0.25f, nullptr);
            float* tmp = zc; zc = zn; zn = tmp;
        }

        // kv = attn3 @ v  [SIMT N=64]
        run_gemm(0,0, ML, DHD, NPAD, p_a3, NPAD, (long long)ML*NPAD, p_v, DHD, ND, p_kv, DHD, MD, BH, 1.f, nullptr);
        // a1z = attn1 @ Z  [tensor]
        run_gemm(0,0, NPAD, ML, ML, p_a1, ML, NM, zc, ML, MM, p_a1z, ML, NM, BH, 1.f, nullptr);
        // ao = a1z @ kv  [SIMT N=64]
        run_gemm(0,0, NPAD, DHD, ML, p_a1z, ML, NM, p_kv, DHD, MD, p_ao, DHD, ND, BH, 1.f, nullptr);
        {
            long long tot = (long long)BH*NPAD*DHD;
            combine_kernel<<<(unsigned)((tot+255)/256),256>>>(conv_k + (long long)lay*NH*KC);
        }
        // out projection + residual [tensor]
        run_gemm(0,4, BATCH*NPAD, DMODEL, DMODEL,
                 p_y, DMODEL, 0,
                 aout_w + (long long)lay*DMODEL*DMODEL, DMODEL, 0,
                 p_h, DMODEL, 0, 1, 1.f, aout_b + (long long)lay*DMODEL);

        // ---- FFN ----
        ln_kernel<<<BATCH*LSEQ,256>>>(p_h, p_x2, ln2_s+(long long)lay*DMODEL, ln2_b+(long long)lay*DMODEL, 0);
        run_gemm(0,2, BATCH*LSEQ, FFD, DMODEL,
                 p_x2, DMODEL, 0,
                 ff_w1 + (long long)lay*DMODEL*FFD, FFD, 0,
                 p_ff, FFD, 0, 1, 1.f, ff_b1 + (long long)lay*FFD);
        run_gemm(0,3, BATCH*LSEQ, DMODEL, FFD,
                 p_ff, FFD, 0,
                 ff_w2 + (long long)lay*FFD*DMODEL, DMODEL, 0,
                 p_h, DMODEL, 0, 1, 1.f, ff_b2 + (long long)lay*DMODEL);
    }

    final_kernel<<<BATCH,256>>>(fin_w, fin_b, out);
}

// round 7
// speedup vs baseline: 1.0807x; 1.0807x over previous
#include <cuda_runtime.h>
#include <math.h>
#include <stdint.h>

// ---------------- model constants ----------------
#define BATCH 16
#define LSEQ  1000
#define DMODEL 512
#define NH    8
#define DHD   64
#define NPAD  1024
#define PADL  24
#define ML    256
#define LMR   4
#define FFD   2048
#define DEPTH 6
#define KC    33
#define QSCALE 0.125f
#define BH (BATCH*NH)

// ---------------- scratch ----------------
__device__ float g_h   [BATCH*LSEQ*DMODEL];
__device__ float g_x   [BATCH*NPAD*DMODEL];
__device__ float g_q   [BH*NPAD*DHD];
__device__ float g_k   [BH*NPAD*DHD];
__device__ float g_v   [BH*NPAD*DHD];
__device__ float g_ql  [BH*ML*DHD];
__device__ float g_kl  [BH*ML*DHD];
__device__ float g_a1  [BH*NPAD*ML];
__device__ float g_a3  [BH*ML*NPAD];
__device__ float g_a2  [BH*ML*ML];
__device__ float g_zb  [BH*ML*ML];
__device__ float g_zb2 [BH*ML*ML];
__device__ float g_pb  [BH*ML*ML];
__device__ float g_tb  [BH*ML*ML];
__device__ float g_tb2 [BH*ML*ML];
__device__ float g_kvb [BH*ML*DHD];
__device__ float g_a1z [BH*NPAD*ML];
__device__ float g_ao  [BH*NPAD*DHD];
__device__ float g_y   [BATCH*NPAD*DMODEL];
__device__ float g_x2  [BATCH*LSEQ*DMODEL];
__device__ float g_ff  [BATCH*LSEQ*FFD];
__device__ int   g_red [2];

// ---------------- reductions ----------------
__device__ __forceinline__ float warpSum(float v){
    #pragma unroll
    for (int o=16;o;o>>=1) v += __shfl_xor_sync(0xffffffffu, v, o);
    return v;
}
__device__ __forceinline__ float warpMax(float v){
    #pragma unroll
    for (int o=16;o;o>>=1) v = fmaxf(v, __shfl_xor_sync(0xffffffffu, v, o));
    return v;
}
__device__ __forceinline__ float blockSumN(float v, float* sh, int nw){
    int w = threadIdx.x>>5, l = threadIdx.x&31;
    v = warpSum(v);
    if (l==0) sh[w] = v;
    __syncthreads();
    if (w==0){
        float x = (l < nw) ? sh[l] : 0.f;
        x = warpSum(x);
        if (l==0) sh[0] = x;
    }
    __syncthreads();
    float r = sh[0];
    __syncthreads();
    return r;
}
__device__ __forceinline__ float blockMaxN(float v, float* sh, int nw){
    int w = threadIdx.x>>5, l = threadIdx.x&31;
    v = warpMax(v);
    if (l==0) sh[w] = v;
    __syncthreads();
    if (w==0){
        float x = (l < nw) ? sh[l] : -3.4e38f;
        x = warpMax(x);
        if (l==0) sh[0] = x;
    }
    __syncthreads();
    float r = sh[0];
    __syncthreads();
    return r;
}

// ---------------- mma / cp.async helpers ----------------
__device__ __forceinline__ void mma_tf32(float c[4],
    unsigned a0, unsigned a1, unsigned a2, unsigned a3,
    unsigned b0, unsigned b1)
{
    asm volatile(
        "mma.sync.aligned.m16n8k8.row.col.f32.tf32.tf32.f32 "
        "{%0,%1,%2,%3}, {%4,%5,%6,%7}, {%8,%9}, {%0,%1,%2,%3};"
        : "+f"(c[0]), "+f"(c[1]), "+f"(c[2]), "+f"(c[3])
        : "r"(a0), "r"(a1), "r"(a2), "r"(a3), "r"(b0), "r"(b1));
}
__device__ __forceinline__ void cp16(unsigned saddr, const void* gptr){
    asm volatile("cp.async.cg.shared.global [%0], [%1], 16;\n"
                 :: "r"(saddr), "l"(gptr));
}
__device__ __forceinline__ void cp_commit(){
    asm volatile("cp.async.commit_group;\n");
}
template<int N>
__device__ __forceinline__ void cp_wait(){
    asm volatile("cp.async.wait_group %0;\n" :: "n"(N));
}

// epilogue: writes 2 consecutive cols at (r, cc)
// EPI 0: C = alpha*val         EPI 2: C = gelu(val+bias)
// EPI 3: C += val+bias         EPI 4: pad-sliced residual add into h
// EPI 5: C = alpha*I - val     EPI 6: C = val ; C2 = alpha*I - val
// EPI 7: fused qkv split: C=q(*QSCALE), C2=k, C3=v in (b,h,n,d) layout
template<int EPI>
__device__ __forceinline__ void store2(
    float* __restrict__ C, float* __restrict__ C2, float* __restrict__ C3,
    int ldc, int r, int cc, float v0, float v1,
    float alpha, const float* __restrict__ bias)
{
    if (EPI==0){
        float2 o = {alpha*v0, alpha*v1};
        *(float2*)&C[(long long)r*ldc + cc] = o;
    } else if (EPI==2){
        float x0 = v0 + bias[cc], x1 = v1 + bias[cc+1];
        float2 o;
        o.x = 0.5f*x0*(1.f+erff(x0*0.70710678118654752f));
        o.y = 0.5f*x1*(1.f+erff(x1*0.70710678118654752f));
        *(float2*)&C[(long long)r*ldc + cc] = o;
    } else if (EPI==3){
        float2 o = *(float2*)&C[(long long)r*ldc + cc];
        o.x += v0 + bias[cc];
        o.y += v1 + bias[cc+1];
        *(float2*)&C[(long long)r*ldc + cc] = o;
    } else if (EPI==4){
        int bb = r / NPAD, nl = r % NPAD;
        if (nl >= PADL){
            long long orow = (long long)bb*LSEQ + (nl - PADL);
            float2 o = *(float2*)&C[orow*ldc + cc];
            o.x += v0 + bias[cc];
            o.y += v1 + bias[cc+1];
            *(float2*)&C[orow*ldc + cc] = o;
        }
    } else if (EPI==5){
        float2 o = {(r==cc ? alpha : 0.f) - v0, (r==cc+1 ? alpha : 0.f) - v1};
        *(float2*)&C[(long long)r*ldc + cc] = o;
    } else if (EPI==6){
        float2 o = {v0, v1};
        *(float2*)&C[(long long)r*ldc + cc] = o;
        float2 o2 = {(r==cc ? alpha : 0.f) - v0, (r==cc+1 ? alpha : 0.f) - v1};
        *(float2*)&C2[(long long)r*ldc + cc] = o2;
    } else if (EPI==7){
        int b = r >> 10, n = r & 1023;
        int which = cc >> 9;
        int hd = cc & 511;
        long long idx = ((((long long)b*NH + (hd>>6))*NPAD) + n)*DHD + (hd&63);
        float2 o;
        if (which==0){ o.x = v0*QSCALE; o.y = v1*QSCALE; *(float2*)&C[idx] = o; }
        else if (which==1){ o.x = v0; o.y = v1; *(float2*)&C2[idx] = o; }
        else { o.x = v0; o.y = v1; *(float2*)&C3[idx] = o; }
    }
}

// === TF32 tensor GEMM v5: 512 thr, CTA 128x256, warp 64x32, 3-stage async ==
// TB=0: B is KxN rm.  TB=1: B is NxK rm (C = A @ B^T).
// Requires M%128==0, N%256==0, K%16==0.
#define AS_STRIDE 20
#define AS_ST     (128*AS_STRIDE)      // 2560 words
#define BS0_STRIDE 264
#define BS1_STRIDE 20
#define BS_ST     (256*BS1_STRIDE)     // 5120 words (>= 16*264=4224)
#define NSTAGE 3
#define SMEM_TC_BYTES (NSTAGE*(AS_ST + BS_ST)*4)   // 92160

template<int TB, int EPI>
__global__ void __launch_bounds__(512,1) gemm_tc_kernel(
    int Ki,
    const float* __restrict__ A, int lda, long long sA,
    const float* __restrict__ Bm, int ldb, long long sB,
    float* __restrict__ C, int ldc, long long sC,
    float alpha, const float* __restrict__ bias,
    float* __restrict__ C2, float* __restrict__ C3)
{
    extern __shared__ unsigned sm[];
    unsigned* As = sm;
    unsigned* Bs = sm + NSTAGE*AS_ST;
    const unsigned As_base = (unsigned)__cvta_generic_to_shared(As);
    const unsigned Bs_base = (unsigned)__cvta_generic_to_shared(Bs);

    const int bz = blockIdx.z;
    A  += (long long)bz*sA;
    Bm += (long long)bz*sB;
    C  += (long long)bz*sC;
    if (EPI==6) C2 += (long long)bz*sC;

    const int row0 = blockIdx.y*128;
    const int col0 = blockIdx.x*256;
    const int tid = threadIdx.x;
    const int warp = tid>>5, lane = tid&31;
    const int wm = warp & 1, wn = warp >> 1;   // 2x8 warp grid, warp tile 64x32
    const int g = lane>>2, qc = lane&3;

    // staging maps: A 512 float4 -> 1/thread; B 1024 float4 -> 2/thread
    const int a_r  = tid>>2;
    const int a_c4 = (tid&3)<<2;

    auto issue = [&](int kt, int st){
        unsigned abase = As_base + (unsigned)(st*AS_ST)*4u;
        cp16(abase + (unsigned)(a_r*AS_STRIDE + a_c4)*4u,
             A + (long long)(row0 + a_r)*lda + kt + a_c4);
        unsigned bbase = Bs_base + (unsigned)(st*BS_ST)*4u;
        if (TB==0){
            #pragma unroll
            for (int i=0;i<2;i++){
                int fidx = tid + i*512;
                int bk = fidx>>6, bn4 = (fidx&63)<<2;
                cp16(bbase + (unsigned)(bk*BS0_STRIDE + bn4)*4u,
                     Bm + (long long)(kt + bk)*ldb + col0 + bn4);
            }
        } else {
            #pragma unroll
            for (int i=0;i<2;i++){
                int fidx = tid + i*512;
                int bn = fidx>>2, bc4 = (fidx&3)<<2;
                cp16(bbase + (unsigned)(bn*BS1_STRIDE + bc4)*4u,
                     Bm + (long long)(col0 + bn)*ldb + kt + bc4);
            }
        }
    };

    float acc[4][4][4];
    #pragma unroll
    for (int mt=0;mt<4;mt++)
        #pragma unroll
        for (int nt=0;nt<4;nt++)
            #pragma unroll
            for (int i=0;i<4;i++) acc[mt][nt][i]=0.f;

    const int nk = Ki >> 4;
    issue(0, 0);  cp_commit();
    issue(16, 1); cp_commit();

    const int a_frag_off  = (wm*64 + g)*AS_STRIDE + qc;
    const int b0_frag_off = qc*BS0_STRIDE + wn*32 + g;
    const int b1_frag_off = (wn*32 + g)*BS1_STRIDE + qc;

    for (int t = 0; t < nk; ++t){
        cp_wait<1>();
        __syncthreads();
        const int rb = t % NSTAGE;
        if (t+2 < nk) issue((t+2)<<4, (t+2)%NSTAGE);
        cp_commit();

        #pragma unroll
        for (int grp=0; grp<2; grp++){
            const int koff = grp*8;
            unsigned af[4][4], bf[4][2];
            const unsigned* Ab = As + rb*AS_ST + a_frag_off + koff;
            #pragma unroll
            for (int mt=0;mt<4;mt++){
                const unsigned* p = Ab + (mt*16)*AS_STRIDE;
                af[mt][0] = p[0];
                af[mt][1] = p[8*AS_STRIDE];
                af[mt][2] = p[4];
                af[mt][3] = p[8*AS_STRIDE+4];
            }
            if (TB==0){
                const unsigned* Bb = Bs + rb*BS_ST + b0_frag_off + koff*BS0_STRIDE;
                #pragma unroll
                for (int nt=0;nt<4;nt++){
                    bf[nt][0] = Bb[nt*8];
                    bf[nt][1] = Bb[4*BS0_STRIDE + nt*8];
                }
            } else {
                const unsigned* Bb = Bs + rb*BS_ST + b1_frag_off + koff;
                #pragma unroll
                for (int nt=0;nt<4;nt++){
                    bf[nt][0] = Bb[nt*8*BS1_STRIDE];
                    bf[nt][1] = Bb[nt*8*BS1_STRIDE + 4];
                }
            }
            #pragma unroll
            for (int mt=0;mt<4;mt++)
                #pragma unroll
                for (int nt=0;nt<4;nt++)
                    mma_tf32(acc[mt][nt], af[mt][0],af[mt][1],af[mt][2],af[mt][3],
                             bf[nt][0],bf[nt][1]);
        }
    }

    // epilogue
    #pragma unroll
    for (int mt=0;mt<4;mt++){
        int r = row0 + wm*64 + mt*16 + g;
        #pragma unroll
        for (int nt=0;nt<4;nt++){
            int cc = col0 + wn*32 + nt*8 + 2*qc;
            store2<EPI>(C, C2, C3, ldc, r,   cc, acc[mt][nt][0], acc[mt][nt][1], alpha, bias);
            store2<EPI>(C, C2, C3, ldc, r+8, cc, acc[mt][nt][2], acc[mt][nt][3], alpha, bias);
        }
    }
}

// ---------------- generic 64x64 tiled SIMT GEMM (small-N fallback) --------
template<int TB, int EPI>
__global__ void __launch_bounds__(256) gemm_kernel(
    int Ki,
    const float* __restrict__ A, int lda, long long sA,
    const float* __restrict__ Bm, int ldb, long long sB,
    float* __restrict__ C, int ldc, long long sC,
    float alpha, const float* __restrict__ bias)
{
    const int bz = blockIdx.z;
    A  += (long long)bz * sA;
    Bm += (long long)bz * sB;
    C  += (long long)bz * sC;
    const int row0 = blockIdx.y * 64;
    const int col0 = blockIdx.x * 64;
    __shared__ float As[16][68];
    __shared__ float Bs[16][68];
    const int tid = threadIdx.x;
    const int ty = tid >> 4, tx = tid & 15;
    const int ar = tid >> 2, akq = (tid & 3) << 2;

    float acc[4][4];
    #pragma unroll
    for (int i=0;i<4;i++)
        #pragma unroll
        for (int j=0;j<4;j++) acc[i][j]=0.f;

    for (int k0 = 0; k0 < Ki; k0 += 16) {
        float4 av = *(const float4*)(A + (long long)(row0+ar)*lda + k0 + akq);
        As[akq+0][ar]=av.x; As[akq+1][ar]=av.y; As[akq+2][ar]=av.z; As[akq+3][ar]=av.w;
        if (TB==0) {
            int bkk = tid >> 4, bc = (tid & 15) << 2;
            float4 bv = *(const float4*)(Bm + (long long)(k0+bkk)*ldb + col0 + bc);
            Bs[bkk][bc+0]=bv.x; Bs[bkk][bc+1]=bv.y; Bs[bkk][bc+2]=bv.z; Bs[bkk][bc+3]=bv.w;
        } else {
            int bc = tid >> 2, bkq = (tid & 3) << 2;
            float4 bv = *(const float4*)(Bm + (long long)(col0+bc)*ldb + k0 + bkq);
            Bs[bkq+0][bc]=bv.x; Bs[bkq+1][bc]=bv.y; Bs[bkq+2][bc]=bv.z; Bs[bkq+3][bc]=bv.w;
        }
        __syncthreads();
        #pragma unroll
        for (int kk=0;kk<16;kk++){
            float a[4], b[4];
            #pragma unroll
            for (int i=0;i<4;i++) a[i]=As[kk][ty+16*i];
            #pragma unroll
            for (int j=0;j<4;j++) b[j]=Bs[kk][tx+16*j];
            #pragma unroll
            for (int i=0;i<4;i++)
                #pragma unroll
                for (int j=0;j<4;j++)
                    acc[i][j] = fmaf(a[i], b[j], acc[i][j]);
        }
        __syncthreads();
    }

    #pragma unroll
    for (int i=0;i<4;i++){
        int r = row0 + ty + 16*i;
        #pragma unroll
        for (int j=0;j<4;j++){
            int c = col0 + tx + 16*j;
            float val = alpha * acc[i][j];
            if (EPI==0) {
                C[(long long)r*ldc + c] = val;
            } else if (EPI==2) {
                float xg = val + bias[c];
                C[(long long)r*ldc + c] = 0.5f*xg*(1.f+erff(xg*0.70710678118654752f));
            } else if (EPI==3) {
                C[(long long)r*ldc + c] += val + bias[c];
            } else if (EPI==4) {
                int bb = r / NPAD, nl = r % NPAD;
                if (nl >= PADL)
                    C[((long long)bb*LSEQ + (nl-PADL))*ldc + c] += val + bias[c];
            }
        }
    }
}

// ---------------- elementwise / small kernels ----------------
__global__ void embed_kernel(const int* __restrict__ x,
                             const float* __restrict__ emb,
                             const float* __restrict__ pos){
    long long idx = (long long)blockIdx.x*blockDim.x + threadIdx.x;
    if (idx >= (long long)BATCH*LSEQ*DMODEL) return;
    int d = (int)(idx % DMODEL);
    long long bl = idx / DMODEL;
    int l = (int)(bl % LSEQ);
    int tok = x[bl];
    g_h[idx] = emb[(long long)tok*DMODEL + d] + pos[(long long)l*DMODEL + d];
}

__global__ void zero_pad_kernel(){
    int idx = blockIdx.x*blockDim.x + threadIdx.x;
    if (idx >= BATCH*PADL*DMODEL) return;
    int d  = idx % DMODEL;
    int bp = idx / DMODEL;
    int b  = bp / PADL, p = bp % PADL;
    g_x[((long long)b*NPAD + p)*DMODEL + d] = 0.f;
}

__global__ void ln_kernel(const float* __restrict__ in, float* __restrict__ out,
                          const float* __restrict__ gm, const float* __restrict__ bt,
                          int padmode){
    __shared__ float sh[8];
    int r = blockIdx.x;
    int t = threadIdx.x;
    const float* p = in + (long long)r*DMODEL;
    float a  = p[t];
    float b2 = p[t+256];
    float s  = blockSumN(a+b2, sh, 8);
    float mu = s * (1.f/512.f);
    float da = a - mu, db = b2 - mu;
    float v  = blockSumN(da*da + db*db, sh, 8) * (1.f/512.f);
    float rstd = rsqrtf(v + 1e-5f);
    long long orow = padmode ? ((long long)(r/LSEQ)*NPAD + PADL + (r%LSEQ)) : (long long)r;
    float* q = out + orow*DMODEL;
    q[t]     = da*rstd*gm[t]     + bt[t];
    q[t+256] = db*rstd*gm[t+256] + bt[t+256];
}

__global__ void landmark_kernel(){
    long long idx = (long long)blockIdx.x*blockDim.x + threadIdx.x;
    if (idx >= (long long)BH*ML*DHD) return;
    int d = (int)(idx & 63);
    long long r = idx >> 6;
    int m  = (int)(r % ML);
    int bh = (int)(r / ML);
    long long base = ((long long)bh*NPAD + (long long)m*LMR)*DHD + d;
    float sq = 0.f, sk = 0.f;
    #pragma unroll
    for (int j=0;j<LMR;j++){ sq += g_q[base + (long long)j*DHD]; sk += g_k[base + (long long)j*DHD]; }
    g_ql[idx] = sq * 0.25f;
    g_kl[idx] = sk * 0.25f;
}

__global__ void softmax_kernel(float* __restrict__ X, int cols){
    __shared__ float sh[4];
    long long row = blockIdx.x;
    float* p = X + row*(long long)cols;
    int t = threadIdx.x;
    int cnt = cols >> 7;
    float v[8];
    float mx = -3.4e38f;
    #pragma unroll
    for (int i=0;i<8;i++) if (i<cnt){ v[i]=p[t + (i<<7)]; mx = fmaxf(mx, v[i]); }
    mx = blockMaxN(mx, sh, 4);
    float s = 0.f;
    #pragma unroll
    for (int i=0;i<8;i++) if (i<cnt){ v[i]=expf(v[i]-mx); s += v[i]; }
    s = blockSumN(s, sh, 4);
    float inv = 1.f/s;
    #pragma unroll
    for (int i=0;i<8;i++) if (i<cnt) p[t + (i<<7)] = v[i]*inv;
}

__global__ void red_init_kernel(){ g_red[0]=0; g_red[1]=0; }

__global__ void colsum_kernel(){
    int idx = blockIdx.x*blockDim.x + threadIdx.x;
    if (idx >= BH*ML) return;
    int c  = idx % ML;
    int bz = idx / ML;
    const float* p = g_a2 + (long long)bz*ML*ML + c;
    float s = 0.f;
    for (int r2=0;r2<ML;r2++) s += fabsf(p[(long long)r2*ML]);
    atomicMax(&g_red[0], __float_as_int(s));
}
__global__ void rowsum_kernel(){
    int idx = blockIdx.x*blockDim.x + threadIdx.x;
    if (idx >= BH*ML) return;
    int r2 = idx % ML;
    int bz = idx / ML;
    const float* p = g_a2 + (long long)bz*ML*ML + (long long)r2*ML;
    float s = 0.f;
    for (int c=0;c<ML;c++) s += fabsf(p[c]);
    atomicMax(&g_red[1], __float_as_int(s));
}
__global__ void zinit_kernel(){
    long long idx = (long long)blockIdx.x*blockDim.x + threadIdx.x;
    if (idx >= (long long)BH*ML*ML) return;
    int j = (int)(idx % ML);
    long long r = idx / ML;
    int i  = (int)(r % ML);
    int bz = (int)(r / ML);
    float c = __int_as_float(g_red[0]) * __int_as_float(g_red[1]);
    g_zb[idx] = g_a2[((long long)bz*ML + j)*ML + i] / c;
}

__global__ void combine_kernel(const float* __restrict__ cw){
    long long idx = (long long)blockIdx.x*blockDim.x + threadIdx.x;
    if (idx >= (long long)BH*NPAD*DHD) return;
    int d = (int)(idx & 63);
    long long r = idx >> 6;
    int n  = (int)(r % NPAD);
    int bh = (int)(r / NPAD);
    int h  = bh % NH, b = bh / NH;
    float s = g_ao[idx];
    const float* w  = cw + h*KC;
    const float* vp = g_v + ((long long)bh*NPAD)*DHD + d;
    int k0 = (16-n > 0) ? (16-n) : 0;
    int k1 = (NPAD+16-n < KC) ? (NPAD+16-n) : KC;
    for (int kk=k0; kk<k1; kk++)
        s = fmaf(vp[(long long)(n+kk-16)*DHD], w[kk], s);
    g_y[((long long)b*NPAD + n)*DMODEL + h*DHD + d] = s;
}

__global__ void final_kernel(const float* __restrict__ fw,
                             const float* __restrict__ fb,
                             float* __restrict__ out){
    __shared__ float sh[8];
    int b = blockIdx.x;
    int t = threadIdx.x;
    const float* hp = g_h + (long long)b*LSEQ*DMODEL;
    float s = 0.f;
    for (long long i=t; i<(long long)LSEQ*DMODEL; i+=256)
        s = fmaf(hp[i], fw[i], s);
    s = blockSumN(s, sh, 8);
    if (t==0) out[b] = s + fb[0];
}

// ---------------- host-side GEMM dispatch ----------------
static void run_gemm(int tb, int epi, int Mi, int Ni, int Ki,
                     const float* A, int lda, long long sA,
                     const float* Bm, int ldb, long long sB,
                     float* C, int ldc, long long sC,
                     int batch, float alpha, const float* bias,
                     float* C2 = nullptr, float* C3 = nullptr)
{
    if ((Mi % 128) == 0 && (Ni % 256) == 0 && (Ki % 16) == 0) {
        dim3 g(Ni/256, Mi/128, batch), t(512);
        size_t sh = SMEM_TC_BYTES;
        if (tb == 0) {
            switch (epi) {
                case 0: gemm_tc_kernel<0,0><<<g,t,sh>>>(Ki,A,lda,sA,Bm,ldb,sB,C,ldc,sC,alpha,bias,C2,C3); break;
                case 2: gemm_tc_kernel<0,2><<<g,t,sh>>>(Ki,A,lda,sA,Bm,ldb,sB,C,ldc,sC,alpha,bias,C2,C3); break;
                case 3: gemm_tc_kernel<0,3><<<g,t,sh>>>(Ki,A,lda,sA,Bm,ldb,sB,C,ldc,sC,alpha,bias,C2,C3); break;
                case 4: gemm_tc_kernel<0,4><<<g,t,sh>>>(Ki,A,lda,sA,Bm,ldb,sB,C,ldc,sC,alpha,bias,C2,C3); break;
                case 5: gemm_tc_kernel<0,5><<<g,t,sh>>>(Ki,A,lda,sA,Bm,ldb,sB,C,ldc,sC,alpha,bias,C2,C3); break;
                case 6: gemm_tc_kernel<0,6><<<g,t,sh>>>(Ki,A,lda,sA,Bm,ldb,sB,C,ldc,sC,alpha,bias,C2,C3); break;
                case 7: gemm_tc_kernel<0,7><<<g,t,sh>>>(Ki,A,lda,sA,Bm,ldb,sB,C,ldc,sC,alpha,bias,C2,C3); break;
            }
        } else {
            gemm_tc_kernel<1,0><<<g,t,sh>>>(Ki,A,lda,sA,Bm,ldb,sB,C,ldc,sC,alpha,bias,C2,C3);
        }
        return;
    }
    dim3 g(Ni/64, Mi/64, batch), t(256);
    if (tb==0){
        if      (epi==0) gemm_kernel<0,0><<<g,t>>>(Ki,A,lda,sA,Bm,ldb,sB,C,ldc,sC,alpha,bias);
        else if (epi==2) gemm_kernel<0,2><<<g,t>>>(Ki,A,lda,sA,Bm,ldb,sB,C,ldc,sC,alpha,bias);
        else if (epi==3) gemm_kernel<0,3><<<g,t>>>(Ki,A,lda,sA,Bm,ldb,sB,C,ldc,sC,alpha,bias);
        else             gemm_kernel<0,4><<<g,t>>>(Ki,A,lda,sA,Bm,ldb,sB,C,ldc,sC,alpha,bias);
    } else {
        gemm_kernel<1,0><<<g,t>>>(Ki,A,lda,sA,Bm,ldb,sB,C,ldc,sC,alpha,bias);
    }
}

static void setup_tc_attrs(){
    cudaFuncSetAttribute(gemm_tc_kernel<0,0>, cudaFuncAttributeMaxDynamicSharedMemorySize, SMEM_TC_BYTES);
    cudaFuncSetAttribute(gemm_tc_kernel<0,2>, cudaFuncAttributeMaxDynamicSharedMemorySize, SMEM_TC_BYTES);
    cudaFuncSetAttribute(gemm_tc_kernel<0,3>, cudaFuncAttributeMaxDynamicSharedMemorySize, SMEM_TC_BYTES);
    cudaFuncSetAttribute(gemm_tc_kernel<0,4>, cudaFuncAttributeMaxDynamicSharedMemorySize, SMEM_TC_BYTES);
    cudaFuncSetAttribute(gemm_tc_kernel<0,5>, cudaFuncAttributeMaxDynamicSharedMemorySize, SMEM_TC_BYTES);
    cudaFuncSetAttribute(gemm_tc_kernel<0,6>, cudaFuncAttributeMaxDynamicSharedMemorySize, SMEM_TC_BYTES);
    cudaFuncSetAttribute(gemm_tc_kernel<0,7>, cudaFuncAttributeMaxDynamicSharedMemorySize, SMEM_TC_BYTES);
    cudaFuncSetAttribute(gemm_tc_kernel<1,0>, cudaFuncAttributeMaxDynamicSharedMemorySize, SMEM_TC_BYTES);
}

extern "C" void kernel_launch(void* const* d_in, const int* in_sizes, int n_in,
                              void* d_out, int out_size)
{
    (void)in_sizes; (void)n_in; (void)out_size;
    const int*   x       = (const int*)  d_in[0];
    const float* enc_emb = (const float*)d_in[1];
    const float* pos_emb = (const float*)d_in[2];
    const float* ln1_s   = (const float*)d_in[3];
    const float* ln1_b   = (const float*)d_in[4];
    const float* qkv_w   = (const float*)d_in[5];
    const float* aout_w  = (const float*)d_in[6];
    const float* aout_b  = (const float*)d_in[7];
    const float* conv_k  = (const float*)d_in[8];
    const float* ln2_s   = (const float*)d_in[9];
    const float* ln2_b   = (const float*)d_in[10];
    const float* ff_w1   = (const float*)d_in[11];
    const float* ff_b1   = (const float*)d_in[12];
    const float* ff_w2   = (const float*)d_in[13];
    const float* ff_b2   = (const float*)d_in[14];
    const float* fin_w   = (const float*)d_in[15];
    const float* fin_b   = (const float*)d_in[16];
    float* out = (float*)d_out;

    setup_tc_attrs();

    float *p_h,*p_x,*p_q,*p_k,*p_v,*p_ql,*p_kl,*p_a1,*p_a3,*p_a2;
    float *p_z,*p_z2,*p_p,*p_t,*p_t2,*p_kv,*p_a1z,*p_ao,*p_y,*p_x2,*p_ff;
    cudaGetSymbolAddress((void**)&p_h,  g_h);
    cudaGetSymbolAddress((void**)&p_x,  g_x);
    cudaGetSymbolAddress((void**)&p_q,  g_q);
    cudaGetSymbolAddress((void**)&p_k,  g_k);
    cudaGetSymbolAddress((void**)&p_v,  g_v);
    cudaGetSymbolAddress((void**)&p_ql, g_ql);
    cudaGetSymbolAddress((void**)&p_kl, g_kl);
    cudaGetSymbolAddress((void**)&p_a1, g_a1);
    cudaGetSymbolAddress((void**)&p_a3, g_a3);
    cudaGetSymbolAddress((void**)&p_a2, g_a2);
    cudaGetSymbolAddress((void**)&p_z,  g_zb);
    cudaGetSymbolAddress((void**)&p_z2, g_zb2);
    cudaGetSymbolAddress((void**)&p_p,  g_pb);
    cudaGetSymbolAddress((void**)&p_t,  g_tb);
    cudaGetSymbolAddress((void**)&p_t2, g_tb2);
    cudaGetSymbolAddress((void**)&p_kv, g_kvb);
    cudaGetSymbolAddress((void**)&p_a1z,g_a1z);
    cudaGetSymbolAddress((void**)&p_ao, g_ao);
    cudaGetSymbolAddress((void**)&p_y,  g_y);
    cudaGetSymbolAddress((void**)&p_x2, g_x2);
    cudaGetSymbolAddress((void**)&p_ff, g_ff);

    const long long MM  = (long long)ML*ML;
    const long long NM  = (long long)NPAD*ML;
    const long long ND  = (long long)NPAD*DHD;
    const long long MD  = (long long)ML*DHD;

    {
        long long tot = (long long)BATCH*LSEQ*DMODEL;
        embed_kernel<<<(unsigned)((tot+255)/256),256>>>(x, enc_emb, pos_emb);
        int tot2 = BATCH*PADL*DMODEL;
        zero_pad_kernel<<<(tot2+255)/256,256>>>();
    }

    for (int lay=0; lay<DEPTH; lay++){
        ln_kernel<<<BATCH*LSEQ,256>>>(p_h, p_x, ln1_s+(long long)lay*DMODEL, ln1_b+(long long)lay*DMODEL, 1);
        // QKV [tensor, fused split into q/k/v]
        run_gemm(0,7, BATCH*NPAD, 3*DMODEL, DMODEL,
                 p_x, DMODEL, 0,
                 qkv_w + (long long)lay*DMODEL*3*DMODEL, 3*DMODEL, 0,
                 p_q, 3*DMODEL, 0, 1, 1.f, nullptr, p_k, p_v);
        {
            long long tot2 = (long long)BH*ML*DHD;
            landmark_kernel<<<(unsigned)((tot2+255)/256),256>>>();
        }
        // attn1 = softmax(q @ kl^T)  [tensor TB=1]
        run_gemm(1,0, NPAD, ML, DHD, p_q, DHD, ND, p_kl, DHD, MD, p_a1, ML, NM, BH, 1.f, nullptr);
        softmax_kernel<<<BH*NPAD,128>>>(p_a1, ML);
        // attn2 = softmax(ql @ kl^T)  [tensor TB=1]
        run_gemm(1,0, ML, ML, DHD, p_ql, DHD, MD, p_kl, DHD, MD, p_a2, ML, MM, BH, 1.f, nullptr);
        softmax_kernel<<<BH*ML,128>>>(p_a2, ML);
        // attn3 = softmax(ql @ k^T)  [tensor TB=1]
        run_gemm(1,0, ML, NPAD, DHD, p_ql, DHD, MD, p_k, DHD, ND, p_a3, NPAD, (long long)ML*NPAD, BH, 1.f, nullptr);
        softmax_kernel<<<BH*ML,128>>>(p_a3, NPAD);

        // ---- pinv (tensor, fused aI-X epilogues) ----
        red_init_kernel<<<1,1>>>();
        colsum_kernel<<<(BH*ML+255)/256,256>>>();
        rowsum_kernel<<<(BH*ML+255)/256,256>>>();
        {
            long long tot = (long long)BH*ML*ML;
            unsigned g = (unsigned)((tot+255)/256);
            zinit_kernel<<<g,256>>>();
        }
        float* zc = p_z; float* zn = p_z2;
        for (int it=0; it<6; it++){
            run_gemm(0,6, ML, ML, ML, p_a2, ML, MM, zc, ML, MM, p_p, ML, MM, BH, 7.f, nullptr, p_t);
            run_gemm(0,5, ML, ML, ML, p_p, ML, MM, p_t, ML, MM, p_t2, ML, MM, BH, 15.f, nullptr);
            run_gemm(0,5, ML, ML, ML, p_p, ML, MM, p_t2, ML, MM, p_t, ML, MM, BH, 13.f, nullptr);
            run_gemm(0,0, ML, ML, ML, zc, ML, MM, p_t, ML, MM, zn, ML, MM, BH, 0.25f, nullptr);
            float* tmp = zc; zc = zn; zn = tmp;
        }

        // kv = attn3 @ v  [SIMT N=64]
        run_gemm(0,0, ML, DHD, NPAD, p_a3, NPAD, (long long)ML*NPAD, p_v, DHD, ND, p_kv, DHD, MD, BH, 1.f, nullptr);
        // a1z = attn1 @ Z  [tensor]
        run_gemm(0,0, NPAD, ML, ML, p_a1, ML, NM, zc, ML, MM, p_a1z, ML, NM, BH, 1.f, nullptr);
        // ao = a1z @ kv  [SIMT N=64]
        run_gemm(0,0, NPAD, DHD, ML, p_a1z, ML, NM, p_kv, DHD, MD, p_ao, DHD, ND, BH, 1.f, nullptr);
        {
            long long tot = (long long)BH*NPAD*DHD;
            combine_kernel<<<(unsigned)((tot+255)/256),256>>>(conv_k + (long long)lay*NH*KC);
        }
        // out projection + residual [tensor]
        run_gemm(0,4, BATCH*NPAD, DMODEL, DMODEL,
                 p_y, DMODEL, 0,
                 aout_w + (long long)lay*DMODEL*DMODEL, DMODEL, 0,
                 p_h, DMODEL, 0, 1, 1.f, aout_b + (long long)lay*DMODEL);

        // ---- FFN ----
        ln_kernel<<<BATCH*LSEQ,256>>>(p_h, p_x2, ln2_s+(long long)lay*DMODEL, ln2_b+(long long)lay*DMODEL, 0);
        run_gemm(0,2, BATCH*LSEQ, FFD, DMODEL,
                 p_x2, DMODEL, 0,
                 ff_w1 + (long long)lay*DMODEL*FFD, FFD, 0,
                 p_ff, FFD, 0, 1, 1.f, ff_b1 + (long long)lay*FFD);
        run_gemm(0,3, BATCH*LSEQ, DMODEL, FFD,
                 p_ff, FFD, 0,
                 ff_w2 + (long long)lay*FFD*DMODEL, DMODEL, 0,
                 p_h, DMODEL, 0, 1, 1.f, ff_b2 + (long long)lay*DMODEL);
    }

    final_kernel<<<BATCH,256>>>(fin_w, fin_b, out);
}

// round 8
// speedup vs baseline: 1.0843x; 1.0033x over previous
#include <cuda_runtime.h>
#include <math.h>
#include <stdint.h>

// ---------------- model constants ----------------
#define BATCH 16
#define LSEQ  1000
#define DMODEL 512
#define NH    8
#define DHD   64
#define NPAD  1024
#define PADL  24
#define ML    256
#define LMR   4
#define FFD   2048
#define DEPTH 6
#define KC    33
#define QSCALE 0.125f
#define BH (BATCH*NH)

// ---------------- scratch ----------------
__device__ float g_h   [BATCH*LSEQ*DMODEL];
__device__ float g_x   [BATCH*NPAD*DMODEL];
__device__ float g_q   [BH*NPAD*DHD];
__device__ float g_k   [BH*NPAD*DHD];
__device__ float g_v   [BH*NPAD*DHD];
__device__ float g_ql  [BH*ML*DHD];
__device__ float g_kl  [BH*ML*DHD];
__device__ float g_a1  [BH*NPAD*ML];
__device__ float g_a3  [BH*ML*NPAD];
__device__ float g_a2  [BH*ML*ML];
__device__ float g_zb  [BH*ML*ML];
__device__ float g_zb2 [BH*ML*ML];
__device__ float g_pb  [BH*ML*ML];
__device__ float g_tb  [BH*ML*ML];
__device__ float g_tb2 [BH*ML*ML];
__device__ float g_kvb [BH*ML*DHD];
__device__ float g_a1z [BH*NPAD*ML];
__device__ float g_ao  [BH*NPAD*DHD];
__device__ float g_y   [BATCH*NPAD*DMODEL];
__device__ float g_x2  [BATCH*LSEQ*DMODEL];
__device__ float g_ff  [BATCH*LSEQ*FFD];
__device__ int   g_red [2];

// ---------------- reductions ----------------
__device__ __forceinline__ float warpSum(float v){
    #pragma unroll
    for (int o=16;o;o>>=1) v += __shfl_xor_sync(0xffffffffu, v, o);
    return v;
}
__device__ __forceinline__ float warpMax(float v){
    #pragma unroll
    for (int o=16;o;o>>=1) v = fmaxf(v, __shfl_xor_sync(0xffffffffu, v, o));
    return v;
}
__device__ __forceinline__ float blockSumN(float v, float* sh, int nw){
    int w = threadIdx.x>>5, l = threadIdx.x&31;
    v = warpSum(v);
    if (l==0) sh[w] = v;
    __syncthreads();
    if (w==0){
        float x = (l < nw) ? sh[l] : 0.f;
        x = warpSum(x);
        if (l==0) sh[0] = x;
    }
    __syncthreads();
    float r = sh[0];
    __syncthreads();
    return r;
}
__device__ __forceinline__ float blockMaxN(float v, float* sh, int nw){
    int w = threadIdx.x>>5, l = threadIdx.x&31;
    v = warpMax(v);
    if (l==0) sh[w] = v;
    __syncthreads();
    if (w==0){
        float x = (l < nw) ? sh[l] : -3.4e38f;
        x = warpMax(x);
        if (l==0) sh[0] = x;
    }
    __syncthreads();
    float r = sh[0];
    __syncthreads();
    return r;
}

// ---------------- mma / cp.async / ldmatrix helpers ----------------
__device__ __forceinline__ void mma_tf32(float c[4],
    unsigned a0, unsigned a1, unsigned a2, unsigned a3,
    unsigned b0, unsigned b1)
{
    asm volatile(
        "mma.sync.aligned.m16n8k8.row.col.f32.tf32.tf32.f32 "
        "{%0,%1,%2,%3}, {%4,%5,%6,%7}, {%8,%9}, {%0,%1,%2,%3};"
        : "+f"(c[0]), "+f"(c[1]), "+f"(c[2]), "+f"(c[3])
        : "r"(a0), "r"(a1), "r"(a2), "r"(a3), "r"(b0), "r"(b1));
}
__device__ __forceinline__ void cp16(unsigned saddr, const void* gptr){
    asm volatile("cp.async.cg.shared.global [%0], [%1], 16;\n"
                 :: "r"(saddr), "l"(gptr));
}
__device__ __forceinline__ void cp_commit(){
    asm volatile("cp.async.commit_group;\n");
}
template<int N>
__device__ __forceinline__ void cp_wait(){
    asm volatile("cp.async.wait_group %0;\n" :: "n"(N));
}
__device__ __forceinline__ void ldsm4(unsigned &r0, unsigned &r1,
                                      unsigned &r2, unsigned &r3,
                                      unsigned addr){
    asm volatile("ldmatrix.sync.aligned.m8n8.x4.shared.b16 {%0,%1,%2,%3}, [%4];"
        : "=r"(r0), "=r"(r1), "=r"(r2), "=r"(r3) : "r"(addr));
}

// epilogue: writes 2 consecutive cols at (r, cc)
// EPI 0: C = alpha*val         EPI 2: C = gelu(val+bias)
// EPI 3: C += val+bias         EPI 4: pad-sliced residual add into h
// EPI 5: C = alpha*I - val     EPI 6: C = val ; C2 = alpha*I - val
// EPI 7: fused qkv split: C=q(*QSCALE), C2=k, C3=v in (b,h,n,d) layout
template<int EPI>
__device__ __forceinline__ void store2(
    float* __restrict__ C, float* __restrict__ C2, float* __restrict__ C3,
    int ldc, int r, int cc, float v0, float v1,
    float alpha, const float* __restrict__ bias)
{
    if (EPI==0){
        float2 o = {alpha*v0, alpha*v1};
        *(float2*)&C[(long long)r*ldc + cc] = o;
    } else if (EPI==2){
        float x0 = v0 + bias[cc], x1 = v1 + bias[cc+1];
        float2 o;
        o.x = 0.5f*x0*(1.f+erff(x0*0.70710678118654752f));
        o.y = 0.5f*x1*(1.f+erff(x1*0.70710678118654752f));
        *(float2*)&C[(long long)r*ldc + cc] = o;
    } else if (EPI==3){
        float2 o = *(float2*)&C[(long long)r*ldc + cc];
        o.x += v0 + bias[cc];
        o.y += v1 + bias[cc+1];
        *(float2*)&C[(long long)r*ldc + cc] = o;
    } else if (EPI==4){
        int bb = r / NPAD, nl = r % NPAD;
        if (nl >= PADL){
            long long orow = (long long)bb*LSEQ + (nl - PADL);
            float2 o = *(float2*)&C[orow*ldc + cc];
            o.x += v0 + bias[cc];
            o.y += v1 + bias[cc+1];
            *(float2*)&C[orow*ldc + cc] = o;
        }
    } else if (EPI==5){
        float2 o = {(r==cc ? alpha : 0.f) - v0, (r==cc+1 ? alpha : 0.f) - v1};
        *(float2*)&C[(long long)r*ldc + cc] = o;
    } else if (EPI==6){
        float2 o = {v0, v1};
        *(float2*)&C[(long long)r*ldc + cc] = o;
        float2 o2 = {(r==cc ? alpha : 0.f) - v0, (r==cc+1 ? alpha : 0.f) - v1};
        *(float2*)&C2[(long long)r*ldc + cc] = o2;
    } else if (EPI==7){
        int b = r >> 10, n = r & 1023;
        int which = cc >> 9;
        int hd = cc & 511;
        long long idx = ((((long long)b*NH + (hd>>6))*NPAD) + n)*DHD + (hd&63);
        float2 o;
        if (which==0){ o.x = v0*QSCALE; o.y = v1*QSCALE; *(float2*)&C[idx] = o; }
        else if (which==1){ o.x = v0; o.y = v1; *(float2*)&C2[idx] = o; }
        else { o.x = v0; o.y = v1; *(float2*)&C3[idx] = o; }
    }
}

// == TF32 tensor GEMM v6: 512 thr, CTA 128x256, LDSM frags, 3-stage async ==
// TB=0: B is KxN rm.  TB=1: B is NxK rm (C = A @ B^T).
// Requires M%128==0, N%256==0, K%16==0.
#define AS_STRIDE 20
#define AS_ST     (128*AS_STRIDE)      // 2560 words
#define BS0_STRIDE 264
#define BS1_STRIDE 20
#define BS_ST     (256*BS1_STRIDE)     // 5120 words (>= 16*264=4224)
#define NSTAGE 3
#define SMEM_TC_BYTES (NSTAGE*(AS_ST + BS_ST)*4)   // 92160

template<int TB, int EPI>
__global__ void __launch_bounds__(512,1) gemm_tc_kernel(
    int Ki,
    const float* __restrict__ A, int lda, long long sA,
    const float* __restrict__ Bm, int ldb, long long sB,
    float* __restrict__ C, int ldc, long long sC,
    float alpha, const float* __restrict__ bias,
    float* __restrict__ C2, float* __restrict__ C3)
{
    extern __shared__ unsigned sm[];
    unsigned* As = sm;
    unsigned* Bs = sm + NSTAGE*AS_ST;
    const unsigned As_base = (unsigned)__cvta_generic_to_shared(As);
    const unsigned Bs_base = (unsigned)__cvta_generic_to_shared(Bs);

    const int bz = blockIdx.z;
    A  += (long long)bz*sA;
    Bm += (long long)bz*sB;
    C  += (long long)bz*sC;
    if (EPI==6) C2 += (long long)bz*sC;

    const int row0 = blockIdx.y*128;
    const int col0 = blockIdx.x*256;
    const int tid = threadIdx.x;
    const int warp = tid>>5, lane = tid&31;
    const int wm = warp & 1, wn = warp >> 1;   // 2x8 warp grid, warp tile 64x32
    const int g = lane>>2, qc = lane&3;

    // staging maps: A 512 float4 -> 1/thread; B 1024 float4 -> 2/thread
    const int a_r  = tid>>2;
    const int a_c4 = (tid&3)<<2;

    auto issue = [&](int kt, int st){
        unsigned abase = As_base + (unsigned)(st*AS_ST)*4u;
        cp16(abase + (unsigned)(a_r*AS_STRIDE + a_c4)*4u,
             A + (long long)(row0 + a_r)*lda + kt + a_c4);
        unsigned bbase = Bs_base + (unsigned)(st*BS_ST)*4u;
        if (TB==0){
            #pragma unroll
            for (int i=0;i<2;i++){
                int fidx = tid + i*512;
                int bk = fidx>>6, bn4 = (fidx&63)<<2;
                cp16(bbase + (unsigned)(bk*BS0_STRIDE + bn4)*4u,
                     Bm + (long long)(kt + bk)*ldb + col0 + bn4);
            }
        } else {
            #pragma unroll
            for (int i=0;i<2;i++){
                int fidx = tid + i*512;
                int bn = fidx>>2, bc4 = (fidx&3)<<2;
                cp16(bbase + (unsigned)(bn*BS1_STRIDE + bc4)*4u,
                     Bm + (long long)(col0 + bn)*ldb + kt + bc4);
            }
        }
    };

    float acc[4][4][4];
    #pragma unroll
    for (int mt=0;mt<4;mt++)
        #pragma unroll
        for (int nt=0;nt<4;nt++)
            #pragma unroll
            for (int i=0;i<4;i++) acc[mt][nt][i]=0.f;

    const int nk = Ki >> 4;
    issue(0, 0);  cp_commit();
    issue(16, 1); cp_commit();

    // ldmatrix per-thread invariants
    const int lane8 = lane & 7;
    const int a_lrow = wm*64 + lane8 + ((lane>>3)&1)*8;  // + mt*16
    const int a_lw   = ((lane>>4)&1)*4;                  // + koff
    const int b_lrow = wn*32 + lane8 + ((lane>>4)&1)*8;  // + np*16  (TB1)
    const int b_lw   = ((lane>>3)&1)*4;                  // + koff   (TB1)
    const int b0_frag_off = qc*BS0_STRIDE + wn*32 + g;   // TB0 scalar path

    for (int t = 0; t < nk; ++t){
        cp_wait<1>();
        __syncthreads();
        const int rb = t % NSTAGE;
        if (t+2 < nk) issue((t+2)<<4, (t+2)%NSTAGE);
        cp_commit();

        const unsigned a_stage = As_base + (unsigned)(rb*AS_ST)*4u;
        const unsigned b_stage = Bs_base + (unsigned)(rb*BS_ST)*4u;

        #pragma unroll
        for (int grp=0; grp<2; grp++){
            const int koff = grp*8;
            unsigned af[4][4], bf[4][2];
            #pragma unroll
            for (int mt=0;mt<4;mt++)
                ldsm4(af[mt][0], af[mt][1], af[mt][2], af[mt][3],
                      a_stage + (unsigned)(((a_lrow + mt*16)*AS_STRIDE) + a_lw + koff)*4u);
            if (TB==0){
                const unsigned* Bb = Bs + rb*BS_ST + b0_frag_off + koff*BS0_STRIDE;
                #pragma unroll
                for (int nt=0;nt<4;nt++){
                    bf[nt][0] = Bb[nt*8];
                    bf[nt][1] = Bb[4*BS0_STRIDE + nt*8];
                }
            } else {
                #pragma unroll
                for (int np=0;np<2;np++)
                    ldsm4(bf[2*np][0], bf[2*np][1], bf[2*np+1][0], bf[2*np+1][1],
                          b_stage + (unsigned)(((b_lrow + np*16)*BS1_STRIDE) + b_lw + koff)*4u);
            }
            #pragma unroll
            for (int mt=0;mt<4;mt++)
                #pragma unroll
                for (int nt=0;nt<4;nt++)
                    mma_tf32(acc[mt][nt], af[mt][0],af[mt][1],af[mt][2],af[mt][3],
                             bf[nt][0],bf[nt][1]);
        }
    }

    // epilogue
    #pragma unroll
    for (int mt=0;mt<4;mt++){
        int r = row0 + wm*64 + mt*16 + g;
        #pragma unroll
        for (int nt=0;nt<4;nt++){
            int cc = col0 + wn*32 + nt*8 + 2*qc;
            store2<EPI>(C, C2, C3, ldc, r,   cc, acc[mt][nt][0], acc[mt][nt][1], alpha, bias);
            store2<EPI>(C, C2, C3, ldc, r+8, cc, acc[mt][nt][2], acc[mt][nt][3], alpha, bias);
        }
    }
}

// ---------------- generic 64x64 tiled SIMT GEMM (small-N fallback) --------
template<int TB, int EPI>
__global__ void __launch_bounds__(256) gemm_kernel(
    int Ki,
    const float* __restrict__ A, int lda, long long sA,
    const float* __restrict__ Bm, int ldb, long long sB,
    float* __restrict__ C, int ldc, long long sC,
    float alpha, const float* __restrict__ bias)
{
    const int bz = blockIdx.z;
    A  += (long long)bz * sA;
    Bm += (long long)bz * sB;
    C  += (long long)bz * sC;
    const int row0 = blockIdx.y * 64;
    const int col0 = blockIdx.x * 64;
    __shared__ float As[16][68];
    __shared__ float Bs[16][68];
    const int tid = threadIdx.x;
    const int ty = tid >> 4, tx = tid & 15;
    const int ar = tid >> 2, akq = (tid & 3) << 2;

    float acc[4][4];
    #pragma unroll
    for (int i=0;i<4;i++)
        #pragma unroll
        for (int j=0;j<4;j++) acc[i][j]=0.f;

    for (int k0 = 0; k0 < Ki; k0 += 16) {
        float4 av = *(const float4*)(A + (long long)(row0+ar)*lda + k0 + akq);
        As[akq+0][ar]=av.x; As[akq+1][ar]=av.y; As[akq+2][ar]=av.z; As[akq+3][ar]=av.w;
        if (TB==0) {
            int bkk = tid >> 4, bc = (tid & 15) << 2;
            float4 bv = *(const float4*)(Bm + (long long)(k0+bkk)*ldb + col0 + bc);
            Bs[bkk][bc+0]=bv.x; Bs[bkk][bc+1]=bv.y; Bs[bkk][bc+2]=bv.z; Bs[bkk][bc+3]=bv.w;
        } else {
            int bc = tid >> 2, bkq = (tid & 3) << 2;
            float4 bv = *(const float4*)(Bm + (long long)(col0+bc)*ldb + k0 + bkq);
            Bs[bkq+0][bc]=bv.x; Bs[bkq+1][bc]=bv.y; Bs[bkq+2][bc]=bv.z; Bs[bkq+3][bc]=bv.w;
        }
        __syncthreads();
        #pragma unroll
        for (int kk=0;kk<16;kk++){
            float a[4], b[4];
            #pragma unroll
            for (int i=0;i<4;i++) a[i]=As[kk][ty+16*i];
            #pragma unroll
            for (int j=0;j<4;j++) b[j]=Bs[kk][tx+16*j];
            #pragma unroll
            for (int i=0;i<4;i++)
                #pragma unroll
                for (int j=0;j<4;j++)
                    acc[i][j] = fmaf(a[i], b[j], acc[i][j]);
        }
        __syncthreads();
    }

    #pragma unroll
    for (int i=0;i<4;i++){
        int r = row0 + ty + 16*i;
        #pragma unroll
        for (int j=0;j<4;j++){
            int c = col0 + tx + 16*j;
            float val = alpha * acc[i][j];
            if (EPI==0) {
                C[(long long)r*ldc + c] = val;
            } else if (EPI==2) {
                float xg = val + bias[c];
                C[(long long)r*ldc + c] = 0.5f*xg*(1.f+erff(xg*0.70710678118654752f));
            } else if (EPI==3) {
                C[(long long)r*ldc + c] += val + bias[c];
            } else if (EPI==4) {
                int bb = r / NPAD, nl = r % NPAD;
                if (nl >= PADL)
                    C[((long long)bb*LSEQ + (nl-PADL))*ldc + c] += val + bias[c];
            }
        }
    }
}

// ---------------- elementwise / small kernels ----------------
__global__ void embed_kernel(const int* __restrict__ x,
                             const float* __restrict__ emb,
                             const float* __restrict__ pos){
    long long idx = (long long)blockIdx.x*blockDim.x + threadIdx.x;
    if (idx >= (long long)BATCH*LSEQ*DMODEL) return;
    int d = (int)(idx % DMODEL);
    long long bl = idx / DMODEL;
    int l = (int)(bl % LSEQ);
    int tok = x[bl];
    g_h[idx] = emb[(long long)tok*DMODEL + d] + pos[(long long)l*DMODEL + d];
}

__global__ void zero_pad_kernel(){
    int idx = blockIdx.x*blockDim.x + threadIdx.x;
    if (idx >= BATCH*PADL*DMODEL) return;
    int d  = idx % DMODEL;
    int bp = idx / DMODEL;
    int b  = bp / PADL, p = bp % PADL;
    g_x[((long long)b*NPAD + p)*DMODEL + d] = 0.f;
}

__global__ void ln_kernel(const float* __restrict__ in, float* __restrict__ out,
                          const float* __restrict__ gm, const float* __restrict__ bt,
                          int padmode){
    __shared__ float sh[8];
    int r = blockIdx.x;
    int t = threadIdx.x;
    const float* p = in + (long long)r*DMODEL;
    float a  = p[t];
    float b2 = p[t+256];
    float s  = blockSumN(a+b2, sh, 8);
    float mu = s * (1.f/512.f);
    float da = a - mu, db = b2 - mu;
    float v  = blockSumN(da*da + db*db, sh, 8) * (1.f/512.f);
    float rstd = rsqrtf(v + 1e-5f);
    long long orow = padmode ? ((long long)(r/LSEQ)*NPAD + PADL + (r%LSEQ)) : (long long)r;
    float* q = out + orow*DMODEL;
    q[t]     = da*rstd*gm[t]     + bt[t];
    q[t+256] = db*rstd*gm[t+256] + bt[t+256];
}

__global__ void landmark_kernel(){
    long long idx = (long long)blockIdx.x*blockDim.x + threadIdx.x;
    if (idx >= (long long)BH*ML*DHD) return;
    int d = (int)(idx & 63);
    long long r = idx >> 6;
    int m  = (int)(r % ML);
    int bh = (int)(r / ML);
    long long base = ((long long)bh*NPAD + (long long)m*LMR)*DHD + d;
    float sq = 0.f, sk = 0.f;
    #pragma unroll
    for (int j=0;j<LMR;j++){ sq += g_q[base + (long long)j*DHD]; sk += g_k[base + (long long)j*DHD]; }
    g_ql[idx] = sq * 0.25f;
    g_kl[idx] = sk * 0.25f;
}

__global__ void softmax_kernel(float* __restrict__ X, int cols){
    __shared__ float sh[4];
    long long row = blockIdx.x;
    float* p = X + row*(long long)cols;
    int t = threadIdx.x;
    int cnt = cols >> 7;
    float v[8];
    float mx = -3.4e38f;
    #pragma unroll
    for (int i=0;i<8;i++) if (i<cnt){ v[i]=p[t + (i<<7)]; mx = fmaxf(mx, v[i]); }
    mx = blockMaxN(mx, sh, 4);
    float s = 0.f;
    #pragma unroll
    for (int i=0;i<8;i++) if (i<cnt){ v[i]=expf(v[i]-mx); s += v[i]; }
    s = blockSumN(s, sh, 4);
    float inv = 1.f/s;
    #pragma unroll
    for (int i=0;i<8;i++) if (i<cnt) p[t + (i<<7)] = v[i]*inv;
}

__global__ void red_init_kernel(){ g_red[0]=0; g_red[1]=0; }

__global__ void colsum_kernel(){
    int idx = blockIdx.x*blockDim.x + threadIdx.x;
    if (idx >= BH*ML) return;
    int c  = idx % ML;
    int bz = idx / ML;
    const float* p = g_a2 + (long long)bz*ML*ML + c;
    float s = 0.f;
    for (int r2=0;r2<ML;r2++) s += fabsf(p[(long long)r2*ML]);
    atomicMax(&g_red[0], __float_as_int(s));
}
__global__ void rowsum_kernel(){
    int idx = blockIdx.x*blockDim.x + threadIdx.x;
    if (idx >= BH*ML) return;
    int r2 = idx % ML;
    int bz = idx / ML;
    const float* p = g_a2 + (long long)bz*ML*ML + (long long)r2*ML;
    float s = 0.f;
    for (int c=0;c<ML;c++) s += fabsf(p[c]);
    atomicMax(&g_red[1], __float_as_int(s));
}
__global__ void zinit_kernel(){
    long long idx = (long long)blockIdx.x*blockDim.x + threadIdx.x;
    if (idx >= (long long)BH*ML*ML) return;
    int j = (int)(idx % ML);
    long long r = idx / ML;
    int i  = (int)(r % ML);
    int bz = (int)(r / ML);
    float c = __int_as_float(g_red[0]) * __int_as_float(g_red[1]);
    g_zb[idx] = g_a2[((long long)bz*ML + j)*ML + i] / c;
}

__global__ void combine_kernel(const float* __restrict__ cw){
    long long idx = (long long)blockIdx.x*blockDim.x + threadIdx.x;
    if (idx >= (long long)BH*NPAD*DHD) return;
    int d = (int)(idx & 63);
    long long r = idx >> 6;
    int n  = (int)(r % NPAD);
    int bh = (int)(r / NPAD);
    int h  = bh % NH, b = bh / NH;
    float s = g_ao[idx];
    const float* w  = cw + h*KC;
    const float* vp = g_v + ((long long)bh*NPAD)*DHD + d;
    int k0 = (16-n > 0) ? (16-n) : 0;
    int k1 = (NPAD+16-n < KC) ? (NPAD+16-n) : KC;
    for (int kk=k0; kk<k1; kk++)
        s = fmaf(vp[(long long)(n+kk-16)*DHD], w[kk], s);
    g_y[((long long)b*NPAD + n)*DMODEL + h*DHD + d] = s;
}

__global__ void final_kernel(const float* __restrict__ fw,
                             const float* __restrict__ fb,
                             float* __restrict__ out){
    __shared__ float sh[8];
    int b = blockIdx.x;
    int t = threadIdx.x;
    const float* hp = g_h + (long long)b*LSEQ*DMODEL;
    float s = 0.f;
    for (long long i=t; i<(long long)LSEQ*DMODEL; i+=256)
        s = fmaf(hp[i], fw[i], s);
    s = blockSumN(s, sh, 8);
    if (t==0) out[b] = s + fb[0];
}

// ---------------- host-side GEMM dispatch ----------------
static void run_gemm(int tb, int epi, int Mi, int Ni, int Ki,
                     const float* A, int lda, long long sA,
                     const float* Bm, int ldb, long long sB,
                     float* C, int ldc, long long sC,
                     int batch, float alpha, const float* bias,
                     float* C2 = nullptr, float* C3 = nullptr)
{
    if ((Mi % 128) == 0 && (Ni % 256) == 0 && (Ki % 16) == 0) {
        dim3 g(Ni/256, Mi/128, batch), t(512);
        size_t sh = SMEM_TC_BYTES;
        if (tb == 0) {
            switch (epi) {
                case 0: gemm_tc_kernel<0,0><<<g,t,sh>>>(Ki,A,lda,sA,Bm,ldb,sB,C,ldc,sC,alpha,bias,C2,C3); break;
                case 2: gemm_tc_kernel<0,2><<<g,t,sh>>>(Ki,A,lda,sA,Bm,ldb,sB,C,ldc,sC,alpha,bias,C2,C3); break;
                case 3: gemm_tc_kernel<0,3><<<g,t,sh>>>(Ki,A,lda,sA,Bm,ldb,sB,C,ldc,sC,alpha,bias,C2,C3); break;
                case 4: gemm_tc_kernel<0,4><<<g,t,sh>>>(Ki,A,lda,sA,Bm,ldb,sB,C,ldc,sC,alpha,bias,C2,C3); break;
                case 5: gemm_tc_kernel<0,5><<<g,t,sh>>>(Ki,A,lda,sA,Bm,ldb,sB,C,ldc,sC,alpha,bias,C2,C3); break;
                case 6: gemm_tc_kernel<0,6><<<g,t,sh>>>(Ki,A,lda,sA,Bm,ldb,sB,C,ldc,sC,alpha,bias,C2,C3); break;
                case 7: gemm_tc_kernel<0,7><<<g,t,sh>>>(Ki,A,lda,sA,Bm,ldb,sB,C,ldc,sC,alpha,bias,C2,C3); break;
            }
        } else {
            gemm_tc_kernel<1,0><<<g,t,sh>>>(Ki,A,lda,sA,Bm,ldb,sB,C,ldc,sC,alpha,bias,C2,C3);
        }
        return;
    }
    dim3 g(Ni/64, Mi/64, batch), t(256);
    if (tb==0){
        if      (epi==0) gemm_kernel<0,0><<<g,t>>>(Ki,A,lda,sA,Bm,ldb,sB,C,ldc,sC,alpha,bias);
        else if (epi==2) gemm_kernel<0,2><<<g,t>>>(Ki,A,lda,sA,Bm,ldb,sB,C,ldc,sC,alpha,bias);
        else if (epi==3) gemm_kernel<0,3><<<g,t>>>(Ki,A,lda,sA,Bm,ldb,sB,C,ldc,sC,alpha,bias);
        else             gemm_kernel<0,4><<<g,t>>>(Ki,A,lda,sA,Bm,ldb,sB,C,ldc,sC,alpha,bias);
    } else {
        gemm_kernel<1,0><<<g,t>>>(Ki,A,lda,sA,Bm,ldb,sB,C,ldc,sC,alpha,bias);
    }
}

static void setup_tc_attrs(){
    cudaFuncSetAttribute(gemm_tc_kernel<0,0>, cudaFuncAttributeMaxDynamicSharedMemorySize, SMEM_TC_BYTES);
    cudaFuncSetAttribute(gemm_tc_kernel<0,2>, cudaFuncAttributeMaxDynamicSharedMemorySize, SMEM_TC_BYTES);
    cudaFuncSetAttribute(gemm_tc_kernel<0,3>, cudaFuncAttributeMaxDynamicSharedMemorySize, SMEM_TC_BYTES);
    cudaFuncSetAttribute(gemm_tc_kernel<0,4>, cudaFuncAttributeMaxDynamicSharedMemorySize, SMEM_TC_BYTES);
    cudaFuncSetAttribute(gemm_tc_kernel<0,5>, cudaFuncAttributeMaxDynamicSharedMemorySize, SMEM_TC_BYTES);
    cudaFuncSetAttribute(gemm_tc_kernel<0,6>, cudaFuncAttributeMaxDynamicSharedMemorySize, SMEM_TC_BYTES);
    cudaFuncSetAttribute(gemm_tc_kernel<0,7>, cudaFuncAttributeMaxDynamicSharedMemorySize, SMEM_TC_BYTES);
    cudaFuncSetAttribute(gemm_tc_kernel<1,0>, cudaFuncAttributeMaxDynamicSharedMemorySize, SMEM_TC_BYTES);
}

extern "C" void kernel_launch(void* const* d_in, const int* in_sizes, int n_in,
                              void* d_out, int out_size)
{
    (void)in_sizes; (void)n_in; (void)out_size;
    const int*   x       = (const int*)  d_in[0];
    const float* enc_emb = (const float*)d_in[1];
    const float* pos_emb = (const float*)d_in[2];
    const float* ln1_s   = (const float*)d_in[3];
    const float* ln1_b   = (const float*)d_in[4];
    const float* qkv_w   = (const float*)d_in[5];
    const float* aout_w  = (const float*)d_in[6];
    const float* aout_b  = (const float*)d_in[7];
    const float* conv_k  = (const float*)d_in[8];
    const float* ln2_s   = (const float*)d_in[9];
    const float* ln2_b   = (const float*)d_in[10];
    const float* ff_w1   = (const float*)d_in[11];
    const float* ff_b1   = (const float*)d_in[12];
    const float* ff_w2   = (const float*)d_in[13];
    const float* ff_b2   = (const float*)d_in[14];
    const float* fin_w   = (const float*)d_in[15];
    const float* fin_b   = (const float*)d_in[16];
    float* out = (float*)d_out;

    setup_tc_attrs();

    float *p_h,*p_x,*p_q,*p_k,*p_v,*p_ql,*p_kl,*p_a1,*p_a3,*p_a2;
    float *p_z,*p_z2,*p_p,*p_t,*p_t2,*p_kv,*p_a1z,*p_ao,*p_y,*p_x2,*p_ff;
    cudaGetSymbolAddress((void**)&p_h,  g_h);
    cudaGetSymbolAddress((void**)&p_x,  g_x);
    cudaGetSymbolAddress((void**)&p_q,  g_q);
    cudaGetSymbolAddress((void**)&p_k,  g_k);
    cudaGetSymbolAddress((void**)&p_v,  g_v);
    cudaGetSymbolAddress((void**)&p_ql, g_ql);
    cudaGetSymbolAddress((void**)&p_kl, g_kl);
    cudaGetSymbolAddress((void**)&p_a1, g_a1);
    cudaGetSymbolAddress((void**)&p_a3, g_a3);
    cudaGetSymbolAddress((void**)&p_a2, g_a2);
    cudaGetSymbolAddress((void**)&p_z,  g_zb);
    cudaGetSymbolAddress((void**)&p_z2, g_zb2);
    cudaGetSymbolAddress((void**)&p_p,  g_pb);
    cudaGetSymbolAddress((void**)&p_t,  g_tb);
    cudaGetSymbolAddress((void**)&p_t2, g_tb2);
    cudaGetSymbolAddress((void**)&p_kv, g_kvb);
    cudaGetSymbolAddress((void**)&p_a1z,g_a1z);
    cudaGetSymbolAddress((void**)&p_ao, g_ao);
    cudaGetSymbolAddress((void**)&p_y,  g_y);
    cudaGetSymbolAddress((void**)&p_x2, g_x2);
    cudaGetSymbolAddress((void**)&p_ff, g_ff);

    const long long MM  = (long long)ML*ML;
    const long long NM  = (long long)NPAD*ML;
    const long long ND  = (long long)NPAD*DHD;
    const long long MD  = (long long)ML*DHD;

    {
        long long tot = (long long)BATCH*LSEQ*DMODEL;
        embed_kernel<<<(unsigned)((tot+255)/256),256>>>(x, enc_emb, pos_emb);
        int tot2 = BATCH*PADL*DMODEL;
        zero_pad_kernel<<<(tot2+255)/256,256>>>();
    }

    for (int lay=0; lay<DEPTH; lay++){
        ln_kernel<<<BATCH*LSEQ,256>>>(p_h, p_x, ln1_s+(long long)lay*DMODEL, ln1_b+(long long)lay*DMODEL, 1);
        // QKV [tensor, fused split into q/k/v]
        run_gemm(0,7, BATCH*NPAD, 3*DMODEL, DMODEL,
                 p_x, DMODEL, 0,
                 qkv_w + (long long)lay*DMODEL*3*DMODEL, 3*DMODEL, 0,
                 p_q, 3*DMODEL, 0, 1, 1.f, nullptr, p_k, p_v);
        {
            long long tot2 = (long long)BH*ML*DHD;
            landmark_kernel<<<(unsigned)((tot2+255)/256),256>>>();
        }
        // attn1 = softmax(q @ kl^T)  [tensor TB=1]
        run_gemm(1,0, NPAD, ML, DHD, p_q, DHD, ND, p_kl, DHD, MD, p_a1, ML, NM, BH, 1.f, nullptr);
        softmax_kernel<<<BH*NPAD,128>>>(p_a1, ML);
        // attn2 = softmax(ql @ kl^T)  [tensor TB=1]
        run_gemm(1,0, ML, ML, DHD, p_ql, DHD, MD, p_kl, DHD, MD, p_a2, ML, MM, BH, 1.f, nullptr);
        softmax_kernel<<<BH*ML,128>>>(p_a2, ML);
        // attn3 = softmax(ql @ k^T)  [tensor TB=1]
        run_gemm(1,0, ML, NPAD, DHD, p_ql, DHD, MD, p_k, DHD, ND, p_a3, NPAD, (long long)ML*NPAD, BH, 1.f, nullptr);
        softmax_kernel<<<BH*ML,128>>>(p_a3, NPAD);

        // ---- pinv (tensor, fused aI-X epilogues) ----
        red_init_kernel<<<1,1>>>();
        colsum_kernel<<<(BH*ML+255)/256,256>>>();
        rowsum_kernel<<<(BH*ML+255)/256,256>>>();
        {
            long long tot = (long long)BH*ML*ML;
            unsigned g = (unsigned)((tot+255)/256);
            zinit_kernel<<<g,256>>>();
        }
        float* zc = p_z; float* zn = p_z2;
        for (int it=0; it<6; it++){
            run_gemm(0,6, ML, ML, ML, p_a2, ML, MM, zc, ML, MM, p_p, ML, MM, BH, 7.f, nullptr, p_t);
            run_gemm(0,5, ML, ML, ML, p_p, ML, MM, p_t, ML, MM, p_t2, ML, MM, BH, 15.f, nullptr);
            run_gemm(0,5, ML, ML, ML, p_p, ML, MM, p_t2, ML, MM, p_t, ML, MM, BH, 13.f, nullptr);
            run_gemm(0,0, ML, ML, ML, zc, ML, MM, p_t, ML, MM, zn, ML, MM, BH, 0.25f, nullptr);
            float* tmp = zc; zc = zn; zn = tmp;
        }

        // kv = attn3 @ v  [SIMT N=64]
        run_gemm(0,0, ML, DHD, NPAD, p_a3, NPAD, (long long)ML*NPAD, p_v, DHD, ND, p_kv, DHD, MD, BH, 1.f, nullptr);
        // a1z = attn1 @ Z  [tensor]
        run_gemm(0,0, NPAD, ML, ML, p_a1, ML, NM, zc, ML, MM, p_a1z, ML, NM, BH, 1.f, nullptr);
        // ao = a1z @ kv  [SIMT N=64]
        run_gemm(0,0, NPAD, DHD, ML, p_a1z, ML, NM, p_kv, DHD, MD, p_ao, DHD, ND, BH, 1.f, nullptr);
        {
            long long tot = (long long)BH*NPAD*DHD;
            combine_kernel<<<(unsigned)((tot+255)/256),256>>>(conv_k + (long long)lay*NH*KC);
        }
        // out projection + residual [tensor]
        run_gemm(0,4, BATCH*NPAD, DMODEL, DMODEL,
                 p_y, DMODEL, 0,
                 aout_w + (long long)lay*DMODEL*DMODEL, DMODEL, 0,
                 p_h, DMODEL, 0, 1, 1.f, aout_b + (long long)lay*DMODEL);

        // ---- FFN ----
        ln_kernel<<<BATCH*LSEQ,256>>>(p_h, p_x2, ln2_s+(long long)lay*DMODEL, ln2_b+(long long)lay*DMODEL, 0);
        run_gemm(0,2, BATCH*LSEQ, FFD, DMODEL,
                 p_x2, DMODEL, 0,
                 ff_w1 + (long long)lay*DMODEL*FFD, FFD, 0,
                 p_ff, FFD, 0, 1, 1.f, ff_b1 + (long long)lay*FFD);
        run_gemm(0,3, BATCH*LSEQ, DMODEL, FFD,
                 p_ff, FFD, 0,
                 ff_w2 + (long long)lay*FFD*DMODEL, DMODEL, 0,
                 p_h, DMODEL, 0, 1, 1.f, ff_b2 + (long long)lay*DMODEL);
    }

    final_kernel<<<BATCH,256>>>(fin_w, fin_b, out);
}

// round 9
// speedup vs baseline: 1.2571x; 1.1594x over previous
#include <cuda_runtime.h>
#include <math.h>
#include <stdint.h>

// ---------------- model constants ----------------
#define BATCH 16
#define LSEQ  1000
#define DMODEL 512
#define NH    8
#define DHD   64
#define NPAD  1024
#define PADL  24
#define ML    256
#define LMR   4
#define FFD   2048
#define DEPTH 6
#define KC    33
#define QSCALE 0.125f
#define BH (BATCH*NH)

// ---------------- scratch ----------------
__device__ float g_h   [BATCH*LSEQ*DMODEL];
__device__ float g_x   [BATCH*NPAD*DMODEL];
__device__ float g_q   [BH*NPAD*DHD];
__device__ float g_k   [BH*NPAD*DHD];
__device__ float g_v   [BH*NPAD*DHD];
__device__ float g_ql  [BH*ML*DHD];
__device__ float g_kl  [BH*ML*DHD];
__device__ float g_a1  [BH*NPAD*ML];
__device__ float g_a3  [BH*ML*NPAD];
__device__ float g_a2  [BH*ML*ML];
__device__ float g_zb  [BH*ML*ML];
__device__ float g_zb2 [BH*ML*ML];
__device__ float g_pb  [BH*ML*ML];
__device__ float g_tb  [BH*ML*ML];
__device__ float g_tb2 [BH*ML*ML];
__device__ float g_kvb [BH*ML*DHD];
__device__ float g_zkv [BH*ML*DHD];
__device__ float g_ao  [BH*NPAD*DHD];
__device__ float g_y   [BATCH*NPAD*DMODEL];
__device__ float g_x2  [BATCH*LSEQ*DMODEL];
__device__ float g_ff  [BATCH*LSEQ*FFD];
__device__ int   g_red [2];

// ---------------- reductions ----------------
__device__ __forceinline__ float warpSum(float v){
    #pragma unroll
    for (int o=16;o;o>>=1) v += __shfl_xor_sync(0xffffffffu, v, o);
    return v;
}
__device__ __forceinline__ float warpMax(float v){
    #pragma unroll
    for (int o=16;o;o>>=1) v = fmaxf(v, __shfl_xor_sync(0xffffffffu, v, o));
    return v;
}
__device__ __forceinline__ float blockSumN(float v, float* sh, int nw){
    int w = threadIdx.x>>5, l = threadIdx.x&31;
    v = warpSum(v);
    if (l==0) sh[w] = v;
    __syncthreads();
    if (w==0){
        float x = (l < nw) ? sh[l] : 0.f;
        x = warpSum(x);
        if (l==0) sh[0] = x;
    }
    __syncthreads();
    float r = sh[0];
    __syncthreads();
    return r;
}
__device__ __forceinline__ float blockMaxN(float v, float* sh, int nw){
    int w = threadIdx.x>>5, l = threadIdx.x&31;
    v = warpMax(v);
    if (l==0) sh[w] = v;
    __syncthreads();
    if (w==0){
        float x = (l < nw) ? sh[l] : -3.4e38f;
        x = warpMax(x);
        if (l==0) sh[0] = x;
    }
    __syncthreads();
    float r = sh[0];
    __syncthreads();
    return r;
}

// ---------------- mma / cp.async / ldmatrix helpers ----------------
__device__ __forceinline__ void mma_tf32(float c[4],
    unsigned a0, unsigned a1, unsigned a2, unsigned a3,
    unsigned b0, unsigned b1)
{
    asm volatile(
        "mma.sync.aligned.m16n8k8.row.col.f32.tf32.tf32.f32 "
        "{%0,%1,%2,%3}, {%4,%5,%6,%7}, {%8,%9}, {%0,%1,%2,%3};"
        : "+f"(c[0]), "+f"(c[1]), "+f"(c[2]), "+f"(c[3])
        : "r"(a0), "r"(a1), "r"(a2), "r"(a3), "r"(b0), "r"(b1));
}
__device__ __forceinline__ void cp16(unsigned saddr, const void* gptr){
    asm volatile("cp.async.cg.shared.global [%0], [%1], 16;\n"
                 :: "r"(saddr), "l"(gptr));
}
__device__ __forceinline__ void cp_commit(){
    asm volatile("cp.async.commit_group;\n");
}
template<int N>
__device__ __forceinline__ void cp_wait(){
    asm volatile("cp.async.wait_group %0;\n" :: "n"(N));
}
__device__ __forceinline__ void ldsm4(unsigned &r0, unsigned &r1,
                                      unsigned &r2, unsigned &r3,
                                      unsigned addr){
    asm volatile("ldmatrix.sync.aligned.m8n8.x4.shared.b16 {%0,%1,%2,%3}, [%4];"
        : "=r"(r0), "=r"(r1), "=r"(r2), "=r"(r3) : "r"(addr));
}

// epilogue: writes 2 consecutive cols at (r, cc)
// EPI 0: C = alpha*val         EPI 2: C = gelu(val+bias)
// EPI 3: C += val+bias         EPI 4: pad-sliced residual add into h
// EPI 5: C = alpha*I - val     EPI 6: C = val ; C2 = alpha*I - val
// EPI 7: fused qkv split: C=q(*QSCALE), C2=k, C3=v in (b,h,n,d) layout
template<int EPI>
__device__ __forceinline__ void store2(
    float* __restrict__ C, float* __restrict__ C2, float* __restrict__ C3,
    int ldc, int r, int cc, float v0, float v1,
    float alpha, const float* __restrict__ bias)
{
    if (EPI==0){
        float2 o = {alpha*v0, alpha*v1};
        *(float2*)&C[(long long)r*ldc + cc] = o;
    } else if (EPI==2){
        float x0 = v0 + bias[cc], x1 = v1 + bias[cc+1];
        float2 o;
        o.x = 0.5f*x0*(1.f+erff(x0*0.70710678118654752f));
        o.y = 0.5f*x1*(1.f+erff(x1*0.70710678118654752f));
        *(float2*)&C[(long long)r*ldc + cc] = o;
    } else if (EPI==3){
        float2 o = *(float2*)&C[(long long)r*ldc + cc];
        o.x += v0 + bias[cc];
        o.y += v1 + bias[cc+1];
        *(float2*)&C[(long long)r*ldc + cc] = o;
    } else if (EPI==4){
        int bb = r / NPAD, nl = r % NPAD;
        if (nl >= PADL){
            long long orow = (long long)bb*LSEQ + (nl - PADL);
            float2 o = *(float2*)&C[orow*ldc + cc];
            o.x += v0 + bias[cc];
            o.y += v1 + bias[cc+1];
            *(float2*)&C[orow*ldc + cc] = o;
        }
    } else if (EPI==5){
        float2 o = {(r==cc ? alpha : 0.f) - v0, (r==cc+1 ? alpha : 0.f) - v1};
        *(float2*)&C[(long long)r*ldc + cc] = o;
    } else if (EPI==6){
        float2 o = {v0, v1};
        *(float2*)&C[(long long)r*ldc + cc] = o;
        float2 o2 = {(r==cc ? alpha : 0.f) - v0, (r==cc+1 ? alpha : 0.f) - v1};
        *(float2*)&C2[(long long)r*ldc + cc] = o2;
    } else if (EPI==7){
        int b = r >> 10, n = r & 1023;
        int which = cc >> 9;
        int hd = cc & 511;
        long long idx = ((((long long)b*NH + (hd>>6))*NPAD) + n)*DHD + (hd&63);
        float2 o;
        if (which==0){ o.x = v0*QSCALE; o.y = v1*QSCALE; *(float2*)&C[idx] = o; }
        else if (which==1){ o.x = v0; o.y = v1; *(float2*)&C2[idx] = o; }
        else { o.x = v0; o.y = v1; *(float2*)&C3[idx] = o; }
    }
}

// == TF32 tensor GEMM v7: 256 thr, CTA 128x256, warp 64x64, LDSM, 3-stage ==
// TB=0: B is KxN rm.  TB=1: B is NxK rm (C = A @ B^T).
// Requires M%128==0, N%256==0, K%16==0.
#define AS_STRIDE 20
#define AS_ST     (128*AS_STRIDE)      // 2560 words
#define BS0_STRIDE 264
#define BS1_STRIDE 20
#define BS_ST     (256*BS1_STRIDE)     // 5120 words (>= 16*264=4224)
#define NSTAGE 3
#define SMEM_TC_BYTES (NSTAGE*(AS_ST + BS_ST)*4)   // 92160

template<int TB, int EPI>
__global__ void __launch_bounds__(256,1) gemm_tc_kernel(
    int Ki,
    const float* __restrict__ A, int lda, long long sA,
    const float* __restrict__ Bm, int ldb, long long sB,
    float* __restrict__ C, int ldc, long long sC,
    float alpha, const float* __restrict__ bias,
    float* __restrict__ C2, float* __restrict__ C3)
{
    extern __shared__ unsigned sm[];
    unsigned* As = sm;
    unsigned* Bs = sm + NSTAGE*AS_ST;
    const unsigned As_base = (unsigned)__cvta_generic_to_shared(As);
    const unsigned Bs_base = (unsigned)__cvta_generic_to_shared(Bs);

    const int bz = blockIdx.z;
    A  += (long long)bz*sA;
    Bm += (long long)bz*sB;
    C  += (long long)bz*sC;
    if (EPI==6) C2 += (long long)bz*sC;

    const int row0 = blockIdx.y*128;
    const int col0 = blockIdx.x*256;
    const int tid = threadIdx.x;
    const int warp = tid>>5, lane = tid&31;
    const int wm = warp & 1, wn = warp >> 1;   // 2x4 warp grid, warp tile 64x64
    const int g = lane>>2, qc = lane&3;

    // staging: A 512 float4 -> 2/thread; B 1024 float4 -> 4/thread
    const int a_r  = tid>>1;
    const int a_c2 = (tid&1)<<1;

    auto issue = [&](int kt, int st){
        unsigned abase = As_base + (unsigned)(st*AS_ST)*4u;
        #pragma unroll
        for (int i=0;i<2;i++)
            cp16(abase + (unsigned)(a_r*AS_STRIDE + (a_c2+i)*4)*4u,
                 A + (long long)(row0 + a_r)*lda + kt + (a_c2+i)*4);
        unsigned bbase = Bs_base + (unsigned)(st*BS_ST)*4u;
        if (TB==0){
            #pragma unroll
            for (int i=0;i<4;i++){
                int fidx = tid + i*256;
                int bk = fidx>>6, bn4 = (fidx&63)<<2;
                cp16(bbase + (unsigned)(bk*BS0_STRIDE + bn4)*4u,
                     Bm + (long long)(kt + bk)*ldb + col0 + bn4);
            }
        } else {
            #pragma unroll
            for (int i=0;i<4;i++){
                int fidx = tid + i*256;
                int bn = fidx>>2, bc4 = (fidx&3)<<2;
                cp16(bbase + (unsigned)(bn*BS1_STRIDE + bc4)*4u,
                     Bm + (long long)(col0 + bn)*ldb + kt + bc4);
            }
        }
    };

    float acc[4][8][4];
    #pragma unroll
    for (int mt=0;mt<4;mt++)
        #pragma unroll
        for (int nt=0;nt<8;nt++)
            #pragma unroll
            for (int i=0;i<4;i++) acc[mt][nt][i]=0.f;

    const int nk = Ki >> 4;
    issue(0, 0);  cp_commit();
    issue(16, 1); cp_commit();

    const int lane8 = lane & 7;
    const int a_lrow = wm*64 + lane8 + ((lane>>3)&1)*8;  // + mt*16
    const int a_lw   = ((lane>>4)&1)*4;                  // + koff
    const int b_lrow = wn*64 + lane8 + ((lane>>4)&1)*8;  // + np*16 (TB1)
    const int b_lw   = ((lane>>3)&1)*4;                  // + koff  (TB1)
    const int b0_frag_off = qc*BS0_STRIDE + wn*64 + g;   // TB0 scalar

    for (int t = 0; t < nk; ++t){
        cp_wait<1>();
        __syncthreads();
        const int rb = t % NSTAGE;
        if (t+2 < nk) issue((t+2)<<4, (t+2)%NSTAGE);
        cp_commit();

        const unsigned a_stage = As_base + (unsigned)(rb*AS_ST)*4u;
        const unsigned b_stage = Bs_base + (unsigned)(rb*BS_ST)*4u;

        #pragma unroll
        for (int grp=0; grp<2; grp++){
            const int koff = grp*8;
            unsigned af[4][4], bf[8][2];
            #pragma unroll
            for (int mt=0;mt<4;mt++)
                ldsm4(af[mt][0], af[mt][1], af[mt][2], af[mt][3],
                      a_stage + (unsigned)(((a_lrow + mt*16)*AS_STRIDE) + a_lw + koff)*4u);
            if (TB==0){
                const unsigned* Bb = Bs + rb*BS_ST + b0_frag_off + koff*BS0_STRIDE;
                #pragma unroll
                for (int nt=0;nt<8;nt++){
                    bf[nt][0] = Bb[nt*8];
                    bf[nt][1] = Bb[4*BS0_STRIDE + nt*8];
                }
            } else {
                #pragma unroll
                for (int np=0;np<4;np++)
                    ldsm4(bf[2*np][0], bf[2*np][1], bf[2*np+1][0], bf[2*np+1][1],
                          b_stage + (unsigned)(((b_lrow + np*16)*BS1_STRIDE) + b_lw + koff)*4u);
            }
            #pragma unroll
            for (int mt=0;mt<4;mt++)
                #pragma unroll
                for (int nt=0;nt<8;nt++)
                    mma_tf32(acc[mt][nt], af[mt][0],af[mt][1],af[mt][2],af[mt][3],
                             bf[nt][0],bf[nt][1]);
        }
    }

    // epilogue
    #pragma unroll
    for (int mt=0;mt<4;mt++){
        int r = row0 + wm*64 + mt*16 + g;
        #pragma unroll
        for (int nt=0;nt<8;nt++){
            int cc = col0 + wn*64 + nt*8 + 2*qc;
            store2<EPI>(C, C2, C3, ldc, r,   cc, acc[mt][nt][0], acc[mt][nt][1], alpha, bias);
            store2<EPI>(C, C2, C3, ldc, r+8, cc, acc[mt][nt][2], acc[mt][nt][3], alpha, bias);
        }
    }
}

// ==== TF32 tensor GEMM N=64: 128 thr, CTA 128x64, warp 64x32, 3-stage =====
// B is KxN rm, EPI0 only. Requires M%128==0, N==64, K%16==0.
#define BS64_STRIDE 72
#define BS64_ST     (16*BS64_STRIDE)     // 1152 words
#define SMEM_TC64_BYTES (NSTAGE*(AS_ST + BS64_ST)*4)   // 44544

__global__ void __launch_bounds__(128) gemm_tc64_kernel(
    int Ki,
    const float* __restrict__ A, int lda, long long sA,
    const float* __restrict__ Bm, int ldb, long long sB,
    float* __restrict__ C, int ldc, long long sC)
{
    extern __shared__ unsigned sm[];
    unsigned* As = sm;
    unsigned* Bs = sm + NSTAGE*AS_ST;
    const unsigned As_base = (unsigned)__cvta_generic_to_shared(As);
    const unsigned Bs_base = (unsigned)__cvta_generic_to_shared(Bs);

    const int bz = blockIdx.z;
    A  += (long long)bz*sA;
    Bm += (long long)bz*sB;
    C  += (long long)bz*sC;

    const int row0 = blockIdx.y*128;
    const int tid = threadIdx.x;
    const int warp = tid>>5, lane = tid&31;
    const int wm = warp & 1, wn = warp >> 1;   // 2x2 warp grid, warp tile 64x32
    const int g = lane>>2, qc = lane&3;

    auto issue = [&](int kt, int st){
        unsigned abase = As_base + (unsigned)(st*AS_ST)*4u;
        #pragma unroll
        for (int i=0;i<4;i++){
            int fidx = tid + i*128;
            int a_r = fidx>>2, a_c4 = (fidx&3)<<2;
            cp16(abase + (unsigned)(a_r*AS_STRIDE + a_c4)*4u,
                 A + (long long)(row0 + a_r)*lda + kt + a_c4);
        }
        unsigned bbase = Bs_base + (unsigned)(st*BS64_ST)*4u;
        #pragma unroll
        for (int i=0;i<2;i++){
            int fidx = tid + i*128;
            int bk = fidx>>4, bn4 = (fidx&15)<<2;
            cp16(bbase + (unsigned)(bk*BS64_STRIDE + bn4)*4u,
                 Bm + (long long)(kt + bk)*ldb + bn4);
        }
    };

    float acc[4][4][4];
    #pragma unroll
    for (int mt=0;mt<4;mt++)
        #pragma unroll
        for (int nt=0;nt<4;nt++)
            #pragma unroll
            for (int i=0;i<4;i++) acc[mt][nt][i]=0.f;

    const int nk = Ki >> 4;
    issue(0, 0);  cp_commit();
    issue(16, 1); cp_commit();

    const int lane8 = lane & 7;
    const int a_lrow = wm*64 + lane8 + ((lane>>3)&1)*8;
    const int a_lw   = ((lane>>4)&1)*4;
    const int b_frag_off = qc*BS64_STRIDE + wn*32 + g;

    for (int t = 0; t < nk; ++t){
        cp_wait<1>();
        __syncthreads();
        const int rb = t % NSTAGE;
        if (t+2 < nk) issue((t+2)<<4, (t+2)%NSTAGE);
        cp_commit();

        const unsigned a_stage = As_base + (unsigned)(rb*AS_ST)*4u;

        #pragma unroll
        for (int grp=0; grp<2; grp++){
            const int koff = grp*8;
            unsigned af[4][4], bf[4][2];
            #pragma unroll
            for (int mt=0;mt<4;mt++)
                ldsm4(af[mt][0], af[mt][1], af[mt][2], af[mt][3],
                      a_stage + (unsigned)(((a_lrow + mt*16)*AS_STRIDE) + a_lw + koff)*4u);
            const unsigned* Bb = Bs + rb*BS64_ST + b_frag_off + koff*BS64_STRIDE;
            #pragma unroll
            for (int nt=0;nt<4;nt++){
                bf[nt][0] = Bb[nt*8];
                bf[nt][1] = Bb[4*BS64_STRIDE + nt*8];
            }
            #pragma unroll
            for (int mt=0;mt<4;mt++)
                #pragma unroll
                for (int nt=0;nt<4;nt++)
                    mma_tf32(acc[mt][nt], af[mt][0],af[mt][1],af[mt][2],af[mt][3],
                             bf[nt][0],bf[nt][1]);
        }
    }

    #pragma unroll
    for (int mt=0;mt<4;mt++){
        int r = row0 + wm*64 + mt*16 + g;
        #pragma unroll
        for (int nt=0;nt<4;nt++){
            int cc = wn*32 + nt*8 + 2*qc;
            float2 o0 = {acc[mt][nt][0], acc[mt][nt][1]};
            float2 o1 = {acc[mt][nt][2], acc[mt][nt][3]};
            *(float2*)&C[(long long)r*ldc + cc] = o0;
            *(float2*)&C[(long long)(r+8)*ldc + cc] = o1;
        }
    }
}

// ---------------- generic 64x64 tiled SIMT GEMM (fallback, unused paths) --
template<int TB, int EPI>
__global__ void __launch_bounds__(256) gemm_kernel(
    int Ki,
    const float* __restrict__ A, int lda, long long sA,
    const float* __restrict__ Bm, int ldb, long long sB,
    float* __restrict__ C, int ldc, long long sC,
    float alpha, const float* __restrict__ bias)
{
    const int bz = blockIdx.z;
    A  += (long long)bz * sA;
    Bm += (long long)bz * sB;
    C  += (long long)bz * sC;
    const int row0 = blockIdx.y * 64;
    const int col0 = blockIdx.x * 64;
    __shared__ float As[16][68];
    __shared__ float Bs[16][68];
    const int tid = threadIdx.x;
    const int ty = tid >> 4, tx = tid & 15;
    const int ar = tid >> 2, akq = (tid & 3) << 2;

    float acc[4][4];
    #pragma unroll
    for (int i=0;i<4;i++)
        #pragma unroll
        for (int j=0;j<4;j++) acc[i][j]=0.f;

    for (int k0 = 0; k0 < Ki; k0 += 16) {
        float4 av = *(const float4*)(A + (long long)(row0+ar)*lda + k0 + akq);
        As[akq+0][ar]=av.x; As[akq+1][ar]=av.y; As[akq+2][ar]=av.z; As[akq+3][ar]=av.w;
        if (TB==0) {
            int bkk = tid >> 4, bc = (tid & 15) << 2;
            float4 bv = *(const float4*)(Bm + (long long)(k0+bkk)*ldb + col0 + bc);
            Bs[bkk][bc+0]=bv.x; Bs[bkk][bc+1]=bv.y; Bs[bkk][bc+2]=bv.z; Bs[bkk][bc+3]=bv.w;
        } else {
            int bc = tid >> 2, bkq = (tid & 3) << 2;
            float4 bv = *(const float4*)(Bm + (long long)(col0+bc)*ldb + k0 + bkq);
            Bs[bkq+0][bc]=bv.x; Bs[bkq+1][bc]=bv.y; Bs[bkq+2][bc]=bv.z; Bs[bkq+3][bc]=bv.w;
        }
        __syncthreads();
        #pragma unroll
        for (int kk=0;kk<16;kk++){
            float a[4], b[4];
            #pragma unroll
            for (int i=0;i<4;i++) a[i]=As[kk][ty+16*i];
            #pragma unroll
            for (int j=0;j<4;j++) b[j]=Bs[kk][tx+16*j];
            #pragma unroll
            for (int i=0;i<4;i++)
                #pragma unroll
                for (int j=0;j<4;j++)
                    acc[i][j] = fmaf(a[i], b[j], acc[i][j]);
        }
        __syncthreads();
    }

    #pragma unroll
    for (int i=0;i<4;i++){
        int r = row0 + ty + 16*i;
        #pragma unroll
        for (int j=0;j<4;j++){
            int c = col0 + tx + 16*j;
            float val = alpha * acc[i][j];
            if (EPI==0) {
                C[(long long)r*ldc + c] = val;
            } else if (EPI==2) {
                float xg = val + bias[c];
                C[(long long)r*ldc + c] = 0.5f*xg*(1.f+erff(xg*0.70710678118654752f));
            } else if (EPI==3) {
                C[(long long)r*ldc + c] += val + bias[c];
            } else if (EPI==4) {
                int bb = r / NPAD, nl = r % NPAD;
                if (nl >= PADL)
                    C[((long long)bb*LSEQ + (nl-PADL))*ldc + c] += val + bias[c];
            }
        }
    }
}

// ---------------- elementwise / small kernels ----------------
__global__ void embed_kernel(const int* __restrict__ x,
                             const float* __restrict__ emb,
                             const float* __restrict__ pos){
    long long idx = (long long)blockIdx.x*blockDim.x + threadIdx.x;
    if (idx >= (long long)BATCH*LSEQ*DMODEL) return;
    int d = (int)(idx % DMODEL);
    long long bl = idx / DMODEL;
    int l = (int)(bl % LSEQ);
    int tok = x[bl];
    g_h[idx] = emb[(long long)tok*DMODEL + d] + pos[(long long)l*DMODEL + d];
}

__global__ void zero_pad_kernel(){
    int idx = blockIdx.x*blockDim.x + threadIdx.x;
    if (idx >= BATCH*PADL*DMODEL) return;
    int d  = idx % DMODEL;
    int bp = idx / DMODEL;
    int b  = bp / PADL, p = bp % PADL;
    g_x[((long long)b*NPAD + p)*DMODEL + d] = 0.f;
}

__global__ void ln_kernel(const float* __restrict__ in, float* __restrict__ out,
                          const float* __restrict__ gm, const float* __restrict__ bt,
                          int padmode){
    __shared__ float sh[8];
    int r = blockIdx.x;
    int t = threadIdx.x;
    const float* p = in + (long long)r*DMODEL;
    float a  = p[t];
    float b2 = p[t+256];
    float s  = blockSumN(a+b2, sh, 8);
    float mu = s * (1.f/512.f);
    float da = a - mu, db = b2 - mu;
    float v  = blockSumN(da*da + db*db, sh, 8) * (1.f/512.f);
    float rstd = rsqrtf(v + 1e-5f);
    long long orow = padmode ? ((long long)(r/LSEQ)*NPAD + PADL + (r%LSEQ)) : (long long)r;
    float* q = out + orow*DMODEL;
    q[t]     = da*rstd*gm[t]     + bt[t];
    q[t+256] = db*rstd*gm[t+256] + bt[t+256];
}

__global__ void landmark_kernel(){
    long long idx = (long long)blockIdx.x*blockDim.x + threadIdx.x;
    if (idx >= (long long)BH*ML*DHD) return;
    int d = (int)(idx & 63);
    long long r = idx >> 6;
    int m  = (int)(r % ML);
    int bh = (int)(r / ML);
    long long base = ((long long)bh*NPAD + (long long)m*LMR)*DHD + d;
    float sq = 0.f, sk = 0.f;
    #pragma unroll
    for (int j=0;j<LMR;j++){ sq += g_q[base + (long long)j*DHD]; sk += g_k[base + (long long)j*DHD]; }
    g_ql[idx] = sq * 0.25f;
    g_kl[idx] = sk * 0.25f;
}

__global__ void softmax_kernel(float* __restrict__ X, int cols){
    __shared__ float sh[4];
    long long row = blockIdx.x;
    float* p = X + row*(long long)cols;
    int t = threadIdx.x;
    int cnt = cols >> 7;
    float v[8];
    float mx = -3.4e38f;
    #pragma unroll
    for (int i=0;i<8;i++) if (i<cnt){ v[i]=p[t + (i<<7)]; mx = fmaxf(mx, v[i]); }
    mx = blockMaxN(mx, sh, 4);
    float s = 0.f;
    #pragma unroll
    for (int i=0;i<8;i++) if (i<cnt){ v[i]=expf(v[i]-mx); s += v[i]; }
    s = blockSumN(s, sh, 4);
    float inv = 1.f/s;
    #pragma unroll
    for (int i=0;i<8;i++) if (i<cnt) p[t + (i<<7)] = v[i]*inv;
}

__global__ void red_init_kernel(){ g_red[0]=0; g_red[1]=0; }

__global__ void colsum_kernel(){
    int idx = blockIdx.x*blockDim.x + threadIdx.x;
    if (idx >= BH*ML) return;
    int c  = idx % ML;
    int bz = idx / ML;
    const float* p = g_a2 + (long long)bz*ML*ML + c;
    float s = 0.f;
    for (int r2=0;r2<ML;r2++) s += fabsf(p[(long long)r2*ML]);
    atomicMax(&g_red[0], __float_as_int(s));
}
__global__ void rowsum_kernel(){
    int idx = blockIdx.x*blockDim.x + threadIdx.x;
    if (idx >= BH*ML) return;
    int r2 = idx % ML;
    int bz = idx / ML;
    const float* p = g_a2 + (long long)bz*ML*ML + (long long)r2*ML;
    float s = 0.f;
    for (int c=0;c<ML;c++) s += fabsf(p[c]);
    atomicMax(&g_red[1], __float_as_int(s));
}
__global__ void zinit_kernel(){
    long long idx = (long long)blockIdx.x*blockDim.x + threadIdx.x;
    if (idx >= (long long)BH*ML*ML) return;
    int j = (int)(idx % ML);
    long long r = idx / ML;
    int i  = (int)(r % ML);
    int bz = (int)(r / ML);
    float c = __int_as_float(g_red[0]) * __int_as_float(g_red[1]);
    g_zb[idx] = g_a2[((long long)bz*ML + j)*ML + i] / c;
}

__global__ void combine_kernel(const float* __restrict__ cw){
    long long idx = (long long)blockIdx.x*blockDim.x + threadIdx.x;
    if (idx >= (long long)BH*NPAD*DHD) return;
    int d = (int)(idx & 63);
    long long r = idx >> 6;
    int n  = (int)(r % NPAD);
    int bh = (int)(r / NPAD);
    int h  = bh % NH, b = bh / NH;
    float s = g_ao[idx];
    const float* w  = cw + h*KC;
    const float* vp = g_v + ((long long)bh*NPAD)*DHD + d;
    int k0 = (16-n > 0) ? (16-n) : 0;
    int k1 = (NPAD+16-n < KC) ? (NPAD+16-n) : KC;
    for (int kk=k0; kk<k1; kk++)
        s = fmaf(vp[(long long)(n+kk-16)*DHD], w[kk], s);
    g_y[((long long)b*NPAD + n)*DMODEL + h*DHD + d] = s;
}

__global__ void final_kernel(const float* __restrict__ fw,
                             const float* __restrict__ fb,
                             float* __restrict__ out){
    __shared__ float sh[8];
    int b = blockIdx.x;
    int t = threadIdx.x;
    const float* hp = g_h + (long long)b*LSEQ*DMODEL;
    float s = 0.f;
    for (long long i=t; i<(long long)LSEQ*DMODEL; i+=256)
        s = fmaf(hp[i], fw[i], s);
    s = blockSumN(s, sh, 8);
    if (t==0) out[b] = s + fb[0];
}

// ---------------- host-side GEMM dispatch ----------------
static void run_gemm(int tb, int epi, int Mi, int Ni, int Ki,
                     const float* A, int lda, long long sA,
                     const float* Bm, int ldb, long long sB,
                     float* C, int ldc, long long sC,
                     int batch, float alpha, const float* bias,
                     float* C2 = nullptr, float* C3 = nullptr)
{
    if ((Mi % 128) == 0 && (Ni % 256) == 0 && (Ki % 16) == 0) {
        dim3 g(Ni/256, Mi/128, batch), t(256);
        size_t sh = SMEM_TC_BYTES;
        if (tb == 0) {
            switch (epi) {
                case 0: gemm_tc_kernel<0,0><<<g,t,sh>>>(Ki,A,lda,sA,Bm,ldb,sB,C,ldc,sC,alpha,bias,C2,C3); break;
                case 2: gemm_tc_kernel<0,2><<<g,t,sh>>>(Ki,A,lda,sA,Bm,ldb,sB,C,ldc,sC,alpha,bias,C2,C3); break;
                case 3: gemm_tc_kernel<0,3><<<g,t,sh>>>(Ki,A,lda,sA,Bm,ldb,sB,C,ldc,sC,alpha,bias,C2,C3); break;
                case 4: gemm_tc_kernel<0,4><<<g,t,sh>>>(Ki,A,lda,sA,Bm,ldb,sB,C,ldc,sC,alpha,bias,C2,C3); break;
                case 5: gemm_tc_kernel<0,5><<<g,t,sh>>>(Ki,A,lda,sA,Bm,ldb,sB,C,ldc,sC,alpha,bias,C2,C3); break;
                case 6: gemm_tc_kernel<0,6><<<g,t,sh>>>(Ki,A,lda,sA,Bm,ldb,sB,C,ldc,sC,alpha,bias,C2,C3); break;
                case 7: gemm_tc_kernel<0,7><<<g,t,sh>>>(Ki,A,lda,sA,Bm,ldb,sB,C,ldc,sC,alpha,bias,C2,C3); break;
            }
        } else {
            gemm_tc_kernel<1,0><<<g,t,sh>>>(Ki,A,lda,sA,Bm,ldb,sB,C,ldc,sC,alpha,bias,C2,C3);
        }
        return;
    }
    dim3 g(Ni/64, Mi/64, batch), t(256);
    if (tb==0){
        if      (epi==0) gemm_kernel<0,0><<<g,t>>>(Ki,A,lda,sA,Bm,ldb,sB,C,ldc,sC,alpha,bias);
        else if (epi==2) gemm_kernel<0,2><<<g,t>>>(Ki,A,lda,sA,Bm,ldb,sB,C,ldc,sC,alpha,bias);
        else if (epi==3) gemm_kernel<0,3><<<g,t>>>(Ki,A,lda,sA,Bm,ldb,sB,C,ldc,sC,alpha,bias);
        else             gemm_kernel<0,4><<<g,t>>>(Ki,A,lda,sA,Bm,ldb,sB,C,ldc,sC,alpha,bias);
    } else {
        gemm_kernel<1,0><<<g,t>>>(Ki,A,lda,sA,Bm,ldb,sB,C,ldc,sC,alpha,bias);
    }
}

// N=64 tensor GEMM (TB0, EPI0)
static void run_gemm64(int Mi, int Ki,
                       const float* A, int lda, long long sA,
                       const float* Bm, int ldb, long long sB,
                       float* C, int ldc, long long sC, int batch)
{
    dim3 g(1, Mi/128, batch), t(128);
    gemm_tc64_kernel<<<g,t,SMEM_TC64_BYTES>>>(Ki,A,lda,sA,Bm,ldb,sB,C,ldc,sC);
}

static void setup_tc_attrs(){
    cudaFuncSetAttribute(gemm_tc_kernel<0,0>, cudaFuncAttributeMaxDynamicSharedMemorySize, SMEM_TC_BYTES);
    cudaFuncSetAttribute(gemm_tc_kernel<0,2>, cudaFuncAttributeMaxDynamicSharedMemorySize, SMEM_TC_BYTES);
    cudaFuncSetAttribute(gemm_tc_kernel<0,3>, cudaFuncAttributeMaxDynamicSharedMemorySize, SMEM_TC_BYTES);
    cudaFuncSetAttribute(gemm_tc_kernel<0,4>, cudaFuncAttributeMaxDynamicSharedMemorySize, SMEM_TC_BYTES);
    cudaFuncSetAttribute(gemm_tc_kernel<0,5>, cudaFuncAttributeMaxDynamicSharedMemorySize, SMEM_TC_BYTES);
    cudaFuncSetAttribute(gemm_tc_kernel<0,6>, cudaFuncAttributeMaxDynamicSharedMemorySize, SMEM_TC_BYTES);
    cudaFuncSetAttribute(gemm_tc_kernel<0,7>, cudaFuncAttributeMaxDynamicSharedMemorySize, SMEM_TC_BYTES);
    cudaFuncSetAttribute(gemm_tc_kernel<1,0>, cudaFuncAttributeMaxDynamicSharedMemorySize, SMEM_TC_BYTES);
    cudaFuncSetAttribute(gemm_tc64_kernel, cudaFuncAttributeMaxDynamicSharedMemorySize, SMEM_TC64_BYTES);
}

extern "C" void kernel_launch(void* const* d_in, const int* in_sizes, int n_in,
                              void* d_out, int out_size)
{
    (void)in_sizes; (void)n_in; (void)out_size;
    const int*   x       = (const int*)  d_in[0];
    const float* enc_emb = (const float*)d_in[1];
    const float* pos_emb = (const float*)d_in[2];
    const float* ln1_s   = (const float*)d_in[3];
    const float* ln1_b   = (const float*)d_in[4];
    const float* qkv_w   = (const float*)d_in[5];
    const float* aout_w  = (const float*)d_in[6];
    const float* aout_b  = (const float*)d_in[7];
    const float* conv_k  = (const float*)d_in[8];
    const float* ln2_s   = (const float*)d_in[9];
    const float* ln2_b   = (const float*)d_in[10];
    const float* ff_w1   = (const float*)d_in[11];
    const float* ff_b1   = (const float*)d_in[12];
    const float* ff_w2   = (const float*)d_in[13];
    const float* ff_b2   = (const float*)d_in[14];
    const float* fin_w   = (const float*)d_in[15];
    const float* fin_b   = (const float*)d_in[16];
    float* out = (float*)d_out;

    setup_tc_attrs();

    float *p_h,*p_x,*p_q,*p_k,*p_v,*p_ql,*p_kl,*p_a1,*p_a3,*p_a2;
    float *p_z,*p_z2,*p_p,*p_t,*p_t2,*p_kv,*p_zkv,*p_ao,*p_y,*p_x2,*p_ff;
    cudaGetSymbolAddress((void**)&p_h,  g_h);
    cudaGetSymbolAddress((void**)&p_x,  g_x);
    cudaGetSymbolAddress((void**)&p_q,  g_q);
    cudaGetSymbolAddress((void**)&p_k,  g_k);
    cudaGetSymbolAddress((void**)&p_v,  g_v);
    cudaGetSymbolAddress((void**)&p_ql, g_ql);
    cudaGetSymbolAddress((void**)&p_kl, g_kl);
    cudaGetSymbolAddress((void**)&p_a1, g_a1);
    cudaGetSymbolAddress((void**)&p_a3, g_a3);
    cudaGetSymbolAddress((void**)&p_a2, g_a2);
    cudaGetSymbolAddress((void**)&p_z,  g_zb);
    cudaGetSymbolAddress((void**)&p_z2, g_zb2);
    cudaGetSymbolAddress((void**)&p_p,  g_pb);
    cudaGetSymbolAddress((void**)&p_t,  g_tb);
    cudaGetSymbolAddress((void**)&p_t2, g_tb2);
    cudaGetSymbolAddress((void**)&p_kv, g_kvb);
    cudaGetSymbolAddress((void**)&p_zkv,g_zkv);
    cudaGetSymbolAddress((void**)&p_ao, g_ao);
    cudaGetSymbolAddress((void**)&p_y,  g_y);
    cudaGetSymbolAddress((void**)&p_x2, g_x2);
    cudaGetSymbolAddress((void**)&p_ff, g_ff);

    const long long MM  = (long long)ML*ML;
    const long long NM  = (long long)NPAD*ML;
    const long long ND  = (long long)NPAD*DHD;
    const long long MD  = (long long)ML*DHD;

    {
        long long tot = (long long)BATCH*LSEQ*DMODEL;
        embed_kernel<<<(unsigned)((tot+255)/256),256>>>(x, enc_emb, pos_emb);
        int tot2 = BATCH*PADL*DMODEL;
        zero_pad_kernel<<<(tot2+255)/256,256>>>();
    }

    for (int lay=0; lay<DEPTH; lay++){
        ln_kernel<<<BATCH*LSEQ,256>>>(p_h, p_x, ln1_s+(long long)lay*DMODEL, ln1_b+(long long)lay*DMODEL, 1);
        // QKV [tensor, fused split into q/k/v]
        run_gemm(0,7, BATCH*NPAD, 3*DMODEL, DMODEL,
                 p_x, DMODEL, 0,
                 qkv_w + (long long)lay*DMODEL*3*DMODEL, 3*DMODEL, 0,
                 p_q, 3*DMODEL, 0, 1, 1.f, nullptr, p_k, p_v);
        {
            long long tot2 = (long long)BH*ML*DHD;
            landmark_kernel<<<(unsigned)((tot2+255)/256),256>>>();
        }
        // attn1 = softmax(q @ kl^T)  [tensor TB=1]
        run_gemm(1,0, NPAD, ML, DHD, p_q, DHD, ND, p_kl, DHD, MD, p_a1, ML, NM, BH, 1.f, nullptr);
        softmax_kernel<<<BH*NPAD,128>>>(p_a1, ML);
        // attn2 = softmax(ql @ kl^T)  [tensor TB=1]
        run_gemm(1,0, ML, ML, DHD, p_ql, DHD, MD, p_kl, DHD, MD, p_a2, ML, MM, BH, 1.f, nullptr);
        softmax_kernel<<<BH*ML,128>>>(p_a2, ML);
        // attn3 = softmax(ql @ k^T)  [tensor TB=1]
        run_gemm(1,0, ML, NPAD, DHD, p_ql, DHD, MD, p_k, DHD, ND, p_a3, NPAD, (long long)ML*NPAD, BH, 1.f, nullptr);
        softmax_kernel<<<BH*ML,128>>>(p_a3, NPAD);

        // ---- pinv (tensor, fused aI-X epilogues) ----
        red_init_kernel<<<1,1>>>();
        colsum_kernel<<<(BH*ML+255)/256,256>>>();
        rowsum_kernel<<<(BH*ML+255)/256,256>>>();
        {
            long long tot = (long long)BH*ML*ML;
            unsigned g = (unsigned)((tot+255)/256);
            zinit_kernel<<<g,256>>>();
        }
        float* zc = p_z; float* zn = p_z2;
        for (int it=0; it<6; it++){
            run_gemm(0,6, ML, ML, ML, p_a2, ML, MM, zc, ML, MM, p_p, ML, MM, BH, 7.f, nullptr, p_t);
            run_gemm(0,5, ML, ML, ML, p_p, ML, MM, p_t, ML, MM, p_t2, ML, MM, BH, 15.f, nullptr);
            run_gemm(0,5, ML, ML, ML, p_p, ML, MM, p_t2, ML, MM, p_t, ML, MM, BH, 13.f, nullptr);
            run_gemm(0,0, ML, ML, ML, zc, ML, MM, p_t, ML, MM, zn, ML, MM, BH, 0.25f, nullptr);
            float* tmp = zc; zc = zn; zn = tmp;
        }

        // kv = attn3 @ v : 256x64, K=1024  [tensor N=64]
        run_gemm64(ML, NPAD, p_a3, NPAD, (long long)ML*NPAD, p_v, DHD, ND, p_kv, DHD, MD, BH);
        // zkv = Z @ kv : 256x64, K=256  [tensor N=64]  (reassociation)
        run_gemm64(ML, ML, zc, ML, MM, p_kv, DHD, MD, p_zkv, DHD, MD, BH);
        // ao = attn1 @ zkv : 1024x64, K=256  [tensor N=64]
        run_gemm64(NPAD, ML, p_a1, ML, NM, p_zkv, DHD, MD, p_ao, DHD, ND, BH);
        {
            long long tot = (long long)BH*NPAD*DHD;
            combine_kernel<<<(unsigned)((tot+255)/256),256>>>(conv_k + (long long)lay*NH*KC);
        }
        // out projection + residual [tensor]
        run_gemm(0,4, BATCH*NPAD, DMODEL, DMODEL,
                 p_y, DMODEL, 0,
                 aout_w + (long long)lay*DMODEL*DMODEL, DMODEL, 0,
                 p_h, DMODEL, 0, 1, 1.f, aout_b + (long long)lay*DMODEL);

        // ---- FFN ----
        ln_kernel<<<BATCH*LSEQ,256>>>(p_h, p_x2, ln2_s+(long long)lay*DMODEL, ln2_b+(long long)lay*DMODEL, 0);
        run_gemm(0,2, BATCH*LSEQ, FFD, DMODEL,
                 p_x2, DMODEL, 0,
                 ff_w1 + (long long)lay*DMODEL*FFD, FFD, 0,
                 p_ff, FFD, 0, 1, 1.f, ff_b1 + (long long)lay*FFD);
        run_gemm(0,3, BATCH*LSEQ, DMODEL, FFD,
                 p_ff, FFD, 0,
                 ff_w2 + (long long)lay*FFD*DMODEL, DMODEL, 0,
                 p_h, DMODEL, 0, 1, 1.f, ff_b2 + (long long)lay*DMODEL);
    }

    final_kernel<<<BATCH,256>>>(fin_w, fin_b, out);
}

// round 10
// speedup vs baseline: 1.4295x; 1.1371x over previous
#include <cuda_runtime.h>
#include <cuda_bf16.h>
#include <math.h>
#include <stdint.h>

// ---------------- model constants ----------------
#define BATCH 16
#define LSEQ  1000
#define DMODEL 512
#define NH    8
#define DHD   64
#define NPAD  1024
#define PADL  24
#define ML    256
#define LMR   4
#define FFD   2048
#define DEPTH 6
#define KC    33
#define QSCALE 0.125f
#define BH (BATCH*NH)

// ---------------- scratch ----------------
__device__ float g_h   [BATCH*LSEQ*DMODEL];
__device__ float g_x   [BATCH*NPAD*DMODEL];
__device__ float g_q   [BH*NPAD*DHD];
__device__ float g_k   [BH*NPAD*DHD];
__device__ float g_v   [BH*NPAD*DHD];
__device__ float g_ql  [BH*ML*DHD];
__device__ float g_kl  [BH*ML*DHD];
__device__ float g_a1  [BH*NPAD*ML];
__device__ float g_a3  [BH*ML*NPAD];
__device__ float g_a2  [BH*ML*ML];
__device__ float g_zb  [BH*ML*ML];
__device__ float g_zb2 [BH*ML*ML];
__device__ float g_pb  [BH*ML*ML];
__device__ float g_tb  [BH*ML*ML];
__device__ float g_tb2 [BH*ML*ML];
__device__ float g_kvb [BH*ML*DHD];
__device__ float g_zkv [BH*ML*DHD];
__device__ float g_ao  [BH*NPAD*DHD];
__device__ float g_y   [BATCH*NPAD*DMODEL];
__device__ float g_x2  [BATCH*LSEQ*DMODEL];
__device__ float g_ff  [BATCH*LSEQ*FFD];
__device__ int   g_red [2];
// bf16 shadows for pinv
__device__ __nv_bfloat16 g_a2h [BH*ML*ML];
__device__ __nv_bfloat16 g_zh  [BH*ML*ML];
__device__ __nv_bfloat16 g_zh2 [BH*ML*ML];
__device__ __nv_bfloat16 g_ph  [BH*ML*ML];
__device__ __nv_bfloat16 g_th  [BH*ML*ML];
__device__ __nv_bfloat16 g_t2h [BH*ML*ML];

// ---------------- reductions ----------------
__device__ __forceinline__ float warpSum(float v){
    #pragma unroll
    for (int o=16;o;o>>=1) v += __shfl_xor_sync(0xffffffffu, v, o);
    return v;
}
__device__ __forceinline__ float warpMax(float v){
    #pragma unroll
    for (int o=16;o;o>>=1) v = fmaxf(v, __shfl_xor_sync(0xffffffffu, v, o));
    return v;
}
__device__ __forceinline__ float blockSumN(float v, float* sh, int nw){
    int w = threadIdx.x>>5, l = threadIdx.x&31;
    v = warpSum(v);
    if (l==0) sh[w] = v;
    __syncthreads();
    if (w==0){
        float x = (l < nw) ? sh[l] : 0.f;
        x = warpSum(x);
        if (l==0) sh[0] = x;
    }
    __syncthreads();
    float r = sh[0];
    __syncthreads();
    return r;
}
__device__ __forceinline__ float blockMaxN(float v, float* sh, int nw){
    int w = threadIdx.x>>5, l = threadIdx.x&31;
    v = warpMax(v);
    if (l==0) sh[w] = v;
    __syncthreads();
    if (w==0){
        float x = (l < nw) ? sh[l] : -3.4e38f;
        x = warpMax(x);
        if (l==0) sh[0] = x;
    }
    __syncthreads();
    float r = sh[0];
    __syncthreads();
    return r;
}

// ---------------- mma / cp.async / ldmatrix helpers ----------------
__device__ __forceinline__ void mma_tf32(float c[4],
    unsigned a0, unsigned a1, unsigned a2, unsigned a3,
    unsigned b0, unsigned b1)
{
    asm volatile(
        "mma.sync.aligned.m16n8k8.row.col.f32.tf32.tf32.f32 "
        "{%0,%1,%2,%3}, {%4,%5,%6,%7}, {%8,%9}, {%0,%1,%2,%3};"
        : "+f"(c[0]), "+f"(c[1]), "+f"(c[2]), "+f"(c[3])
        : "r"(a0), "r"(a1), "r"(a2), "r"(a3), "r"(b0), "r"(b1));
}
__device__ __forceinline__ void mma_bf16(float c[4],
    unsigned a0, unsigned a1, unsigned a2, unsigned a3,
    unsigned b0, unsigned b1)
{
    asm volatile(
        "mma.sync.aligned.m16n8k16.row.col.f32.bf16.bf16.f32 "
        "{%0,%1,%2,%3}, {%4,%5,%6,%7}, {%8,%9}, {%0,%1,%2,%3};"
        : "+f"(c[0]), "+f"(c[1]), "+f"(c[2]), "+f"(c[3])
        : "r"(a0), "r"(a1), "r"(a2), "r"(a3), "r"(b0), "r"(b1));
}
__device__ __forceinline__ void cp16(unsigned saddr, const void* gptr){
    asm volatile("cp.async.cg.shared.global [%0], [%1], 16;\n"
                 :: "r"(saddr), "l"(gptr));
}
__device__ __forceinline__ void cp_commit(){
    asm volatile("cp.async.commit_group;\n");
}
template<int N>
__device__ __forceinline__ void cp_wait(){
    asm volatile("cp.async.wait_group %0;\n" :: "n"(N));
}
__device__ __forceinline__ void ldsm4(unsigned &r0, unsigned &r1,
                                      unsigned &r2, unsigned &r3,
                                      unsigned addr){
    asm volatile("ldmatrix.sync.aligned.m8n8.x4.shared.b16 {%0,%1,%2,%3}, [%4];"
        : "=r"(r0), "=r"(r1), "=r"(r2), "=r"(r3) : "r"(addr));
}
__device__ __forceinline__ void ldsm4t(unsigned &r0, unsigned &r1,
                                       unsigned &r2, unsigned &r3,
                                       unsigned addr){
    asm volatile("ldmatrix.sync.aligned.m8n8.x4.trans.shared.b16 {%0,%1,%2,%3}, [%4];"
        : "=r"(r0), "=r"(r1), "=r"(r2), "=r"(r3) : "r"(addr));
}

// epilogue (tf32 kernels): writes 2 consecutive cols at (r, cc)
template<int EPI>
__device__ __forceinline__ void store2(
    float* __restrict__ C, float* __restrict__ C2, float* __restrict__ C3,
    int ldc, int r, int cc, float v0, float v1,
    float alpha, const float* __restrict__ bias)
{
    if (EPI==0){
        float2 o = {alpha*v0, alpha*v1};
        *(float2*)&C[(long long)r*ldc + cc] = o;
    } else if (EPI==2){
        float x0 = v0 + bias[cc], x1 = v1 + bias[cc+1];
        float2 o;
        o.x = 0.5f*x0*(1.f+erff(x0*0.70710678118654752f));
        o.y = 0.5f*x1*(1.f+erff(x1*0.70710678118654752f));
        *(float2*)&C[(long long)r*ldc + cc] = o;
    } else if (EPI==3){
        float2 o = *(float2*)&C[(long long)r*ldc + cc];
        o.x += v0 + bias[cc];
        o.y += v1 + bias[cc+1];
        *(float2*)&C[(long long)r*ldc + cc] = o;
    } else if (EPI==4){
        int bb = r / NPAD, nl = r % NPAD;
        if (nl >= PADL){
            long long orow = (long long)bb*LSEQ + (nl - PADL);
            float2 o = *(float2*)&C[orow*ldc + cc];
            o.x += v0 + bias[cc];
            o.y += v1 + bias[cc+1];
            *(float2*)&C[orow*ldc + cc] = o;
        }
    } else if (EPI==5){
        float2 o = {(r==cc ? alpha : 0.f) - v0, (r==cc+1 ? alpha : 0.f) - v1};
        *(float2*)&C[(long long)r*ldc + cc] = o;
    } else if (EPI==6){
        float2 o = {v0, v1};
        *(float2*)&C[(long long)r*ldc + cc] = o;
        float2 o2 = {(r==cc ? alpha : 0.f) - v0, (r==cc+1 ? alpha : 0.f) - v1};
        *(float2*)&C2[(long long)r*ldc + cc] = o2;
    } else if (EPI==7){
        int b = r >> 10, n = r & 1023;
        int which = cc >> 9;
        int hd = cc & 511;
        long long idx = ((((long long)b*NH + (hd>>6))*NPAD) + n)*DHD + (hd&63);
        float2 o;
        if (which==0){ o.x = v0*QSCALE; o.y = v1*QSCALE; *(float2*)&C[idx] = o; }
        else if (which==1){ o.x = v0; o.y = v1; *(float2*)&C2[idx] = o; }
        else { o.x = v0; o.y = v1; *(float2*)&C3[idx] = o; }
    }
}

// == TF32 tensor GEMM: 256 thr, CTA 128x256, warp 64x64, LDSM, 3-stage =====
#define AS_STRIDE 20
#define AS_ST     (128*AS_STRIDE)
#define BS0_STRIDE 264
#define BS1_STRIDE 20
#define BS_ST     (256*BS1_STRIDE)
#define NSTAGE 3
#define SMEM_TC_BYTES (NSTAGE*(AS_ST + BS_ST)*4)   // 92160

template<int TB, int EPI>
__global__ void __launch_bounds__(256,1) gemm_tc_kernel(
    int Ki,
    const float* __restrict__ A, int lda, long long sA,
    const float* __restrict__ Bm, int ldb, long long sB,
    float* __restrict__ C, int ldc, long long sC,
    float alpha, const float* __restrict__ bias,
    float* __restrict__ C2, float* __restrict__ C3)
{
    extern __shared__ unsigned sm[];
    unsigned* As = sm;
    unsigned* Bs = sm + NSTAGE*AS_ST;
    const unsigned As_base = (unsigned)__cvta_generic_to_shared(As);
    const unsigned Bs_base = (unsigned)__cvta_generic_to_shared(Bs);

    const int bz = blockIdx.z;
    A  += (long long)bz*sA;
    Bm += (long long)bz*sB;
    C  += (long long)bz*sC;
    if (EPI==6) C2 += (long long)bz*sC;

    const int row0 = blockIdx.y*128;
    const int col0 = blockIdx.x*256;
    const int tid = threadIdx.x;
    const int warp = tid>>5, lane = tid&31;
    const int wm = warp & 1, wn = warp >> 1;
    const int g = lane>>2, qc = lane&3;

    const int a_r  = tid>>1;
    const int a_c2 = (tid&1)<<1;

    auto issue = [&](int kt, int st){
        unsigned abase = As_base + (unsigned)(st*AS_ST)*4u;
        #pragma unroll
        for (int i=0;i<2;i++)
            cp16(abase + (unsigned)(a_r*AS_STRIDE + (a_c2+i)*4)*4u,
                 A + (long long)(row0 + a_r)*lda + kt + (a_c2+i)*4);
        unsigned bbase = Bs_base + (unsigned)(st*BS_ST)*4u;
        if (TB==0){
            #pragma unroll
            for (int i=0;i<4;i++){
                int fidx = tid + i*256;
                int bk = fidx>>6, bn4 = (fidx&63)<<2;
                cp16(bbase + (unsigned)(bk*BS0_STRIDE + bn4)*4u,
                     Bm + (long long)(kt + bk)*ldb + col0 + bn4);
            }
        } else {
            #pragma unroll
            for (int i=0;i<4;i++){
                int fidx = tid + i*256;
                int bn = fidx>>2, bc4 = (fidx&3)<<2;
                cp16(bbase + (unsigned)(bn*BS1_STRIDE + bc4)*4u,
                     Bm + (long long)(col0 + bn)*ldb + kt + bc4);
            }
        }
    };

    float acc[4][8][4];
    #pragma unroll
    for (int mt=0;mt<4;mt++)
        #pragma unroll
        for (int nt=0;nt<8;nt++)
            #pragma unroll
            for (int i=0;i<4;i++) acc[mt][nt][i]=0.f;

    const int nk = Ki >> 4;
    issue(0, 0);  cp_commit();
    issue(16, 1); cp_commit();

    const int lane8 = lane & 7;
    const int a_lrow = wm*64 + lane8 + ((lane>>3)&1)*8;
    const int a_lw   = ((lane>>4)&1)*4;
    const int b_lrow = wn*64 + lane8 + ((lane>>4)&1)*8;
    const int b_lw   = ((lane>>3)&1)*4;
    const int b0_frag_off = qc*BS0_STRIDE + wn*64 + g;

    for (int t = 0; t < nk; ++t){
        cp_wait<1>();
        __syncthreads();
        const int rb = t % NSTAGE;
        if (t+2 < nk) issue((t+2)<<4, (t+2)%NSTAGE);
        cp_commit();

        const unsigned a_stage = As_base + (unsigned)(rb*AS_ST)*4u;
        const unsigned b_stage = Bs_base + (unsigned)(rb*BS_ST)*4u;

        #pragma unroll
        for (int grp=0; grp<2; grp++){
            const int koff = grp*8;
            unsigned af[4][4], bf[8][2];
            #pragma unroll
            for (int mt=0;mt<4;mt++)
                ldsm4(af[mt][0], af[mt][1], af[mt][2], af[mt][3],
                      a_stage + (unsigned)(((a_lrow + mt*16)*AS_STRIDE) + a_lw + koff)*4u);
            if (TB==0){
                const unsigned* Bb = Bs + rb*BS_ST + b0_frag_off + koff*BS0_STRIDE;
                #pragma unroll
                for (int nt=0;nt<8;nt++){
                    bf[nt][0] = Bb[nt*8];
                    bf[nt][1] = Bb[4*BS0_STRIDE + nt*8];
                }
            } else {
                #pragma unroll
                for (int np=0;np<4;np++)
                    ldsm4(bf[2*np][0], bf[2*np][1], bf[2*np+1][0], bf[2*np+1][1],
                          b_stage + (unsigned)(((b_lrow + np*16)*BS1_STRIDE) + b_lw + koff)*4u);
            }
            #pragma unroll
            for (int mt=0;mt<4;mt++)
                #pragma unroll
                for (int nt=0;nt<8;nt++)
                    mma_tf32(acc[mt][nt], af[mt][0],af[mt][1],af[mt][2],af[mt][3],
                             bf[nt][0],bf[nt][1]);
        }
    }

    #pragma unroll
    for (int mt=0;mt<4;mt++){
        int r = row0 + wm*64 + mt*16 + g;
        #pragma unroll
        for (int nt=0;nt<8;nt++){
            int cc = col0 + wn*64 + nt*8 + 2*qc;
            store2<EPI>(C, C2, C3, ldc, r,   cc, acc[mt][nt][0], acc[mt][nt][1], alpha, bias);
            store2<EPI>(C, C2, C3, ldc, r+8, cc, acc[mt][nt][2], acc[mt][nt][3], alpha, bias);
        }
    }
}

// ==== BF16 batched GEMM for pinv: 256x256x256, CTA 128x256, warp 64x64 ====
// A,B bf16 [256,256] rm per batch. fp32 accumulate.
// EPI 0: Cb = bf16(alpha*val)
// EPI 1: Cf = alpha*val (fp32)
// EPI 5: Cb = bf16(alpha*I - val)
// EPI 6: Cb = bf16(val); C2b = bf16(alpha*I - val)
#define ASH 40
#define AH_ST (128*ASH)          // 5120 bf16
#define BSH 264
#define BH_ST (32*BSH)           // 8448 bf16
#define SMEM_BF_BYTES (NSTAGE*(AH_ST + BH_ST)*2)   // 81408

template<int EPI>
__global__ void __launch_bounds__(256,1) gemm_bf16_kernel(
    const __nv_bfloat16* __restrict__ A,
    const __nv_bfloat16* __restrict__ Bm,
    __nv_bfloat16* __restrict__ Cb,
    __nv_bfloat16* __restrict__ C2b,
    float* __restrict__ Cf,
    float alpha)
{
    extern __shared__ __nv_bfloat16 smh[];
    const unsigned As_base = (unsigned)__cvta_generic_to_shared(smh);
    const unsigned Bs_base = As_base + NSTAGE*AH_ST*2u;

    const long long boff = (long long)blockIdx.z * (ML*ML);
    A  += boff; Bm += boff;

    const int row0 = blockIdx.y*128;
    const int tid = threadIdx.x;
    const int warp = tid>>5, lane = tid&31;
    const int wm = warp & 1, wn = warp >> 1;   // 2x4, warp tile 64x64
    const int g = lane>>2, qc = lane&3;

    auto issue = [&](int kt, int st){
        unsigned abase = As_base + (unsigned)(st*AH_ST)*2u;
        #pragma unroll
        for (int i=0;i<2;i++){
            int r = tid>>1, ch = ((tid&1)<<1) + i;          // 16B chunks (8 bf16)
            cp16(abase + (unsigned)(r*ASH + ch*8)*2u,
                 A + (long long)(row0 + r)*ML + kt + ch*8);
        }
        unsigned bbase = Bs_base + (unsigned)(st*BH_ST)*2u;
        #pragma unroll
        for (int i=0;i<4;i++){
            int fidx = tid + i*256;
            int r = fidx>>5, ch = fidx&31;
            cp16(bbase + (unsigned)(r*BSH + ch*8)*2u,
                 Bm + (long long)(kt + r)*ML + ch*8);
        }
    };

    float acc[4][8][4];
    #pragma unroll
    for (int mt=0;mt<4;mt++)
        #pragma unroll
        for (int nt=0;nt<8;nt++)
            #pragma unroll
            for (int i=0;i<4;i++) acc[mt][nt][i]=0.f;

    const int nk = ML >> 5;    // 8 k32 tiles
    issue(0, 0);  cp_commit();
    issue(32, 1); cp_commit();

    const int lane8 = lane & 7;
    const int a_row = wm*64 + lane8 + ((lane>>3)&1)*8;   // + mt*16
    const int a_col = ((lane>>4)&1)*8;                   // + k16 offset
    const int b_row = lane8 + ((lane>>3)&1)*8;           // + k16 offset (k rows)
    const int b_col = ((lane>>4)&1)*8;                   // + n0

    for (int t = 0; t < nk; ++t){
        cp_wait<1>();
        __syncthreads();
        const int rb = t % NSTAGE;
        if (t+2 < nk) issue((t+2)<<5, (t+2)%NSTAGE);
        cp_commit();

        const unsigned a_st = As_base + (unsigned)(rb*AH_ST)*2u;
        const unsigned b_st = Bs_base + (unsigned)(rb*BH_ST)*2u;

        #pragma unroll
        for (int kk=0; kk<2; kk++){
            const int k0 = kk*16;
            unsigned af[4][4], bf[8][2];
            #pragma unroll
            for (int mt=0;mt<4;mt++)
                ldsm4(af[mt][0], af[mt][1], af[mt][2], af[mt][3],
                      a_st + (unsigned)((a_row + mt*16)*ASH + k0 + a_col)*2u);
            #pragma unroll
            for (int np=0;np<4;np++)
                ldsm4t(bf[2*np][0], bf[2*np][1], bf[2*np+1][0], bf[2*np+1][1],
                       b_st + (unsigned)((k0 + b_row)*BSH + wn*64 + np*16 + b_col)*2u);
            #pragma unroll
            for (int mt=0;mt<4;mt++)
                #pragma unroll
                for (int nt=0;nt<8;nt++)
                    mma_bf16(acc[mt][nt], af[mt][0],af[mt][1],af[mt][2],af[mt][3],
                             bf[nt][0],bf[nt][1]);
        }
    }

    // epilogue
    #pragma unroll
    for (int mt=0;mt<4;mt++){
        #pragma unroll
        for (int half=0; half<2; half++){
            int r = row0 + wm*64 + mt*16 + g + half*8;
            #pragma unroll
            for (int nt=0;nt<8;nt++){
                int cc = wn*64 + nt*8 + 2*qc;
                float v0 = acc[mt][nt][2*half+0];
                float v1 = acc[mt][nt][2*half+1];
                long long idx = boff + (long long)r*ML + cc;
                if (EPI==0){
                    __nv_bfloat162 pk;
                    pk.x = __float2bfloat16(alpha*v0);
                    pk.y = __float2bfloat16(alpha*v1);
                    *(__nv_bfloat162*)&Cb[idx] = pk;
                } else if (EPI==1){
                    float2 o = {alpha*v0, alpha*v1};
                    *(float2*)&Cf[idx] = o;
                } else if (EPI==5){
                    __nv_bfloat162 pk;
                    pk.x = __float2bfloat16((r==cc   ? alpha : 0.f) - v0);
                    pk.y = __float2bfloat16((r==cc+1 ? alpha : 0.f) - v1);
                    *(__nv_bfloat162*)&Cb[idx] = pk;
                } else if (EPI==6){
                    __nv_bfloat162 pk;
                    pk.x = __float2bfloat16(v0);
                    pk.y = __float2bfloat16(v1);
                    *(__nv_bfloat162*)&Cb[idx] = pk;
                    __nv_bfloat162 pk2;
                    pk2.x = __float2bfloat16((r==cc   ? alpha : 0.f) - v0);
                    pk2.y = __float2bfloat16((r==cc+1 ? alpha : 0.f) - v1);
                    *(__nv_bfloat162*)&C2b[idx] = pk2;
                }
            }
        }
    }
}

// ==== TF32 tensor GEMM N=64: 128 thr, CTA 128x64, warp 64x32, 3-stage =====
#define BS64_STRIDE 72
#define BS64_ST     (16*BS64_STRIDE)
#define SMEM_TC64_BYTES (NSTAGE*(AS_ST + BS64_ST)*4)

__global__ void __launch_bounds__(128) gemm_tc64_kernel(
    int Ki,
    const float* __restrict__ A, int lda, long long sA,
    const float* __restrict__ Bm, int ldb, long long sB,
    float* __restrict__ C, int ldc, long long sC)
{
    extern __shared__ unsigned sm[];
    unsigned* As = sm;
    unsigned* Bs = sm + NSTAGE*AS_ST;
    const unsigned As_base = (unsigned)__cvta_generic_to_shared(As);
    const unsigned Bs_base = (unsigned)__cvta_generic_to_shared(Bs);

    const int bz = blockIdx.z;
    A  += (long long)bz*sA;
    Bm += (long long)bz*sB;
    C  += (long long)bz*sC;

    const int row0 = blockIdx.y*128;
    const int tid = threadIdx.x;
    const int warp = tid>>5, lane = tid&31;
    const int wm = warp & 1, wn = warp >> 1;
    const int g = lane>>2, qc = lane&3;

    auto issue = [&](int kt, int st){
        unsigned abase = As_base + (unsigned)(st*AS_ST)*4u;
        #pragma unroll
        for (int i=0;i<4;i++){
            int fidx = tid + i*128;
            int a_r = fidx>>2, a_c4 = (fidx&3)<<2;
            cp16(abase + (unsigned)(a_r*AS_STRIDE + a_c4)*4u,
                 A + (long long)(row0 + a_r)*lda + kt + a_c4);
        }
        unsigned bbase = Bs_base + (unsigned)(st*BS64_ST)*4u;
        #pragma unroll
        for (int i=0;i<2;i++){
            int fidx = tid + i*128;
            int bk = fidx>>4, bn4 = (fidx&15)<<2;
            cp16(bbase + (unsigned)(bk*BS64_STRIDE + bn4)*4u,
                 Bm + (long long)(kt + bk)*ldb + bn4);
        }
    };

    float acc[4][4][4];
    #pragma unroll
    for (int mt=0;mt<4;mt++)
        #pragma unroll
        for (int nt=0;nt<4;nt++)
            #pragma unroll
            for (int i=0;i<4;i++) acc[mt][nt][i]=0.f;

    const int nk = Ki >> 4;
    issue(0, 0);  cp_commit();
    issue(16, 1); cp_commit();

    const int lane8 = lane & 7;
    const int a_lrow = wm*64 + lane8 + ((lane>>3)&1)*8;
    const int a_lw   = ((lane>>4)&1)*4;
    const int b_frag_off = qc*BS64_STRIDE + wn*32 + g;

    for (int t = 0; t < nk; ++t){
        cp_wait<1>();
        __syncthreads();
        const int rb = t % NSTAGE;
        if (t+2 < nk) issue((t+2)<<4, (t+2)%NSTAGE);
        cp_commit();

        const unsigned a_stage = As_base + (unsigned)(rb*AS_ST)*4u;

        #pragma unroll
        for (int grp=0; grp<2; grp++){
            const int koff = grp*8;
            unsigned af[4][4], bf[4][2];
            #pragma unroll
            for (int mt=0;mt<4;mt++)
                ldsm4(af[mt][0], af[mt][1], af[mt][2], af[mt][3],
                      a_stage + (unsigned)(((a_lrow + mt*16)*AS_STRIDE) + a_lw + koff)*4u);
            const unsigned* Bb = Bs + rb*BS64_ST + b_frag_off + koff*BS64_STRIDE;
            #pragma unroll
            for (int nt=0;nt<4;nt++){
                bf[nt][0] = Bb[nt*8];
                bf[nt][1] = Bb[4*BS64_STRIDE + nt*8];
            }
            #pragma unroll
            for (int mt=0;mt<4;mt++)
                #pragma unroll
                for (int nt=0;nt<4;nt++)
                    mma_tf32(acc[mt][nt], af[mt][0],af[mt][1],af[mt][2],af[mt][3],
                             bf[nt][0],bf[nt][1]);
        }
    }

    #pragma unroll
    for (int mt=0;mt<4;mt++){
        int r = row0 + wm*64 + mt*16 + g;
        #pragma unroll
        for (int nt=0;nt<4;nt++){
            int cc = wn*32 + nt*8 + 2*qc;
            float2 o0 = {acc[mt][nt][0], acc[mt][nt][1]};
            float2 o1 = {acc[mt][nt][2], acc[mt][nt][3]};
            *(float2*)&C[(long long)r*ldc + cc] = o0;
            *(float2*)&C[(long long)(r+8)*ldc + cc] = o1;
        }
    }
}

// ---------------- elementwise / small kernels ----------------
__global__ void embed_kernel(const int* __restrict__ x,
                             const float* __restrict__ emb,
                             const float* __restrict__ pos){
    long long idx = (long long)blockIdx.x*blockDim.x + threadIdx.x;
    if (idx >= (long long)BATCH*LSEQ*DMODEL) return;
    int d = (int)(idx % DMODEL);
    long long bl = idx / DMODEL;
    int l = (int)(bl % LSEQ);
    int tok = x[bl];
    g_h[idx] = emb[(long long)tok*DMODEL + d] + pos[(long long)l*DMODEL + d];
}

__global__ void zero_pad_kernel(){
    int idx = blockIdx.x*blockDim.x + threadIdx.x;
    if (idx >= BATCH*PADL*DMODEL) return;
    int d  = idx % DMODEL;
    int bp = idx / DMODEL;
    int b  = bp / PADL, p = bp % PADL;
    g_x[((long long)b*NPAD + p)*DMODEL + d] = 0.f;
}

__global__ void ln_kernel(const float* __restrict__ in, float* __restrict__ out,
                          const float* __restrict__ gm, const float* __restrict__ bt,
                          int padmode){
    __shared__ float sh[8];
    int r = blockIdx.x;
    int t = threadIdx.x;
    const float* p = in + (long long)r*DMODEL;
    float a  = p[t];
    float b2 = p[t+256];
    float s  = blockSumN(a+b2, sh, 8);
    float mu = s * (1.f/512.f);
    float da = a - mu, db = b2 - mu;
    float v  = blockSumN(da*da + db*db, sh, 8) * (1.f/512.f);
    float rstd = rsqrtf(v + 1e-5f);
    long long orow = padmode ? ((long long)(r/LSEQ)*NPAD + PADL + (r%LSEQ)) : (long long)r;
    float* q = out + orow*DMODEL;
    q[t]     = da*rstd*gm[t]     + bt[t];
    q[t+256] = db*rstd*gm[t+256] + bt[t+256];
}

__global__ void landmark_kernel(){
    long long idx = (long long)blockIdx.x*blockDim.x + threadIdx.x;
    if (idx >= (long long)BH*ML*DHD) return;
    int d = (int)(idx & 63);
    long long r = idx >> 6;
    int m  = (int)(r % ML);
    int bh = (int)(r / ML);
    long long base = ((long long)bh*NPAD + (long long)m*LMR)*DHD + d;
    float sq = 0.f, sk = 0.f;
    #pragma unroll
    for (int j=0;j<LMR;j++){ sq += g_q[base + (long long)j*DHD]; sk += g_k[base + (long long)j*DHD]; }
    g_ql[idx] = sq * 0.25f;
    g_kl[idx] = sk * 0.25f;
}

__global__ void softmax_kernel(float* __restrict__ X, int cols){
    __shared__ float sh[4];
    long long row = blockIdx.x;
    float* p = X + row*(long long)cols;
    int t = threadIdx.x;
    int cnt = cols >> 7;
    float v[8];
    float mx = -3.4e38f;
    #pragma unroll
    for (int i=0;i<8;i++) if (i<cnt){ v[i]=p[t + (i<<7)]; mx = fmaxf(mx, v[i]); }
    mx = blockMaxN(mx, sh, 4);
    float s = 0.f;
    #pragma unroll
    for (int i=0;i<8;i++) if (i<cnt){ v[i]=expf(v[i]-mx); s += v[i]; }
    s = blockSumN(s, sh, 4);
    float inv = 1.f/s;
    #pragma unroll
    for (int i=0;i<8;i++) if (i<cnt) p[t + (i<<7)] = v[i]*inv;
}

__global__ void red_init_kernel(){ g_red[0]=0; g_red[1]=0; }

__global__ void colsum_kernel(){
    int idx = blockIdx.x*blockDim.x + threadIdx.x;
    if (idx >= BH*ML) return;
    int c  = idx % ML;
    int bz = idx / ML;
    const float* p = g_a2 + (long long)bz*ML*ML + c;
    float s = 0.f;
    for (int r2=0;r2<ML;r2++) s += fabsf(p[(long long)r2*ML]);
    atomicMax(&g_red[0], __float_as_int(s));
}
__global__ void rowsum_kernel(){
    int idx = blockIdx.x*blockDim.x + threadIdx.x;
    if (idx >= BH*ML) return;
    int r2 = idx % ML;
    int bz = idx / ML;
    const float* p = g_a2 + (long long)bz*ML*ML + (long long)r2*ML;
    float s = 0.f;
    for (int c=0;c<ML;c++) s += fabsf(p[c]);
    atomicMax(&g_red[1], __float_as_int(s));
}
// Z0 = A2^T / c, dual fp32 + bf16; also bf16 shadow of A2
__global__ void zinit_kernel(){
    long long idx = (long long)blockIdx.x*blockDim.x + threadIdx.x;
    if (idx >= (long long)BH*ML*ML) return;
    int j = (int)(idx % ML);
    long long r = idx / ML;
    int i  = (int)(r % ML);
    int bz = (int)(r / ML);
    float c = __int_as_float(g_red[0]) * __int_as_float(g_red[1]);
    float val = g_a2[((long long)bz*ML + j)*ML + i] / c;
    g_zb[idx] = val;
    g_zh[idx] = __float2bfloat16(val);
    g_a2h[idx] = __float2bfloat16(g_a2[idx]);
}

__global__ void combine_kernel(const float* __restrict__ cw){
    long long idx = (long long)blockIdx.x*blockDim.x + threadIdx.x;
    if (idx >= (long long)BH*NPAD*DHD) return;
    int d = (int)(idx & 63);
    long long r = idx >> 6;
    int n  = (int)(r % NPAD);
    int bh = (int)(r / NPAD);
    int h  = bh % NH, b = bh / NH;
    float s = g_ao[idx];
    const float* w  = cw + h*KC;
    const float* vp = g_v + ((long long)bh*NPAD)*DHD + d;
    int k0 = (16-n > 0) ? (16-n) : 0;
    int k1 = (NPAD+16-n < KC) ? (NPAD+16-n) : KC;
    for (int kk=k0; kk<k1; kk++)
        s = fmaf(vp[(long long)(n+kk-16)*DHD], w[kk], s);
    g_y[((long long)b*NPAD + n)*DMODEL + h*DHD + d] = s;
}

__global__ void final_kernel(const float* __restrict__ fw,
                             const float* __restrict__ fb,
                             float* __restrict__ out){
    __shared__ float sh[8];
    int b = blockIdx.x;
    int t = threadIdx.x;
    const float* hp = g_h + (long long)b*LSEQ*DMODEL;
    float s = 0.f;
    for (long long i=t; i<(long long)LSEQ*DMODEL; i+=256)
        s = fmaf(hp[i], fw[i], s);
    s = blockSumN(s, sh, 8);
    if (t==0) out[b] = s + fb[0];
}

// ---------------- host-side GEMM dispatch ----------------
static void run_gemm(int tb, int epi, int Mi, int Ni, int Ki,
                     const float* A, int lda, long long sA,
                     const float* Bm, int ldb, long long sB,
                     float* C, int ldc, long long sC,
                     int batch, float alpha, const float* bias,
                     float* C2 = nullptr, float* C3 = nullptr)
{
    dim3 g(Ni/256, Mi/128, batch), t(256);
    size_t sh = SMEM_TC_BYTES;
    if (tb == 0) {
        switch (epi) {
            case 0: gemm_tc_kernel<0,0><<<g,t,sh>>>(Ki,A,lda,sA,Bm,ldb,sB,C,ldc,sC,alpha,bias,C2,C3); break;
            case 2: gemm_tc_kernel<0,2><<<g,t,sh>>>(Ki,A,lda,sA,Bm,ldb,sB,C,ldc,sC,alpha,bias,C2,C3); break;
            case 3: gemm_tc_kernel<0,3><<<g,t,sh>>>(Ki,A,lda,sA,Bm,ldb,sB,C,ldc,sC,alpha,bias,C2,C3); break;
            case 4: gemm_tc_kernel<0,4><<<g,t,sh>>>(Ki,A,lda,sA,Bm,ldb,sB,C,ldc,sC,alpha,bias,C2,C3); break;
            case 5: gemm_tc_kernel<0,5><<<g,t,sh>>>(Ki,A,lda,sA,Bm,ldb,sB,C,ldc,sC,alpha,bias,C2,C3); break;
            case 6: gemm_tc_kernel<0,6><<<g,t,sh>>>(Ki,A,lda,sA,Bm,ldb,sB,C,ldc,sC,alpha,bias,C2,C3); break;
            case 7: gemm_tc_kernel<0,7><<<g,t,sh>>>(Ki,A,lda,sA,Bm,ldb,sB,C,ldc,sC,alpha,bias,C2,C3); break;
        }
    } else {
        gemm_tc_kernel<1,0><<<g,t,sh>>>(Ki,A,lda,sA,Bm,ldb,sB,C,ldc,sC,alpha,bias,C2,C3);
    }
}

static void run_gemm64(int Mi, int Ki,
                       const float* A, int lda, long long sA,
                       const float* Bm, int ldb, long long sB,
                       float* C, int ldc, long long sC, int batch)
{
    dim3 g(1, Mi/128, batch), t(128);
    gemm_tc64_kernel<<<g,t,SMEM_TC64_BYTES>>>(Ki,A,lda,sA,Bm,ldb,sB,C,ldc,sC);
}

static void run_gemm_bf16(int epi,
                          const __nv_bfloat16* A, const __nv_bfloat16* Bm,
                          __nv_bfloat16* Cb, __nv_bfloat16* C2b, float* Cf,
                          float alpha)
{
    dim3 g(1, ML/128, BH), t(256);
    size_t sh = SMEM_BF_BYTES;
    switch (epi) {
        case 0: gemm_bf16_kernel<0><<<g,t,sh>>>(A,Bm,Cb,C2b,Cf,alpha); break;
        case 1: gemm_bf16_kernel<1><<<g,t,sh>>>(A,Bm,Cb,C2b,Cf,alpha); break;
        case 5: gemm_bf16_kernel<5><<<g,t,sh>>>(A,Bm,Cb,C2b,Cf,alpha); break;
        case 6: gemm_bf16_kernel<6><<<g,t,sh>>>(A,Bm,Cb,C2b,Cf,alpha); break;
    }
}

static void setup_tc_attrs(){
    cudaFuncSetAttribute(gemm_tc_kernel<0,0>, cudaFuncAttributeMaxDynamicSharedMemorySize, SMEM_TC_BYTES);
    cudaFuncSetAttribute(gemm_tc_kernel<0,2>, cudaFuncAttributeMaxDynamicSharedMemorySize, SMEM_TC_BYTES);
    cudaFuncSetAttribute(gemm_tc_kernel<0,3>, cudaFuncAttributeMaxDynamicSharedMemorySize, SMEM_TC_BYTES);
    cudaFuncSetAttribute(gemm_tc_kernel<0,4>, cudaFuncAttributeMaxDynamicSharedMemorySize, SMEM_TC_BYTES);
    cudaFuncSetAttribute(gemm_tc_kernel<0,5>, cudaFuncAttributeMaxDynamicSharedMemorySize, SMEM_TC_BYTES);
    cudaFuncSetAttribute(gemm_tc_kernel<0,6>, cudaFuncAttributeMaxDynamicSharedMemorySize, SMEM_TC_BYTES);
    cudaFuncSetAttribute(gemm_tc_kernel<0,7>, cudaFuncAttributeMaxDynamicSharedMemorySize, SMEM_TC_BYTES);
    cudaFuncSetAttribute(gemm_tc_kernel<1,0>, cudaFuncAttributeMaxDynamicSharedMemorySize, SMEM_TC_BYTES);
    cudaFuncSetAttribute(gemm_tc64_kernel, cudaFuncAttributeMaxDynamicSharedMemorySize, SMEM_TC64_BYTES);
    cudaFuncSetAttribute(gemm_bf16_kernel<0>, cudaFuncAttributeMaxDynamicSharedMemorySize, SMEM_BF_BYTES);
    cudaFuncSetAttribute(gemm_bf16_kernel<1>, cudaFuncAttributeMaxDynamicSharedMemorySize, SMEM_BF_BYTES);
    cudaFuncSetAttribute(gemm_bf16_kernel<5>, cudaFuncAttributeMaxDynamicSharedMemorySize, SMEM_BF_BYTES);
    cudaFuncSetAttribute(gemm_bf16_kernel<6>, cudaFuncAttributeMaxDynamicSharedMemorySize, SMEM_BF_BYTES);
}

extern "C" void kernel_launch(void* const* d_in, const int* in_sizes, int n_in,
                              void* d_out, int out_size)
{
    (void)in_sizes; (void)n_in; (void)out_size;
    const int*   x       = (const int*)  d_in[0];
    const float* enc_emb = (const float*)d_in[1];
    const float* pos_emb = (const float*)d_in[2];
    const float* ln1_s   = (const float*)d_in[3];
    const float* ln1_b   = (const float*)d_in[4];
    const float* qkv_w   = (const float*)d_in[5];
    const float* aout_w  = (const float*)d_in[6];
    const float* aout_b  = (const float*)d_in[7];
    const float* conv_k  = (const float*)d_in[8];
    const float* ln2_s   = (const float*)d_in[9];
    const float* ln2_b   = (const float*)d_in[10];
    const float* ff_w1   = (const float*)d_in[11];
    const float* ff_b1   = (const float*)d_in[12];
    const float* ff_w2   = (const float*)d_in[13];
    const float* ff_b2   = (const float*)d_in[14];
    const float* fin_w   = (const float*)d_in[15];
    const float* fin_b   = (const float*)d_in[16];
    float* out = (float*)d_out;

    setup_tc_attrs();

    float *p_h,*p_x,*p_q,*p_k,*p_v,*p_ql,*p_kl,*p_a1,*p_a3,*p_a2;
    float *p_z,*p_z2,*p_p,*p_t,*p_t2,*p_kv,*p_zkv,*p_ao,*p_y,*p_x2,*p_ff;
    __nv_bfloat16 *p_a2h,*p_zh,*p_zh2,*p_ph,*p_th,*p_t2h;
    cudaGetSymbolAddress((void**)&p_h,  g_h);
    cudaGetSymbolAddress((void**)&p_x,  g_x);
    cudaGetSymbolAddress((void**)&p_q,  g_q);
    cudaGetSymbolAddress((void**)&p_k,  g_k);
    cudaGetSymbolAddress((void**)&p_v,  g_v);
    cudaGetSymbolAddress((void**)&p_ql, g_ql);
    cudaGetSymbolAddress((void**)&p_kl, g_kl);
    cudaGetSymbolAddress((void**)&p_a1, g_a1);
    cudaGetSymbolAddress((void**)&p_a3, g_a3);
    cudaGetSymbolAddress((void**)&p_a2, g_a2);
    cudaGetSymbolAddress((void**)&p_z,  g_zb);
    cudaGetSymbolAddress((void**)&p_z2, g_zb2);
    cudaGetSymbolAddress((void**)&p_p,  g_pb);
    cudaGetSymbolAddress((void**)&p_t,  g_tb);
    cudaGetSymbolAddress((void**)&p_t2, g_tb2);
    cudaGetSymbolAddress((void**)&p_kv, g_kvb);
    cudaGetSymbolAddress((void**)&p_zkv,g_zkv);
    cudaGetSymbolAddress((void**)&p_ao, g_ao);
    cudaGetSymbolAddress((void**)&p_y,  g_y);
    cudaGetSymbolAddress((void**)&p_x2, g_x2);
    cudaGetSymbolAddress((void**)&p_ff, g_ff);
    cudaGetSymbolAddress((void**)&p_a2h, g_a2h);
    cudaGetSymbolAddress((void**)&p_zh,  g_zh);
    cudaGetSymbolAddress((void**)&p_zh2, g_zh2);
    cudaGetSymbolAddress((void**)&p_ph,  g_ph);
    cudaGetSymbolAddress((void**)&p_th,  g_th);
    cudaGetSymbolAddress((void**)&p_t2h, g_t2h);

    const long long MM  = (long long)ML*ML;
    const long long NM  = (long long)NPAD*ML;
    const long long ND  = (long long)NPAD*DHD;
    const long long MD  = (long long)ML*DHD;

    {
        long long tot = (long long)BATCH*LSEQ*DMODEL;
        embed_kernel<<<(unsigned)((tot+255)/256),256>>>(x, enc_emb, pos_emb);
        int tot2 = BATCH*PADL*DMODEL;
        zero_pad_kernel<<<(tot2+255)/256,256>>>();
    }

    for (int lay=0; lay<DEPTH; lay++){
        ln_kernel<<<BATCH*LSEQ,256>>>(p_h, p_x, ln1_s+(long long)lay*DMODEL, ln1_b+(long long)lay*DMODEL, 1);
        // QKV [tensor, fused split into q/k/v]
        run_gemm(0,7, BATCH*NPAD, 3*DMODEL, DMODEL,
                 p_x, DMODEL, 0,
                 qkv_w + (long long)lay*DMODEL*3*DMODEL, 3*DMODEL, 0,
                 p_q, 3*DMODEL, 0, 1, 1.f, nullptr, p_k, p_v);
        {
            long long tot2 = (long long)BH*ML*DHD;
            landmark_kernel<<<(unsigned)((tot2+255)/256),256>>>();
        }
        // attn1 = softmax(q @ kl^T)  [tensor TB=1]
        run_gemm(1,0, NPAD, ML, DHD, p_q, DHD, ND, p_kl, DHD, MD, p_a1, ML, NM, BH, 1.f, nullptr);
        softmax_kernel<<<BH*NPAD,128>>>(p_a1, ML);
        // attn2 = softmax(ql @ kl^T)  [tensor TB=1]
        run_gemm(1,0, ML, ML, DHD, p_ql, DHD, MD, p_kl, DHD, MD, p_a2, ML, MM, BH, 1.f, nullptr);
        softmax_kernel<<<BH*ML,128>>>(p_a2, ML);
        // attn3 = softmax(ql @ k^T)  [tensor TB=1]
        run_gemm(1,0, ML, NPAD, DHD, p_ql, DHD, MD, p_k, DHD, ND, p_a3, NPAD, (long long)ML*NPAD, BH, 1.f, nullptr);
        softmax_kernel<<<BH*ML,128>>>(p_a3, NPAD);

        // ---- pinv: 4 bf16 iterations + 2 tf32 polish iterations ----
        red_init_kernel<<<1,1>>>();
        colsum_kernel<<<(BH*ML+255)/256,256>>>();
        rowsum_kernel<<<(BH*ML+255)/256,256>>>();
        {
            long long tot = (long long)BH*ML*ML;
            unsigned g = (unsigned)((tot+255)/256);
            zinit_kernel<<<g,256>>>();   // Z0 fp32+bf16, A2 bf16 shadow
        }
        __nv_bfloat16* zhc = p_zh; __nv_bfloat16* zhn = p_zh2;
        for (int it=0; it<4; it++){
            run_gemm_bf16(6, p_a2h, zhc, p_ph, p_th, nullptr, 7.f);      // P, T=7I-P
            run_gemm_bf16(5, p_ph, p_th,  p_t2h, nullptr, nullptr, 15.f); // T2=15I-P@T
            run_gemm_bf16(5, p_ph, p_t2h, p_th,  nullptr, nullptr, 13.f); // T=13I-P@T2
            if (it < 3){
                run_gemm_bf16(0, zhc, p_th, zhn, nullptr, nullptr, 0.25f);
                __nv_bfloat16* tmp = zhc; zhc = zhn; zhn = tmp;
            } else {
                run_gemm_bf16(1, zhc, p_th, nullptr, nullptr, p_z, 0.25f); // fp32 Z4
            }
        }
        float* zc = p_z; float* zn = p_z2;
        for (int it=0; it<2; it++){
            run_gemm(0,6, ML, ML, ML, p_a2, ML, MM, zc, ML, MM, p_p, ML, MM, BH, 7.f, nullptr, p_t);
            run_gemm(0,5, ML, ML, ML, p_p, ML, MM, p_t, ML, MM, p_t2, ML, MM, BH, 15.f, nullptr);
            run_gemm(0,5, ML, ML, ML, p_p, ML, MM, p_t2, ML, MM, p_t, ML, MM, BH, 13.f, nullptr);
            run_gemm(0,0, ML, ML, ML, zc, ML, MM, p_t, ML, MM, zn, ML, MM, BH, 0.25f, nullptr);
            float* tmp = zc; zc = zn; zn = tmp;
        }

        // kv = attn3 @ v  [tensor N=64]
        run_gemm64(ML, NPAD, p_a3, NPAD, (long long)ML*NPAD, p_v, DHD, ND, p_kv, DHD, MD, BH);
        // zkv = Z @ kv  [tensor N=64]
        run_gemm64(ML, ML, zc, ML, MM, p_kv, DHD, MD, p_zkv, DHD, MD, BH);
        // ao = attn1 @ zkv  [tensor N=64]
        run_gemm64(NPAD, ML, p_a1, ML, NM, p_zkv, DHD, MD, p_ao, DHD, ND, BH);
        {
            long long tot = (long long)BH*NPAD*DHD;
            combine_kernel<<<(unsigned)((tot+255)/256),256>>>(conv_k + (long long)lay*NH*KC);
        }
        // out projection + residual [tensor]
        run_gemm(0,4, BATCH*NPAD, DMODEL, DMODEL,
                 p_y, DMODEL, 0,
                 aout_w + (long long)lay*DMODEL*DMODEL, DMODEL, 0,
                 p_h, DMODEL, 0, 1, 1.f, aout_b + (long long)lay*DMODEL);

        // ---- FFN ----
        ln_kernel<<<BATCH*LSEQ,256>>>(p_h, p_x2, ln2_s+(long long)lay*DMODEL, ln2_b+(long long)lay*DMODEL, 0);
        run_gemm(0,2, BATCH*LSEQ, FFD, DMODEL,
                 p_x2, DMODEL, 0,
                 ff_w1 + (long long)lay*DMODEL*FFD, FFD, 0,
                 p_ff, FFD, 0, 1, 1.f, ff_b1 + (long long)lay*FFD);
        run_gemm(0,3, BATCH*LSEQ, DMODEL, FFD,
                 p_ff, FFD, 0,
                 ff_w2 + (long long)lay*FFD*DMODEL, DMODEL, 0,
                 p_h, DMODEL, 0, 1, 1.f, ff_b2 + (long long)lay*DMODEL);
    }

    final_kernel<<<BATCH,256>>>(fin_w, fin_b, out);
}

// round 11
// speedup vs baseline: 1.5423x; 1.0789x over previous
#include <cuda_runtime.h>
#include <cuda_bf16.h>
#include <math.h>
#include <stdint.h>

// ---------------- model constants ----------------
#define BATCH 16
#define LSEQ  1000
#define DMODEL 512
#define NH    8
#define DHD   64
#define NPAD  1024
#define PADL  24
#define ML    256
#define LMR   4
#define FFD   2048
#define DEPTH 6
#define KC    33
#define QSCALE 0.125f
#define BH (BATCH*NH)

// ---------------- scratch ----------------
__device__ float g_h   [BATCH*LSEQ*DMODEL];
__device__ float g_x   [BATCH*NPAD*DMODEL];
__device__ float g_q   [BH*NPAD*DHD];
__device__ float g_k   [BH*NPAD*DHD];
__device__ float g_v   [BH*NPAD*DHD];
__device__ float g_ql  [BH*ML*DHD];
__device__ float g_kl  [BH*ML*DHD];
__device__ float g_a1  [BH*NPAD*ML];
__device__ float g_a3  [BH*ML*NPAD];
__device__ float g_a2  [BH*ML*ML];
__device__ float g_zb  [BH*ML*ML];
__device__ float g_zb2 [BH*ML*ML];
__device__ float g_pb  [BH*ML*ML];
__device__ float g_tb  [BH*ML*ML];
__device__ float g_tb2 [BH*ML*ML];
__device__ float g_kvb [BH*ML*DHD];
__device__ float g_zkv [BH*ML*DHD];
__device__ float g_ao  [BH*NPAD*DHD];
__device__ float g_y   [BATCH*NPAD*DMODEL];
__device__ float g_x2  [BATCH*LSEQ*DMODEL];
__device__ float g_ff  [BATCH*LSEQ*FFD];
__device__ int   g_red [2];
// bf16 shadows for pinv
__device__ __nv_bfloat16 g_a2h [BH*ML*ML];
__device__ __nv_bfloat16 g_zh  [BH*ML*ML];
__device__ __nv_bfloat16 g_zh2 [BH*ML*ML];
__device__ __nv_bfloat16 g_ph  [BH*ML*ML];
__device__ __nv_bfloat16 g_th  [BH*ML*ML];
__device__ __nv_bfloat16 g_t2h [BH*ML*ML];

// ---------------- reductions ----------------
__device__ __forceinline__ float warpSum(float v){
    #pragma unroll
    for (int o=16;o;o>>=1) v += __shfl_xor_sync(0xffffffffu, v, o);
    return v;
}
__device__ __forceinline__ float warpMax(float v){
    #pragma unroll
    for (int o=16;o;o>>=1) v = fmaxf(v, __shfl_xor_sync(0xffffffffu, v, o));
    return v;
}
__device__ __forceinline__ float blockSumN(float v, float* sh, int nw){
    int w = threadIdx.x>>5, l = threadIdx.x&31;
    v = warpSum(v);
    if (l==0) sh[w] = v;
    __syncthreads();
    if (w==0){
        float x = (l < nw) ? sh[l] : 0.f;
        x = warpSum(x);
        if (l==0) sh[0] = x;
    }
    __syncthreads();
    float r = sh[0];
    __syncthreads();
    return r;
}
__device__ __forceinline__ float blockMaxN(float v, float* sh, int nw){
    int w = threadIdx.x>>5, l = threadIdx.x&31;
    v = warpMax(v);
    if (l==0) sh[w] = v;
    __syncthreads();
    if (w==0){
        float x = (l < nw) ? sh[l] : -3.4e38f;
        x = warpMax(x);
        if (l==0) sh[0] = x;
    }
    __syncthreads();
    float r = sh[0];
    __syncthreads();
    return r;
}

// ---------------- mma / cp.async / ldmatrix helpers ----------------
__device__ __forceinline__ void mma_tf32(float c[4],
    unsigned a0, unsigned a1, unsigned a2, unsigned a3,
    unsigned b0, unsigned b1)
{
    asm volatile(
        "mma.sync.aligned.m16n8k8.row.col.f32.tf32.tf32.f32 "
        "{%0,%1,%2,%3}, {%4,%5,%6,%7}, {%8,%9}, {%0,%1,%2,%3};"
        : "+f"(c[0]), "+f"(c[1]), "+f"(c[2]), "+f"(c[3])
        : "r"(a0), "r"(a1), "r"(a2), "r"(a3), "r"(b0), "r"(b1));
}
__device__ __forceinline__ void mma_bf16(float c[4],
    unsigned a0, unsigned a1, unsigned a2, unsigned a3,
    unsigned b0, unsigned b1)
{
    asm volatile(
        "mma.sync.aligned.m16n8k16.row.col.f32.bf16.bf16.f32 "
        "{%0,%1,%2,%3}, {%4,%5,%6,%7}, {%8,%9}, {%0,%1,%2,%3};"
        : "+f"(c[0]), "+f"(c[1]), "+f"(c[2]), "+f"(c[3])
        : "r"(a0), "r"(a1), "r"(a2), "r"(a3), "r"(b0), "r"(b1));
}
__device__ __forceinline__ void cp16(unsigned saddr, const void* gptr){
    asm volatile("cp.async.cg.shared.global [%0], [%1], 16;\n"
                 :: "r"(saddr), "l"(gptr));
}
__device__ __forceinline__ void cp_commit(){
    asm volatile("cp.async.commit_group;\n");
}
template<int N>
__device__ __forceinline__ void cp_wait(){
    asm volatile("cp.async.wait_group %0;\n" :: "n"(N));
}
__device__ __forceinline__ void ldsm4(unsigned &r0, unsigned &r1,
                                      unsigned &r2, unsigned &r3,
                                      unsigned addr){
    asm volatile("ldmatrix.sync.aligned.m8n8.x4.shared.b16 {%0,%1,%2,%3}, [%4];"
        : "=r"(r0), "=r"(r1), "=r"(r2), "=r"(r3) : "r"(addr));
}
__device__ __forceinline__ void ldsm4t(unsigned &r0, unsigned &r1,
                                       unsigned &r2, unsigned &r3,
                                       unsigned addr){
    asm volatile("ldmatrix.sync.aligned.m8n8.x4.trans.shared.b16 {%0,%1,%2,%3}, [%4];"
        : "=r"(r0), "=r"(r1), "=r"(r2), "=r"(r3) : "r"(addr));
}

// epilogue (tf32 kernels): writes 2 consecutive cols at (r, cc)
template<int EPI>
__device__ __forceinline__ void store2(
    float* __restrict__ C, float* __restrict__ C2, float* __restrict__ C3,
    int ldc, int r, int cc, float v0, float v1,
    float alpha, const float* __restrict__ bias)
{
    if (EPI==0){
        float2 o = {alpha*v0, alpha*v1};
        *(float2*)&C[(long long)r*ldc + cc] = o;
    } else if (EPI==2){
        float x0 = v0 + bias[cc], x1 = v1 + bias[cc+1];
        float2 o;
        o.x = 0.5f*x0*(1.f+erff(x0*0.70710678118654752f));
        o.y = 0.5f*x1*(1.f+erff(x1*0.70710678118654752f));
        *(float2*)&C[(long long)r*ldc + cc] = o;
    } else if (EPI==3){
        float2 o = *(float2*)&C[(long long)r*ldc + cc];
        o.x += v0 + bias[cc];
        o.y += v1 + bias[cc+1];
        *(float2*)&C[(long long)r*ldc + cc] = o;
    } else if (EPI==4){
        int bb = r / NPAD, nl = r % NPAD;
        if (nl >= PADL){
            long long orow = (long long)bb*LSEQ + (nl - PADL);
            float2 o = *(float2*)&C[orow*ldc + cc];
            o.x += v0 + bias[cc];
            o.y += v1 + bias[cc+1];
            *(float2*)&C[orow*ldc + cc] = o;
        }
    } else if (EPI==5){
        float2 o = {(r==cc ? alpha : 0.f) - v0, (r==cc+1 ? alpha : 0.f) - v1};
        *(float2*)&C[(long long)r*ldc + cc] = o;
    } else if (EPI==6){
        float2 o = {v0, v1};
        *(float2*)&C[(long long)r*ldc + cc] = o;
        float2 o2 = {(r==cc ? alpha : 0.f) - v0, (r==cc+1 ? alpha : 0.f) - v1};
        *(float2*)&C2[(long long)r*ldc + cc] = o2;
    } else if (EPI==7){
        int b = r >> 10, n = r & 1023;
        int which = cc >> 9;
        int hd = cc & 511;
        long long idx = ((((long long)b*NH + (hd>>6))*NPAD) + n)*DHD + (hd&63);
        float2 o;
        if (which==0){ o.x = v0*QSCALE; o.y = v1*QSCALE; *(float2*)&C[idx] = o; }
        else if (which==1){ o.x = v0; o.y = v1; *(float2*)&C2[idx] = o; }
        else { o.x = v0; o.y = v1; *(float2*)&C3[idx] = o; }
    }
}

// == TF32 tensor GEMM: 256 thr, CTA 128x256, warp 64x64, LDSM, 3-stage =====
// EPI 8: fused row-softmax store (requires gridDim.x==1, ldc==256)
#define AS_STRIDE 20
#define AS_ST     (128*AS_STRIDE)
#define BS0_STRIDE 264
#define BS1_STRIDE 20
#define BS_ST     (256*BS1_STRIDE)
#define NSTAGE 3
#define SMEM_TC_BYTES (NSTAGE*(AS_ST + BS_ST)*4)   // 92160

template<int TB, int EPI>
__global__ void __launch_bounds__(256,1) gemm_tc_kernel(
    int Ki,
    const float* __restrict__ A, int lda, long long sA,
    const float* __restrict__ Bm, int ldb, long long sB,
    float* __restrict__ C, int ldc, long long sC,
    float alpha, const float* __restrict__ bias,
    float* __restrict__ C2, float* __restrict__ C3)
{
    extern __shared__ unsigned sm[];
    unsigned* As = sm;
    unsigned* Bs = sm + NSTAGE*AS_ST;
    const unsigned As_base = (unsigned)__cvta_generic_to_shared(As);
    const unsigned Bs_base = (unsigned)__cvta_generic_to_shared(Bs);

    const int bz = blockIdx.z;
    A  += (long long)bz*sA;
    Bm += (long long)bz*sB;
    C  += (long long)bz*sC;
    if (EPI==6) C2 += (long long)bz*sC;

    const int row0 = blockIdx.y*128;
    const int col0 = blockIdx.x*256;
    const int tid = threadIdx.x;
    const int warp = tid>>5, lane = tid&31;
    const int wm = warp & 1, wn = warp >> 1;
    const int g = lane>>2, qc = lane&3;

    const int a_r  = tid>>1;
    const int a_c2 = (tid&1)<<1;

    auto issue = [&](int kt, int st){
        unsigned abase = As_base + (unsigned)(st*AS_ST)*4u;
        #pragma unroll
        for (int i=0;i<2;i++)
            cp16(abase + (unsigned)(a_r*AS_STRIDE + (a_c2+i)*4)*4u,
                 A + (long long)(row0 + a_r)*lda + kt + (a_c2+i)*4);
        unsigned bbase = Bs_base + (unsigned)(st*BS_ST)*4u;
        if (TB==0){
            #pragma unroll
            for (int i=0;i<4;i++){
                int fidx = tid + i*256;
                int bk = fidx>>6, bn4 = (fidx&63)<<2;
                cp16(bbase + (unsigned)(bk*BS0_STRIDE + bn4)*4u,
                     Bm + (long long)(kt + bk)*ldb + col0 + bn4);
            }
        } else {
            #pragma unroll
            for (int i=0;i<4;i++){
                int fidx = tid + i*256;
                int bn = fidx>>2, bc4 = (fidx&3)<<2;
                cp16(bbase + (unsigned)(bn*BS1_STRIDE + bc4)*4u,
                     Bm + (long long)(col0 + bn)*ldb + kt + bc4);
            }
        }
    };

    float acc[4][8][4];
    #pragma unroll
    for (int mt=0;mt<4;mt++)
        #pragma unroll
        for (int nt=0;nt<8;nt++)
            #pragma unroll
            for (int i=0;i<4;i++) acc[mt][nt][i]=0.f;

    const int nk = Ki >> 4;
    issue(0, 0);  cp_commit();
    issue(16, 1); cp_commit();

    const int lane8 = lane & 7;
    const int a_lrow = wm*64 + lane8 + ((lane>>3)&1)*8;
    const int a_lw   = ((lane>>4)&1)*4;
    const int b_lrow = wn*64 + lane8 + ((lane>>4)&1)*8;
    const int b_lw   = ((lane>>3)&1)*4;
    const int b0_frag_off = qc*BS0_STRIDE + wn*64 + g;

    for (int t = 0; t < nk; ++t){
        cp_wait<1>();
        __syncthreads();
        const int rb = t % NSTAGE;
        if (t+2 < nk) issue((t+2)<<4, (t+2)%NSTAGE);
        cp_commit();

        const unsigned a_stage = As_base + (unsigned)(rb*AS_ST)*4u;
        const unsigned b_stage = Bs_base + (unsigned)(rb*BS_ST)*4u;

        #pragma unroll
        for (int grp=0; grp<2; grp++){
            const int koff = grp*8;
            unsigned af[4][4], bf[8][2];
            #pragma unroll
            for (int mt=0;mt<4;mt++)
                ldsm4(af[mt][0], af[mt][1], af[mt][2], af[mt][3],
                      a_stage + (unsigned)(((a_lrow + mt*16)*AS_STRIDE) + a_lw + koff)*4u);
            if (TB==0){
                const unsigned* Bb = Bs + rb*BS_ST + b0_frag_off + koff*BS0_STRIDE;
                #pragma unroll
                for (int nt=0;nt<8;nt++){
                    bf[nt][0] = Bb[nt*8];
                    bf[nt][1] = Bb[4*BS0_STRIDE + nt*8];
                }
            } else {
                #pragma unroll
                for (int np=0;np<4;np++)
                    ldsm4(bf[2*np][0], bf[2*np][1], bf[2*np+1][0], bf[2*np+1][1],
                          b_stage + (unsigned)(((b_lrow + np*16)*BS1_STRIDE) + b_lw + koff)*4u);
            }
            #pragma unroll
            for (int mt=0;mt<4;mt++)
                #pragma unroll
                for (int nt=0;nt<8;nt++)
                    mma_tf32(acc[mt][nt], af[mt][0],af[mt][1],af[mt][2],af[mt][3],
                             bf[nt][0],bf[nt][1]);
        }
    }

    if (EPI==8){
        // fused softmax over the 256-wide row (one CTA per row-span)
        __syncthreads();
        float* redmax = (float*)sm;          // [128][4]
        float* redsum = (float*)sm + 512;    // [128][4]
        float rm[4][2];
        #pragma unroll
        for (int mt=0;mt<4;mt++){
            #pragma unroll
            for (int half=0; half<2; half++){
                float m = -3.4e38f;
                #pragma unroll
                for (int nt=0;nt<8;nt++){
                    m = fmaxf(m, acc[mt][nt][2*half]);
                    m = fmaxf(m, acc[mt][nt][2*half+1]);
                }
                m = fmaxf(m, __shfl_xor_sync(0xffffffffu, m, 1));
                m = fmaxf(m, __shfl_xor_sync(0xffffffffu, m, 2));
                rm[mt][half] = m;
            }
        }
        if (qc==0){
            #pragma unroll
            for (int mt=0;mt<4;mt++)
                #pragma unroll
                for (int half=0; half<2; half++){
                    int rl = wm*64 + mt*16 + g + half*8;
                    redmax[rl*4 + wn] = rm[mt][half];
                }
        }
        __syncthreads();
        float inv[4][2];
        #pragma unroll
        for (int mt=0;mt<4;mt++){
            #pragma unroll
            for (int half=0; half<2; half++){
                int rl = wm*64 + mt*16 + g + half*8;
                float m = fmaxf(fmaxf(redmax[rl*4+0], redmax[rl*4+1]),
                                fmaxf(redmax[rl*4+2], redmax[rl*4+3]));
                float s = 0.f;
                #pragma unroll
                for (int nt=0;nt<8;nt++){
                    float e0 = expf(acc[mt][nt][2*half]   - m);
                    float e1 = expf(acc[mt][nt][2*half+1] - m);
                    acc[mt][nt][2*half]   = e0;
                    acc[mt][nt][2*half+1] = e1;
                    s += e0 + e1;
                }
                s += __shfl_xor_sync(0xffffffffu, s, 1);
                s += __shfl_xor_sync(0xffffffffu, s, 2);
                if (qc==0) redsum[rl*4 + wn] = s;
                inv[mt][half] = 0.f;  // filled after sync
            }
        }
        __syncthreads();
        #pragma unroll
        for (int mt=0;mt<4;mt++)
            #pragma unroll
            for (int half=0; half<2; half++){
                int rl = wm*64 + mt*16 + g + half*8;
                float s = redsum[rl*4+0] + redsum[rl*4+1] + redsum[rl*4+2] + redsum[rl*4+3];
                inv[mt][half] = 1.f / s;
            }
        #pragma unroll
        for (int mt=0;mt<4;mt++){
            #pragma unroll
            for (int half=0; half<2; half++){
                int r = row0 + wm*64 + mt*16 + g + half*8;
                #pragma unroll
                for (int nt=0;nt<8;nt++){
                    int cc = wn*64 + nt*8 + 2*qc;
                    float2 o = {acc[mt][nt][2*half]*inv[mt][half],
                                acc[mt][nt][2*half+1]*inv[mt][half]};
                    *(float2*)&C[(long long)r*ldc + cc] = o;
                }
            }
        }
        return;
    }

    #pragma unroll
    for (int mt=0;mt<4;mt++){
        int r = row0 + wm*64 + mt*16 + g;
        #pragma unroll
        for (int nt=0;nt<8;nt++){
            int cc = col0 + wn*64 + nt*8 + 2*qc;
            store2<EPI>(C, C2, C3, ldc, r,   cc, acc[mt][nt][0], acc[mt][nt][1], alpha, bias);
            store2<EPI>(C, C2, C3, ldc, r+8, cc, acc[mt][nt][2], acc[mt][nt][3], alpha, bias);
        }
    }
}

// ==== BF16 batched GEMM for pinv: 256x256x256, CTA 128x256, warp 64x64 ====
#define ASH 40
#define AH_ST (128*ASH)
#define BSH 264
#define BH_ST (32*BSH)
#define SMEM_BF_BYTES (NSTAGE*(AH_ST + BH_ST)*2)

template<int EPI>
__global__ void __launch_bounds__(256,1) gemm_bf16_kernel(
    const __nv_bfloat16* __restrict__ A,
    const __nv_bfloat16* __restrict__ Bm,
    __nv_bfloat16* __restrict__ Cb,
    __nv_bfloat16* __restrict__ C2b,
    float* __restrict__ Cf,
    float alpha)
{
    extern __shared__ __nv_bfloat16 smh[];
    const unsigned As_base = (unsigned)__cvta_generic_to_shared(smh);
    const unsigned Bs_base = As_base + NSTAGE*AH_ST*2u;

    const long long boff = (long long)blockIdx.z * (ML*ML);
    A  += boff; Bm += boff;

    const int row0 = blockIdx.y*128;
    const int tid = threadIdx.x;
    const int warp = tid>>5, lane = tid&31;
    const int wm = warp & 1, wn = warp >> 1;
    const int g = lane>>2, qc = lane&3;

    auto issue = [&](int kt, int st){
        unsigned abase = As_base + (unsigned)(st*AH_ST)*2u;
        #pragma unroll
        for (int i=0;i<2;i++){
            int r = tid>>1, ch = ((tid&1)<<1) + i;
            cp16(abase + (unsigned)(r*ASH + ch*8)*2u,
                 A + (long long)(row0 + r)*ML + kt + ch*8);
        }
        unsigned bbase = Bs_base + (unsigned)(st*BH_ST)*2u;
        #pragma unroll
        for (int i=0;i<4;i++){
            int fidx = tid + i*256;
            int r = fidx>>5, ch = fidx&31;
            cp16(bbase + (unsigned)(r*BSH + ch*8)*2u,
                 Bm + (long long)(kt + r)*ML + ch*8);
        }
    };

    float acc[4][8][4];
    #pragma unroll
    for (int mt=0;mt<4;mt++)
        #pragma unroll
        for (int nt=0;nt<8;nt++)
            #pragma unroll
            for (int i=0;i<4;i++) acc[mt][nt][i]=0.f;

    const int nk = ML >> 5;
    issue(0, 0);  cp_commit();
    issue(32, 1); cp_commit();

    const int lane8 = lane & 7;
    const int a_row = wm*64 + lane8 + ((lane>>3)&1)*8;
    const int a_col = ((lane>>4)&1)*8;
    const int b_row = lane8 + ((lane>>3)&1)*8;
    const int b_col = ((lane>>4)&1)*8;

    for (int t = 0; t < nk; ++t){
        cp_wait<1>();
        __syncthreads();
        const int rb = t % NSTAGE;
        if (t+2 < nk) issue((t+2)<<5, (t+2)%NSTAGE);
        cp_commit();

        const unsigned a_st = As_base + (unsigned)(rb*AH_ST)*2u;
        const unsigned b_st = Bs_base + (unsigned)(rb*BH_ST)*2u;

        #pragma unroll
        for (int kk=0; kk<2; kk++){
            const int k0 = kk*16;
            unsigned af[4][4], bf[8][2];
            #pragma unroll
            for (int mt=0;mt<4;mt++)
                ldsm4(af[mt][0], af[mt][1], af[mt][2], af[mt][3],
                      a_st + (unsigned)((a_row + mt*16)*ASH + k0 + a_col)*2u);
            #pragma unroll
            for (int np=0;np<4;np++)
                ldsm4t(bf[2*np][0], bf[2*np][1], bf[2*np+1][0], bf[2*np+1][1],
                       b_st + (unsigned)((k0 + b_row)*BSH + wn*64 + np*16 + b_col)*2u);
            #pragma unroll
            for (int mt=0;mt<4;mt++)
                #pragma unroll
                for (int nt=0;nt<8;nt++)
                    mma_bf16(acc[mt][nt], af[mt][0],af[mt][1],af[mt][2],af[mt][3],
                             bf[nt][0],bf[nt][1]);
        }
    }

    #pragma unroll
    for (int mt=0;mt<4;mt++){
        #pragma unroll
        for (int half=0; half<2; half++){
            int r = row0 + wm*64 + mt*16 + g + half*8;
            #pragma unroll
            for (int nt=0;nt<8;nt++){
                int cc = wn*64 + nt*8 + 2*qc;
                float v0 = acc[mt][nt][2*half+0];
                float v1 = acc[mt][nt][2*half+1];
                long long idx = boff + (long long)r*ML + cc;
                if (EPI==0){
                    __nv_bfloat162 pk;
                    pk.x = __float2bfloat16(alpha*v0);
                    pk.y = __float2bfloat16(alpha*v1);
                    *(__nv_bfloat162*)&Cb[idx] = pk;
                } else if (EPI==1){
                    float2 o = {alpha*v0, alpha*v1};
                    *(float2*)&Cf[idx] = o;
                } else if (EPI==5){
                    __nv_bfloat162 pk;
                    pk.x = __float2bfloat16((r==cc   ? alpha : 0.f) - v0);
                    pk.y = __float2bfloat16((r==cc+1 ? alpha : 0.f) - v1);
                    *(__nv_bfloat162*)&Cb[idx] = pk;
                } else if (EPI==6){
                    __nv_bfloat162 pk;
                    pk.x = __float2bfloat16(v0);
                    pk.y = __float2bfloat16(v1);
                    *(__nv_bfloat162*)&Cb[idx] = pk;
                    __nv_bfloat162 pk2;
                    pk2.x = __float2bfloat16((r==cc   ? alpha : 0.f) - v0);
                    pk2.y = __float2bfloat16((r==cc+1 ? alpha : 0.f) - v1);
                    *(__nv_bfloat162*)&C2b[idx] = pk2;
                }
            }
        }
    }
}

// ==== TF32 tensor GEMM N=64: 128 thr, CTA 128x64, warp 64x32, 3-stage =====
#define BS64_STRIDE 72
#define BS64_ST     (16*BS64_STRIDE)
#define SMEM_TC64_BYTES (NSTAGE*(AS_ST + BS64_ST)*4)

__global__ void __launch_bounds__(128) gemm_tc64_kernel(
    int Ki,
    const float* __restrict__ A, int lda, long long sA,
    const float* __restrict__ Bm, int ldb, long long sB,
    float* __restrict__ C, int ldc, long long sC)
{
    extern __shared__ unsigned sm[];
    unsigned* As = sm;
    unsigned* Bs = sm + NSTAGE*AS_ST;
    const unsigned As_base = (unsigned)__cvta_generic_to_shared(As);
    const unsigned Bs_base = (unsigned)__cvta_generic_to_shared(Bs);

    const int bz = blockIdx.z;
    A  += (long long)bz*sA;
    Bm += (long long)bz*sB;
    C  += (long long)bz*sC;

    const int row0 = blockIdx.y*128;
    const int tid = threadIdx.x;
    const int warp = tid>>5, lane = tid&31;
    const int wm = warp & 1, wn = warp >> 1;
    const int g = lane>>2, qc = lane&3;

    auto issue = [&](int kt, int st){
        unsigned abase = As_base + (unsigned)(st*AS_ST)*4u;
        #pragma unroll
        for (int i=0;i<4;i++){
            int fidx = tid + i*128;
            int a_r = fidx>>2, a_c4 = (fidx&3)<<2;
            cp16(abase + (unsigned)(a_r*AS_STRIDE + a_c4)*4u,
                 A + (long long)(row0 + a_r)*lda + kt + a_c4);
        }
        unsigned bbase = Bs_base + (unsigned)(st*BS64_ST)*4u;
        #pragma unroll
        for (int i=0;i<2;i++){
            int fidx = tid + i*128;
            int bk = fidx>>4, bn4 = (fidx&15)<<2;
            cp16(bbase + (unsigned)(bk*BS64_STRIDE + bn4)*4u,
                 Bm + (long long)(kt + bk)*ldb + bn4);
        }
    };

    float acc[4][4][4];
    #pragma unroll
    for (int mt=0;mt<4;mt++)
        #pragma unroll
        for (int nt=0;nt<4;nt++)
            #pragma unroll
            for (int i=0;i<4;i++) acc[mt][nt][i]=0.f;

    const int nk = Ki >> 4;
    issue(0, 0);  cp_commit();
    issue(16, 1); cp_commit();

    const int lane8 = lane & 7;
    const int a_lrow = wm*64 + lane8 + ((lane>>3)&1)*8;
    const int a_lw   = ((lane>>4)&1)*4;
    const int b_frag_off = qc*BS64_STRIDE + wn*32 + g;

    for (int t = 0; t < nk; ++t){
        cp_wait<1>();
        __syncthreads();
        const int rb = t % NSTAGE;
        if (t+2 < nk) issue((t+2)<<4, (t+2)%NSTAGE);
        cp_commit();

        const unsigned a_stage = As_base + (unsigned)(rb*AS_ST)*4u;

        #pragma unroll
        for (int grp=0; grp<2; grp++){
            const int koff = grp*8;
            unsigned af[4][4], bf[4][2];
            #pragma unroll
            for (int mt=0;mt<4;mt++)
                ldsm4(af[mt][0], af[mt][1], af[mt][2], af[mt][3],
                      a_stage + (unsigned)(((a_lrow + mt*16)*AS_STRIDE) + a_lw + koff)*4u);
            const unsigned* Bb = Bs + rb*BS64_ST + b_frag_off + koff*BS64_STRIDE;
            #pragma unroll
            for (int nt=0;nt<4;nt++){
                bf[nt][0] = Bb[nt*8];
                bf[nt][1] = Bb[4*BS64_STRIDE + nt*8];
            }
            #pragma unroll
            for (int mt=0;mt<4;mt++)
                #pragma unroll
                for (int nt=0;nt<4;nt++)
                    mma_tf32(acc[mt][nt], af[mt][0],af[mt][1],af[mt][2],af[mt][3],
                             bf[nt][0],bf[nt][1]);
        }
    }

    #pragma unroll
    for (int mt=0;mt<4;mt++){
        int r = row0 + wm*64 + mt*16 + g;
        #pragma unroll
        for (int nt=0;nt<4;nt++){
            int cc = wn*32 + nt*8 + 2*qc;
            float2 o0 = {acc[mt][nt][0], acc[mt][nt][1]};
            float2 o1 = {acc[mt][nt][2], acc[mt][nt][3]};
            *(float2*)&C[(long long)r*ldc + cc] = o0;
            *(float2*)&C[(long long)(r+8)*ldc + cc] = o1;
        }
    }
}

// ---------------- elementwise / small kernels ----------------
__global__ void embed_kernel(const int* __restrict__ x,
                             const float* __restrict__ emb,
                             const float* __restrict__ pos){
    long long idx = (long long)blockIdx.x*blockDim.x + threadIdx.x;
    if (idx >= (long long)BATCH*LSEQ*DMODEL) return;
    int d = (int)(idx % DMODEL);
    long long bl = idx / DMODEL;
    int l = (int)(bl % LSEQ);
    int tok = x[bl];
    g_h[idx] = emb[(long long)tok*DMODEL + d] + pos[(long long)l*DMODEL + d];
}

__global__ void zero_pad_kernel(){
    int idx = blockIdx.x*blockDim.x + threadIdx.x;
    if (idx >= BATCH*PADL*DMODEL) return;
    int d  = idx % DMODEL;
    int bp = idx / DMODEL;
    int b  = bp / PADL, p = bp % PADL;
    g_x[((long long)b*NPAD + p)*DMODEL + d] = 0.f;
}

__global__ void ln_kernel(const float* __restrict__ in, float* __restrict__ out,
                          const float* __restrict__ gm, const float* __restrict__ bt,
                          int padmode){
    __shared__ float sh[8];
    int r = blockIdx.x;
    int t = threadIdx.x;
    const float* p = in + (long long)r*DMODEL;
    float a  = p[t];
    float b2 = p[t+256];
    float s  = blockSumN(a+b2, sh, 8);
    float mu = s * (1.f/512.f);
    float da = a - mu, db = b2 - mu;
    float v  = blockSumN(da*da + db*db, sh, 8) * (1.f/512.f);
    float rstd = rsqrtf(v + 1e-5f);
    long long orow = padmode ? ((long long)(r/LSEQ)*NPAD + PADL + (r%LSEQ)) : (long long)r;
    float* q = out + orow*DMODEL;
    q[t]     = da*rstd*gm[t]     + bt[t];
    q[t+256] = db*rstd*gm[t+256] + bt[t+256];
}

__global__ void landmark_kernel(){
    long long idx = (long long)blockIdx.x*blockDim.x + threadIdx.x;
    if (idx >= (long long)BH*ML*DHD) return;
    int d = (int)(idx & 63);
    long long r = idx >> 6;
    int m  = (int)(r % ML);
    int bh = (int)(r / ML);
    long long base = ((long long)bh*NPAD + (long long)m*LMR)*DHD + d;
    float sq = 0.f, sk = 0.f;
    #pragma unroll
    for (int j=0;j<LMR;j++){ sq += g_q[base + (long long)j*DHD]; sk += g_k[base + (long long)j*DHD]; }
    g_ql[idx] = sq * 0.25f;
    g_kl[idx] = sk * 0.25f;
}

__global__ void softmax_kernel(float* __restrict__ X, int cols){
    __shared__ float sh[4];
    long long row = blockIdx.x;
    float* p = X + row*(long long)cols;
    int t = threadIdx.x;
    int cnt = cols >> 7;
    float v[8];
    float mx = -3.4e38f;
    #pragma unroll
    for (int i=0;i<8;i++) if (i<cnt){ v[i]=p[t + (i<<7)]; mx = fmaxf(mx, v[i]); }
    mx = blockMaxN(mx, sh, 4);
    float s = 0.f;
    #pragma unroll
    for (int i=0;i<8;i++) if (i<cnt){ v[i]=expf(v[i]-mx); s += v[i]; }
    s = blockSumN(s, sh, 4);
    float inv = 1.f/s;
    #pragma unroll
    for (int i=0;i<8;i++) if (i<cnt) p[t + (i<<7)] = v[i]*inv;
}

__global__ void red_init_kernel(){ g_red[0]=0; g_red[1]=0; }

__global__ void colsum_kernel(){
    int idx = blockIdx.x*blockDim.x + threadIdx.x;
    if (idx >= BH*ML) return;
    int c  = idx % ML;
    int bz = idx / ML;
    const float* p = g_a2 + (long long)bz*ML*ML + c;
    float s = 0.f;
    for (int r2=0;r2<ML;r2++) s += fabsf(p[(long long)r2*ML]);
    atomicMax(&g_red[0], __float_as_int(s));
}
__global__ void rowsum_kernel(){
    int idx = blockIdx.x*blockDim.x + threadIdx.x;
    if (idx >= BH*ML) return;
    int r2 = idx % ML;
    int bz = idx / ML;
    const float* p = g_a2 + (long long)bz*ML*ML + (long long)r2*ML;
    float s = 0.f;
    for (int c=0;c<ML;c++) s += fabsf(p[c]);
    atomicMax(&g_red[1], __float_as_int(s));
}
// Z0 = A2^T / c, dual fp32 + bf16; also bf16 shadow of A2
__global__ void zinit_kernel(){
    long long idx = (long long)blockIdx.x*blockDim.x + threadIdx.x;
    if (idx >= (long long)BH*ML*ML) return;
    int j = (int)(idx % ML);
    long long r = idx / ML;
    int i  = (int)(r % ML);
    int bz = (int)(r / ML);
    float c = __int_as_float(g_red[0]) * __int_as_float(g_red[1]);
    float val = g_a2[((long long)bz*ML + j)*ML + i] / c;
    g_zb[idx] = val;
    g_zh[idx] = __float2bfloat16(val);
    g_a2h[idx] = __float2bfloat16(g_a2[idx]);
}

__global__ void combine_kernel(const float* __restrict__ cw){
    long long idx = (long long)blockIdx.x*blockDim.x + threadIdx.x;
    if (idx >= (long long)BH*NPAD*DHD) return;
    int d = (int)(idx & 63);
    long long r = idx >> 6;
    int n  = (int)(r % NPAD);
    int bh = (int)(r / NPAD);
    int h  = bh % NH, b = bh / NH;
    float s = g_ao[idx];
    const float* w  = cw + h*KC;
    const float* vp = g_v + ((long long)bh*NPAD)*DHD + d;
    int k0 = (16-n > 0) ? (16-n) : 0;
    int k1 = (NPAD+16-n < KC) ? (NPAD+16-n) : KC;
    for (int kk=k0; kk<k1; kk++)
        s = fmaf(vp[(long long)(n+kk-16)*DHD], w[kk], s);
    g_y[((long long)b*NPAD + n)*DMODEL + h*DHD + d] = s;
}

__global__ void final_kernel(const float* __restrict__ fw,
                             const float* __restrict__ fb,
                             float* __restrict__ out){
    __shared__ float sh[8];
    int b = blockIdx.x;
    int t = threadIdx.x;
    const float* hp = g_h + (long long)b*LSEQ*DMODEL;
    float s = 0.f;
    for (long long i=t; i<(long long)LSEQ*DMODEL; i+=256)
        s = fmaf(hp[i], fw[i], s);
    s = blockSumN(s, sh, 8);
    if (t==0) out[b] = s + fb[0];
}

// ---------------- host-side GEMM dispatch ----------------
static void run_gemm(int tb, int epi, int Mi, int Ni, int Ki,
                     const float* A, int lda, long long sA,
                     const float* Bm, int ldb, long long sB,
                     float* C, int ldc, long long sC,
                     int batch, float alpha, const float* bias,
                     float* C2 = nullptr, float* C3 = nullptr)
{
    dim3 g(Ni/256, Mi/128, batch), t(256);
    size_t sh = SMEM_TC_BYTES;
    if (tb == 0) {
        switch (epi) {
            case 0: gemm_tc_kernel<0,0><<<g,t,sh>>>(Ki,A,lda,sA,Bm,ldb,sB,C,ldc,sC,alpha,bias,C2,C3); break;
            case 2: gemm_tc_kernel<0,2><<<g,t,sh>>>(Ki,A,lda,sA,Bm,ldb,sB,C,ldc,sC,alpha,bias,C2,C3); break;
            case 3: gemm_tc_kernel<0,3><<<g,t,sh>>>(Ki,A,lda,sA,Bm,ldb,sB,C,ldc,sC,alpha,bias,C2,C3); break;
            case 4: gemm_tc_kernel<0,4><<<g,t,sh>>>(Ki,A,lda,sA,Bm,ldb,sB,C,ldc,sC,alpha,bias,C2,C3); break;
            case 5: gemm_tc_kernel<0,5><<<g,t,sh>>>(Ki,A,lda,sA,Bm,ldb,sB,C,ldc,sC,alpha,bias,C2,C3); break;
            case 6: gemm_tc_kernel<0,6><<<g,t,sh>>>(Ki,A,lda,sA,Bm,ldb,sB,C,ldc,sC,alpha,bias,C2,C3); break;
            case 7: gemm_tc_kernel<0,7><<<g,t,sh>>>(Ki,A,lda,sA,Bm,ldb,sB,C,ldc,sC,alpha,bias,C2,C3); break;
        }
    } else {
        if (epi == 8)
            gemm_tc_kernel<1,8><<<g,t,sh>>>(Ki,A,lda,sA,Bm,ldb,sB,C,ldc,sC,alpha,bias,C2,C3);
        else
            gemm_tc_kernel<1,0><<<g,t,sh>>>(Ki,A,lda,sA,Bm,ldb,sB,C,ldc,sC,alpha,bias,C2,C3);
    }
}

static void run_gemm64(int Mi, int Ki,
                       const float* A, int lda, long long sA,
                       const float* Bm, int ldb, long long sB,
                       float* C, int ldc, long long sC, int batch)
{
    dim3 g(1, Mi/128, batch), t(128);
    gemm_tc64_kernel<<<g,t,SMEM_TC64_BYTES>>>(Ki,A,lda,sA,Bm,ldb,sB,C,ldc,sC);
}

static void run_gemm_bf16(int epi,
                          const __nv_bfloat16* A, const __nv_bfloat16* Bm,
                          __nv_bfloat16* Cb, __nv_bfloat16* C2b, float* Cf,
                          float alpha)
{
    dim3 g(1, ML/128, BH), t(256);
    size_t sh = SMEM_BF_BYTES;
    switch (epi) {
        case 0: gemm_bf16_kernel<0><<<g,t,sh>>>(A,Bm,Cb,C2b,Cf,alpha); break;
        case 1: gemm_bf16_kernel<1><<<g,t,sh>>>(A,Bm,Cb,C2b,Cf,alpha); break;
        case 5: gemm_bf16_kernel<5><<<g,t,sh>>>(A,Bm,Cb,C2b,Cf,alpha); break;
        case 6: gemm_bf16_kernel<6><<<g,t,sh>>>(A,Bm,Cb,C2b,Cf,alpha); break;
    }
}

static void setup_tc_attrs(){
    cudaFuncSetAttribute(gemm_tc_kernel<0,0>, cudaFuncAttributeMaxDynamicSharedMemorySize, SMEM_TC_BYTES);
    cudaFuncSetAttribute(gemm_tc_kernel<0,2>, cudaFuncAttributeMaxDynamicSharedMemorySize, SMEM_TC_BYTES);
    cudaFuncSetAttribute(gemm_tc_kernel<0,3>, cudaFuncAttributeMaxDynamicSharedMemorySize, SMEM_TC_BYTES);
    cudaFuncSetAttribute(gemm_tc_kernel<0,4>, cudaFuncAttributeMaxDynamicSharedMemorySize, SMEM_TC_BYTES);
    cudaFuncSetAttribute(gemm_tc_kernel<0,5>, cudaFuncAttributeMaxDynamicSharedMemorySize, SMEM_TC_BYTES);
    cudaFuncSetAttribute(gemm_tc_kernel<0,6>, cudaFuncAttributeMaxDynamicSharedMemorySize, SMEM_TC_BYTES);
    cudaFuncSetAttribute(gemm_tc_kernel<0,7>, cudaFuncAttributeMaxDynamicSharedMemorySize, SMEM_TC_BYTES);
    cudaFuncSetAttribute(gemm_tc_kernel<1,0>, cudaFuncAttributeMaxDynamicSharedMemorySize, SMEM_TC_BYTES);
    cudaFuncSetAttribute(gemm_tc_kernel<1,8>, cudaFuncAttributeMaxDynamicSharedMemorySize, SMEM_TC_BYTES);
    cudaFuncSetAttribute(gemm_tc64_kernel, cudaFuncAttributeMaxDynamicSharedMemorySize, SMEM_TC64_BYTES);
    cudaFuncSetAttribute(gemm_bf16_kernel<0>, cudaFuncAttributeMaxDynamicSharedMemorySize, SMEM_BF_BYTES);
    cudaFuncSetAttribute(gemm_bf16_kernel<1>, cudaFuncAttributeMaxDynamicSharedMemorySize, SMEM_BF_BYTES);
    cudaFuncSetAttribute(gemm_bf16_kernel<5>, cudaFuncAttributeMaxDynamicSharedMemorySize, SMEM_BF_BYTES);
    cudaFuncSetAttribute(gemm_bf16_kernel<6>, cudaFuncAttributeMaxDynamicSharedMemorySize, SMEM_BF_BYTES);
}

extern "C" void kernel_launch(void* const* d_in, const int* in_sizes, int n_in,
                              void* d_out, int out_size)
{
    (void)in_sizes; (void)n_in; (void)out_size;
    const int*   x       = (const int*)  d_in[0];
    const float* enc_emb = (const float*)d_in[1];
    const float* pos_emb = (const float*)d_in[2];
    const float* ln1_s   = (const float*)d_in[3];
    const float* ln1_b   = (const float*)d_in[4];
    const float* qkv_w   = (const float*)d_in[5];
    const float* aout_w  = (const float*)d_in[6];
    const float* aout_b  = (const float*)d_in[7];
    const float* conv_k  = (const float*)d_in[8];
    const float* ln2_s   = (const float*)d_in[9];
    const float* ln2_b   = (const float*)d_in[10];
    const float* ff_w1   = (const float*)d_in[11];
    const float* ff_b1   = (const float*)d_in[12];
    const float* ff_w2   = (const float*)d_in[13];
    const float* ff_b2   = (const float*)d_in[14];
    const float* fin_w   = (const float*)d_in[15];
    const float* fin_b   = (const float*)d_in[16];
    float* out = (float*)d_out;

    setup_tc_attrs();

    float *p_h,*p_x,*p_q,*p_k,*p_v,*p_ql,*p_kl,*p_a1,*p_a3,*p_a2;
    float *p_z,*p_z2,*p_p,*p_t,*p_t2,*p_kv,*p_zkv,*p_ao,*p_y,*p_x2,*p_ff;
    __nv_bfloat16 *p_a2h,*p_zh,*p_zh2,*p_ph,*p_th,*p_t2h;
    cudaGetSymbolAddress((void**)&p_h,  g_h);
    cudaGetSymbolAddress((void**)&p_x,  g_x);
    cudaGetSymbolAddress((void**)&p_q,  g_q);
    cudaGetSymbolAddress((void**)&p_k,  g_k);
    cudaGetSymbolAddress((void**)&p_v,  g_v);
    cudaGetSymbolAddress((void**)&p_ql, g_ql);
    cudaGetSymbolAddress((void**)&p_kl, g_kl);
    cudaGetSymbolAddress((void**)&p_a1, g_a1);
    cudaGetSymbolAddress((void**)&p_a3, g_a3);
    cudaGetSymbolAddress((void**)&p_a2, g_a2);
    cudaGetSymbolAddress((void**)&p_z,  g_zb);
    cudaGetSymbolAddress((void**)&p_z2, g_zb2);
    cudaGetSymbolAddress((void**)&p_p,  g_pb);
    cudaGetSymbolAddress((void**)&p_t,  g_tb);
    cudaGetSymbolAddress((void**)&p_t2, g_tb2);
    cudaGetSymbolAddress((void**)&p_kv, g_kvb);
    cudaGetSymbolAddress((void**)&p_zkv,g_zkv);
    cudaGetSymbolAddress((void**)&p_ao, g_ao);
    cudaGetSymbolAddress((void**)&p_y,  g_y);
    cudaGetSymbolAddress((void**)&p_x2, g_x2);
    cudaGetSymbolAddress((void**)&p_ff, g_ff);
    cudaGetSymbolAddress((void**)&p_a2h, g_a2h);
    cudaGetSymbolAddress((void**)&p_zh,  g_zh);
    cudaGetSymbolAddress((void**)&p_zh2, g_zh2);
    cudaGetSymbolAddress((void**)&p_ph,  g_ph);
    cudaGetSymbolAddress((void**)&p_th,  g_th);
    cudaGetSymbolAddress((void**)&p_t2h, g_t2h);

    const long long MM  = (long long)ML*ML;
    const long long NM  = (long long)NPAD*ML;
    const long long ND  = (long long)NPAD*DHD;
    const long long MD  = (long long)ML*DHD;

    {
        long long tot = (long long)BATCH*LSEQ*DMODEL;
        embed_kernel<<<(unsigned)((tot+255)/256),256>>>(x, enc_emb, pos_emb);
        int tot2 = BATCH*PADL*DMODEL;
        zero_pad_kernel<<<(tot2+255)/256,256>>>();
    }

    for (int lay=0; lay<DEPTH; lay++){
        ln_kernel<<<BATCH*LSEQ,256>>>(p_h, p_x, ln1_s+(long long)lay*DMODEL, ln1_b+(long long)lay*DMODEL, 1);
        // QKV [tensor, fused split into q/k/v]
        run_gemm(0,7, BATCH*NPAD, 3*DMODEL, DMODEL,
                 p_x, DMODEL, 0,
                 qkv_w + (long long)lay*DMODEL*3*DMODEL, 3*DMODEL, 0,
                 p_q, 3*DMODEL, 0, 1, 1.f, nullptr, p_k, p_v);
        {
            long long tot2 = (long long)BH*ML*DHD;
            landmark_kernel<<<(unsigned)((tot2+255)/256),256>>>();
        }
        // attn1 = softmax(q @ kl^T)  [tensor TB=1, FUSED softmax]
        run_gemm(1,8, NPAD, ML, DHD, p_q, DHD, ND, p_kl, DHD, MD, p_a1, ML, NM, BH, 1.f, nullptr);
        // attn2 = softmax(ql @ kl^T)  [tensor TB=1, FUSED softmax]
        run_gemm(1,8, ML, ML, DHD, p_ql, DHD, MD, p_kl, DHD, MD, p_a2, ML, MM, BH, 1.f, nullptr);
        // attn3 = softmax(ql @ k^T)  [tensor TB=1 + separate softmax (N=1024)]
        run_gemm(1,0, ML, NPAD, DHD, p_ql, DHD, MD, p_k, DHD, ND, p_a3, NPAD, (long long)ML*NPAD, BH, 1.f, nullptr);
        softmax_kernel<<<BH*ML,128>>>(p_a3, NPAD);

        // ---- pinv: 5 bf16 iterations + 1 tf32 polish ----
        red_init_kernel<<<1,1>>>();
        colsum_kernel<<<(BH*ML+255)/256,256>>>();
        rowsum_kernel<<<(BH*ML+255)/256,256>>>();
        {
            long long tot = (long long)BH*ML*ML;
            unsigned g = (unsigned)((tot+255)/256);
            zinit_kernel<<<g,256>>>();
        }
        __nv_bfloat16* zhc = p_zh; __nv_bfloat16* zhn = p_zh2;
        for (int it=0; it<5; it++){
            run_gemm_bf16(6, p_a2h, zhc, p_ph, p_th, nullptr, 7.f);
            run_gemm_bf16(5, p_ph, p_th,  p_t2h, nullptr, nullptr, 15.f);
            run_gemm_bf16(5, p_ph, p_t2h, p_th,  nullptr, nullptr, 13.f);
            if (it < 4){
                run_gemm_bf16(0, zhc, p_th, zhn, nullptr, nullptr, 0.25f);
                __nv_bfloat16* tmp = zhc; zhc = zhn; zhn = tmp;
            } else {
                run_gemm_bf16(1, zhc, p_th, nullptr, nullptr, p_z, 0.25f); // fp32 Z5
            }
        }
        // tf32 polish iteration (6th)
        run_gemm(0,6, ML, ML, ML, p_a2, ML, MM, p_z, ML, MM, p_p, ML, MM, BH, 7.f, nullptr, p_t);
        run_gemm(0,5, ML, ML, ML, p_p, ML, MM, p_t, ML, MM, p_t2, ML, MM, BH, 15.f, nullptr);
        run_gemm(0,5, ML, ML, ML, p_p, ML, MM, p_t2, ML, MM, p_t, ML, MM, BH, 13.f, nullptr);
        run_gemm(0,0, ML, ML, ML, p_z, ML, MM, p_t, ML, MM, p_z2, ML, MM, BH, 0.25f, nullptr);
        float* zc = p_z2;

        // kv = attn3 @ v  [tensor N=64]
        run_gemm64(ML, NPAD, p_a3, NPAD, (long long)ML*NPAD, p_v, DHD, ND, p_kv, DHD, MD, BH);
        // zkv = Z @ kv  [tensor N=64]
        run_gemm64(ML, ML, zc, ML, MM, p_kv, DHD, MD, p_zkv, DHD, MD, BH);
        // ao = attn1 @ zkv  [tensor N=64]
        run_gemm64(NPAD, ML, p_a1, ML, NM, p_zkv, DHD, MD, p_ao, DHD, ND, BH);
        {
            long long tot = (long long)BH*NPAD*DHD;
            combine_kernel<<<(unsigned)((tot+255)/256),256>>>(conv_k + (long long)lay*NH*KC);
        }
        // out projection + residual [tensor]
        run_gemm(0,4, BATCH*NPAD, DMODEL, DMODEL,
                 p_y, DMODEL, 0,
                 aout_w + (long long)lay*DMODEL*DMODEL, DMODEL, 0,
                 p_h, DMODEL, 0, 1, 1.f, aout_b + (long long)lay*DMODEL);

        // ---- FFN ----
        ln_kernel<<<BATCH*LSEQ,256>>>(p_h, p_x2, ln2_s+(long long)lay*DMODEL, ln2_b+(long long)lay*DMODEL, 0);
        run_gemm(0,2, BATCH*LSEQ, FFD, DMODEL,
                 p_x2, DMODEL, 0,
                 ff_w1 + (long long)lay*DMODEL*FFD, FFD, 0,
                 p_ff, FFD, 0, 1, 1.f, ff_b1 + (long long)lay*FFD);
        run_gemm(0,3, BATCH*LSEQ, DMODEL, FFD,
                 p_ff, FFD, 0,
                 ff_w2 + (long long)lay*FFD*DMODEL, DMODEL, 0,
                 p_h, DMODEL, 0, 1, 1.f, ff_b2 + (long long)lay*DMODEL);
    }

    final_kernel<<<BATCH,256>>>(fin_w, fin_b, out);
}

// round 13
// speedup vs baseline: 1.5450x; 1.0018x over previous
#include <cuda_runtime.h>
#include <cuda_bf16.h>
#include <math.h>
#include <stdint.h>

// ---------------- model constants ----------------
#define BATCH 16
#define LSEQ  1000
#define DMODEL 512
#define NH    8
#define DHD   64
#define NPAD  1024
#define PADL  24
#define ML    256
#define LMR   4
#define FFD   2048
#define DEPTH 6
#define KC    33
#define QSCALE 0.125f
#define BH (BATCH*NH)

// ---------------- scratch ----------------
__device__ float g_h   [BATCH*LSEQ*DMODEL];
__device__ float g_x   [BATCH*NPAD*DMODEL];
__device__ float g_q   [BH*NPAD*DHD];
__device__ float g_k   [BH*NPAD*DHD];
__device__ float g_v   [BH*NPAD*DHD];
__device__ float g_ql  [BH*ML*DHD];
__device__ float g_kl  [BH*ML*DHD];
__device__ float g_a1  [BH*NPAD*ML];
__device__ float g_a3  [BH*ML*NPAD];
__device__ float g_a2  [BH*ML*ML];
__device__ float g_zb  [BH*ML*ML];
__device__ float g_zb2 [BH*ML*ML];
__device__ float g_pb  [BH*ML*ML];
__device__ float g_tb  [BH*ML*ML];
__device__ float g_tb2 [BH*ML*ML];
__device__ float g_kvb [BH*ML*DHD];
__device__ float g_zkv [BH*ML*DHD];
__device__ float g_y   [BATCH*NPAD*DMODEL];
__device__ float g_x2  [BATCH*LSEQ*DMODEL];
__device__ float g_ff  [BATCH*LSEQ*FFD];
__device__ int   g_red [2];
// bf16 shadows for pinv
__device__ __nv_bfloat16 g_a2h [BH*ML*ML];
__device__ __nv_bfloat16 g_zh  [BH*ML*ML];
__device__ __nv_bfloat16 g_zh2 [BH*ML*ML];
__device__ __nv_bfloat16 g_ph  [BH*ML*ML];
__device__ __nv_bfloat16 g_th  [BH*ML*ML];
__device__ __nv_bfloat16 g_t2h [BH*ML*ML];

// ---------------- reductions ----------------
__device__ __forceinline__ float warpSum(float v){
    #pragma unroll
    for (int o=16;o;o>>=1) v += __shfl_xor_sync(0xffffffffu, v, o);
    return v;
}
__device__ __forceinline__ float warpMax(float v){
    #pragma unroll
    for (int o=16;o;o>>=1) v = fmaxf(v, __shfl_xor_sync(0xffffffffu, v, o));
    return v;
}
__device__ __forceinline__ float blockSumN(float v, float* sh, int nw){
    int w = threadIdx.x>>5, l = threadIdx.x&31;
    v = warpSum(v);
    if (l==0) sh[w] = v;
    __syncthreads();
    if (w==0){
        float x = (l < nw) ? sh[l] : 0.f;
        x = warpSum(x);
        if (l==0) sh[0] = x;
    }
    __syncthreads();
    float r = sh[0];
    __syncthreads();
    return r;
}
__device__ __forceinline__ float blockMaxN(float v, float* sh, int nw){
    int w = threadIdx.x>>5, l = threadIdx.x&31;
    v = warpMax(v);
    if (l==0) sh[w] = v;
    __syncthreads();
    if (w==0){
        float x = (l < nw) ? sh[l] : -3.4e38f;
        x = warpMax(x);
        if (l==0) sh[0] = x;
    }
    __syncthreads();
    float r = sh[0];
    __syncthreads();
    return r;
}

// ---------------- mma / cp.async / ldmatrix helpers ----------------
__device__ __forceinline__ void mma_tf32(float c[4],
    unsigned a0, unsigned a1, unsigned a2, unsigned a3,
    unsigned b0, unsigned b1)
{
    asm volatile(
        "mma.sync.aligned.m16n8k8.row.col.f32.tf32.tf32.f32 "
        "{%0,%1,%2,%3}, {%4,%5,%6,%7}, {%8,%9}, {%0,%1,%2,%3};"
        : "+f"(c[0]), "+f"(c[1]), "+f"(c[2]), "+f"(c[3])
        : "r"(a0), "r"(a1), "r"(a2), "r"(a3), "r"(b0), "r"(b1));
}
__device__ __forceinline__ void mma_bf16(float c[4],
    unsigned a0, unsigned a1, unsigned a2, unsigned a3,
    unsigned b0, unsigned b1)
{
    asm volatile(
        "mma.sync.aligned.m16n8k16.row.col.f32.bf16.bf16.f32 "
        "{%0,%1,%2,%3}, {%4,%5,%6,%7}, {%8,%9}, {%0,%1,%2,%3};"
        : "+f"(c[0]), "+f"(c[1]), "+f"(c[2]), "+f"(c[3])
        : "r"(a0), "r"(a1), "r"(a2), "r"(a3), "r"(b0), "r"(b1));
}
__device__ __forceinline__ void cp16(unsigned saddr, const void* gptr){
    asm volatile("cp.async.cg.shared.global [%0], [%1], 16;\n"
                 :: "r"(saddr), "l"(gptr));
}
__device__ __forceinline__ void cp_commit(){
    asm volatile("cp.async.commit_group;\n");
}
template<int N>
__device__ __forceinline__ void cp_wait(){
    asm volatile("cp.async.wait_group %0;\n" :: "n"(N));
}
__device__ __forceinline__ void ldsm4(unsigned &r0, unsigned &r1,
                                      unsigned &r2, unsigned &r3,
                                      unsigned addr){
    asm volatile("ldmatrix.sync.aligned.m8n8.x4.shared.b16 {%0,%1,%2,%3}, [%4];"
        : "=r"(r0), "=r"(r1), "=r"(r2), "=r"(r3) : "r"(addr));
}
__device__ __forceinline__ void ldsm4t(unsigned &r0, unsigned &r1,
                                       unsigned &r2, unsigned &r3,
                                       unsigned addr){
    asm volatile("ldmatrix.sync.aligned.m8n8.x4.trans.shared.b16 {%0,%1,%2,%3}, [%4];"
        : "=r"(r0), "=r"(r1), "=r"(r2), "=r"(r3) : "r"(addr));
}

// epilogue (tf32 kernels): writes 2 consecutive cols at (r, cc)
template<int EPI>
__device__ __forceinline__ void store2(
    float* __restrict__ C, float* __restrict__ C2, float* __restrict__ C3,
    int ldc, int r, int cc, float v0, float v1,
    float alpha, const float* __restrict__ bias)
{
    if (EPI==0){
        float2 o = {alpha*v0, alpha*v1};
        *(float2*)&C[(long long)r*ldc + cc] = o;
    } else if (EPI==2){
        float x0 = v0 + bias[cc], x1 = v1 + bias[cc+1];
        float2 o;
        o.x = 0.5f*x0*(1.f+erff(x0*0.70710678118654752f));
        o.y = 0.5f*x1*(1.f+erff(x1*0.70710678118654752f));
        *(float2*)&C[(long long)r*ldc + cc] = o;
    } else if (EPI==3){
        float2 o = *(float2*)&C[(long long)r*ldc + cc];
        o.x += v0 + bias[cc];
        o.y += v1 + bias[cc+1];
        *(float2*)&C[(long long)r*ldc + cc] = o;
    } else if (EPI==4){
        int bb = r / NPAD, nl = r % NPAD;
        if (nl >= PADL){
            long long orow = (long long)bb*LSEQ + (nl - PADL);
            float2 o = *(float2*)&C[orow*ldc + cc];
            o.x += v0 + bias[cc];
            o.y += v1 + bias[cc+1];
            *(float2*)&C[orow*ldc + cc] = o;
        }
    } else if (EPI==5){
        float2 o = {(r==cc ? alpha : 0.f) - v0, (r==cc+1 ? alpha : 0.f) - v1};
        *(float2*)&C[(long long)r*ldc + cc] = o;
    } else if (EPI==6){
        float2 o = {v0, v1};
        *(float2*)&C[(long long)r*ldc + cc] = o;
        float2 o2 = {(r==cc ? alpha : 0.f) - v0, (r==cc+1 ? alpha : 0.f) - v1};
        *(float2*)&C2[(long long)r*ldc + cc] = o2;
    } else if (EPI==7){
        int b = r >> 10, n = r & 1023;
        int which = cc >> 9;
        int hd = cc & 511;
        long long idx = ((((long long)b*NH + (hd>>6))*NPAD) + n)*DHD + (hd&63);
        float2 o;
        if (which==0){ o.x = v0*QSCALE; o.y = v1*QSCALE; *(float2*)&C[idx] = o; }
        else if (which==1){ o.x = v0; o.y = v1; *(float2*)&C2[idx] = o; }
        else { o.x = v0; o.y = v1; *(float2*)&C3[idx] = o; }
    }
}

// == TF32 tensor GEMM: 256 thr, CTA 128x256, warp 64x64, LDSM, 3-stage =====
// EPI 8: fused row-softmax store (requires gridDim.x==1, ldc==256)
#define AS_STRIDE 20
#define AS_ST     (128*AS_STRIDE)
#define BS0_STRIDE 264
#define BS1_STRIDE 20
#define BS_ST     (256*BS1_STRIDE)
#define NSTAGE 3
#define SMEM_TC_BYTES (NSTAGE*(AS_ST + BS_ST)*4)   // 92160

template<int TB, int EPI>
__global__ void __launch_bounds__(256,1) gemm_tc_kernel(
    int Ki,
    const float* __restrict__ A, int lda, long long sA,
    const float* __restrict__ Bm, int ldb, long long sB,
    float* __restrict__ C, int ldc, long long sC,
    float alpha, const float* __restrict__ bias,
    float* __restrict__ C2, float* __restrict__ C3)
{
    extern __shared__ unsigned sm[];
    unsigned* As = sm;
    unsigned* Bs = sm + NSTAGE*AS_ST;
    const unsigned As_base = (unsigned)__cvta_generic_to_shared(As);
    const unsigned Bs_base = (unsigned)__cvta_generic_to_shared(Bs);

    const int bz = blockIdx.z;
    A  += (long long)bz*sA;
    Bm += (long long)bz*sB;
    C  += (long long)bz*sC;
    if (EPI==6) C2 += (long long)bz*sC;

    const int row0 = blockIdx.y*128;
    const int col0 = blockIdx.x*256;
    const int tid = threadIdx.x;
    const int warp = tid>>5, lane = tid&31;
    const int wm = warp & 1, wn = warp >> 1;
    const int g = lane>>2, qc = lane&3;

    const int a_r  = tid>>1;
    const int a_c2 = (tid&1)<<1;

    auto issue = [&](int kt, int st){
        unsigned abase = As_base + (unsigned)(st*AS_ST)*4u;
        #pragma unroll
        for (int i=0;i<2;i++)
            cp16(abase + (unsigned)(a_r*AS_STRIDE + (a_c2+i)*4)*4u,
                 A + (long long)(row0 + a_r)*lda + kt + (a_c2+i)*4);
        unsigned bbase = Bs_base + (unsigned)(st*BS_ST)*4u;
        if (TB==0){
            #pragma unroll
            for (int i=0;i<4;i++){
                int fidx = tid + i*256;
                int bk = fidx>>6, bn4 = (fidx&63)<<2;
                cp16(bbase + (unsigned)(bk*BS0_STRIDE + bn4)*4u,
                     Bm + (long long)(kt + bk)*ldb + col0 + bn4);
            }
        } else {
            #pragma unroll
            for (int i=0;i<4;i++){
                int fidx = tid + i*256;
                int bn = fidx>>2, bc4 = (fidx&3)<<2;
                cp16(bbase + (unsigned)(bn*BS1_STRIDE + bc4)*4u,
                     Bm + (long long)(col0 + bn)*ldb + kt + bc4);
            }
        }
    };

    float acc[4][8][4];
    #pragma unroll
    for (int mt=0;mt<4;mt++)
        #pragma unroll
        for (int nt=0;nt<8;nt++)
            #pragma unroll
            for (int i=0;i<4;i++) acc[mt][nt][i]=0.f;

    const int nk = Ki >> 4;
    issue(0, 0);  cp_commit();
    issue(16, 1); cp_commit();

    const int lane8 = lane & 7;
    const int a_lrow = wm*64 + lane8 + ((lane>>3)&1)*8;
    const int a_lw   = ((lane>>4)&1)*4;
    const int b_lrow = wn*64 + lane8 + ((lane>>4)&1)*8;
    const int b_lw   = ((lane>>3)&1)*4;
    const int b0_frag_off = qc*BS0_STRIDE + wn*64 + g;

    for (int t = 0; t < nk; ++t){
        cp_wait<1>();
        __syncthreads();
        const int rb = t % NSTAGE;
        if (t+2 < nk) issue((t+2)<<4, (t+2)%NSTAGE);
        cp_commit();

        const unsigned a_stage = As_base + (unsigned)(rb*AS_ST)*4u;
        const unsigned b_stage = Bs_base + (unsigned)(rb*BS_ST)*4u;

        #pragma unroll
        for (int grp=0; grp<2; grp++){
            const int koff = grp*8;
            unsigned af[4][4], bf[8][2];
            #pragma unroll
            for (int mt=0;mt<4;mt++)
                ldsm4(af[mt][0], af[mt][1], af[mt][2], af[mt][3],
                      a_stage + (unsigned)(((a_lrow + mt*16)*AS_STRIDE) + a_lw + koff)*4u);
            if (TB==0){
                const unsigned* Bb = Bs + rb*BS_ST + b0_frag_off + koff*BS0_STRIDE;
                #pragma unroll
                for (int nt=0;nt<8;nt++){
                    bf[nt][0] = Bb[nt*8];
                    bf[nt][1] = Bb[4*BS0_STRIDE + nt*8];
                }
            } else {
                #pragma unroll
                for (int np=0;np<4;np++)
                    ldsm4(bf[2*np][0], bf[2*np][1], bf[2*np+1][0], bf[2*np+1][1],
                          b_stage + (unsigned)(((b_lrow + np*16)*BS1_STRIDE) + b_lw + koff)*4u);
            }
            #pragma unroll
            for (int mt=0;mt<4;mt++)
                #pragma unroll
                for (int nt=0;nt<8;nt++)
                    mma_tf32(acc[mt][nt], af[mt][0],af[mt][1],af[mt][2],af[mt][3],
                             bf[nt][0],bf[nt][1]);
        }
    }

    if (EPI==8){
        __syncthreads();
        float* redmax = (float*)sm;
        float* redsum = (float*)sm + 512;
        float rm[4][2];
        #pragma unroll
        for (int mt=0;mt<4;mt++){
            #pragma unroll
            for (int half=0; half<2; half++){
                float m = -3.4e38f;
                #pragma unroll
                for (int nt=0;nt<8;nt++){
                    m = fmaxf(m, acc[mt][nt][2*half]);
                    m = fmaxf(m, acc[mt][nt][2*half+1]);
                }
                m = fmaxf(m, __shfl_xor_sync(0xffffffffu, m, 1));
                m = fmaxf(m, __shfl_xor_sync(0xffffffffu, m, 2));
                rm[mt][half] = m;
            }
        }
        if (qc==0){
            #pragma unroll
            for (int mt=0;mt<4;mt++)
                #pragma unroll
                for (int half=0; half<2; half++){
                    int rl = wm*64 + mt*16 + g + half*8;
                    redmax[rl*4 + wn] = rm[mt][half];
                }
        }
        __syncthreads();
        float inv[4][2];
        #pragma unroll
        for (int mt=0;mt<4;mt++){
            #pragma unroll
            for (int half=0; half<2; half++){
                int rl = wm*64 + mt*16 + g + half*8;
                float m = fmaxf(fmaxf(redmax[rl*4+0], redmax[rl*4+1]),
                                fmaxf(redmax[rl*4+2], redmax[rl*4+3]));
                float s = 0.f;
                #pragma unroll
                for (int nt=0;nt<8;nt++){
                    float e0 = expf(acc[mt][nt][2*half]   - m);
                    float e1 = expf(acc[mt][nt][2*half+1] - m);
                    acc[mt][nt][2*half]   = e0;
                    acc[mt][nt][2*half+1] = e1;
                    s += e0 + e1;
                }
                s += __shfl_xor_sync(0xffffffffu, s, 1);
                s += __shfl_xor_sync(0xffffffffu, s, 2);
                if (qc==0) redsum[rl*4 + wn] = s;
                inv[mt][half] = 0.f;
            }
        }
        __syncthreads();
        #pragma unroll
        for (int mt=0;mt<4;mt++)
            #pragma unroll
            for (int half=0; half<2; half++){
                int rl = wm*64 + mt*16 + g + half*8;
                float s = redsum[rl*4+0] + redsum[rl*4+1] + redsum[rl*4+2] + redsum[rl*4+3];
                inv[mt][half] = 1.f / s;
            }
        #pragma unroll
        for (int mt=0;mt<4;mt++){
            #pragma unroll
            for (int half=0; half<2; half++){
                int r = row0 + wm*64 + mt*16 + g + half*8;
                #pragma unroll
                for (int nt=0;nt<8;nt++){
                    int cc = wn*64 + nt*8 + 2*qc;
                    float2 o = {acc[mt][nt][2*half]*inv[mt][half],
                                acc[mt][nt][2*half+1]*inv[mt][half]};
                    *(float2*)&C[(long long)r*ldc + cc] = o;
                }
            }
        }
        return;
    }

    #pragma unroll
    for (int mt=0;mt<4;mt++){
        int r = row0 + wm*64 + mt*16 + g;
        #pragma unroll
        for (int nt=0;nt<8;nt++){
            int cc = col0 + wn*64 + nt*8 + 2*qc;
            store2<EPI>(C, C2, C3, ldc, r,   cc, acc[mt][nt][0], acc[mt][nt][1], alpha, bias);
            store2<EPI>(C, C2, C3, ldc, r+8, cc, acc[mt][nt][2], acc[mt][nt][3], alpha, bias);
        }
    }
}

// ==== BF16 batched GEMM for pinv: 256x256x256, CTA 128x256, warp 64x64 ====
#define ASH 40
#define AH_ST (128*ASH)
#define BSH 264
#define BH_ST (32*BSH)
#define SMEM_BF_BYTES (NSTAGE*(AH_ST + BH_ST)*2)

template<int EPI>
__global__ void __launch_bounds__(256,1) gemm_bf16_kernel(
    const __nv_bfloat16* __restrict__ A,
    const __nv_bfloat16* __restrict__ Bm,
    __nv_bfloat16* __restrict__ Cb,
    __nv_bfloat16* __restrict__ C2b,
    float* __restrict__ Cf,
    float alpha)
{
    extern __shared__ __nv_bfloat16 smh[];
    const unsigned As_base = (unsigned)__cvta_generic_to_shared(smh);
    const unsigned Bs_base = As_base + NSTAGE*AH_ST*2u;

    const long long boff = (long long)blockIdx.z * (ML*ML);
    A  += boff; Bm += boff;

    const int row0 = blockIdx.y*128;
    const int tid = threadIdx.x;
    const int warp = tid>>5, lane = tid&31;
    const int wm = warp & 1, wn = warp >> 1;
    const int g = lane>>2, qc = lane&3;

    auto issue = [&](int kt, int st){
        unsigned abase = As_base + (unsigned)(st*AH_ST)*2u;
        #pragma unroll
        for (int i=0;i<2;i++){
            int r = tid>>1, ch = ((tid&1)<<1) + i;
            cp16(abase + (unsigned)(r*ASH + ch*8)*2u,
                 A + (long long)(row0 + r)*ML + kt + ch*8);
        }
        unsigned bbase = Bs_base + (unsigned)(st*BH_ST)*2u;
        #pragma unroll
        for (int i=0;i<4;i++){
            int fidx = tid + i*256;
            int r = fidx>>5, ch = fidx&31;
            cp16(bbase + (unsigned)(r*BSH + ch*8)*2u,
                 Bm + (long long)(kt + r)*ML + ch*8);
        }
    };

    float acc[4][8][4];
    #pragma unroll
    for (int mt=0;mt<4;mt++)
        #pragma unroll
        for (int nt=0;nt<8;nt++)
            #pragma unroll
            for (int i=0;i<4;i++) acc[mt][nt][i]=0.f;

    const int nk = ML >> 5;
    issue(0, 0);  cp_commit();
    issue(32, 1); cp_commit();

    const int lane8 = lane & 7;
    const int a_row = wm*64 + lane8 + ((lane>>3)&1)*8;
    const int a_col = ((lane>>4)&1)*8;
    const int b_row = lane8 + ((lane>>3)&1)*8;
    const int b_col = ((lane>>4)&1)*8;

    for (int t = 0; t < nk; ++t){
        cp_wait<1>();
        __syncthreads();
        const int rb = t % NSTAGE;
        if (t+2 < nk) issue((t+2)<<5, (t+2)%NSTAGE);
        cp_commit();

        const unsigned a_st = As_base + (unsigned)(rb*AH_ST)*2u;
        const unsigned b_st = Bs_base + (unsigned)(rb*BH_ST)*2u;

        #pragma unroll
        for (int kk=0; kk<2; kk++){
            const int k0 = kk*16;
            unsigned af[4][4], bf[8][2];
            #pragma unroll
            for (int mt=0;mt<4;mt++)
                ldsm4(af[mt][0], af[mt][1], af[mt][2], af[mt][3],
                      a_st + (unsigned)((a_row + mt*16)*ASH + k0 + a_col)*2u);
            #pragma unroll
            for (int np=0;np<4;np++)
                ldsm4t(bf[2*np][0], bf[2*np][1], bf[2*np+1][0], bf[2*np+1][1],
                       b_st + (unsigned)((k0 + b_row)*BSH + wn*64 + np*16 + b_col)*2u);
            #pragma unroll
            for (int mt=0;mt<4;mt++)
                #pragma unroll
                for (int nt=0;nt<8;nt++)
                    mma_bf16(acc[mt][nt], af[mt][0],af[mt][1],af[mt][2],af[mt][3],
                             bf[nt][0],bf[nt][1]);
        }
    }

    #pragma unroll
    for (int mt=0;mt<4;mt++){
        #pragma unroll
        for (int half=0; half<2; half++){
            int r = row0 + wm*64 + mt*16 + g + half*8;
            #pragma unroll
            for (int nt=0;nt<8;nt++){
                int cc = wn*64 + nt*8 + 2*qc;
                float v0 = acc[mt][nt][2*half+0];
                float v1 = acc[mt][nt][2*half+1];
                long long idx = boff + (long long)r*ML + cc;
                if (EPI==0){
                    __nv_bfloat162 pk;
                    pk.x = __float2bfloat16(alpha*v0);
                    pk.y = __float2bfloat16(alpha*v1);
                    *(__nv_bfloat162*)&Cb[idx] = pk;
                } else if (EPI==1){
                    float2 o = {alpha*v0, alpha*v1};
                    *(float2*)&Cf[idx] = o;
                } else if (EPI==5){
                    __nv_bfloat162 pk;
                    pk.x = __float2bfloat16((r==cc   ? alpha : 0.f) - v0);
                    pk.y = __float2bfloat16((r==cc+1 ? alpha : 0.f) - v1);
                    *(__nv_bfloat162*)&Cb[idx] = pk;
                } else if (EPI==6){
                    __nv_bfloat162 pk;
                    pk.x = __float2bfloat16(v0);
                    pk.y = __float2bfloat16(v1);
                    *(__nv_bfloat162*)&Cb[idx] = pk;
                    __nv_bfloat162 pk2;
                    pk2.x = __float2bfloat16((r==cc   ? alpha : 0.f) - v0);
                    pk2.y = __float2bfloat16((r==cc+1 ? alpha : 0.f) - v1);
                    *(__nv_bfloat162*)&C2b[idx] = pk2;
                }
            }
        }
    }
}

// ==== TF32 tensor GEMM N=64: 128 thr, CTA 128x64, warp 64x32, 3-stage =====
// EPI 0: C = val.   EPI 1: fused depthwise conv over v + relayout to g_y.
#define BS64_STRIDE 72
#define BS64_ST     (16*BS64_STRIDE)
#define SMEM_TC64_BYTES (NSTAGE*(AS_ST + BS64_ST)*4)

template<int EPI>
__global__ void __launch_bounds__(128) gemm_tc64_kernel(
    int Ki,
    const float* __restrict__ A, int lda, long long sA,
    const float* __restrict__ Bm, int ldb, long long sB,
    float* __restrict__ C, int ldc, long long sC,
    const float* __restrict__ Vg, const float* __restrict__ cw,
    float* __restrict__ Y)
{
    extern __shared__ unsigned sm[];
    unsigned* As = sm;
    unsigned* Bs = sm + NSTAGE*AS_ST;
    const unsigned As_base = (unsigned)__cvta_generic_to_shared(As);
    const unsigned Bs_base = (unsigned)__cvta_generic_to_shared(Bs);
    __shared__ float ws[KC];

    const int bz = blockIdx.z;
    A  += (long long)bz*sA;
    Bm += (long long)bz*sB;
    C  += (long long)bz*sC;

    const int row0 = blockIdx.y*128;
    const int tid = threadIdx.x;
    const int warp = tid>>5, lane = tid&31;
    const int wm = warp & 1, wn = warp >> 1;
    const int g = lane>>2, qc = lane&3;

    if (EPI==1 && tid < KC) ws[tid] = cw[(bz % NH)*KC + tid];

    auto issue = [&](int kt, int st){
        unsigned abase = As_base + (unsigned)(st*AS_ST)*4u;
        #pragma unroll
        for (int i=0;i<4;i++){
            int fidx = tid + i*128;
            int a_r = fidx>>2, a_c4 = (fidx&3)<<2;
            cp16(abase + (unsigned)(a_r*AS_STRIDE + a_c4)*4u,
                 A + (long long)(row0 + a_r)*lda + kt + a_c4);
        }
        unsigned bbase = Bs_base + (unsigned)(st*BS64_ST)*4u;
        #pragma unroll
        for (int i=0;i<2;i++){
            int fidx = tid + i*128;
            int bk = fidx>>4, bn4 = (fidx&15)<<2;
            cp16(bbase + (unsigned)(bk*BS64_STRIDE + bn4)*4u,
                 Bm + (long long)(kt + bk)*ldb + bn4);
        }
    };

    float acc[4][4][4];
    #pragma unroll
    for (int mt=0;mt<4;mt++)
        #pragma unroll
        for (int nt=0;nt<4;nt++)
            #pragma unroll
            for (int i=0;i<4;i++) acc[mt][nt][i]=0.f;

    const int nk = Ki >> 4;
    issue(0, 0);  cp_commit();
    issue(16, 1); cp_commit();

    const int lane8 = lane & 7;
    const int a_lrow = wm*64 + lane8 + ((lane>>3)&1)*8;
    const int a_lw   = ((lane>>4)&1)*4;
    const int b_frag_off = qc*BS64_STRIDE + wn*32 + g;

    for (int t = 0; t < nk; ++t){
        cp_wait<1>();
        __syncthreads();
        const int rb = t % NSTAGE;
        if (t+2 < nk) issue((t+2)<<4, (t+2)%NSTAGE);
        cp_commit();

        const unsigned a_stage = As_base + (unsigned)(rb*AS_ST)*4u;

        #pragma unroll
        for (int grp=0; grp<2; grp++){
            const int koff = grp*8;
            unsigned af[4][4], bf[4][2];
            #pragma unroll
            for (int mt=0;mt<4;mt++)
                ldsm4(af[mt][0], af[mt][1], af[mt][2], af[mt][3],
                      a_stage + (unsigned)(((a_lrow + mt*16)*AS_STRIDE) + a_lw + koff)*4u);
            const unsigned* Bb = Bs + rb*BS64_ST + b_frag_off + koff*BS64_STRIDE;
            #pragma unroll
            for (int nt=0;nt<4;nt++){
                bf[nt][0] = Bb[nt*8];
                bf[nt][1] = Bb[4*BS64_STRIDE + nt*8];
            }
            #pragma unroll
            for (int mt=0;mt<4;mt++)
                #pragma unroll
                for (int nt=0;nt<4;nt++)
                    mma_tf32(acc[mt][nt], af[mt][0],af[mt][1],af[mt][2],af[mt][3],
                             bf[nt][0],bf[nt][1]);
        }
    }

    if (EPI==1){
        const int h = bz % NH, b = bz / NH;
        const float* vp = Vg + (long long)bz*NPAD*DHD;
        #pragma unroll
        for (int mt=0;mt<4;mt++){
            #pragma unroll
            for (int half=0; half<2; half++){
                int n = row0 + wm*64 + mt*16 + g + half*8;
                int k0 = (16-n > 0) ? (16-n) : 0;
                int k1 = (NPAD+16-n < KC) ? (NPAD+16-n) : KC;
                #pragma unroll
                for (int nt=0;nt<4;nt++){
                    int cc = wn*32 + nt*8 + 2*qc;
                    float s0 = acc[mt][nt][2*half+0];
                    float s1 = acc[mt][nt][2*half+1];
                    for (int kk=k0; kk<k1; kk++){
                        float2 vv = *(const float2*)&vp[(long long)(n+kk-16)*DHD + cc];
                        s0 = fmaf(vv.x, ws[kk], s0);
                        s1 = fmaf(vv.y, ws[kk], s1);
                    }
                    float2 o = {s0, s1};
                    *(float2*)&Y[((long long)b*NPAD + n)*DMODEL + h*DHD + cc] = o;
                }
            }
        }
        return;
    }

    #pragma unroll
    for (int mt=0;mt<4;mt++){
        int r = row0 + wm*64 + mt*16 + g;
        #pragma unroll
        for (int nt=0;nt<4;nt++){
            int cc = wn*32 + nt*8 + 2*qc;
            float2 o0 = {acc[mt][nt][0], acc[mt][nt][1]};
            float2 o1 = {acc[mt][nt][2], acc[mt][nt][3]};
            *(float2*)&C[(long long)r*ldc + cc] = o0;
            *(float2*)&C[(long long)(r+8)*ldc + cc] = o1;
        }
    }
}

// ---------------- elementwise / small kernels ----------------
__global__ void embed_kernel(const int* __restrict__ x,
                             const float* __restrict__ emb,
                             const float* __restrict__ pos){
    long long idx = (long long)blockIdx.x*blockDim.x + threadIdx.x;
    if (idx >= (long long)BATCH*LSEQ*DMODEL) return;
    int d = (int)(idx % DMODEL);
    long long bl = idx / DMODEL;
    int l = (int)(bl % LSEQ);
    int tok = x[bl];
    g_h[idx] = emb[(long long)tok*DMODEL + d] + pos[(long long)l*DMODEL + d];
}

__global__ void zero_pad_kernel(){
    int idx = blockIdx.x*blockDim.x + threadIdx.x;
    if (idx >= BATCH*PADL*DMODEL) return;
    int d  = idx % DMODEL;
    int bp = idx / DMODEL;
    int b  = bp / PADL, p = bp % PADL;
    g_x[((long long)b*NPAD + p)*DMODEL + d] = 0.f;
}

__global__ void ln_kernel(const float* __restrict__ in, float* __restrict__ out,
                          const float* __restrict__ gm, const float* __restrict__ bt,
                          int padmode){
    __shared__ float sh[8];
    int r = blockIdx.x;
    int t = threadIdx.x;
    const float* p = in + (long long)r*DMODEL;
    float a  = p[t];
    float b2 = p[t+256];
    float s  = blockSumN(a+b2, sh, 8);
    float mu = s * (1.f/512.f);
    float da = a - mu, db = b2 - mu;
    float v  = blockSumN(da*da + db*db, sh, 8) * (1.f/512.f);
    float rstd = rsqrtf(v + 1e-5f);
    long long orow = padmode ? ((long long)(r/LSEQ)*NPAD + PADL + (r%LSEQ)) : (long long)r;
    float* q = out + orow*DMODEL;
    q[t]     = da*rstd*gm[t]     + bt[t];
    q[t+256] = db*rstd*gm[t+256] + bt[t+256];
}

__global__ void landmark_kernel(){
    long long idx = (long long)blockIdx.x*blockDim.x + threadIdx.x;
    if (idx >= (long long)BH*ML*DHD) return;
    int d = (int)(idx & 63);
    long long r = idx >> 6;
    int m  = (int)(r % ML);
    int bh = (int)(r / ML);
    long long base = ((long long)bh*NPAD + (long long)m*LMR)*DHD + d;
    float sq = 0.f, sk = 0.f;
    #pragma unroll
    for (int j=0;j<LMR;j++){ sq += g_q[base + (long long)j*DHD]; sk += g_k[base + (long long)j*DHD]; }
    g_ql[idx] = sq * 0.25f;
    g_kl[idx] = sk * 0.25f;
}

__global__ void softmax_kernel(float* __restrict__ X, int cols){
    __shared__ float sh[4];
    long long row = blockIdx.x;
    float* p = X + row*(long long)cols;
    int t = threadIdx.x;
    int cnt = cols >> 7;
    float v[8];
    float mx = -3.4e38f;
    #pragma unroll
    for (int i=0;i<8;i++) if (i<cnt){ v[i]=p[t + (i<<7)]; mx = fmaxf(mx, v[i]); }
    mx = blockMaxN(mx, sh, 4);
    float s = 0.f;
    #pragma unroll
    for (int i=0;i<8;i++) if (i<cnt){ v[i]=expf(v[i]-mx); s += v[i]; }
    s = blockSumN(s, sh, 4);
    float inv = 1.f/s;
    #pragma unroll
    for (int i=0;i<8;i++) if (i<cnt) p[t + (i<<7)] = v[i]*inv;
}

__global__ void red_init_kernel(){ g_red[0]=0; g_red[1]=0; }

// coalesced: one block (256 thr) per batch; thread c sums |column c|
__global__ void colsum_kernel(){
    __shared__ float sh[8];
    int bz = blockIdx.x;
    const float* p = g_a2 + (long long)bz*ML*ML;
    int c = threadIdx.x;
    float s = 0.f;
    for (int r=0;r<ML;r++) s += fabsf(p[(long long)r*ML + c]);
    float m = blockMaxN(s, sh, 8);
    if (threadIdx.x==0) atomicMax(&g_red[0], __float_as_int(m));
}
// coalesced: one block (256 thr = 8 warps) per batch; warp w sums rows w, w+8...
__global__ void rowsum_kernel(){
    __shared__ float sh[8];
    int bz = blockIdx.x;
    const float* p = g_a2 + (long long)bz*ML*ML;
    int w = threadIdx.x>>5, l = threadIdx.x&31;
    float m = -3.4e38f;
    for (int r=w; r<ML; r+=8){
        float s = 0.f;
        for (int c=l; c<ML; c+=32) s += fabsf(p[(long long)r*ML + c]);
        s = warpSum(s);
        m = fmaxf(m, s);
    }
    m = blockMaxN(m, sh, 8);
    if (threadIdx.x==0) atomicMax(&g_red[1], __float_as_int(m));
}
// tiled transpose: Z0[i][j] = A2[j][i]/c (fp32+bf16), plus bf16 shadow of A2
__global__ void zinit_kernel(){
    __shared__ float tile[32][33];
    int bz = blockIdx.z;
    int i0 = blockIdx.x*32;
    int j0 = blockIdx.y*32;
    const long long base = (long long)bz*ML*ML;
    float c = __int_as_float(g_red[0]) * __int_as_float(g_red[1]);
    float invc = 1.f/c;
    #pragma unroll
    for (int k=0;k<4;k++){
        int j = j0 + threadIdx.y + k*8;
        float v = g_a2[base + (long long)j*ML + i0 + threadIdx.x];
        tile[threadIdx.y + k*8][threadIdx.x] = v;
        g_a2h[base + (long long)j*ML + i0 + threadIdx.x] = __float2bfloat16(v);
    }
    __syncthreads();
    #pragma unroll
    for (int k=0;k<4;k++){
        int i = i0 + threadIdx.y + k*8;
        float v = tile[threadIdx.x][threadIdx.y + k*8] * invc;
        long long idx = base + (long long)i*ML + j0 + threadIdx.x;
        g_zb[idx] = v;
        g_zh[idx] = __float2bfloat16(v);
    }
}

__global__ void final_kernel(const float* __restrict__ fw,
                             const float* __restrict__ fb,
                             float* __restrict__ out){
    __shared__ float sh[8];
    int b = blockIdx.x;
    int t = threadIdx.x;
    const float* hp = g_h + (long long)b*LSEQ*DMODEL;
    float s = 0.f;
    for (long long i=t; i<(long long)LSEQ*DMODEL; i+=256)
        s = fmaf(hp[i], fw[i], s);
    s = blockSumN(s, sh, 8);
    if (t==0) out[b] = s + fb[0];
}

// ---------------- host-side GEMM dispatch ----------------
static void run_gemm(int tb, int epi, int Mi, int Ni, int Ki,
                     const float* A, int lda, long long sA,
                     const float* Bm, int ldb, long long sB,
                     float* C, int ldc, long long sC,
                     int batch, float alpha, const float* bias,
                     float* C2 = nullptr, float* C3 = nullptr)
{
    dim3 g(Ni/256, Mi/128, batch), t(256);
    size_t sh = SMEM_TC_BYTES;
    if (tb == 0) {
        switch (epi) {
            case 0: gemm_tc_kernel<0,0><<<g,t,sh>>>(Ki,A,lda,sA,Bm,ldb,sB,C,ldc,sC,alpha,bias,C2,C3); break;
            case 2: gemm_tc_kernel<0,2><<<g,t,sh>>>(Ki,A,lda,sA,Bm,ldb,sB,C,ldc,sC,alpha,bias,C2,C3); break;
            case 3: gemm_tc_kernel<0,3><<<g,t,sh>>>(Ki,A,lda,sA,Bm,ldb,sB,C,ldc,sC,alpha,bias,C2,C3); break;
            case 4: gemm_tc_kernel<0,4><<<g,t,sh>>>(Ki,A,lda,sA,Bm,ldb,sB,C,ldc,sC,alpha,bias,C2,C3); break;
            case 5: gemm_tc_kernel<0,5><<<g,t,sh>>>(Ki,A,lda,sA,Bm,ldb,sB,C,ldc,sC,alpha,bias,C2,C3); break;
            case 6: gemm_tc_kernel<0,6><<<g,t,sh>>>(Ki,A,lda,sA,Bm,ldb,sB,C,ldc,sC,alpha,bias,C2,C3); break;
            case 7: gemm_tc_kernel<0,7><<<g,t,sh>>>(Ki,A,lda,sA,Bm,ldb,sB,C,ldc,sC,alpha,bias,C2,C3); break;
        }
    } else {
        if (epi == 8)
            gemm_tc_kernel<1,8><<<g,t,sh>>>(Ki,A,lda,sA,Bm,ldb,sB,C,ldc,sC,alpha,bias,C2,C3);
        else
            gemm_tc_kernel<1,0><<<g,t,sh>>>(Ki,A,lda,sA,Bm,ldb,sB,C,ldc,sC,alpha,bias,C2,C3);
    }
}

static void run_gemm64(int epi, int Mi, int Ki,
                       const float* A, int lda, long long sA,
                       const float* Bm, int ldb, long long sB,
                       float* C, int ldc, long long sC, int batch,
                       const float* Vg = nullptr, const float* cw = nullptr,
                       float* Y = nullptr)
{
    dim3 g(1, Mi/128, batch), t(128);
    if (epi == 0)
        gemm_tc64_kernel<0><<<g,t,SMEM_TC64_BYTES>>>(Ki,A,lda,sA,Bm,ldb,sB,C,ldc,sC,Vg,cw,Y);
    else
        gemm_tc64_kernel<1><<<g,t,SMEM_TC64_BYTES>>>(Ki,A,lda,sA,Bm,ldb,sB,C,ldc,sC,Vg,cw,Y);
}

static void run_gemm_bf16(int epi,
                          const __nv_bfloat16* A, const __nv_bfloat16* Bm,
                          __nv_bfloat16* Cb, __nv_bfloat16* C2b, float* Cf,
                          float alpha)
{
    dim3 g(1, ML/128, BH), t(256);
    size_t sh = SMEM_BF_BYTES;
    switch (epi) {
        case 0: gemm_bf16_kernel<0><<<g,t,sh>>>(A,Bm,Cb,C2b,Cf,alpha); break;
        case 1: gemm_bf16_kernel<1><<<g,t,sh>>>(A,Bm,Cb,C2b,Cf,alpha); break;
        case 5: gemm_bf16_kernel<5><<<g,t,sh>>>(A,Bm,Cb,C2b,Cf,alpha); break;
        case 6: gemm_bf16_kernel<6><<<g,t,sh>>>(A,Bm,Cb,C2b,Cf,alpha); break;
    }
}

static void setup_tc_attrs(){
    cudaFuncSetAttribute(gemm_tc_kernel<0,0>, cudaFuncAttributeMaxDynamicSharedMemorySize, SMEM_TC_BYTES);
    cudaFuncSetAttribute(gemm_tc_kernel<0,2>, cudaFuncAttributeMaxDynamicSharedMemorySize, SMEM_TC_BYTES);
    cudaFuncSetAttribute(gemm_tc_kernel<0,3>, cudaFuncAttributeMaxDynamicSharedMemorySize, SMEM_TC_BYTES);
    cudaFuncSetAttribute(gemm_tc_kernel<0,4>, cudaFuncAttributeMaxDynamicSharedMemorySize, SMEM_TC_BYTES);
    cudaFuncSetAttribute(gemm_tc_kernel<0,5>, cudaFuncAttributeMaxDynamicSharedMemorySize, SMEM_TC_BYTES);
    cudaFuncSetAttribute(gemm_tc_kernel<0,6>, cudaFuncAttributeMaxDynamicSharedMemorySize, SMEM_TC_BYTES);
    cudaFuncSetAttribute(gemm_tc_kernel<0,7>, cudaFuncAttributeMaxDynamicSharedMemorySize, SMEM_TC_BYTES);
    cudaFuncSetAttribute(gemm_tc_kernel<1,0>, cudaFuncAttributeMaxDynamicSharedMemorySize, SMEM_TC_BYTES);
    cudaFuncSetAttribute(gemm_tc_kernel<1,8>, cudaFuncAttributeMaxDynamicSharedMemorySize, SMEM_TC_BYTES);
    cudaFuncSetAttribute(gemm_tc64_kernel<0>, cudaFuncAttributeMaxDynamicSharedMemorySize, SMEM_TC64_BYTES);
    cudaFuncSetAttribute(gemm_tc64_kernel<1>, cudaFuncAttributeMaxDynamicSharedMemorySize, SMEM_TC64_BYTES);
    cudaFuncSetAttribute(gemm_bf16_kernel<0>, cudaFuncAttributeMaxDynamicSharedMemorySize, SMEM_BF_BYTES);
    cudaFuncSetAttribute(gemm_bf16_kernel<1>, cudaFuncAttributeMaxDynamicSharedMemorySize, SMEM_BF_BYTES);
    cudaFuncSetAttribute(gemm_bf16_kernel<5>, cudaFuncAttributeMaxDynamicSharedMemorySize, SMEM_BF_BYTES);
    cudaFuncSetAttribute(gemm_bf16_kernel<6>, cudaFuncAttributeMaxDynamicSharedMemorySize, SMEM_BF_BYTES);
}

extern "C" void kernel_launch(void* const* d_in, const int* in_sizes, int n_in,
                              void* d_out, int out_size)
{
    (void)in_sizes; (void)n_in; (void)out_size;
    const int*   x       = (const int*)  d_in[0];
    const float* enc_emb = (const float*)d_in[1];
    const float* pos_emb = (const float*)d_in[2];
    const float* ln1_s   = (const float*)d_in[3];
    const float* ln1_b   = (const float*)d_in[4];
    const float* qkv_w   = (const float*)d_in[5];
    const float* aout_w  = (const float*)d_in[6];
    const float* aout_b  = (const float*)d_in[7];
    const float* conv_k  = (const float*)d_in[8];
    const float* ln2_s   = (const float*)d_in[9];
    const float* ln2_b   = (const float*)d_in[10];
    const float* ff_w1   = (const float*)d_in[11];
    const float* ff_b1   = (const float*)d_in[12];
    const float* ff_w2   = (const float*)d_in[13];
    const float* ff_b2   = (const float*)d_in[14];
    const float* fin_w   = (const float*)d_in[15];
    const float* fin_b   = (const float*)d_in[16];
    float* out = (float*)d_out;

    setup_tc_attrs();

    float *p_h,*p_x,*p_q,*p_k,*p_v,*p_ql,*p_kl,*p_a1,*p_a3,*p_a2;
    float *p_z,*p_z2,*p_p,*p_t,*p_t2,*p_kv,*p_zkv,*p_y,*p_x2,*p_ff;
    __nv_bfloat16 *p_a2h,*p_zh,*p_zh2,*p_ph,*p_th,*p_t2h;
    cudaGetSymbolAddress((void**)&p_h,  g_h);
    cudaGetSymbolAddress((void**)&p_x,  g_x);
    cudaGetSymbolAddress((void**)&p_q,  g_q);
    cudaGetSymbolAddress((void**)&p_k,  g_k);
    cudaGetSymbolAddress((void**)&p_v,  g_v);
    cudaGetSymbolAddress((void**)&p_ql, g_ql);
    cudaGetSymbolAddress((void**)&p_kl, g_kl);
    cudaGetSymbolAddress((void**)&p_a1, g_a1);
    cudaGetSymbolAddress((void**)&p_a3, g_a3);
    cudaGetSymbolAddress((void**)&p_a2, g_a2);
    cudaGetSymbolAddress((void**)&p_z,  g_zb);
    cudaGetSymbolAddress((void**)&p_z2, g_zb2);
    cudaGetSymbolAddress((void**)&p_p,  g_pb);
    cudaGetSymbolAddress((void**)&p_t,  g_tb);
    cudaGetSymbolAddress((void**)&p_t2, g_tb2);
    cudaGetSymbolAddress((void**)&p_kv, g_kvb);
    cudaGetSymbolAddress((void**)&p_zkv,g_zkv);
    cudaGetSymbolAddress((void**)&p_y,  g_y);
    cudaGetSymbolAddress((void**)&p_x2, g_x2);
    cudaGetSymbolAddress((void**)&p_ff, g_ff);
    cudaGetSymbolAddress((void**)&p_a2h, g_a2h);
    cudaGetSymbolAddress((void**)&p_zh,  g_zh);
    cudaGetSymbolAddress((void**)&p_zh2, g_zh2);
    cudaGetSymbolAddress((void**)&p_ph,  g_ph);
    cudaGetSymbolAddress((void**)&p_th,  g_th);
    cudaGetSymbolAddress((void**)&p_t2h, g_t2h);

    const long long MM  = (long long)ML*ML;
    const long long NM  = (long long)NPAD*ML;
    const long long ND  = (long long)NPAD*DHD;
    const long long MD  = (long long)ML*DHD;

    {
        long long tot = (long long)BATCH*LSEQ*DMODEL;
        embed_kernel<<<(unsigned)((tot+255)/256),256>>>(x, enc_emb, pos_emb);
        int tot2 = BATCH*PADL*DMODEL;
        zero_pad_kernel<<<(tot2+255)/256,256>>>();
    }

    for (int lay=0; lay<DEPTH; lay++){
        ln_kernel<<<BATCH*LSEQ,256>>>(p_h, p_x, ln1_s+(long long)lay*DMODEL, ln1_b+(long long)lay*DMODEL, 1);
        // QKV [tensor, fused split into q/k/v]
        run_gemm(0,7, BATCH*NPAD, 3*DMODEL, DMODEL,
                 p_x, DMODEL, 0,
                 qkv_w + (long long)lay*DMODEL*3*DMODEL, 3*DMODEL, 0,
                 p_q, 3*DMODEL, 0, 1, 1.f, nullptr, p_k, p_v);
        {
            long long tot2 = (long long)BH*ML*DHD;
            landmark_kernel<<<(unsigned)((tot2+255)/256),256>>>();
        }
        // attn1 = softmax(q @ kl^T)  [tensor TB=1, FUSED softmax]
        run_gemm(1,8, NPAD, ML, DHD, p_q, DHD, ND, p_kl, DHD, MD, p_a1, ML, NM, BH, 1.f, nullptr);
        // attn2 = softmax(ql @ kl^T)  [tensor TB=1, FUSED softmax]
        run_gemm(1,8, ML, ML, DHD, p_ql, DHD, MD, p_kl, DHD, MD, p_a2, ML, MM, BH, 1.f, nullptr);
        // attn3 = softmax(ql @ k^T)  [tensor TB=1 + separate softmax (N=1024)]
        run_gemm(1,0, ML, NPAD, DHD, p_ql, DHD, MD, p_k, DHD, ND, p_a3, NPAD, (long long)ML*NPAD, BH, 1.f, nullptr);
        softmax_kernel<<<BH*ML,128>>>(p_a3, NPAD);

        // ---- pinv: 5 bf16 quintic iterations + 1 tf32 quintic polish ----
        red_init_kernel<<<1,1>>>();
        colsum_kernel<<<BH,256>>>();
        rowsum_kernel<<<BH,256>>>();
        {
            dim3 gz(ML/32, ML/32, BH), tz(32, 8);
            zinit_kernel<<<gz, tz>>>();
        }
        __nv_bfloat16* zhc = p_zh; __nv_bfloat16* zhn = p_zh2;
        for (int it=0; it<5; it++){
            run_gemm_bf16(6, p_a2h, zhc, p_ph, p_th, nullptr, 7.f);
            run_gemm_bf16(5, p_ph, p_th,  p_t2h, nullptr, nullptr, 15.f);
            run_gemm_bf16(5, p_ph, p_t2h, p_th,  nullptr, nullptr, 13.f);
            if (it < 4){
                run_gemm_bf16(0, zhc, p_th, zhn, nullptr, nullptr, 0.25f);
                __nv_bfloat16* tmp = zhc; zhc = zhn; zhn = tmp;
            } else {
                run_gemm_bf16(1, zhc, p_th, nullptr, nullptr, p_z, 0.25f); // fp32 Z5
            }
        }
        // tf32 quintic polish (6th iteration, same map as reference)
        run_gemm(0,6, ML, ML, ML, p_a2, ML, MM, p_z, ML, MM, p_p, ML, MM, BH, 7.f, nullptr, p_t);
        run_gemm(0,5, ML, ML, ML, p_p, ML, MM, p_t, ML, MM, p_t2, ML, MM, BH, 15.f, nullptr);
        run_gemm(0,5, ML, ML, ML, p_p, ML, MM, p_t2, ML, MM, p_t, ML, MM, BH, 13.f, nullptr);
        run_gemm(0,0, ML, ML, ML, p_z, ML, MM, p_t, ML, MM, p_z2, ML, MM, BH, 0.25f, nullptr);
        float* zc = p_z2;

        // kv = attn3 @ v  [tensor N=64]
        run_gemm64(0, ML, NPAD, p_a3, NPAD, (long long)ML*NPAD, p_v, DHD, ND, p_kv, DHD, MD, BH);
        // zkv = Z @ kv  [tensor N=64]
        run_gemm64(0, ML, ML, zc, ML, MM, p_kv, DHD, MD, p_zkv, DHD, MD, BH);
        // ao = attn1 @ zkv + depthwise conv(v), relayout -> g_y  [tensor N=64, fused]
        run_gemm64(1, NPAD, ML, p_a1, ML, NM, p_zkv, DHD, MD, nullptr, DHD, ND, BH,
                   p_v, conv_k + (long long)lay*NH*KC, p_y);
        // out projection + residual [tensor]
        run_gemm(0,4, BATCH*NPAD, DMODEL, DMODEL,
                 p_y, DMODEL, 0,
                 aout_w + (long long)lay*DMODEL*DMODEL, DMODEL, 0,
                 p_h, DMODEL, 0, 1, 1.f, aout_b + (long long)lay*DMODEL);

        // ---- FFN ----
        ln_kernel<<<BATCH*LSEQ,256>>>(p_h, p_x2, ln2_s+(long long)lay*DMODEL, ln2_b+(long long)lay*DMODEL, 0);
        run_gemm(0,2, BATCH*LSEQ, FFD, DMODEL,
                 p_x2, DMODEL, 0,
                 ff_w1 + (long long)lay*DMODEL*FFD, FFD, 0,
                 p_ff, FFD, 0, 1, 1.f, ff_b1 + (long long)lay*FFD);
        run_gemm(0,3, BATCH*LSEQ, DMODEL, FFD,
                 p_ff, FFD, 0,
                 ff_w2 + (long long)lay*FFD*DMODEL, DMODEL, 0,
                 p_h, DMODEL, 0, 1, 1.f, ff_b2 + (long long)lay*DMODEL);
    }

    final_kernel<<<BATCH,256>>>(fin_w, fin_b, out);
}

// round 14
// speedup vs baseline: 1.9069x; 1.2343x over previous
#include <cuda_runtime.h>
#include <cuda_bf16.h>
#include <cuda_fp16.h>
#include <math.h>
#include <stdint.h>

// ---------------- model constants ----------------
#define BATCH 16
#define LSEQ  1000
#define DMODEL 512
#define NH    8
#define DHD   64
#define NPAD  1024
#define PADL  24
#define ML    256
#define LMR   4
#define FFD   2048
#define DEPTH 6
#define KC    33
#define QSCALE 0.125f
#define BH (BATCH*NH)

// ---------------- scratch ----------------
__device__ float g_h   [BATCH*LSEQ*DMODEL];
__device__ float g_q   [BH*NPAD*DHD];
__device__ float g_k   [BH*NPAD*DHD];
__device__ float g_v   [BH*NPAD*DHD];
__device__ float g_ql  [BH*ML*DHD];
__device__ float g_kl  [BH*ML*DHD];
__device__ float g_a1  [BH*NPAD*ML];
__device__ float g_a3  [BH*ML*NPAD];
__device__ float g_a2  [BH*ML*ML];
__device__ float g_zb  [BH*ML*ML];
__device__ float g_zb2 [BH*ML*ML];
__device__ float g_pb  [BH*ML*ML];
__device__ float g_tb  [BH*ML*ML];
__device__ float g_tb2 [BH*ML*ML];
__device__ float g_kvb [BH*ML*DHD];
__device__ float g_zkv [BH*ML*DHD];
__device__ int   g_red [2];
// fp16 activations / weights
__device__ __half g_xh  [BATCH*NPAD*DMODEL];
__device__ __half g_x2h [BATCH*LSEQ*DMODEL];
__device__ __half g_ffh [BATCH*LSEQ*FFD];
__device__ __half g_yh  [BATCH*NPAD*DMODEL];
__device__ __half g_wqkv[DEPTH*DMODEL*3*DMODEL];
__device__ __half g_wout[DEPTH*DMODEL*DMODEL];
__device__ __half g_wf1 [DEPTH*DMODEL*FFD];
__device__ __half g_wf2 [DEPTH*FFD*DMODEL];
// bf16 shadows for pinv
__device__ __nv_bfloat16 g_a2h [BH*ML*ML];
__device__ __nv_bfloat16 g_zh  [BH*ML*ML];
__device__ __nv_bfloat16 g_zh2 [BH*ML*ML];
__device__ __nv_bfloat16 g_ph  [BH*ML*ML];
__device__ __nv_bfloat16 g_th  [BH*ML*ML];
__device__ __nv_bfloat16 g_t2h [BH*ML*ML];

// ---------------- reductions ----------------
__device__ __forceinline__ float warpSum(float v){
    #pragma unroll
    for (int o=16;o;o>>=1) v += __shfl_xor_sync(0xffffffffu, v, o);
    return v;
}
__device__ __forceinline__ float warpMax(float v){
    #pragma unroll
    for (int o=16;o;o>>=1) v = fmaxf(v, __shfl_xor_sync(0xffffffffu, v, o));
    return v;
}
__device__ __forceinline__ float blockSumN(float v, float* sh, int nw){
    int w = threadIdx.x>>5, l = threadIdx.x&31;
    v = warpSum(v);
    if (l==0) sh[w] = v;
    __syncthreads();
    if (w==0){
        float x = (l < nw) ? sh[l] : 0.f;
        x = warpSum(x);
        if (l==0) sh[0] = x;
    }
    __syncthreads();
    float r = sh[0];
    __syncthreads();
    return r;
}
__device__ __forceinline__ float blockMaxN(float v, float* sh, int nw){
    int w = threadIdx.x>>5, l = threadIdx.x&31;
    v = warpMax(v);
    if (l==0) sh[w] = v;
    __syncthreads();
    if (w==0){
        float x = (l < nw) ? sh[l] : -3.4e38f;
        x = warpMax(x);
        if (l==0) sh[0] = x;
    }
    __syncthreads();
    float r = sh[0];
    __syncthreads();
    return r;
}

// ---------------- mma / cp.async / ldmatrix helpers ----------------
__device__ __forceinline__ void mma_tf32(float c[4],
    unsigned a0, unsigned a1, unsigned a2, unsigned a3,
    unsigned b0, unsigned b1)
{
    asm volatile(
        "mma.sync.aligned.m16n8k8.row.col.f32.tf32.tf32.f32 "
        "{%0,%1,%2,%3}, {%4,%5,%6,%7}, {%8,%9}, {%0,%1,%2,%3};"
        : "+f"(c[0]), "+f"(c[1]), "+f"(c[2]), "+f"(c[3])
        : "r"(a0), "r"(a1), "r"(a2), "r"(a3), "r"(b0), "r"(b1));
}
__device__ __forceinline__ void mma_bf16(float c[4],
    unsigned a0, unsigned a1, unsigned a2, unsigned a3,
    unsigned b0, unsigned b1)
{
    asm volatile(
        "mma.sync.aligned.m16n8k16.row.col.f32.bf16.bf16.f32 "
        "{%0,%1,%2,%3}, {%4,%5,%6,%7}, {%8,%9}, {%0,%1,%2,%3};"
        : "+f"(c[0]), "+f"(c[1]), "+f"(c[2]), "+f"(c[3])
        : "r"(a0), "r"(a1), "r"(a2), "r"(a3), "r"(b0), "r"(b1));
}
__device__ __forceinline__ void mma_f16(float c[4],
    unsigned a0, unsigned a1, unsigned a2, unsigned a3,
    unsigned b0, unsigned b1)
{
    asm volatile(
        "mma.sync.aligned.m16n8k16.row.col.f32.f16.f16.f32 "
        "{%0,%1,%2,%3}, {%4,%5,%6,%7}, {%8,%9}, {%0,%1,%2,%3};"
        : "+f"(c[0]), "+f"(c[1]), "+f"(c[2]), "+f"(c[3])
        : "r"(a0), "r"(a1), "r"(a2), "r"(a3), "r"(b0), "r"(b1));
}
__device__ __forceinline__ void cp16(unsigned saddr, const void* gptr){
    asm volatile("cp.async.cg.shared.global [%0], [%1], 16;\n"
                 :: "r"(saddr), "l"(gptr));
}
__device__ __forceinline__ void cp_commit(){
    asm volatile("cp.async.commit_group;\n");
}
template<int N>
__device__ __forceinline__ void cp_wait(){
    asm volatile("cp.async.wait_group %0;\n" :: "n"(N));
}
__device__ __forceinline__ void ldsm4(unsigned &r0, unsigned &r1,
                                      unsigned &r2, unsigned &r3,
                                      unsigned addr){
    asm volatile("ldmatrix.sync.aligned.m8n8.x4.shared.b16 {%0,%1,%2,%3}, [%4];"
        : "=r"(r0), "=r"(r1), "=r"(r2), "=r"(r3) : "r"(addr));
}
__device__ __forceinline__ void ldsm4t(unsigned &r0, unsigned &r1,
                                       unsigned &r2, unsigned &r3,
                                       unsigned addr){
    asm volatile("ldmatrix.sync.aligned.m8n8.x4.trans.shared.b16 {%0,%1,%2,%3}, [%4];"
        : "=r"(r0), "=r"(r1), "=r"(r2), "=r"(r3) : "r"(addr));
}

// epilogue (tf32 kernels): writes 2 consecutive cols at (r, cc)
template<int EPI>
__device__ __forceinline__ void store2(
    float* __restrict__ C, float* __restrict__ C2, float* __restrict__ C3,
    int ldc, int r, int cc, float v0, float v1,
    float alpha, const float* __restrict__ bias)
{
    if (EPI==0){
        float2 o = {alpha*v0, alpha*v1};
        *(float2*)&C[(long long)r*ldc + cc] = o;
    } else if (EPI==5){
        float2 o = {(r==cc ? alpha : 0.f) - v0, (r==cc+1 ? alpha : 0.f) - v1};
        *(float2*)&C[(long long)r*ldc + cc] = o;
    } else if (EPI==6){
        float2 o = {v0, v1};
        *(float2*)&C[(long long)r*ldc + cc] = o;
        float2 o2 = {(r==cc ? alpha : 0.f) - v0, (r==cc+1 ? alpha : 0.f) - v1};
        *(float2*)&C2[(long long)r*ldc + cc] = o2;
    }
}

// == TF32 tensor GEMM: 256 thr, CTA 128x256, warp 64x64, LDSM, 3-stage =====
// EPI 8: fused row-softmax store (requires gridDim.x==1, ldc==256)
#define AS_STRIDE 20
#define AS_ST     (128*AS_STRIDE)
#define BS0_STRIDE 264
#define BS1_STRIDE 20
#define BS_ST     (256*BS1_STRIDE)
#define NSTAGE 3
#define SMEM_TC_BYTES (NSTAGE*(AS_ST + BS_ST)*4)   // 92160

template<int TB, int EPI>
__global__ void __launch_bounds__(256,1) gemm_tc_kernel(
    int Ki,
    const float* __restrict__ A, int lda, long long sA,
    const float* __restrict__ Bm, int ldb, long long sB,
    float* __restrict__ C, int ldc, long long sC,
    float alpha, const float* __restrict__ bias,
    float* __restrict__ C2, float* __restrict__ C3)
{
    extern __shared__ unsigned sm[];
    unsigned* As = sm;
    unsigned* Bs = sm + NSTAGE*AS_ST;
    const unsigned As_base = (unsigned)__cvta_generic_to_shared(As);
    const unsigned Bs_base = (unsigned)__cvta_generic_to_shared(Bs);

    const int bz = blockIdx.z;
    A  += (long long)bz*sA;
    Bm += (long long)bz*sB;
    C  += (long long)bz*sC;
    if (EPI==6) C2 += (long long)bz*sC;

    const int row0 = blockIdx.y*128;
    const int col0 = blockIdx.x*256;
    const int tid = threadIdx.x;
    const int warp = tid>>5, lane = tid&31;
    const int wm = warp & 1, wn = warp >> 1;
    const int g = lane>>2, qc = lane&3;

    const int a_r  = tid>>1;
    const int a_c2 = (tid&1)<<1;

    auto issue = [&](int kt, int st){
        unsigned abase = As_base + (unsigned)(st*AS_ST)*4u;
        #pragma unroll
        for (int i=0;i<2;i++)
            cp16(abase + (unsigned)(a_r*AS_STRIDE + (a_c2+i)*4)*4u,
                 A + (long long)(row0 + a_r)*lda + kt + (a_c2+i)*4);
        unsigned bbase = Bs_base + (unsigned)(st*BS_ST)*4u;
        if (TB==0){
            #pragma unroll
            for (int i=0;i<4;i++){
                int fidx = tid + i*256;
                int bk = fidx>>6, bn4 = (fidx&63)<<2;
                cp16(bbase + (unsigned)(bk*BS0_STRIDE + bn4)*4u,
                     Bm + (long long)(kt + bk)*ldb + col0 + bn4);
            }
        } else {
            #pragma unroll
            for (int i=0;i<4;i++){
                int fidx = tid + i*256;
                int bn = fidx>>2, bc4 = (fidx&3)<<2;
                cp16(bbase + (unsigned)(bn*BS1_STRIDE + bc4)*4u,
                     Bm + (long long)(col0 + bn)*ldb + kt + bc4);
            }
        }
    };

    float acc[4][8][4];
    #pragma unroll
    for (int mt=0;mt<4;mt++)
        #pragma unroll
        for (int nt=0;nt<8;nt++)
            #pragma unroll
            for (int i=0;i<4;i++) acc[mt][nt][i]=0.f;

    const int nk = Ki >> 4;
    issue(0, 0);  cp_commit();
    issue(16, 1); cp_commit();

    const int lane8 = lane & 7;
    const int a_lrow = wm*64 + lane8 + ((lane>>3)&1)*8;
    const int a_lw   = ((lane>>4)&1)*4;
    const int b_lrow = wn*64 + lane8 + ((lane>>4)&1)*8;
    const int b_lw   = ((lane>>3)&1)*4;
    const int b0_frag_off = qc*BS0_STRIDE + wn*64 + g;

    for (int t = 0; t < nk; ++t){
        cp_wait<1>();
        __syncthreads();
        const int rb = t % NSTAGE;
        if (t+2 < nk) issue((t+2)<<4, (t+2)%NSTAGE);
        cp_commit();

        const unsigned a_stage = As_base + (unsigned)(rb*AS_ST)*4u;
        const unsigned b_stage = Bs_base + (unsigned)(rb*BS_ST)*4u;

        #pragma unroll
        for (int grp=0; grp<2; grp++){
            const int koff = grp*8;
            unsigned af[4][4], bf[8][2];
            #pragma unroll
            for (int mt=0;mt<4;mt++)
                ldsm4(af[mt][0], af[mt][1], af[mt][2], af[mt][3],
                      a_stage + (unsigned)(((a_lrow + mt*16)*AS_STRIDE) + a_lw + koff)*4u);
            if (TB==0){
                const unsigned* Bb = Bs + rb*BS_ST + b0_frag_off + koff*BS0_STRIDE;
                #pragma unroll
                for (int nt=0;nt<8;nt++){
                    bf[nt][0] = Bb[nt*8];
                    bf[nt][1] = Bb[4*BS0_STRIDE + nt*8];
                }
            } else {
                #pragma unroll
                for (int np=0;np<4;np++)
                    ldsm4(bf[2*np][0], bf[2*np][1], bf[2*np+1][0], bf[2*np+1][1],
                          b_stage + (unsigned)(((b_lrow + np*16)*BS1_STRIDE) + b_lw + koff)*4u);
            }
            #pragma unroll
            for (int mt=0;mt<4;mt++)
                #pragma unroll
                for (int nt=0;nt<8;nt++)
                    mma_tf32(acc[mt][nt], af[mt][0],af[mt][1],af[mt][2],af[mt][3],
                             bf[nt][0],bf[nt][1]);
        }
    }

    if (EPI==8){
        __syncthreads();
        float* redmax = (float*)sm;
        float* redsum = (float*)sm + 512;
        float rm[4][2];
        #pragma unroll
        for (int mt=0;mt<4;mt++){
            #pragma unroll
            for (int half=0; half<2; half++){
                float m = -3.4e38f;
                #pragma unroll
                for (int nt=0;nt<8;nt++){
                    m = fmaxf(m, acc[mt][nt][2*half]);
                    m = fmaxf(m, acc[mt][nt][2*half+1]);
                }
                m = fmaxf(m, __shfl_xor_sync(0xffffffffu, m, 1));
                m = fmaxf(m, __shfl_xor_sync(0xffffffffu, m, 2));
                rm[mt][half] = m;
            }
        }
        if (qc==0){
            #pragma unroll
            for (int mt=0;mt<4;mt++)
                #pragma unroll
                for (int half=0; half<2; half++){
                    int rl = wm*64 + mt*16 + g + half*8;
                    redmax[rl*4 + wn] = rm[mt][half];
                }
        }
        __syncthreads();
        float inv[4][2];
        #pragma unroll
        for (int mt=0;mt<4;mt++){
            #pragma unroll
            for (int half=0; half<2; half++){
                int rl = wm*64 + mt*16 + g + half*8;
                float m = fmaxf(fmaxf(redmax[rl*4+0], redmax[rl*4+1]),
                                fmaxf(redmax[rl*4+2], redmax[rl*4+3]));
                float s = 0.f;
                #pragma unroll
                for (int nt=0;nt<8;nt++){
                    float e0 = expf(acc[mt][nt][2*half]   - m);
                    float e1 = expf(acc[mt][nt][2*half+1] - m);
                    acc[mt][nt][2*half]   = e0;
                    acc[mt][nt][2*half+1] = e1;
                    s += e0 + e1;
                }
                s += __shfl_xor_sync(0xffffffffu, s, 1);
                s += __shfl_xor_sync(0xffffffffu, s, 2);
                if (qc==0) redsum[rl*4 + wn] = s;
                inv[mt][half] = 0.f;
            }
        }
        __syncthreads();
        #pragma unroll
        for (int mt=0;mt<4;mt++)
            #pragma unroll
            for (int half=0; half<2; half++){
                int rl = wm*64 + mt*16 + g + half*8;
                float s = redsum[rl*4+0] + redsum[rl*4+1] + redsum[rl*4+2] + redsum[rl*4+3];
                inv[mt][half] = 1.f / s;
            }
        #pragma unroll
        for (int mt=0;mt<4;mt++){
            #pragma unroll
            for (int half=0; half<2; half++){
                int r = row0 + wm*64 + mt*16 + g + half*8;
                #pragma unroll
                for (int nt=0;nt<8;nt++){
                    int cc = wn*64 + nt*8 + 2*qc;
                    float2 o = {acc[mt][nt][2*half]*inv[mt][half],
                                acc[mt][nt][2*half+1]*inv[mt][half]};
                    *(float2*)&C[(long long)r*ldc + cc] = o;
                }
            }
        }
        return;
    }

    #pragma unroll
    for (int mt=0;mt<4;mt++){
        int r = row0 + wm*64 + mt*16 + g;
        #pragma unroll
        for (int nt=0;nt<8;nt++){
            int cc = col0 + wn*64 + nt*8 + 2*qc;
            store2<EPI>(C, C2, C3, ldc, r,   cc, acc[mt][nt][0], acc[mt][nt][1], alpha, bias);
            store2<EPI>(C, C2, C3, ldc, r+8, cc, acc[mt][nt][2], acc[mt][nt][3], alpha, bias);
        }
    }
}

// ==== BF16 batched GEMM for pinv: 256x256x256, CTA 128x256, warp 64x64 ====
#define ASH 40
#define AH_ST (128*ASH)
#define BSH 264
#define BH_ST (32*BSH)
#define SMEM_BF_BYTES (NSTAGE*(AH_ST + BH_ST)*2)

template<int EPI>
__global__ void __launch_bounds__(256,1) gemm_bf16_kernel(
    const __nv_bfloat16* __restrict__ A,
    const __nv_bfloat16* __restrict__ Bm,
    __nv_bfloat16* __restrict__ Cb,
    __nv_bfloat16* __restrict__ C2b,
    float* __restrict__ Cf,
    float alpha)
{
    extern __shared__ __nv_bfloat16 smh[];
    const unsigned As_base = (unsigned)__cvta_generic_to_shared(smh);
    const unsigned Bs_base = As_base + NSTAGE*AH_ST*2u;

    const long long boff = (long long)blockIdx.z * (ML*ML);
    A  += boff; Bm += boff;

    const int row0 = blockIdx.y*128;
    const int tid = threadIdx.x;
    const int warp = tid>>5, lane = tid&31;
    const int wm = warp & 1, wn = warp >> 1;
    const int g = lane>>2, qc = lane&3;

    auto issue = [&](int kt, int st){
        unsigned abase = As_base + (unsigned)(st*AH_ST)*2u;
        #pragma unroll
        for (int i=0;i<2;i++){
            int r = tid>>1, ch = ((tid&1)<<1) + i;
            cp16(abase + (unsigned)(r*ASH + ch*8)*2u,
                 A + (long long)(row0 + r)*ML + kt + ch*8);
        }
        unsigned bbase = Bs_base + (unsigned)(st*BH_ST)*2u;
        #pragma unroll
        for (int i=0;i<4;i++){
            int fidx = tid + i*256;
            int r = fidx>>5, ch = fidx&31;
            cp16(bbase + (unsigned)(r*BSH + ch*8)*2u,
                 Bm + (long long)(kt + r)*ML + ch*8);
        }
    };

    float acc[4][8][4];
    #pragma unroll
    for (int mt=0;mt<4;mt++)
        #pragma unroll
        for (int nt=0;nt<8;nt++)
            #pragma unroll
            for (int i=0;i<4;i++) acc[mt][nt][i]=0.f;

    const int nk = ML >> 5;
    issue(0, 0);  cp_commit();
    issue(32, 1); cp_commit();

    const int lane8 = lane & 7;
    const int a_row = wm*64 + lane8 + ((lane>>3)&1)*8;
    const int a_col = ((lane>>4)&1)*8;
    const int b_row = lane8 + ((lane>>3)&1)*8;
    const int b_col = ((lane>>4)&1)*8;

    for (int t = 0; t < nk; ++t){
        cp_wait<1>();
        __syncthreads();
        const int rb = t % NSTAGE;
        if (t+2 < nk) issue((t+2)<<5, (t+2)%NSTAGE);
        cp_commit();

        const unsigned a_st = As_base + (unsigned)(rb*AH_ST)*2u;
        const unsigned b_st = Bs_base + (unsigned)(rb*BH_ST)*2u;

        #pragma unroll
        for (int kk=0; kk<2; kk++){
            const int k0 = kk*16;
            unsigned af[4][4], bf[8][2];
            #pragma unroll
            for (int mt=0;mt<4;mt++)
                ldsm4(af[mt][0], af[mt][1], af[mt][2], af[mt][3],
                      a_st + (unsigned)((a_row + mt*16)*ASH + k0 + a_col)*2u);
            #pragma unroll
            for (int np=0;np<4;np++)
                ldsm4t(bf[2*np][0], bf[2*np][1], bf[2*np+1][0], bf[2*np+1][1],
                       b_st + (unsigned)((k0 + b_row)*BSH + wn*64 + np*16 + b_col)*2u);
            #pragma unroll
            for (int mt=0;mt<4;mt++)
                #pragma unroll
                for (int nt=0;nt<8;nt++)
                    mma_bf16(acc[mt][nt], af[mt][0],af[mt][1],af[mt][2],af[mt][3],
                             bf[nt][0],bf[nt][1]);
        }
    }

    #pragma unroll
    for (int mt=0;mt<4;mt++){
        #pragma unroll
        for (int half=0; half<2; half++){
            int r = row0 + wm*64 + mt*16 + g + half*8;
            #pragma unroll
            for (int nt=0;nt<8;nt++){
                int cc = wn*64 + nt*8 + 2*qc;
                float v0 = acc[mt][nt][2*half+0];
                float v1 = acc[mt][nt][2*half+1];
                long long idx = boff + (long long)r*ML + cc;
                if (EPI==0){
                    __nv_bfloat162 pk;
                    pk.x = __float2bfloat16(alpha*v0);
                    pk.y = __float2bfloat16(alpha*v1);
                    *(__nv_bfloat162*)&Cb[idx] = pk;
                } else if (EPI==1){
                    float2 o = {alpha*v0, alpha*v1};
                    *(float2*)&Cf[idx] = o;
                } else if (EPI==5){
                    __nv_bfloat162 pk;
                    pk.x = __float2bfloat16((r==cc   ? alpha : 0.f) - v0);
                    pk.y = __float2bfloat16((r==cc+1 ? alpha : 0.f) - v1);
                    *(__nv_bfloat162*)&Cb[idx] = pk;
                } else if (EPI==6){
                    __nv_bfloat162 pk;
                    pk.x = __float2bfloat16(v0);
                    pk.y = __float2bfloat16(v1);
                    *(__nv_bfloat162*)&Cb[idx] = pk;
                    __nv_bfloat162 pk2;
                    pk2.x = __float2bfloat16((r==cc   ? alpha : 0.f) - v0);
                    pk2.y = __float2bfloat16((r==cc+1 ? alpha : 0.f) - v1);
                    *(__nv_bfloat162*)&C2b[idx] = pk2;
                }
            }
        }
    }
}

// ==== FP16 general GEMM: CTA 128x256, K-tile 32, warp 64x64, 3-stage ======
// A [M,K] rm fp16, B [K,N] rm fp16, fp32 accumulate. M%128==0, N%256==0, K%32==0.
// EPI 7: qkv split (fp32 q/k/v).   EPI 4: pad-residual into C (fp32).
// EPI 2: gelu(val+bias) -> Ch fp16.  EPI 3: C += val + bias (fp32).
template<int EPI>
__global__ void __launch_bounds__(256,1) gemm_h_kernel(
    int Ki,
    const __half* __restrict__ A, int lda,
    const __half* __restrict__ Bm, int ldb,
    float* __restrict__ C, int ldc,
    float alpha, const float* __restrict__ bias,
    float* __restrict__ C2, float* __restrict__ C3,
    __half* __restrict__ Ch)
{
    extern __shared__ __half smhh[];
    const unsigned As_base = (unsigned)__cvta_generic_to_shared(smhh);
    const unsigned Bs_base = As_base + NSTAGE*AH_ST*2u;

    const int row0 = blockIdx.y*128;
    const int col0 = blockIdx.x*256;
    const int tid = threadIdx.x;
    const int warp = tid>>5, lane = tid&31;
    const int wm = warp & 1, wn = warp >> 1;
    const int g = lane>>2, qc = lane&3;

    auto issue = [&](int kt, int st){
        unsigned abase = As_base + (unsigned)(st*AH_ST)*2u;
        #pragma unroll
        for (int i=0;i<2;i++){
            int r = tid>>1, ch = ((tid&1)<<1) + i;
            cp16(abase + (unsigned)(r*ASH + ch*8)*2u,
                 A + (long long)(row0 + r)*lda + kt + ch*8);
        }
        unsigned bbase = Bs_base + (unsigned)(st*BH_ST)*2u;
        #pragma unroll
        for (int i=0;i<4;i++){
            int fidx = tid + i*256;
            int r = fidx>>5, ch = fidx&31;
            cp16(bbase + (unsigned)(r*BSH + ch*8)*2u,
                 Bm + (long long)(kt + r)*ldb + col0 + ch*8);
        }
    };

    float acc[4][8][4];
    #pragma unroll
    for (int mt=0;mt<4;mt++)
        #pragma unroll
        for (int nt=0;nt<8;nt++)
            #pragma unroll
            for (int i=0;i<4;i++) acc[mt][nt][i]=0.f;

    const int nk = Ki >> 5;
    issue(0, 0);  cp_commit();
    issue(32, 1); cp_commit();

    const int lane8 = lane & 7;
    const int a_row = wm*64 + lane8 + ((lane>>3)&1)*8;
    const int a_col = ((lane>>4)&1)*8;
    const int b_row = lane8 + ((lane>>3)&1)*8;
    const int b_col = ((lane>>4)&1)*8;

    for (int t = 0; t < nk; ++t){
        cp_wait<1>();
        __syncthreads();
        const int rb = t % NSTAGE;
        if (t+2 < nk) issue((t+2)<<5, (t+2)%NSTAGE);
        cp_commit();

        const unsigned a_st = As_base + (unsigned)(rb*AH_ST)*2u;
        const unsigned b_st = Bs_base + (unsigned)(rb*BH_ST)*2u;

        #pragma unroll
        for (int kk=0; kk<2; kk++){
            const int k0 = kk*16;
            unsigned af[4][4], bf[8][2];
            #pragma unroll
            for (int mt=0;mt<4;mt++)
                ldsm4(af[mt][0], af[mt][1], af[mt][2], af[mt][3],
                      a_st + (unsigned)((a_row + mt*16)*ASH + k0 + a_col)*2u);
            #pragma unroll
            for (int np=0;np<4;np++)
                ldsm4t(bf[2*np][0], bf[2*np][1], bf[2*np+1][0], bf[2*np+1][1],
                       b_st + (unsigned)((k0 + b_row)*BSH + wn*64 + np*16 + b_col)*2u);
            #pragma unroll
            for (int mt=0;mt<4;mt++)
                #pragma unroll
                for (int nt=0;nt<8;nt++)
                    mma_f16(acc[mt][nt], af[mt][0],af[mt][1],af[mt][2],af[mt][3],
                            bf[nt][0],bf[nt][1]);
        }
    }

    #pragma unroll
    for (int mt=0;mt<4;mt++){
        #pragma unroll
        for (int half=0; half<2; half++){
            int r = row0 + wm*64 + mt*16 + g + half*8;
            #pragma unroll
            for (int nt=0;nt<8;nt++){
                int cc = col0 + wn*64 + nt*8 + 2*qc;
                float v0 = acc[mt][nt][2*half+0];
                float v1 = acc[mt][nt][2*half+1];
                if (EPI==7){
                    int b = r >> 10, n = r & 1023;
                    int which = cc >> 9;
                    int hd = cc & 511;
                    long long idx = ((((long long)b*NH + (hd>>6))*NPAD) + n)*DHD + (hd&63);
                    float2 o;
                    if (which==0){ o.x = v0*QSCALE; o.y = v1*QSCALE; *(float2*)&C[idx] = o; }
                    else if (which==1){ o.x = v0; o.y = v1; *(float2*)&C2[idx] = o; }
                    else { o.x = v0; o.y = v1; *(float2*)&C3[idx] = o; }
                } else if (EPI==4){
                    int bb = r / NPAD, nl = r % NPAD;
                    if (nl >= PADL){
                        long long orow = (long long)bb*LSEQ + (nl - PADL);
                        float2 o = *(float2*)&C[orow*ldc + cc];
                        o.x += v0 + bias[cc];
                        o.y += v1 + bias[cc+1];
                        *(float2*)&C[orow*ldc + cc] = o;
                    }
                } else if (EPI==2){
                    float x0 = v0 + bias[cc], x1 = v1 + bias[cc+1];
                    float g0 = 0.5f*x0*(1.f+erff(x0*0.70710678118654752f));
                    float g1 = 0.5f*x1*(1.f+erff(x1*0.70710678118654752f));
                    __half2 o = __floats2half2_rn(g0, g1);
                    *(__half2*)&Ch[(long long)r*ldc + cc] = o;
                } else if (EPI==3){
                    float2 o = *(float2*)&C[(long long)r*ldc + cc];
                    o.x += v0 + bias[cc];
                    o.y += v1 + bias[cc+1];
                    *(float2*)&C[(long long)r*ldc + cc] = o;
                }
            }
        }
    }
}

// ==== TF32 tensor GEMM N=64: 128 thr, CTA 128x64, warp 64x32, 3-stage =====
// EPI 0: C = val.   EPI 1: fused depthwise conv over v + relayout to fp16 Y.
#define BS64_STRIDE 72
#define BS64_ST     (16*BS64_STRIDE)
#define SMEM_TC64_BYTES (NSTAGE*(AS_ST + BS64_ST)*4)

template<int EPI>
__global__ void __launch_bounds__(128) gemm_tc64_kernel(
    int Ki,
    const float* __restrict__ A, int lda, long long sA,
    const float* __restrict__ Bm, int ldb, long long sB,
    float* __restrict__ C, int ldc, long long sC,
    const float* __restrict__ Vg, const float* __restrict__ cw,
    __half* __restrict__ Y)
{
    extern __shared__ unsigned sm[];
    unsigned* As = sm;
    unsigned* Bs = sm + NSTAGE*AS_ST;
    const unsigned As_base = (unsigned)__cvta_generic_to_shared(As);
    const unsigned Bs_base = (unsigned)__cvta_generic_to_shared(Bs);
    __shared__ float ws[KC];

    const int bz = blockIdx.z;
    A  += (long long)bz*sA;
    Bm += (long long)bz*sB;
    C  += (long long)bz*sC;

    const int row0 = blockIdx.y*128;
    const int tid = threadIdx.x;
    const int warp = tid>>5, lane = tid&31;
    const int wm = warp & 1, wn = warp >> 1;
    const int g = lane>>2, qc = lane&3;

    if (EPI==1 && tid < KC) ws[tid] = cw[(bz % NH)*KC + tid];

    auto issue = [&](int kt, int st){
        unsigned abase = As_base + (unsigned)(st*AS_ST)*4u;
        #pragma unroll
        for (int i=0;i<4;i++){
            int fidx = tid + i*128;
            int a_r = fidx>>2, a_c4 = (fidx&3)<<2;
            cp16(abase + (unsigned)(a_r*AS_STRIDE + a_c4)*4u,
                 A + (long long)(row0 + a_r)*lda + kt + a_c4);
        }
        unsigned bbase = Bs_base + (unsigned)(st*BS64_ST)*4u;
        #pragma unroll
        for (int i=0;i<2;i++){
            int fidx = tid + i*128;
            int bk = fidx>>4, bn4 = (fidx&15)<<2;
            cp16(bbase + (unsigned)(bk*BS64_STRIDE + bn4)*4u,
                 Bm + (long long)(kt + bk)*ldb + bn4);
        }
    };

    float acc[4][4][4];
    #pragma unroll
    for (int mt=0;mt<4;mt++)
        #pragma unroll
        for (int nt=0;nt<4;nt++)
            #pragma unroll
            for (int i=0;i<4;i++) acc[mt][nt][i]=0.f;

    const int nk = Ki >> 4;
    issue(0, 0);  cp_commit();
    issue(16, 1); cp_commit();

    const int lane8 = lane & 7;
    const int a_lrow = wm*64 + lane8 + ((lane>>3)&1)*8;
    const int a_lw   = ((lane>>4)&1)*4;
    const int b_frag_off = qc*BS64_STRIDE + wn*32 + g;

    for (int t = 0; t < nk; ++t){
        cp_wait<1>();
        __syncthreads();
        const int rb = t % NSTAGE;
        if (t+2 < nk) issue((t+2)<<4, (t+2)%NSTAGE);
        cp_commit();

        const unsigned a_stage = As_base + (unsigned)(rb*AS_ST)*4u;

        #pragma unroll
        for (int grp=0; grp<2; grp++){
            const int koff = grp*8;
            unsigned af[4][4], bf[4][2];
            #pragma unroll
            for (int mt=0;mt<4;mt++)
                ldsm4(af[mt][0], af[mt][1], af[mt][2], af[mt][3],
                      a_stage + (unsigned)(((a_lrow + mt*16)*AS_STRIDE) + a_lw + koff)*4u);
            const unsigned* Bb = Bs + rb*BS64_ST + b_frag_off + koff*BS64_STRIDE;
            #pragma unroll
            for (int nt=0;nt<4;nt++){
                bf[nt][0] = Bb[nt*8];
                bf[nt][1] = Bb[4*BS64_STRIDE + nt*8];
            }
            #pragma unroll
            for (int mt=0;mt<4;mt++)
                #pragma unroll
                for (int nt=0;nt<4;nt++)
                    mma_tf32(acc[mt][nt], af[mt][0],af[mt][1],af[mt][2],af[mt][3],
                             bf[nt][0],bf[nt][1]);
        }
    }

    if (EPI==1){
        const int h = bz % NH, b = bz / NH;
        const float* vp = Vg + (long long)bz*NPAD*DHD;
        #pragma unroll
        for (int mt=0;mt<4;mt++){
            #pragma unroll
            for (int half=0; half<2; half++){
                int n = row0 + wm*64 + mt*16 + g + half*8;
                int k0 = (16-n > 0) ? (16-n) : 0;
                int k1 = (NPAD+16-n < KC) ? (NPAD+16-n) : KC;
                #pragma unroll
                for (int nt=0;nt<4;nt++){
                    int cc = wn*32 + nt*8 + 2*qc;
                    float s0 = acc[mt][nt][2*half+0];
                    float s1 = acc[mt][nt][2*half+1];
                    for (int kk=k0; kk<k1; kk++){
                        float2 vv = *(const float2*)&vp[(long long)(n+kk-16)*DHD + cc];
                        s0 = fmaf(vv.x, ws[kk], s0);
                        s1 = fmaf(vv.y, ws[kk], s1);
                    }
                    __half2 o = __floats2half2_rn(s0, s1);
                    *(__half2*)&Y[((long long)b*NPAD + n)*DMODEL + h*DHD + cc] = o;
                }
            }
        }
        return;
    }

    #pragma unroll
    for (int mt=0;mt<4;mt++){
        int r = row0 + wm*64 + mt*16 + g;
        #pragma unroll
        for (int nt=0;nt<4;nt++){
            int cc = wn*32 + nt*8 + 2*qc;
            float2 o0 = {acc[mt][nt][0], acc[mt][nt][1]};
            float2 o1 = {acc[mt][nt][2], acc[mt][nt][3]};
            *(float2*)&C[(long long)r*ldc + cc] = o0;
            *(float2*)&C[(long long)(r+8)*ldc + cc] = o1;
        }
    }
}

// ---------------- elementwise / small kernels ----------------
__global__ void embed_kernel(const int* __restrict__ x,
                             const float* __restrict__ emb,
                             const float* __restrict__ pos){
    long long idx = (long long)blockIdx.x*blockDim.x + threadIdx.x;
    if (idx >= (long long)BATCH*LSEQ*DMODEL) return;
    int d = (int)(idx % DMODEL);
    long long bl = idx / DMODEL;
    int l = (int)(bl % LSEQ);
    int tok = x[bl];
    g_h[idx] = emb[(long long)tok*DMODEL + d] + pos[(long long)l*DMODEL + d];
}

__global__ void zero_pad_kernel(){
    int idx = blockIdx.x*blockDim.x + threadIdx.x;
    if (idx >= BATCH*PADL*DMODEL) return;
    int d  = idx % DMODEL;
    int bp = idx / DMODEL;
    int b  = bp / PADL, p = bp % PADL;
    g_xh[((long long)b*NPAD + p)*DMODEL + d] = __float2half(0.f);
}

__global__ void cvtw_kernel(const float* __restrict__ src, __half* __restrict__ dst, long long n){
    long long idx = (long long)blockIdx.x*blockDim.x + threadIdx.x;
    if (idx < n) dst[idx] = __float2half(src[idx]);
}

// LN -> fp16 output
__global__ void ln_kernel(const float* __restrict__ in, __half* __restrict__ out,
                          const float* __restrict__ gm, const float* __restrict__ bt,
                          int padmode){
    __shared__ float sh[8];
    int r = blockIdx.x;
    int t = threadIdx.x;
    const float* p = in + (long long)r*DMODEL;
    float a  = p[t];
    float b2 = p[t+256];
    float s  = blockSumN(a+b2, sh, 8);
    float mu = s * (1.f/512.f);
    float da = a - mu, db = b2 - mu;
    float v  = blockSumN(da*da + db*db, sh, 8) * (1.f/512.f);
    float rstd = rsqrtf(v + 1e-5f);
    long long orow = padmode ? ((long long)(r/LSEQ)*NPAD + PADL + (r%LSEQ)) : (long long)r;
    __half* q = out + orow*DMODEL;
    q[t]     = __float2half(da*rstd*gm[t]     + bt[t]);
    q[t+256] = __float2half(db*rstd*gm[t+256] + bt[t+256]);
}

__global__ void landmark_kernel(){
    long long idx = (long long)blockIdx.x*blockDim.x + threadIdx.x;
    if (idx >= (long long)BH*ML*DHD) return;
    int d = (int)(idx & 63);
    long long r = idx >> 6;
    int m  = (int)(r % ML);
    int bh = (int)(r / ML);
    long long base = ((long long)bh*NPAD + (long long)m*LMR)*DHD + d;
    float sq = 0.f, sk = 0.f;
    #pragma unroll
    for (int j=0;j<LMR;j++){ sq += g_q[base + (long long)j*DHD]; sk += g_k[base + (long long)j*DHD]; }
    g_ql[idx] = sq * 0.25f;
    g_kl[idx] = sk * 0.25f;
}

__global__ void softmax_kernel(float* __restrict__ X, int cols){
    __shared__ float sh[4];
    long long row = blockIdx.x;
    float* p = X + row*(long long)cols;
    int t = threadIdx.x;
    int cnt = cols >> 7;
    float v[8];
    float mx = -3.4e38f;
    #pragma unroll
    for (int i=0;i<8;i++) if (i<cnt){ v[i]=p[t + (i<<7)]; mx = fmaxf(mx, v[i]); }
    mx = blockMaxN(mx, sh, 4);
    float s = 0.f;
    #pragma unroll
    for (int i=0;i<8;i++) if (i<cnt){ v[i]=expf(v[i]-mx); s += v[i]; }
    s = blockSumN(s, sh, 4);
    float inv = 1.f/s;
    #pragma unroll
    for (int i=0;i<8;i++) if (i<cnt) p[t + (i<<7)] = v[i]*inv;
}

__global__ void red_init_kernel(){ g_red[0]=0; g_red[1]=0; }

__global__ void colsum_kernel(){
    __shared__ float sh[8];
    int bz = blockIdx.x;
    const float* p = g_a2 + (long long)bz*ML*ML;
    int c = threadIdx.x;
    float s = 0.f;
    for (int r=0;r<ML;r++) s += fabsf(p[(long long)r*ML + c]);
    float m = blockMaxN(s, sh, 8);
    if (threadIdx.x==0) atomicMax(&g_red[0], __float_as_int(m));
}
__global__ void rowsum_kernel(){
    __shared__ float sh[8];
    int bz = blockIdx.x;
    const float* p = g_a2 + (long long)bz*ML*ML;
    int w = threadIdx.x>>5, l = threadIdx.x&31;
    float m = -3.4e38f;
    for (int r=w; r<ML; r+=8){
        float s = 0.f;
        for (int c=l; c<ML; c+=32) s += fabsf(p[(long long)r*ML + c]);
        s = warpSum(s);
        m = fmaxf(m, s);
    }
    m = blockMaxN(m, sh, 8);
    if (threadIdx.x==0) atomicMax(&g_red[1], __float_as_int(m));
}
__global__ void zinit_kernel(){
    __shared__ float tile[32][33];
    int bz = blockIdx.z;
    int i0 = blockIdx.x*32;
    int j0 = blockIdx.y*32;
    const long long base = (long long)bz*ML*ML;
    float c = __int_as_float(g_red[0]) * __int_as_float(g_red[1]);
    float invc = 1.f/c;
    #pragma unroll
    for (int k=0;k<4;k++){
        int j = j0 + threadIdx.y + k*8;
        float v = g_a2[base + (long long)j*ML + i0 + threadIdx.x];
        tile[threadIdx.y + k*8][threadIdx.x] = v;
        g_a2h[base + (long long)j*ML + i0 + threadIdx.x] = __float2bfloat16(v);
    }
    __syncthreads();
    #pragma unroll
    for (int k=0;k<4;k++){
        int i = i0 + threadIdx.y + k*8;
        float v = tile[threadIdx.x][threadIdx.y + k*8] * invc;
        long long idx = base + (long long)i*ML + j0 + threadIdx.x;
        g_zb[idx] = v;
        g_zh[idx] = __float2bfloat16(v);
    }
}

__global__ void final_kernel(const float* __restrict__ fw,
                             const float* __restrict__ fb,
                             float* __restrict__ out){
    __shared__ float sh[8];
    int b = blockIdx.x;
    int t = threadIdx.x;
    const float* hp = g_h + (long long)b*LSEQ*DMODEL;
    float s = 0.f;
    for (long long i=t; i<(long long)LSEQ*DMODEL; i+=256)
        s = fmaf(hp[i], fw[i], s);
    s = blockSumN(s, sh, 8);
    if (t==0) out[b] = s + fb[0];
}

// ---------------- host-side GEMM dispatch ----------------
static void run_gemm(int tb, int epi, int Mi, int Ni, int Ki,
                     const float* A, int lda, long long sA,
                     const float* Bm, int ldb, long long sB,
                     float* C, int ldc, long long sC,
                     int batch, float alpha, const float* bias,
                     float* C2 = nullptr, float* C3 = nullptr)
{
    dim3 g(Ni/256, Mi/128, batch), t(256);
    size_t sh = SMEM_TC_BYTES;
    if (tb == 0) {
        switch (epi) {
            case 0: gemm_tc_kernel<0,0><<<g,t,sh>>>(Ki,A,lda,sA,Bm,ldb,sB,C,ldc,sC,alpha,bias,C2,C3); break;
            case 5: gemm_tc_kernel<0,5><<<g,t,sh>>>(Ki,A,lda,sA,Bm,ldb,sB,C,ldc,sC,alpha,bias,C2,C3); break;
            case 6: gemm_tc_kernel<0,6><<<g,t,sh>>>(Ki,A,lda,sA,Bm,ldb,sB,C,ldc,sC,alpha,bias,C2,C3); break;
        }
    } else {
        if (epi == 8)
            gemm_tc_kernel<1,8><<<g,t,sh>>>(Ki,A,lda,sA,Bm,ldb,sB,C,ldc,sC,alpha,bias,C2,C3);
        else
            gemm_tc_kernel<1,0><<<g,t,sh>>>(Ki,A,lda,sA,Bm,ldb,sB,C,ldc,sC,alpha,bias,C2,C3);
    }
}

static void run_gemm_h(int epi, int Mi, int Ni, int Ki,
                       const __half* A, int lda,
                       const __half* Bm, int ldb,
                       float* C, int ldc,
                       float alpha, const float* bias,
                       float* C2 = nullptr, float* C3 = nullptr,
                       __half* Ch = nullptr)
{
    dim3 g(Ni/256, Mi/128, 1), t(256);
    size_t sh = SMEM_BF_BYTES;
    switch (epi) {
        case 2: gemm_h_kernel<2><<<g,t,sh>>>(Ki,A,lda,Bm,ldb,C,ldc,alpha,bias,C2,C3,Ch); break;
        case 3: gemm_h_kernel<3><<<g,t,sh>>>(Ki,A,lda,Bm,ldb,C,ldc,alpha,bias,C2,C3,Ch); break;
        case 4: gemm_h_kernel<4><<<g,t,sh>>>(Ki,A,lda,Bm,ldb,C,ldc,alpha,bias,C2,C3,Ch); break;
        case 7: gemm_h_kernel<7><<<g,t,sh>>>(Ki,A,lda,Bm,ldb,C,ldc,alpha,bias,C2,C3,Ch); break;
    }
}

static void run_gemm64(int epi, int Mi, int Ki,
                       const float* A, int lda, long long sA,
                       const float* Bm, int ldb, long long sB,
                       float* C, int ldc, long long sC, int batch,
                       const float* Vg = nullptr, const float* cw = nullptr,
                       __half* Y = nullptr)
{
    dim3 g(1, Mi/128, batch), t(128);
    if (epi == 0)
        gemm_tc64_kernel<0><<<g,t,SMEM_TC64_BYTES>>>(Ki,A,lda,sA,Bm,ldb,sB,C,ldc,sC,Vg,cw,Y);
    else
        gemm_tc64_kernel<1><<<g,t,SMEM_TC64_BYTES>>>(Ki,A,lda,sA,Bm,ldb,sB,C,ldc,sC,Vg,cw,Y);
}

static void run_gemm_bf16(int epi,
                          const __nv_bfloat16* A, const __nv_bfloat16* Bm,
                          __nv_bfloat16* Cb, __nv_bfloat16* C2b, float* Cf,
                          float alpha)
{
    dim3 g(1, ML/128, BH), t(256);
    size_t sh = SMEM_BF_BYTES;
    switch (epi) {
        case 0: gemm_bf16_kernel<0><<<g,t,sh>>>(A,Bm,Cb,C2b,Cf,alpha); break;
        case 1: gemm_bf16_kernel<1><<<g,t,sh>>>(A,Bm,Cb,C2b,Cf,alpha); break;
        case 5: gemm_bf16_kernel<5><<<g,t,sh>>>(A,Bm,Cb,C2b,Cf,alpha); break;
        case 6: gemm_bf16_kernel<6><<<g,t,sh>>>(A,Bm,Cb,C2b,Cf,alpha); break;
    }
}

static void setup_tc_attrs(){
    cudaFuncSetAttribute(gemm_tc_kernel<0,0>, cudaFuncAttributeMaxDynamicSharedMemorySize, SMEM_TC_BYTES);
    cudaFuncSetAttribute(gemm_tc_kernel<0,5>, cudaFuncAttributeMaxDynamicSharedMemorySize, SMEM_TC_BYTES);
    cudaFuncSetAttribute(gemm_tc_kernel<0,6>, cudaFuncAttributeMaxDynamicSharedMemorySize, SMEM_TC_BYTES);
    cudaFuncSetAttribute(gemm_tc_kernel<1,0>, cudaFuncAttributeMaxDynamicSharedMemorySize, SMEM_TC_BYTES);
    cudaFuncSetAttribute(gemm_tc_kernel<1,8>, cudaFuncAttributeMaxDynamicSharedMemorySize, SMEM_TC_BYTES);
    cudaFuncSetAttribute(gemm_tc64_kernel<0>, cudaFuncAttributeMaxDynamicSharedMemorySize, SMEM_TC64_BYTES);
    cudaFuncSetAttribute(gemm_tc64_kernel<1>, cudaFuncAttributeMaxDynamicSharedMemorySize, SMEM_TC64_BYTES);
    cudaFuncSetAttribute(gemm_bf16_kernel<0>, cudaFuncAttributeMaxDynamicSharedMemorySize, SMEM_BF_BYTES);
    cudaFuncSetAttribute(gemm_bf16_kernel<1>, cudaFuncAttributeMaxDynamicSharedMemorySize, SMEM_BF_BYTES);
    cudaFuncSetAttribute(gemm_bf16_kernel<5>, cudaFuncAttributeMaxDynamicSharedMemorySize, SMEM_BF_BYTES);
    cudaFuncSetAttribute(gemm_bf16_kernel<6>, cudaFuncAttributeMaxDynamicSharedMemorySize, SMEM_BF_BYTES);
    cudaFuncSetAttribute(gemm_h_kernel<2>, cudaFuncAttributeMaxDynamicSharedMemorySize, SMEM_BF_BYTES);
    cudaFuncSetAttribute(gemm_h_kernel<3>, cudaFuncAttributeMaxDynamicSharedMemorySize, SMEM_BF_BYTES);
    cudaFuncSetAttribute(gemm_h_kernel<4>, cudaFuncAttributeMaxDynamicSharedMemorySize, SMEM_BF_BYTES);
    cudaFuncSetAttribute(gemm_h_kernel<7>, cudaFuncAttributeMaxDynamicSharedMemorySize, SMEM_BF_BYTES);
}

extern "C" void kernel_launch(void* const* d_in, const int* in_sizes, int n_in,
                              void* d_out, int out_size)
{
    (void)in_sizes; (void)n_in; (void)out_size;
    const int*   x       = (const int*)  d_in[0];
    const float* enc_emb = (const float*)d_in[1];
    const float* pos_emb = (const float*)d_in[2];
    const float* ln1_s   = (const float*)d_in[3];
    const float* ln1_b   = (const float*)d_in[4];
    const float* qkv_w   = (const float*)d_in[5];
    const float* aout_w  = (const float*)d_in[6];
    const float* aout_b  = (const float*)d_in[7];
    const float* conv_k  = (const float*)d_in[8];
    const float* ln2_s   = (const float*)d_in[9];
    const float* ln2_b   = (const float*)d_in[10];
    const float* ff_w1   = (const float*)d_in[11];
    const float* ff_b1   = (const float*)d_in[12];
    const float* ff_w2   = (const float*)d_in[13];
    const float* ff_b2   = (const float*)d_in[14];
    const float* fin_w   = (const float*)d_in[15];
    const float* fin_b   = (const float*)d_in[16];
    float* out = (float*)d_out;

    setup_tc_attrs();

    float *p_h,*p_q,*p_k,*p_v,*p_ql,*p_kl,*p_a1,*p_a3,*p_a2;
    float *p_z,*p_z2,*p_p,*p_t,*p_t2,*p_kv,*p_zkv;
    __half *p_xh,*p_x2h,*p_ffh,*p_yh,*p_wqkv,*p_wout,*p_wf1,*p_wf2;
    __nv_bfloat16 *p_a2h,*p_zh,*p_zh2,*p_ph,*p_th,*p_t2h;
    cudaGetSymbolAddress((void**)&p_h,  g_h);
    cudaGetSymbolAddress((void**)&p_q,  g_q);
    cudaGetSymbolAddress((void**)&p_k,  g_k);
    cudaGetSymbolAddress((void**)&p_v,  g_v);
    cudaGetSymbolAddress((void**)&p_ql, g_ql);
    cudaGetSymbolAddress((void**)&p_kl, g_kl);
    cudaGetSymbolAddress((void**)&p_a1, g_a1);
    cudaGetSymbolAddress((void**)&p_a3, g_a3);
    cudaGetSymbolAddress((void**)&p_a2, g_a2);
    cudaGetSymbolAddress((void**)&p_z,  g_zb);
    cudaGetSymbolAddress((void**)&p_z2, g_zb2);
    cudaGetSymbolAddress((void**)&p_p,  g_pb);
    cudaGetSymbolAddress((void**)&p_t,  g_tb);
    cudaGetSymbolAddress((void**)&p_t2, g_tb2);
    cudaGetSymbolAddress((void**)&p_kv, g_kvb);
    cudaGetSymbolAddress((void**)&p_zkv,g_zkv);
    cudaGetSymbolAddress((void**)&p_xh,  g_xh);
    cudaGetSymbolAddress((void**)&p_x2h, g_x2h);
    cudaGetSymbolAddress((void**)&p_ffh, g_ffh);
    cudaGetSymbolAddress((void**)&p_yh,  g_yh);
    cudaGetSymbolAddress((void**)&p_wqkv,g_wqkv);
    cudaGetSymbolAddress((void**)&p_wout,g_wout);
    cudaGetSymbolAddress((void**)&p_wf1, g_wf1);
    cudaGetSymbolAddress((void**)&p_wf2, g_wf2);
    cudaGetSymbolAddress((void**)&p_a2h, g_a2h);
    cudaGetSymbolAddress((void**)&p_zh,  g_zh);
    cudaGetSymbolAddress((void**)&p_zh2, g_zh2);
    cudaGetSymbolAddress((void**)&p_ph,  g_ph);
    cudaGetSymbolAddress((void**)&p_th,  g_th);
    cudaGetSymbolAddress((void**)&p_t2h, g_t2h);

    const long long MM  = (long long)ML*ML;
    const long long NM  = (long long)NPAD*ML;
    const long long ND  = (long long)NPAD*DHD;
    const long long MD  = (long long)ML*DHD;

    // weight fp16 conversion (once per launch; graph-capturable)
    {
        long long n1 = (long long)DEPTH*DMODEL*3*DMODEL;
        long long n2 = (long long)DEPTH*DMODEL*DMODEL;
        long long n3 = (long long)DEPTH*DMODEL*FFD;
        long long n4 = (long long)DEPTH*FFD*DMODEL;
        cvtw_kernel<<<(unsigned)((n1+255)/256),256>>>(qkv_w, p_wqkv, n1);
        cvtw_kernel<<<(unsigned)((n2+255)/256),256>>>(aout_w, p_wout, n2);
        cvtw_kernel<<<(unsigned)((n3+255)/256),256>>>(ff_w1, p_wf1, n3);
        cvtw_kernel<<<(unsigned)((n4+255)/256),256>>>(ff_w2, p_wf2, n4);
    }

    {
        long long tot = (long long)BATCH*LSEQ*DMODEL;
        embed_kernel<<<(unsigned)((tot+255)/256),256>>>(x, enc_emb, pos_emb);
        int tot2 = BATCH*PADL*DMODEL;
        zero_pad_kernel<<<(tot2+255)/256,256>>>();
    }

    for (int lay=0; lay<DEPTH; lay++){
        ln_kernel<<<BATCH*LSEQ,256>>>(p_h, p_xh, ln1_s+(long long)lay*DMODEL, ln1_b+(long long)lay*DMODEL, 1);
        // QKV [fp16 tensor, fused split into q/k/v]
        run_gemm_h(7, BATCH*NPAD, 3*DMODEL, DMODEL,
                   p_xh, DMODEL,
                   p_wqkv + (long long)lay*DMODEL*3*DMODEL, 3*DMODEL,
                   p_q, 3*DMODEL, 1.f, nullptr, p_k, p_v);
        {
            long long tot2 = (long long)BH*ML*DHD;
            landmark_kernel<<<(unsigned)((tot2+255)/256),256>>>();
        }
        // attn1 = softmax(q @ kl^T)  [tensor TB=1, FUSED softmax]
        run_gemm(1,8, NPAD, ML, DHD, p_q, DHD, ND, p_kl, DHD, MD, p_a1, ML, NM, BH, 1.f, nullptr);
        // attn2 = softmax(ql @ kl^T)  [tensor TB=1, FUSED softmax]
        run_gemm(1,8, ML, ML, DHD, p_ql, DHD, MD, p_kl, DHD, MD, p_a2, ML, MM, BH, 1.f, nullptr);
        // attn3 = softmax(ql @ k^T)  [tensor TB=1 + separate softmax (N=1024)]
        run_gemm(1,0, ML, NPAD, DHD, p_ql, DHD, MD, p_k, DHD, ND, p_a3, NPAD, (long long)ML*NPAD, BH, 1.f, nullptr);
        softmax_kernel<<<BH*ML,128>>>(p_a3, NPAD);

        // ---- pinv: 5 bf16 quintic iterations + 1 tf32 quintic polish ----
        red_init_kernel<<<1,1>>>();
        colsum_kernel<<<BH,256>>>();
        rowsum_kernel<<<BH,256>>>();
        {
            dim3 gz(ML/32, ML/32, BH), tz(32, 8);
            zinit_kernel<<<gz, tz>>>();
        }
        __nv_bfloat16* zhc = p_zh; __nv_bfloat16* zhn = p_zh2;
        for (int it=0; it<5; it++){
            run_gemm_bf16(6, p_a2h, zhc, p_ph, p_th, nullptr, 7.f);
            run_gemm_bf16(5, p_ph, p_th,  p_t2h, nullptr, nullptr, 15.f);
            run_gemm_bf16(5, p_ph, p_t2h, p_th,  nullptr, nullptr, 13.f);
            if (it < 4){
                run_gemm_bf16(0, zhc, p_th, zhn, nullptr, nullptr, 0.25f);
                __nv_bfloat16* tmp = zhc; zhc = zhn; zhn = tmp;
            } else {
                run_gemm_bf16(1, zhc, p_th, nullptr, nullptr, p_z, 0.25f); // fp32 Z5
            }
        }
        // tf32 quintic polish (6th iteration, same map as reference)
        run_gemm(0,6, ML, ML, ML, p_a2, ML, MM, p_z, ML, MM, p_p, ML, MM, BH, 7.f, nullptr, p_t);
        run_gemm(0,5, ML, ML, ML, p_p, ML, MM, p_t, ML, MM, p_t2, ML, MM, BH, 15.f, nullptr);
        run_gemm(0,5, ML, ML, ML, p_p, ML, MM, p_t2, ML, MM, p_t, ML, MM, BH, 13.f, nullptr);
        run_gemm(0,0, ML, ML, ML, p_z, ML, MM, p_t, ML, MM, p_z2, ML, MM, BH, 0.25f, nullptr);
        float* zc = p_z2;

        // kv = attn3 @ v  [tensor N=64]
        run_gemm64(0, ML, NPAD, p_a3, NPAD, (long long)ML*NPAD, p_v, DHD, ND, p_kv, DHD, MD, BH);
        // zkv = Z @ kv  [tensor N=64]
        run_gemm64(0, ML, ML, zc, ML, MM, p_kv, DHD, MD, p_zkv, DHD, MD, BH);
        // ao = attn1 @ zkv + depthwise conv(v), relayout -> fp16 y  [tensor N=64, fused]
        run_gemm64(1, NPAD, ML, p_a1, ML, NM, p_zkv, DHD, MD, nullptr, DHD, ND, BH,
                   p_v, conv_k + (long long)lay*NH*KC, p_yh);
        // out projection + residual [fp16 tensor]
        run_gemm_h(4, BATCH*NPAD, DMODEL, DMODEL,
                   p_yh, DMODEL,
                   p_wout + (long long)lay*DMODEL*DMODEL, DMODEL,
                   p_h, DMODEL, 1.f, aout_b + (long long)lay*DMODEL);

        // ---- FFN [fp16 tensor] ----
        ln_kernel<<<BATCH*LSEQ,256>>>(p_h, p_x2h, ln2_s+(long long)lay*DMODEL, ln2_b+(long long)lay*DMODEL, 0);
        run_gemm_h(2, BATCH*LSEQ, FFD, DMODEL,
                   p_x2h, DMODEL,
                   p_wf1 + (long long)lay*DMODEL*FFD, FFD,
                   nullptr, FFD, 1.f, ff_b1 + (long long)lay*FFD,
                   nullptr, nullptr, p_ffh);
        run_gemm_h(3, BATCH*LSEQ, DMODEL, FFD,
                   p_ffh, FFD,
                   p_wf2 + (long long)lay*FFD*DMODEL, DMODEL,
                   p_h, DMODEL, 1.f, ff_b2 + (long long)lay*DMODEL);
    }

    final_kernel<<<BATCH,256>>>(fin_w, fin_b, out);
}

// round 15
// speedup vs baseline: 1.9686x; 1.0323x over previous
#include <cuda_runtime.h>
#include <cuda_bf16.h>
#include <cuda_fp16.h>
#include <math.h>
#include <stdint.h>

// ---------------- model constants ----------------
#define BATCH 16
#define LSEQ  1000
#define DMODEL 512
#define NH    8
#define DHD   64
#define NPAD  1024
#define PADL  24
#define ML    256
#define LMR   4
#define FFD   2048
#define DEPTH 6
#define KC    33
#define QSCALE 0.125f
#define BH (BATCH*NH)
#define ZKV_SCALE 16.f

// ---------------- scratch ----------------
__device__ float g_h   [BATCH*LSEQ*DMODEL];
__device__ float g_v   [BH*NPAD*DHD];
__device__ float g_a3  [BH*ML*NPAD];
__device__ float g_a2  [BH*ML*ML];
__device__ float g_zb  [BH*ML*ML];
__device__ float g_zb2 [BH*ML*ML];
__device__ float g_pb  [BH*ML*ML];
__device__ float g_tb  [BH*ML*ML];
__device__ float g_tb2 [BH*ML*ML];
__device__ float g_kvb [BH*ML*DHD];
__device__ int   g_red [2];
// fp16 activations / weights
__device__ __half g_qh  [BH*NPAD*DHD];
__device__ __half g_kh  [BH*NPAD*DHD];
__device__ __half g_qlh [BH*ML*DHD];
__device__ __half g_klh [BH*ML*DHD];
__device__ __half g_a1h [BH*NPAD*ML];
__device__ __half g_zkvh[BH*ML*DHD];
__device__ __half g_xh  [BATCH*NPAD*DMODEL];
__device__ __half g_x2h [BATCH*LSEQ*DMODEL];
__device__ __half g_ffh [BATCH*LSEQ*FFD];
__device__ __half g_yh  [BATCH*NPAD*DMODEL];
__device__ __half g_wqkv[DEPTH*DMODEL*3*DMODEL];
__device__ __half g_wout[DEPTH*DMODEL*DMODEL];
__device__ __half g_wf1 [DEPTH*DMODEL*FFD];
__device__ __half g_wf2 [DEPTH*FFD*DMODEL];
// bf16 shadows for pinv
__device__ __nv_bfloat16 g_a2h [BH*ML*ML];
__device__ __nv_bfloat16 g_zh  [BH*ML*ML];
__device__ __nv_bfloat16 g_zh2 [BH*ML*ML];
__device__ __nv_bfloat16 g_ph  [BH*ML*ML];
__device__ __nv_bfloat16 g_th  [BH*ML*ML];
__device__ __nv_bfloat16 g_t2h [BH*ML*ML];

// ---------------- reductions ----------------
__device__ __forceinline__ float warpSum(float v){
    #pragma unroll
    for (int o=16;o;o>>=1) v += __shfl_xor_sync(0xffffffffu, v, o);
    return v;
}
__device__ __forceinline__ float warpMax(float v){
    #pragma unroll
    for (int o=16;o;o>>=1) v = fmaxf(v, __shfl_xor_sync(0xffffffffu, v, o));
    return v;
}
__device__ __forceinline__ float blockSumN(float v, float* sh, int nw){
    int w = threadIdx.x>>5, l = threadIdx.x&31;
    v = warpSum(v);
    if (l==0) sh[w] = v;
    __syncthreads();
    if (w==0){
        float x = (l < nw) ? sh[l] : 0.f;
        x = warpSum(x);
        if (l==0) sh[0] = x;
    }
    __syncthreads();
    float r = sh[0];
    __syncthreads();
    return r;
}
__device__ __forceinline__ float blockMaxN(float v, float* sh, int nw){
    int w = threadIdx.x>>5, l = threadIdx.x&31;
    v = warpMax(v);
    if (l==0) sh[w] = v;
    __syncthreads();
    if (w==0){
        float x = (l < nw) ? sh[l] : -3.4e38f;
        x = warpMax(x);
        if (l==0) sh[0] = x;
    }
    __syncthreads();
    float r = sh[0];
    __syncthreads();
    return r;
}

// ---------------- mma / cp.async / ldmatrix helpers ----------------
__device__ __forceinline__ void mma_tf32(float c[4],
    unsigned a0, unsigned a1, unsigned a2, unsigned a3,
    unsigned b0, unsigned b1)
{
    asm volatile(
        "mma.sync.aligned.m16n8k8.row.col.f32.tf32.tf32.f32 "
        "{%0,%1,%2,%3}, {%4,%5,%6,%7}, {%8,%9}, {%0,%1,%2,%3};"
        : "+f"(c[0]), "+f"(c[1]), "+f"(c[2]), "+f"(c[3])
        : "r"(a0), "r"(a1), "r"(a2), "r"(a3), "r"(b0), "r"(b1));
}
__device__ __forceinline__ void mma_bf16(float c[4],
    unsigned a0, unsigned a1, unsigned a2, unsigned a3,
    unsigned b0, unsigned b1)
{
    asm volatile(
        "mma.sync.aligned.m16n8k16.row.col.f32.bf16.bf16.f32 "
        "{%0,%1,%2,%3}, {%4,%5,%6,%7}, {%8,%9}, {%0,%1,%2,%3};"
        : "+f"(c[0]), "+f"(c[1]), "+f"(c[2]), "+f"(c[3])
        : "r"(a0), "r"(a1), "r"(a2), "r"(a3), "r"(b0), "r"(b1));
}
__device__ __forceinline__ void mma_f16(float c[4],
    unsigned a0, unsigned a1, unsigned a2, unsigned a3,
    unsigned b0, unsigned b1)
{
    asm volatile(
        "mma.sync.aligned.m16n8k16.row.col.f32.f16.f16.f32 "
        "{%0,%1,%2,%3}, {%4,%5,%6,%7}, {%8,%9}, {%0,%1,%2,%3};"
        : "+f"(c[0]), "+f"(c[1]), "+f"(c[2]), "+f"(c[3])
        : "r"(a0), "r"(a1), "r"(a2), "r"(a3), "r"(b0), "r"(b1));
}
__device__ __forceinline__ void cp16(unsigned saddr, const void* gptr){
    asm volatile("cp.async.cg.shared.global [%0], [%1], 16;\n"
                 :: "r"(saddr), "l"(gptr));
}
__device__ __forceinline__ void cp_commit(){
    asm volatile("cp.async.commit_group;\n");
}
template<int N>
__device__ __forceinline__ void cp_wait(){
    asm volatile("cp.async.wait_group %0;\n" :: "n"(N));
}
__device__ __forceinline__ void ldsm4(unsigned &r0, unsigned &r1,
                                      unsigned &r2, unsigned &r3,
                                      unsigned addr){
    asm volatile("ldmatrix.sync.aligned.m8n8.x4.shared.b16 {%0,%1,%2,%3}, [%4];"
        : "=r"(r0), "=r"(r1), "=r"(r2), "=r"(r3) : "r"(addr));
}
__device__ __forceinline__ void ldsm4t(unsigned &r0, unsigned &r1,
                                       unsigned &r2, unsigned &r3,
                                       unsigned addr){
    asm volatile("ldmatrix.sync.aligned.m8n8.x4.trans.shared.b16 {%0,%1,%2,%3}, [%4];"
        : "=r"(r0), "=r"(r1), "=r"(r2), "=r"(r3) : "r"(addr));
}

// ---------------- common tile constants ----------------
#define AS_STRIDE 20
#define AS_ST     (128*AS_STRIDE)
#define NSTAGE 3
#define ASH 40
#define AH_ST (128*ASH)
#define BSH 264
#define BH_ST (32*BSH)
#define SMEM_BF_BYTES (NSTAGE*(AH_ST + BH_ST)*2)
// fp16 TB1 (score) kernel
#define HS_B_ST (256*ASH)
#define SMEM_HS_BYTES (NSTAGE*(AH_ST + HS_B_ST)*2)   // 92160
// tf32 TB0 pinv kernel B
#define BS0_STRIDE 264
#define BS_TF_ST  (16*BS0_STRIDE)
#define SMEM_TC_BYTES (NSTAGE*(AS_ST + BS_TF_ST)*4)
// tf32 N=64 kernel
#define BS64_STRIDE 72
#define BS64_ST     (16*BS64_STRIDE)
#define SMEM_TC64_BYTES (NSTAGE*(AS_ST + BS64_ST)*4)
// fp16 N=64 kernel
#define H64_B_ST (32*72)
#define SMEM_H64_BYTES (NSTAGE*(AH_ST + H64_B_ST)*2)

// == TF32 tensor GEMM (pinv polish): 256 thr, CTA 128x256, TB0, LDSM ======
// EPI 0: C=alpha*val  EPI 5: C=alpha*I-val  EPI 6: C=val, C2=alpha*I-val
template<int EPI>
__global__ void __launch_bounds__(256,1) gemm_tc_kernel(
    int Ki,
    const float* __restrict__ A, int lda, long long sA,
    const float* __restrict__ Bm, int ldb, long long sB,
    float* __restrict__ C, int ldc, long long sC,
    float alpha, float* __restrict__ C2)
{
    extern __shared__ unsigned sm[];
    unsigned* As = sm;
    unsigned* Bs = sm + NSTAGE*AS_ST;
    const unsigned As_base = (unsigned)__cvta_generic_to_shared(As);
    const unsigned Bs_base = (unsigned)__cvta_generic_to_shared(Bs);

    const int bz = blockIdx.z;
    A  += (long long)bz*sA;
    Bm += (long long)bz*sB;
    C  += (long long)bz*sC;
    if (EPI==6) C2 += (long long)bz*sC;

    const int row0 = blockIdx.y*128;
    const int col0 = blockIdx.x*256;
    const int tid = threadIdx.x;
    const int warp = tid>>5, lane = tid&31;
    const int wm = warp & 1, wn = warp >> 1;
    const int g = lane>>2, qc = lane&3;

    const int a_r  = tid>>1;
    const int a_c2 = (tid&1)<<1;

    auto issue = [&](int kt, int st){
        unsigned abase = As_base + (unsigned)(st*AS_ST)*4u;
        #pragma unroll
        for (int i=0;i<2;i++)
            cp16(abase + (unsigned)(a_r*AS_STRIDE + (a_c2+i)*4)*4u,
                 A + (long long)(row0 + a_r)*lda + kt + (a_c2+i)*4);
        unsigned bbase = Bs_base + (unsigned)(st*BS_TF_ST)*4u;
        #pragma unroll
        for (int i=0;i<4;i++){
            int fidx = tid + i*256;
            int bk = fidx>>6, bn4 = (fidx&63)<<2;
            cp16(bbase + (unsigned)(bk*BS0_STRIDE + bn4)*4u,
                 Bm + (long long)(kt + bk)*ldb + col0 + bn4);
        }
    };

    float acc[4][8][4];
    #pragma unroll
    for (int mt=0;mt<4;mt++)
        #pragma unroll
        for (int nt=0;nt<8;nt++)
            #pragma unroll
            for (int i=0;i<4;i++) acc[mt][nt][i]=0.f;

    const int nk = Ki >> 4;
    issue(0, 0);  cp_commit();
    issue(16, 1); cp_commit();

    const int lane8 = lane & 7;
    const int a_lrow = wm*64 + lane8 + ((lane>>3)&1)*8;
    const int a_lw   = ((lane>>4)&1)*4;
    const int b0_frag_off = qc*BS0_STRIDE + wn*64 + g;

    for (int t = 0; t < nk; ++t){
        cp_wait<1>();
        __syncthreads();
        const int rb = t % NSTAGE;
        if (t+2 < nk) issue((t+2)<<4, (t+2)%NSTAGE);
        cp_commit();

        const unsigned a_stage = As_base + (unsigned)(rb*AS_ST)*4u;

        #pragma unroll
        for (int grp=0; grp<2; grp++){
            const int koff = grp*8;
            unsigned af[4][4], bf[8][2];
            #pragma unroll
            for (int mt=0;mt<4;mt++)
                ldsm4(af[mt][0], af[mt][1], af[mt][2], af[mt][3],
                      a_stage + (unsigned)(((a_lrow + mt*16)*AS_STRIDE) + a_lw + koff)*4u);
            const unsigned* Bb = Bs + rb*BS_TF_ST + b0_frag_off + koff*BS0_STRIDE;
            #pragma unroll
            for (int nt=0;nt<8;nt++){
                bf[nt][0] = Bb[nt*8];
                bf[nt][1] = Bb[4*BS0_STRIDE + nt*8];
            }
            #pragma unroll
            for (int mt=0;mt<4;mt++)
                #pragma unroll
                for (int nt=0;nt<8;nt++)
                    mma_tf32(acc[mt][nt], af[mt][0],af[mt][1],af[mt][2],af[mt][3],
                             bf[nt][0],bf[nt][1]);
        }
    }

    #pragma unroll
    for (int mt=0;mt<4;mt++){
        #pragma unroll
        for (int half=0; half<2; half++){
            int r = row0 + wm*64 + mt*16 + g + half*8;
            #pragma unroll
            for (int nt=0;nt<8;nt++){
                int cc = col0 + wn*64 + nt*8 + 2*qc;
                float v0 = acc[mt][nt][2*half+0];
                float v1 = acc[mt][nt][2*half+1];
                if (EPI==0){
                    float2 o = {alpha*v0, alpha*v1};
                    *(float2*)&C[(long long)r*ldc + cc] = o;
                } else if (EPI==5){
                    float2 o = {(r==cc ? alpha : 0.f) - v0, (r==cc+1 ? alpha : 0.f) - v1};
                    *(float2*)&C[(long long)r*ldc + cc] = o;
                } else if (EPI==6){
                    float2 o = {v0, v1};
                    *(float2*)&C[(long long)r*ldc + cc] = o;
                    float2 o2 = {(r==cc ? alpha : 0.f) - v0, (r==cc+1 ? alpha : 0.f) - v1};
                    *(float2*)&C2[(long long)r*ldc + cc] = o2;
                }
            }
        }
    }
}

// ==== BF16 batched GEMM for pinv (unchanged structure) ====================
template<int EPI>
__global__ void __launch_bounds__(256,1) gemm_bf16_kernel(
    const __nv_bfloat16* __restrict__ A,
    const __nv_bfloat16* __restrict__ Bm,
    __nv_bfloat16* __restrict__ Cb,
    __nv_bfloat16* __restrict__ C2b,
    float* __restrict__ Cf,
    float alpha)
{
    extern __shared__ __nv_bfloat16 smh[];
    const unsigned As_base = (unsigned)__cvta_generic_to_shared(smh);
    const unsigned Bs_base = As_base + NSTAGE*AH_ST*2u;

    const long long boff = (long long)blockIdx.z * (ML*ML);
    A  += boff; Bm += boff;

    const int row0 = blockIdx.y*128;
    const int tid = threadIdx.x;
    const int warp = tid>>5, lane = tid&31;
    const int wm = warp & 1, wn = warp >> 1;
    const int g = lane>>2, qc = lane&3;

    auto issue = [&](int kt, int st){
        unsigned abase = As_base + (unsigned)(st*AH_ST)*2u;
        #pragma unroll
        for (int i=0;i<2;i++){
            int r = tid>>1, ch = ((tid&1)<<1) + i;
            cp16(abase + (unsigned)(r*ASH + ch*8)*2u,
                 A + (long long)(row0 + r)*ML + kt + ch*8);
        }
        unsigned bbase = Bs_base + (unsigned)(st*BH_ST)*2u;
        #pragma unroll
        for (int i=0;i<4;i++){
            int fidx = tid + i*256;
            int r = fidx>>5, ch = fidx&31;
            cp16(bbase + (unsigned)(r*BSH + ch*8)*2u,
                 Bm + (long long)(kt + r)*ML + ch*8);
        }
    };

    float acc[4][8][4];
    #pragma unroll
    for (int mt=0;mt<4;mt++)
        #pragma unroll
        for (int nt=0;nt<8;nt++)
            #pragma unroll
            for (int i=0;i<4;i++) acc[mt][nt][i]=0.f;

    const int nk = ML >> 5;
    issue(0, 0);  cp_commit();
    issue(32, 1); cp_commit();

    const int lane8 = lane & 7;
    const int a_row = wm*64 + lane8 + ((lane>>3)&1)*8;
    const int a_col = ((lane>>4)&1)*8;
    const int b_row = lane8 + ((lane>>3)&1)*8;
    const int b_col = ((lane>>4)&1)*8;

    for (int t = 0; t < nk; ++t){
        cp_wait<1>();
        __syncthreads();
        const int rb = t % NSTAGE;
        if (t+2 < nk) issue((t+2)<<5, (t+2)%NSTAGE);
        cp_commit();

        const unsigned a_st = As_base + (unsigned)(rb*AH_ST)*2u;
        const unsigned b_st = Bs_base + (unsigned)(rb*BH_ST)*2u;

        #pragma unroll
        for (int kk=0; kk<2; kk++){
            const int k0 = kk*16;
            unsigned af[4][4], bf[8][2];
            #pragma unroll
            for (int mt=0;mt<4;mt++)
                ldsm4(af[mt][0], af[mt][1], af[mt][2], af[mt][3],
                      a_st + (unsigned)((a_row + mt*16)*ASH + k0 + a_col)*2u);
            #pragma unroll
            for (int np=0;np<4;np++)
                ldsm4t(bf[2*np][0], bf[2*np][1], bf[2*np+1][0], bf[2*np+1][1],
                       b_st + (unsigned)((k0 + b_row)*BSH + wn*64 + np*16 + b_col)*2u);
            #pragma unroll
            for (int mt=0;mt<4;mt++)
                #pragma unroll
                for (int nt=0;nt<8;nt++)
                    mma_bf16(acc[mt][nt], af[mt][0],af[mt][1],af[mt][2],af[mt][3],
                             bf[nt][0],bf[nt][1]);
        }
    }

    #pragma unroll
    for (int mt=0;mt<4;mt++){
        #pragma unroll
        for (int half=0; half<2; half++){
            int r = row0 + wm*64 + mt*16 + g + half*8;
            #pragma unroll
            for (int nt=0;nt<8;nt++){
                int cc = wn*64 + nt*8 + 2*qc;
                float v0 = acc[mt][nt][2*half+0];
                float v1 = acc[mt][nt][2*half+1];
                long long idx = boff + (long long)r*ML + cc;
                if (EPI==0){
                    __nv_bfloat162 pk;
                    pk.x = __float2bfloat16(alpha*v0);
                    pk.y = __float2bfloat16(alpha*v1);
                    *(__nv_bfloat162*)&Cb[idx] = pk;
                } else if (EPI==1){
                    float2 o = {alpha*v0, alpha*v1};
                    *(float2*)&Cf[idx] = o;
                } else if (EPI==5){
                    __nv_bfloat162 pk;
                    pk.x = __float2bfloat16((r==cc   ? alpha : 0.f) - v0);
                    pk.y = __float2bfloat16((r==cc+1 ? alpha : 0.f) - v1);
                    *(__nv_bfloat162*)&Cb[idx] = pk;
                } else if (EPI==6){
                    __nv_bfloat162 pk;
                    pk.x = __float2bfloat16(v0);
                    pk.y = __float2bfloat16(v1);
                    *(__nv_bfloat162*)&Cb[idx] = pk;
                    __nv_bfloat162 pk2;
                    pk2.x = __float2bfloat16((r==cc   ? alpha : 0.f) - v0);
                    pk2.y = __float2bfloat16((r==cc+1 ? alpha : 0.f) - v1);
                    *(__nv_bfloat162*)&C2b[idx] = pk2;
                }
            }
        }
    }
}

// ==== FP16 general GEMM (big mats): CTA 128x256, K-tile 32, TB0 ===========
// EPI 7: qkv split -> fp16 q(Ch, *QSCALE), fp16 k(Ch2), fp32 v(C).
// EPI 4: pad-residual into C. EPI 2: gelu->Ch. EPI 3: C += val+bias.
template<int EPI>
__global__ void __launch_bounds__(256,1) gemm_h_kernel(
    int Ki,
    const __half* __restrict__ A, int lda,
    const __half* __restrict__ Bm, int ldb,
    float* __restrict__ C, int ldc,
    float alpha, const float* __restrict__ bias,
    __half* __restrict__ Ch, __half* __restrict__ Ch2)
{
    extern __shared__ __half smhh[];
    const unsigned As_base = (unsigned)__cvta_generic_to_shared(smhh);
    const unsigned Bs_base = As_base + NSTAGE*AH_ST*2u;

    const int row0 = blockIdx.y*128;
    const int col0 = blockIdx.x*256;
    const int tid = threadIdx.x;
    const int warp = tid>>5, lane = tid&31;
    const int wm = warp & 1, wn = warp >> 1;
    const int g = lane>>2, qc = lane&3;

    auto issue = [&](int kt, int st){
        unsigned abase = As_base + (unsigned)(st*AH_ST)*2u;
        #pragma unroll
        for (int i=0;i<2;i++){
            int r = tid>>1, ch = ((tid&1)<<1) + i;
            cp16(abase + (unsigned)(r*ASH + ch*8)*2u,
                 A + (long long)(row0 + r)*lda + kt + ch*8);
        }
        unsigned bbase = Bs_base + (unsigned)(st*BH_ST)*2u;
        #pragma unroll
        for (int i=0;i<4;i++){
            int fidx = tid + i*256;
            int r = fidx>>5, ch = fidx&31;
            cp16(bbase + (unsigned)(r*BSH + ch*8)*2u,
                 Bm + (long long)(kt + r)*ldb + col0 + ch*8);
        }
    };

    float acc[4][8][4];
    #pragma unroll
    for (int mt=0;mt<4;mt++)
        #pragma unroll
        for (int nt=0;nt<8;nt++)
            #pragma unroll
            for (int i=0;i<4;i++) acc[mt][nt][i]=0.f;

    const int nk = Ki >> 5;
    issue(0, 0);  cp_commit();
    issue(32, 1); cp_commit();

    const int lane8 = lane & 7;
    const int a_row = wm*64 + lane8 + ((lane>>3)&1)*8;
    const int a_col = ((lane>>4)&1)*8;
    const int b_row = lane8 + ((lane>>3)&1)*8;
    const int b_col = ((lane>>4)&1)*8;

    for (int t = 0; t < nk; ++t){
        cp_wait<1>();
        __syncthreads();
        const int rb = t % NSTAGE;
        if (t+2 < nk) issue((t+2)<<5, (t+2)%NSTAGE);
        cp_commit();

        const unsigned a_st = As_base + (unsigned)(rb*AH_ST)*2u;
        const unsigned b_st = Bs_base + (unsigned)(rb*BH_ST)*2u;

        #pragma unroll
        for (int kk=0; kk<2; kk++){
            const int k0 = kk*16;
            unsigned af[4][4], bf[8][2];
            #pragma unroll
            for (int mt=0;mt<4;mt++)
                ldsm4(af[mt][0], af[mt][1], af[mt][2], af[mt][3],
                      a_st + (unsigned)((a_row + mt*16)*ASH + k0 + a_col)*2u);
            #pragma unroll
            for (int np=0;np<4;np++)
                ldsm4t(bf[2*np][0], bf[2*np][1], bf[2*np+1][0], bf[2*np+1][1],
                       b_st + (unsigned)((k0 + b_row)*BSH + wn*64 + np*16 + b_col)*2u);
            #pragma unroll
            for (int mt=0;mt<4;mt++)
                #pragma unroll
                for (int nt=0;nt<8;nt++)
                    mma_f16(acc[mt][nt], af[mt][0],af[mt][1],af[mt][2],af[mt][3],
                            bf[nt][0],bf[nt][1]);
        }
    }

    #pragma unroll
    for (int mt=0;mt<4;mt++){
        #pragma unroll
        for (int half=0; half<2; half++){
            int r = row0 + wm*64 + mt*16 + g + half*8;
            #pragma unroll
            for (int nt=0;nt<8;nt++){
                int cc = col0 + wn*64 + nt*8 + 2*qc;
                float v0 = acc[mt][nt][2*half+0];
                float v1 = acc[mt][nt][2*half+1];
                if (EPI==7){
                    int b = r >> 10, n = r & 1023;
                    int which = cc >> 9;
                    int hd = cc & 511;
                    long long idx = ((((long long)b*NH + (hd>>6))*NPAD) + n)*DHD + (hd&63);
                    if (which==0){
                        *(__half2*)&Ch[idx] = __floats2half2_rn(v0*QSCALE, v1*QSCALE);
                    } else if (which==1){
                        *(__half2*)&Ch2[idx] = __floats2half2_rn(v0, v1);
                    } else {
                        float2 o = {v0, v1};
                        *(float2*)&C[idx] = o;
                    }
                } else if (EPI==4){
                    int bb = r / NPAD, nl = r % NPAD;
                    if (nl >= PADL){
                        long long orow = (long long)bb*LSEQ + (nl - PADL);
                        float2 o = *(float2*)&C[orow*ldc + cc];
                        o.x += v0 + bias[cc];
                        o.y += v1 + bias[cc+1];
                        *(float2*)&C[orow*ldc + cc] = o;
                    }
                } else if (EPI==2){
                    float x0 = v0 + bias[cc], x1 = v1 + bias[cc+1];
                    float g0 = 0.5f*x0*(1.f+erff(x0*0.70710678118654752f));
                    float g1 = 0.5f*x1*(1.f+erff(x1*0.70710678118654752f));
                    *(__half2*)&Ch[(long long)r*ldc + cc] = __floats2half2_rn(g0, g1);
                } else if (EPI==3){
                    float2 o = *(float2*)&C[(long long)r*ldc + cc];
                    o.x += v0 + bias[cc];
                    o.y += v1 + bias[cc+1];
                    *(float2*)&C[(long long)r*ldc + cc] = o;
                }
            }
        }
    }
}

// ==== FP16 TB1 score GEMM: CTA 128x256, B is NxK rm, K<=64, batched =======
// EPI 8: fused softmax -> fp16 Chh.  EPI 9: fused softmax -> fp32 C.
// EPI 0: plain fp32 C (with col0 offset; for attn3 N=1024).
template<int EPI>
__global__ void __launch_bounds__(256,1) gemm_hs_kernel(
    int Ki,
    const __half* __restrict__ A, int lda, long long sA,
    const __half* __restrict__ Bm, int ldb, long long sB,
    float* __restrict__ C, int ldc, long long sC,
    __half* __restrict__ Chh)
{
    extern __shared__ __half smhh[];
    const unsigned As_base = (unsigned)__cvta_generic_to_shared(smhh);
    const unsigned Bs_base = As_base + NSTAGE*AH_ST*2u;

    const int bz = blockIdx.z;
    A  += (long long)bz*sA;
    Bm += (long long)bz*sB;
    if (EPI==0) C += (long long)bz*sC;
    else if (EPI==9) C += (long long)bz*sC;
    else Chh += (long long)bz*sC;

    const int row0 = blockIdx.y*128;
    const int col0 = blockIdx.x*256;
    const int tid = threadIdx.x;
    const int warp = tid>>5, lane = tid&31;
    const int wm = warp & 1, wn = warp >> 1;
    const int g = lane>>2, qc = lane&3;

    auto issue = [&](int kt, int st){
        unsigned abase = As_base + (unsigned)(st*AH_ST)*2u;
        #pragma unroll
        for (int i=0;i<2;i++){
            int r = tid>>1, ch = ((tid&1)<<1) + i;
            cp16(abase + (unsigned)(r*ASH + ch*8)*2u,
                 A + (long long)(row0 + r)*lda + kt + ch*8);
        }
        unsigned bbase = Bs_base + (unsigned)(st*HS_B_ST)*2u;
        #pragma unroll
        for (int i=0;i<4;i++){
            int fidx = tid + i*256;
            int r = fidx>>2, ch = fidx&3;
            cp16(bbase + (unsigned)(r*ASH + ch*8)*2u,
                 Bm + (long long)(col0 + r)*ldb + kt + ch*8);
        }
    };

    float acc[4][8][4];
    #pragma unroll
    for (int mt=0;mt<4;mt++)
        #pragma unroll
        for (int nt=0;nt<8;nt++)
            #pragma unroll
            for (int i=0;i<4;i++) acc[mt][nt][i]=0.f;

    const int nk = Ki >> 5;   // K=64 -> 2 tiles
    issue(0, 0);  cp_commit();
    if (nk > 1){ issue(32, 1); cp_commit(); }
    else cp_commit();

    const int lane8 = lane & 7;
    const int a_row = wm*64 + lane8 + ((lane>>3)&1)*8;
    const int a_col = ((lane>>4)&1)*8;
    const int b_rowm = lane8 + ((lane>>4)&1)*8;   // row-bit from lane>>4
    const int b_colm = ((lane>>3)&1)*8;           // col-bit from lane>>3

    for (int t = 0; t < nk; ++t){
        cp_wait<1>();
        __syncthreads();
        const int rb = t % NSTAGE;
        if (t+2 < nk) issue((t+2)<<5, (t+2)%NSTAGE);
        cp_commit();

        const unsigned a_st = As_base + (unsigned)(rb*AH_ST)*2u;
        const unsigned b_st = Bs_base + (unsigned)(rb*HS_B_ST)*2u;

        #pragma unroll
        for (int kk=0; kk<2; kk++){
            const int k0 = kk*16;
            unsigned af[4][4], bf[8][2];
            #pragma unroll
            for (int mt=0;mt<4;mt++)
                ldsm4(af[mt][0], af[mt][1], af[mt][2], af[mt][3],
                      a_st + (unsigned)((a_row + mt*16)*ASH + k0 + a_col)*2u);
            #pragma unroll
            for (int np=0;np<4;np++)
                ldsm4(bf[2*np][0], bf[2*np][1], bf[2*np+1][0], bf[2*np+1][1],
                      b_st + (unsigned)((wn*64 + np*16 + b_rowm)*ASH + k0 + b_colm)*2u);
            #pragma unroll
            for (int mt=0;mt<4;mt++)
                #pragma unroll
                for (int nt=0;nt<8;nt++)
                    mma_f16(acc[mt][nt], af[mt][0],af[mt][1],af[mt][2],af[mt][3],
                            bf[nt][0],bf[nt][1]);
        }
    }

    if (EPI==8 || EPI==9){
        __syncthreads();
        float* redmax = (float*)smhh;
        float* redsum = (float*)smhh + 512;
        float rm[4][2];
        #pragma unroll
        for (int mt=0;mt<4;mt++){
            #pragma unroll
            for (int half=0; half<2; half++){
                float m = -3.4e38f;
                #pragma unroll
                for (int nt=0;nt<8;nt++){
                    m = fmaxf(m, acc[mt][nt][2*half]);
                    m = fmaxf(m, acc[mt][nt][2*half+1]);
                }
                m = fmaxf(m, __shfl_xor_sync(0xffffffffu, m, 1));
                m = fmaxf(m, __shfl_xor_sync(0xffffffffu, m, 2));
                rm[mt][half] = m;
            }
        }
        if (qc==0){
            #pragma unroll
            for (int mt=0;mt<4;mt++)
                #pragma unroll
                for (int half=0; half<2; half++){
                    int rl = wm*64 + mt*16 + g + half*8;
                    redmax[rl*4 + wn] = rm[mt][half];
                }
        }
        __syncthreads();
        float inv[4][2];
        #pragma unroll
        for (int mt=0;mt<4;mt++){
            #pragma unroll
            for (int half=0; half<2; half++){
                int rl = wm*64 + mt*16 + g + half*8;
                float m = fmaxf(fmaxf(redmax[rl*4+0], redmax[rl*4+1]),
                                fmaxf(redmax[rl*4+2], redmax[rl*4+3]));
                float s = 0.f;
                #pragma unroll
                for (int nt=0;nt<8;nt++){
                    float e0 = expf(acc[mt][nt][2*half]   - m);
                    float e1 = expf(acc[mt][nt][2*half+1] - m);
                    acc[mt][nt][2*half]   = e0;
                    acc[mt][nt][2*half+1] = e1;
                    s += e0 + e1;
                }
                s += __shfl_xor_sync(0xffffffffu, s, 1);
                s += __shfl_xor_sync(0xffffffffu, s, 2);
                if (qc==0) redsum[rl*4 + wn] = s;
                inv[mt][half] = 0.f;
            }
        }
        __syncthreads();
        #pragma unroll
        for (int mt=0;mt<4;mt++)
            #pragma unroll
            for (int half=0; half<2; half++){
                int rl = wm*64 + mt*16 + g + half*8;
                float s = redsum[rl*4+0] + redsum[rl*4+1] + redsum[rl*4+2] + redsum[rl*4+3];
                inv[mt][half] = 1.f / s;
            }
        #pragma unroll
        for (int mt=0;mt<4;mt++){
            #pragma unroll
            for (int half=0; half<2; half++){
                int r = row0 + wm*64 + mt*16 + g + half*8;
                #pragma unroll
                for (int nt=0;nt<8;nt++){
                    int cc = wn*64 + nt*8 + 2*qc;
                    float o0 = acc[mt][nt][2*half]*inv[mt][half];
                    float o1 = acc[mt][nt][2*half+1]*inv[mt][half];
                    if (EPI==8)
                        *(__half2*)&Chh[(long long)r*ldc + cc] = __floats2half2_rn(o0, o1);
                    else {
                        float2 o = {o0, o1};
                        *(float2*)&C[(long long)r*ldc + cc] = o;
                    }
                }
            }
        }
        return;
    }

    // EPI 0: plain fp32 with col0
    #pragma unroll
    for (int mt=0;mt<4;mt++){
        #pragma unroll
        for (int half=0; half<2; half++){
            int r = row0 + wm*64 + mt*16 + g + half*8;
            #pragma unroll
            for (int nt=0;nt<8;nt++){
                int cc = col0 + wn*64 + nt*8 + 2*qc;
                float2 o = {acc[mt][nt][2*half], acc[mt][nt][2*half+1]};
                *(float2*)&C[(long long)r*ldc + cc] = o;
            }
        }
    }
}

// ==== FP16 N=64 ao GEMM + fused conv: CTA 128x64, 128 thr, K-tile 32 ======
__global__ void __launch_bounds__(128) gemm_h64_kernel(
    int Ki,
    const __half* __restrict__ A, int lda, long long sA,
    const __half* __restrict__ Bm, long long sB,
    const float* __restrict__ Vg, const float* __restrict__ cw,
    __half* __restrict__ Y)
{
    extern __shared__ __half smhh[];
    const unsigned As_base = (unsigned)__cvta_generic_to_shared(smhh);
    const unsigned Bs_base = As_base + NSTAGE*AH_ST*2u;
    __shared__ float ws[KC];

    const int bz = blockIdx.z;
    A  += (long long)bz*sA;
    Bm += (long long)bz*sB;

    const int row0 = blockIdx.y*128;
    const int tid = threadIdx.x;
    const int warp = tid>>5, lane = tid&31;
    const int wm = warp & 1, wn = warp >> 1;
    const int g = lane>>2, qc = lane&3;

    if (tid < KC) ws[tid] = cw[(bz % NH)*KC + tid];

    auto issue = [&](int kt, int st){
        unsigned abase = As_base + (unsigned)(st*AH_ST)*2u;
        #pragma unroll
        for (int i=0;i<4;i++){
            int fidx = tid + i*128;
            int r = fidx>>2, ch = fidx&3;
            cp16(abase + (unsigned)(r*ASH + ch*8)*2u,
                 A + (long long)(row0 + r)*lda + kt + ch*8);
        }
        unsigned bbase = Bs_base + (unsigned)(st*H64_B_ST)*2u;
        #pragma unroll
        for (int i=0;i<2;i++){
            int fidx = tid + i*128;
            int r = fidx>>3, ch = fidx&7;
            cp16(bbase + (unsigned)(r*72 + ch*8)*2u,
                 Bm + (long long)(kt + r)*DHD + ch*8);
        }
    };

    float acc[4][4][4];
    #pragma unroll
    for (int mt=0;mt<4;mt++)
        #pragma unroll
        for (int nt=0;nt<4;nt++)
            #pragma unroll
            for (int i=0;i<4;i++) acc[mt][nt][i]=0.f;

    const int nk = Ki >> 5;
    issue(0, 0);  cp_commit();
    issue(32, 1); cp_commit();

    const int lane8 = lane & 7;
    const int a_row = wm*64 + lane8 + ((lane>>3)&1)*8;
    const int a_col = ((lane>>4)&1)*8;
    const int b_row = lane8 + ((lane>>3)&1)*8;
    const int b_col = ((lane>>4)&1)*8;

    for (int t = 0; t < nk; ++t){
        cp_wait<1>();
        __syncthreads();
        const int rb = t % NSTAGE;
        if (t+2 < nk) issue((t+2)<<5, (t+2)%NSTAGE);
        cp_commit();

        const unsigned a_st = As_base + (unsigned)(rb*AH_ST)*2u;
        const unsigned b_st = Bs_base + (unsigned)(rb*H64_B_ST)*2u;

        #pragma unroll
        for (int kk=0; kk<2; kk++){
            const int k0 = kk*16;
            unsigned af[4][4], bf[4][2];
            #pragma unroll
            for (int mt=0;mt<4;mt++)
                ldsm4(af[mt][0], af[mt][1], af[mt][2], af[mt][3],
                      a_st + (unsigned)((a_row + mt*16)*ASH + k0 + a_col)*2u);
            #pragma unroll
            for (int np=0;np<2;np++)
                ldsm4t(bf[2*np][0], bf[2*np][1], bf[2*np+1][0], bf[2*np+1][1],
                       b_st + (unsigned)((k0 + b_row)*72 + wn*32 + np*16 + b_col)*2u);
            #pragma unroll
            for (int mt=0;mt<4;mt++)
                #pragma unroll
                for (int nt=0;nt<4;nt++)
                    mma_f16(acc[mt][nt], af[mt][0],af[mt][1],af[mt][2],af[mt][3],
                            bf[nt][0],bf[nt][1]);
        }
    }

    const int h = bz % NH, b = bz / NH;
    const float* vp = Vg + (long long)bz*NPAD*DHD;
    #pragma unroll
    for (int mt=0;mt<4;mt++){
        #pragma unroll
        for (int half=0; half<2; half++){
            int n = row0 + wm*64 + mt*16 + g + half*8;
            int k0 = (16-n > 0) ? (16-n) : 0;
            int k1 = (NPAD+16-n < KC) ? (NPAD+16-n) : KC;
            #pragma unroll
            for (int nt=0;nt<4;nt++){
                int cc = wn*32 + nt*8 + 2*qc;
                float s0 = acc[mt][nt][2*half+0] * ZKV_SCALE;
                float s1 = acc[mt][nt][2*half+1] * ZKV_SCALE;
                for (int kk=k0; kk<k1; kk++){
                    float2 vv = *(const float2*)&vp[(long long)(n+kk-16)*DHD + cc];
                    s0 = fmaf(vv.x, ws[kk], s0);
                    s1 = fmaf(vv.y, ws[kk], s1);
                }
                *(__half2*)&Y[((long long)b*NPAD + n)*DMODEL + h*DHD + cc] = __floats2half2_rn(s0, s1);
            }
        }
    }
}

// ==== TF32 tensor GEMM N=64 (kv, zkv): 128 thr, CTA 128x64 ================
// EPI 0: C = val (fp32).  EPI 2: Ch = half(val / ZKV_SCALE).
template<int EPI>
__global__ void __launch_bounds__(128) gemm_tc64_kernel(
    int Ki,
    const float* __restrict__ A, int lda, long long sA,
    const float* __restrict__ Bm, int ldb, long long sB,
    float* __restrict__ C, int ldc, long long sC,
    __half* __restrict__ Ch)
{
    extern __shared__ unsigned sm[];
    unsigned* As = sm;
    unsigned* Bs = sm + NSTAGE*AS_ST;
    const unsigned As_base = (unsigned)__cvta_generic_to_shared(As);
    const unsigned Bs_base = (unsigned)__cvta_generic_to_shared(Bs);

    const int bz = blockIdx.z;
    A  += (long long)bz*sA;
    Bm += (long long)bz*sB;
    if (EPI==0) C += (long long)bz*sC; else Ch += (long long)bz*sC;

    const int row0 = blockIdx.y*128;
    const int tid = threadIdx.x;
    const int warp = tid>>5, lane = tid&31;
    const int wm = warp & 1, wn = warp >> 1;
    const int g = lane>>2, qc = lane&3;

    auto issue = [&](int kt, int st){
        unsigned abase = As_base + (unsigned)(st*AS_ST)*4u;
        #pragma unroll
        for (int i=0;i<4;i++){
            int fidx = tid + i*128;
            int a_r = fidx>>2, a_c4 = (fidx&3)<<2;
            cp16(abase + (unsigned)(a_r*AS_STRIDE + a_c4)*4u,
                 A + (long long)(row0 + a_r)*lda + kt + a_c4);
        }
        unsigned bbase = Bs_base + (unsigned)(st*BS64_ST)*4u;
        #pragma unroll
        for (int i=0;i<2;i++){
            int fidx = tid + i*128;
            int bk = fidx>>4, bn4 = (fidx&15)<<2;
            cp16(bbase + (unsigned)(bk*BS64_STRIDE + bn4)*4u,
                 Bm + (long long)(kt + bk)*ldb + bn4);
        }
    };

    float acc[4][4][4];
    #pragma unroll
    for (int mt=0;mt<4;mt++)
        #pragma unroll
        for (int nt=0;nt<4;nt++)
            #pragma unroll
            for (int i=0;i<4;i++) acc[mt][nt][i]=0.f;

    const int nk = Ki >> 4;
    issue(0, 0);  cp_commit();
    issue(16, 1); cp_commit();

    const int lane8 = lane & 7;
    const int a_lrow = wm*64 + lane8 + ((lane>>3)&1)*8;
    const int a_lw   = ((lane>>4)&1)*4;
    const int b_frag_off = qc*BS64_STRIDE + wn*32 + g;

    for (int t = 0; t < nk; ++t){
        cp_wait<1>();
        __syncthreads();
        const int rb = t % NSTAGE;
        if (t+2 < nk) issue((t+2)<<4, (t+2)%NSTAGE);
        cp_commit();

        const unsigned a_stage = As_base + (unsigned)(rb*AS_ST)*4u;

        #pragma unroll
        for (int grp=0; grp<2; grp++){
            const int koff = grp*8;
            unsigned af[4][4], bf[4][2];
            #pragma unroll
            for (int mt=0;mt<4;mt++)
                ldsm4(af[mt][0], af[mt][1], af[mt][2], af[mt][3],
                      a_stage + (unsigned)(((a_lrow + mt*16)*AS_STRIDE) + a_lw + koff)*4u);
            const unsigned* Bb = Bs + rb*BS64_ST + b_frag_off + koff*BS64_STRIDE;
            #pragma unroll
            for (int nt=0;nt<4;nt++){
                bf[nt][0] = Bb[nt*8];
                bf[nt][1] = Bb[4*BS64_STRIDE + nt*8];
            }
            #pragma unroll
            for (int mt=0;mt<4;mt++)
                #pragma unroll
                for (int nt=0;nt<4;nt++)
                    mma_tf32(acc[mt][nt], af[mt][0],af[mt][1],af[mt][2],af[mt][3],
                             bf[nt][0],bf[nt][1]);
        }
    }

    #pragma unroll
    for (int mt=0;mt<4;mt++){
        #pragma unroll
        for (int half=0; half<2; half++){
            int r = row0 + wm*64 + mt*16 + g + half*8;
            #pragma unroll
            for (int nt=0;nt<4;nt++){
                int cc = wn*32 + nt*8 + 2*qc;
                float v0 = acc[mt][nt][2*half+0];
                float v1 = acc[mt][nt][2*half+1];
                if (EPI==0){
                    float2 o = {v0, v1};
                    *(float2*)&C[(long long)r*ldc + cc] = o;
                } else {
                    *(__half2*)&Ch[(long long)r*ldc + cc] =
                        __floats2half2_rn(v0*(1.f/ZKV_SCALE), v1*(1.f/ZKV_SCALE));
                }
            }
        }
    }
}

// ---------------- elementwise / small kernels ----------------
__global__ void embed_kernel(const int* __restrict__ x,
                             const float* __restrict__ emb,
                             const float* __restrict__ pos){
    long long idx = (long long)blockIdx.x*blockDim.x + threadIdx.x;
    if (idx >= (long long)BATCH*LSEQ*DMODEL) return;
    int d = (int)(idx % DMODEL);
    long long bl = idx / DMODEL;
    int l = (int)(bl % LSEQ);
    int tok = x[bl];
    g_h[idx] = emb[(long long)tok*DMODEL + d] + pos[(long long)l*DMODEL + d];
}

__global__ void zero_pad_kernel(){
    int idx = blockIdx.x*blockDim.x + threadIdx.x;
    if (idx >= BATCH*PADL*DMODEL) return;
    int d  = idx % DMODEL;
    int bp = idx / DMODEL;
    int b  = bp / PADL, p = bp % PADL;
    g_xh[((long long)b*NPAD + p)*DMODEL + d] = __float2half(0.f);
}

__global__ void cvtw_kernel(const float* __restrict__ src, __half* __restrict__ dst, long long n){
    long long idx = (long long)blockIdx.x*blockDim.x + threadIdx.x;
    if (idx < n) dst[idx] = __float2half(src[idx]);
}

__global__ void ln_kernel(const float* __restrict__ in, __half* __restrict__ out,
                          const float* __restrict__ gm, const float* __restrict__ bt,
                          int padmode){
    __shared__ float sh[8];
    int r = blockIdx.x;
    int t = threadIdx.x;
    const float* p = in + (long long)r*DMODEL;
    float a  = p[t];
    float b2 = p[t+256];
    float s  = blockSumN(a+b2, sh, 8);
    float mu = s * (1.f/512.f);
    float da = a - mu, db = b2 - mu;
    float v  = blockSumN(da*da + db*db, sh, 8) * (1.f/512.f);
    float rstd = rsqrtf(v + 1e-5f);
    long long orow = padmode ? ((long long)(r/LSEQ)*NPAD + PADL + (r%LSEQ)) : (long long)r;
    __half* q = out + orow*DMODEL;
    q[t]     = __float2half(da*rstd*gm[t]     + bt[t]);
    q[t+256] = __float2half(db*rstd*gm[t+256] + bt[t+256]);
}

// landmark means in fp16 in/out
__global__ void landmark_kernel(){
    long long idx = (long long)blockIdx.x*blockDim.x + threadIdx.x;
    if (idx >= (long long)BH*ML*DHD) return;
    int d = (int)(idx & 63);
    long long r = idx >> 6;
    int m  = (int)(r % ML);
    int bh = (int)(r / ML);
    long long base = ((long long)bh*NPAD + (long long)m*LMR)*DHD + d;
    float sq = 0.f, sk = 0.f;
    #pragma unroll
    for (int j=0;j<LMR;j++){
        sq += __half2float(g_qh[base + (long long)j*DHD]);
        sk += __half2float(g_kh[base + (long long)j*DHD]);
    }
    g_qlh[idx] = __float2half(sq * 0.25f);
    g_klh[idx] = __float2half(sk * 0.25f);
}

__global__ void softmax_kernel(float* __restrict__ X, int cols){
    __shared__ float sh[4];
    long long row = blockIdx.x;
    float* p = X + row*(long long)cols;
    int t = threadIdx.x;
    int cnt = cols >> 7;
    float v[8];
    float mx = -3.4e38f;
    #pragma unroll
    for (int i=0;i<8;i++) if (i<cnt){ v[i]=p[t + (i<<7)]; mx = fmaxf(mx, v[i]); }
    mx = blockMaxN(mx, sh, 4);
    float s = 0.f;
    #pragma unroll
    for (int i=0;i<8;i++) if (i<cnt){ v[i]=expf(v[i]-mx); s += v[i]; }
    s = blockSumN(s, sh, 4);
    float inv = 1.f/s;
    #pragma unroll
    for (int i=0;i<8;i++) if (i<cnt) p[t + (i<<7)] = v[i]*inv;
}

__global__ void red_init_kernel(){ g_red[0]=0; g_red[1]=0; }

__global__ void colsum_kernel(){
    __shared__ float sh[8];
    int bz = blockIdx.x;
    const float* p = g_a2 + (long long)bz*ML*ML;
    int c = threadIdx.x;
    float s = 0.f;
    for (int r=0;r<ML;r++) s += fabsf(p[(long long)r*ML + c]);
    float m = blockMaxN(s, sh, 8);
    if (threadIdx.x==0) atomicMax(&g_red[0], __float_as_int(m));
}
__global__ void rowsum_kernel(){
    __shared__ float sh[8];
    int bz = blockIdx.x;
    const float* p = g_a2 + (long long)bz*ML*ML;
    int w = threadIdx.x>>5, l = threadIdx.x&31;
    float m = -3.4e38f;
    for (int r=w; r<ML; r+=8){
        float s = 0.f;
        for (int c=l; c<ML; c+=32) s += fabsf(p[(long long)r*ML + c]);
        s = warpSum(s);
        m = fmaxf(m, s);
    }
    m = blockMaxN(m, sh, 8);
    if (threadIdx.x==0) atomicMax(&g_red[1], __float_as_int(m));
}
__global__ void zinit_kernel(){
    __shared__ float tile[32][33];
    int bz = blockIdx.z;
    int i0 = blockIdx.x*32;
    int j0 = blockIdx.y*32;
    const long long base = (long long)bz*ML*ML;
    float c = __int_as_float(g_red[0]) * __int_as_float(g_red[1]);
    float invc = 1.f/c;
    #pragma unroll
    for (int k=0;k<4;k++){
        int j = j0 + threadIdx.y + k*8;
        float v = g_a2[base + (long long)j*ML + i0 + threadIdx.x];
        tile[threadIdx.y + k*8][threadIdx.x] = v;
        g_a2h[base + (long long)j*ML + i0 + threadIdx.x] = __float2bfloat16(v);
    }
    __syncthreads();
    #pragma unroll
    for (int k=0;k<4;k++){
        int i = i0 + threadIdx.y + k*8;
        float v = tile[threadIdx.x][threadIdx.y + k*8] * invc;
        long long idx = base + (long long)i*ML + j0 + threadIdx.x;
        g_zb[idx] = v;
        g_zh[idx] = __float2bfloat16(v);
    }
}

__global__ void final_kernel(const float* __restrict__ fw,
                             const float* __restrict__ fb,
                             float* __restrict__ out){
    __shared__ float sh[8];
    int b = blockIdx.x;
    int t = threadIdx.x;
    const float* hp = g_h + (long long)b*LSEQ*DMODEL;
    float s = 0.f;
    for (long long i=t; i<(long long)LSEQ*DMODEL; i+=256)
        s = fmaf(hp[i], fw[i], s);
    s = blockSumN(s, sh, 8);
    if (t==0) out[b] = s + fb[0];
}

// ---------------- host-side dispatch ----------------
static void run_gemm(int epi, int Mi, int Ni, int Ki,
                     const float* A, int lda, long long sA,
                     const float* Bm, int ldb, long long sB,
                     float* C, int ldc, long long sC,
                     int batch, float alpha, float* C2 = nullptr)
{
    dim3 g(Ni/256, Mi/128, batch), t(256);
    size_t sh = SMEM_TC_BYTES;
    switch (epi) {
        case 0: gemm_tc_kernel<0><<<g,t,sh>>>(Ki,A,lda,sA,Bm,ldb,sB,C,ldc,sC,alpha,C2); break;
        case 5: gemm_tc_kernel<5><<<g,t,sh>>>(Ki,A,lda,sA,Bm,ldb,sB,C,ldc,sC,alpha,C2); break;
        case 6: gemm_tc_kernel<6><<<g,t,sh>>>(Ki,A,lda,sA,Bm,ldb,sB,C,ldc,sC,alpha,C2); break;
    }
}

static void run_gemm_h(int epi, int Mi, int Ni, int Ki,
                       const __half* A, int lda,
                       const __half* Bm, int ldb,
                       float* C, int ldc,
                       const float* bias,
                       __half* Ch = nullptr, __half* Ch2 = nullptr)
{
    dim3 g(Ni/256, Mi/128, 1), t(256);
    size_t sh = SMEM_BF_BYTES;
    switch (epi) {
        case 2: gemm_h_kernel<2><<<g,t,sh>>>(Ki,A,lda,Bm,ldb,C,ldc,1.f,bias,Ch,Ch2); break;
        case 3: gemm_h_kernel<3><<<g,t,sh>>>(Ki,A,lda,Bm,ldb,C,ldc,1.f,bias,Ch,Ch2); break;
        case 4: gemm_h_kernel<4><<<g,t,sh>>>(Ki,A,lda,Bm,ldb,C,ldc,1.f,bias,Ch,Ch2); break;
        case 7: gemm_h_kernel<7><<<g,t,sh>>>(Ki,A,lda,Bm,ldb,C,ldc,1.f,bias,Ch,Ch2); break;
    }
}

static void run_gemm_hs(int epi, int Mi, int Ni, int Ki,
                        const __half* A, int lda, long long sA,
                        const __half* Bm, int ldb, long long sB,
                        float* C, int ldc, long long sC, int batch,
                        __half* Chh = nullptr)
{
    dim3 g(Ni/256, Mi/128, batch), t(256);
    size_t sh = SMEM_HS_BYTES;
    switch (epi) {
        case 0: gemm_hs_kernel<0><<<g,t,sh>>>(Ki,A,lda,sA,Bm,ldb,sB,C,ldc,sC,Chh); break;
        case 8: gemm_hs_kernel<8><<<g,t,sh>>>(Ki,A,lda,sA,Bm,ldb,sB,C,ldc,sC,Chh); break;
        case 9: gemm_hs_kernel<9><<<g,t,sh>>>(Ki,A,lda,sA,Bm,ldb,sB,C,ldc,sC,Chh); break;
    }
}

static void run_gemm64(int epi, int Mi, int Ki,
                       const float* A, int lda, long long sA,
                       const float* Bm, int ldb, long long sB,
                       float* C, int ldc, long long sC, int batch,
                       __half* Ch = nullptr)
{
    dim3 g(1, Mi/128, batch), t(128);
    if (epi == 0)
        gemm_tc64_kernel<0><<<g,t,SMEM_TC64_BYTES>>>(Ki,A,lda,sA,Bm,ldb,sB,C,ldc,sC,Ch);
    else
        gemm_tc64_kernel<2><<<g,t,SMEM_TC64_BYTES>>>(Ki,A,lda,sA,Bm,ldb,sB,C,ldc,sC,Ch);
}

static void run_gemm_bf16(int epi,
                          const __nv_bfloat16* A, const __nv_bfloat16* Bm,
                          __nv_bfloat16* Cb, __nv_bfloat16* C2b, float* Cf,
                          float alpha)
{
    dim3 g(1, ML/128, BH), t(256);
    size_t sh = SMEM_BF_BYTES;
    switch (epi) {
        case 0: gemm_bf16_kernel<0><<<g,t,sh>>>(A,Bm,Cb,C2b,Cf,alpha); break;
        case 1: gemm_bf16_kernel<1><<<g,t,sh>>>(A,Bm,Cb,C2b,Cf,alpha); break;
        case 5: gemm_bf16_kernel<5><<<g,t,sh>>>(A,Bm,Cb,C2b,Cf,alpha); break;
        case 6: gemm_bf16_kernel<6><<<g,t,sh>>>(A,Bm,Cb,C2b,Cf,alpha); break;
    }
}

static void setup_tc_attrs(){
    cudaFuncSetAttribute(gemm_tc_kernel<0>, cudaFuncAttributeMaxDynamicSharedMemorySize, SMEM_TC_BYTES);
    cudaFuncSetAttribute(gemm_tc_kernel<5>, cudaFuncAttributeMaxDynamicSharedMemorySize, SMEM_TC_BYTES);
    cudaFuncSetAttribute(gemm_tc_kernel<6>, cudaFuncAttributeMaxDynamicSharedMemorySize, SMEM_TC_BYTES);
    cudaFuncSetAttribute(gemm_tc64_kernel<0>, cudaFuncAttributeMaxDynamicSharedMemorySize, SMEM_TC64_BYTES);
    cudaFuncSetAttribute(gemm_tc64_kernel<2>, cudaFuncAttributeMaxDynamicSharedMemorySize, SMEM_TC64_BYTES);
    cudaFuncSetAttribute(gemm_bf16_kernel<0>, cudaFuncAttributeMaxDynamicSharedMemorySize, SMEM_BF_BYTES);
    cudaFuncSetAttribute(gemm_bf16_kernel<1>, cudaFuncAttributeMaxDynamicSharedMemorySize, SMEM_BF_BYTES);
    cudaFuncSetAttribute(gemm_bf16_kernel<5>, cudaFuncAttributeMaxDynamicSharedMemorySize, SMEM_BF_BYTES);
    cudaFuncSetAttribute(gemm_bf16_kernel<6>, cudaFuncAttributeMaxDynamicSharedMemorySize, SMEM_BF_BYTES);
    cudaFuncSetAttribute(gemm_h_kernel<2>, cudaFuncAttributeMaxDynamicSharedMemorySize, SMEM_BF_BYTES);
    cudaFuncSetAttribute(gemm_h_kernel<3>, cudaFuncAttributeMaxDynamicSharedMemorySize, SMEM_BF_BYTES);
    cudaFuncSetAttribute(gemm_h_kernel<4>, cudaFuncAttributeMaxDynamicSharedMemorySize, SMEM_BF_BYTES);
    cudaFuncSetAttribute(gemm_h_kernel<7>, cudaFuncAttributeMaxDynamicSharedMemorySize, SMEM_BF_BYTES);
    cudaFuncSetAttribute(gemm_hs_kernel<0>, cudaFuncAttributeMaxDynamicSharedMemorySize, SMEM_HS_BYTES);
    cudaFuncSetAttribute(gemm_hs_kernel<8>, cudaFuncAttributeMaxDynamicSharedMemorySize, SMEM_HS_BYTES);
    cudaFuncSetAttribute(gemm_hs_kernel<9>, cudaFuncAttributeMaxDynamicSharedMemorySize, SMEM_HS_BYTES);
    cudaFuncSetAttribute(gemm_h64_kernel, cudaFuncAttributeMaxDynamicSharedMemorySize, SMEM_H64_BYTES);
}

extern "C" void kernel_launch(void* const* d_in, const int* in_sizes, int n_in,
                              void* d_out, int out_size)
{
    (void)in_sizes; (void)n_in; (void)out_size;
    const int*   x       = (const int*)  d_in[0];
    const float* enc_emb = (const float*)d_in[1];
    const float* pos_emb = (const float*)d_in[2];
    const float* ln1_s   = (const float*)d_in[3];
    const float* ln1_b   = (const float*)d_in[4];
    const float* qkv_w   = (const float*)d_in[5];
    const float* aout_w  = (const float*)d_in[6];
    const float* aout_b  = (const float*)d_in[7];
    const float* conv_k  = (const float*)d_in[8];
    const float* ln2_s   = (const float*)d_in[9];
    const float* ln2_b   = (const float*)d_in[10];
    const float* ff_w1   = (const float*)d_in[11];
    const float* ff_b1   = (const float*)d_in[12];
    const float* ff_w2   = (const float*)d_in[13];
    const float* ff_b2   = (const float*)d_in[14];
    const float* fin_w   = (const float*)d_in[15];
    const float* fin_b   = (const float*)d_in[16];
    float* out = (float*)d_out;

    setup_tc_attrs();

    float *p_h,*p_v,*p_a3,*p_a2,*p_z,*p_z2,*p_p,*p_t,*p_t2,*p_kv;
    __half *p_qh,*p_kh,*p_qlh,*p_klh,*p_a1h,*p_zkvh;
    __half *p_xh,*p_x2h,*p_ffh,*p_yh,*p_wqkv,*p_wout,*p_wf1,*p_wf2;
    __nv_bfloat16 *p_a2h,*p_zh,*p_zh2,*p_ph,*p_th,*p_t2h;
    cudaGetSymbolAddress((void**)&p_h,  g_h);
    cudaGetSymbolAddress((void**)&p_v,  g_v);
    cudaGetSymbolAddress((void**)&p_a3, g_a3);
    cudaGetSymbolAddress((void**)&p_a2, g_a2);
    cudaGetSymbolAddress((void**)&p_z,  g_zb);
    cudaGetSymbolAddress((void**)&p_z2, g_zb2);
    cudaGetSymbolAddress((void**)&p_p,  g_pb);
    cudaGetSymbolAddress((void**)&p_t,  g_tb);
    cudaGetSymbolAddress((void**)&p_t2, g_tb2);
    cudaGetSymbolAddress((void**)&p_kv, g_kvb);
    cudaGetSymbolAddress((void**)&p_qh,  g_qh);
    cudaGetSymbolAddress((void**)&p_kh,  g_kh);
    cudaGetSymbolAddress((void**)&p_qlh, g_qlh);
    cudaGetSymbolAddress((void**)&p_klh, g_klh);
    cudaGetSymbolAddress((void**)&p_a1h, g_a1h);
    cudaGetSymbolAddress((void**)&p_zkvh,g_zkvh);
    cudaGetSymbolAddress((void**)&p_xh,  g_xh);
    cudaGetSymbolAddress((void**)&p_x2h, g_x2h);
    cudaGetSymbolAddress((void**)&p_ffh, g_ffh);
    cudaGetSymbolAddress((void**)&p_yh,  g_yh);
    cudaGetSymbolAddress((void**)&p_wqkv,g_wqkv);
    cudaGetSymbolAddress((void**)&p_wout,g_wout);
    cudaGetSymbolAddress((void**)&p_wf1, g_wf1);
    cudaGetSymbolAddress((void**)&p_wf2, g_wf2);
    cudaGetSymbolAddress((void**)&p_a2h, g_a2h);
    cudaGetSymbolAddress((void**)&p_zh,  g_zh);
    cudaGetSymbolAddress((void**)&p_zh2, g_zh2);
    cudaGetSymbolAddress((void**)&p_ph,  g_ph);
    cudaGetSymbolAddress((void**)&p_th,  g_th);
    cudaGetSymbolAddress((void**)&p_t2h, g_t2h);

    const long long MM  = (long long)ML*ML;
    const long long NM  = (long long)NPAD*ML;
    const long long ND  = (long long)NPAD*DHD;
    const long long MD  = (long long)ML*DHD;

    // weight fp16 conversion (once per launch)
    {
        long long n1 = (long long)DEPTH*DMODEL*3*DMODEL;
        long long n2 = (long long)DEPTH*DMODEL*DMODEL;
        long long n3 = (long long)DEPTH*DMODEL*FFD;
        long long n4 = (long long)DEPTH*FFD*DMODEL;
        cvtw_kernel<<<(unsigned)((n1+255)/256),256>>>(qkv_w, p_wqkv, n1);
        cvtw_kernel<<<(unsigned)((n2+255)/256),256>>>(aout_w, p_wout, n2);
        cvtw_kernel<<<(unsigned)((n3+255)/256),256>>>(ff_w1, p_wf1, n3);
        cvtw_kernel<<<(unsigned)((n4+255)/256),256>>>(ff_w2, p_wf2, n4);
    }

    {
        long long tot = (long long)BATCH*LSEQ*DMODEL;
        embed_kernel<<<(unsigned)((tot+255)/256),256>>>(x, enc_emb, pos_emb);
        int tot2 = BATCH*PADL*DMODEL;
        zero_pad_kernel<<<(tot2+255)/256,256>>>();
    }

    for (int lay=0; lay<DEPTH; lay++){
        ln_kernel<<<BATCH*LSEQ,256>>>(p_h, p_xh, ln1_s+(long long)lay*DMODEL, ln1_b+(long long)lay*DMODEL, 1);
        // QKV [fp16, fused split: fp16 q/k, fp32 v]
        run_gemm_h(7, BATCH*NPAD, 3*DMODEL, DMODEL,
                   p_xh, DMODEL,
                   p_wqkv + (long long)lay*DMODEL*3*DMODEL, 3*DMODEL,
                   p_v, 3*DMODEL, nullptr, p_qh, p_kh);
        {
            long long tot2 = (long long)BH*ML*DHD;
            landmark_kernel<<<(unsigned)((tot2+255)/256),256>>>();
        }
        // attn1 = softmax(q @ kl^T)  [fp16 TB1, fused softmax -> fp16 a1]
        run_gemm_hs(8, NPAD, ML, DHD, p_qh, DHD, ND, p_klh, DHD, MD, nullptr, ML, NM, BH, p_a1h);
        // attn2 = softmax(ql @ kl^T)  [fp16 TB1, fused softmax -> fp32 a2]
        run_gemm_hs(9, ML, ML, DHD, p_qlh, DHD, MD, p_klh, DHD, MD, p_a2, ML, MM, BH);
        // attn3 = ql @ k^T  [fp16 TB1 -> fp32] + separate softmax (N=1024)
        run_gemm_hs(0, ML, NPAD, DHD, p_qlh, DHD, MD, p_kh, DHD, ND, p_a3, NPAD, (long long)ML*NPAD, BH);
        softmax_kernel<<<BH*ML,128>>>(p_a3, NPAD);

        // ---- pinv: 5 bf16 quintic iterations + 1 tf32 quintic polish ----
        red_init_kernel<<<1,1>>>();
        colsum_kernel<<<BH,256>>>();
        rowsum_kernel<<<BH,256>>>();
        {
            dim3 gz(ML/32, ML/32, BH), tz(32, 8);
            zinit_kernel<<<gz, tz>>>();
        }
        __nv_bfloat16* zhc = p_zh; __nv_bfloat16* zhn = p_zh2;
        for (int it=0; it<5; it++){
            run_gemm_bf16(6, p_a2h, zhc, p_ph, p_th, nullptr, 7.f);
            run_gemm_bf16(5, p_ph, p_th,  p_t2h, nullptr, nullptr, 15.f);
            run_gemm_bf16(5, p_ph, p_t2h, p_th,  nullptr, nullptr, 13.f);
            if (it < 4){
                run_gemm_bf16(0, zhc, p_th, zhn, nullptr, nullptr, 0.25f);
                __nv_bfloat16* tmp = zhc; zhc = zhn; zhn = tmp;
            } else {
                run_gemm_bf16(1, zhc, p_th, nullptr, nullptr, p_z, 0.25f); // fp32 Z5
            }
        }
        run_gemm(6, ML, ML, ML, p_a2, ML, MM, p_z, ML, MM, p_p, ML, MM, BH, 7.f, p_t);
        run_gemm(5, ML, ML, ML, p_p, ML, MM, p_t, ML, MM, p_t2, ML, MM, BH, 15.f);
        run_gemm(5, ML, ML, ML, p_p, ML, MM, p_t2, ML, MM, p_t, ML, MM, BH, 13.f);
        run_gemm(0, ML, ML, ML, p_z, ML, MM, p_t, ML, MM, p_z2, ML, MM, BH, 0.25f);
        float* zc = p_z2;

        // kv = attn3 @ v  [tf32 N=64 -> fp32]
        run_gemm64(0, ML, NPAD, p_a3, NPAD, (long long)ML*NPAD, p_v, DHD, ND, p_kv, DHD, MD, BH);
        // zkv = Z @ kv  [tf32 N=64 -> fp16/16]
        run_gemm64(2, ML, ML, zc, ML, MM, p_kv, DHD, MD, nullptr, DHD, MD, BH, p_zkvh);
        // ao = a1h @ zkvh*16 + conv(v) -> fp16 y  [fp16 N=64, fused]
        {
            dim3 g(1, NPAD/128, BH), t(128);
            gemm_h64_kernel<<<g,t,SMEM_H64_BYTES>>>(ML, p_a1h, ML, NM, p_zkvh, MD,
                                                    p_v, conv_k + (long long)lay*NH*KC, p_yh);
        }
        // out projection + residual [fp16]
        run_gemm_h(4, BATCH*NPAD, DMODEL, DMODEL,
                   p_yh, DMODEL,
                   p_wout + (long long)lay*DMODEL*DMODEL, DMODEL,
                   p_h, DMODEL, aout_b + (long long)lay*DMODEL);

        // ---- FFN [fp16] ----
        ln_kernel<<<BATCH*LSEQ,256>>>(p_h, p_x2h, ln2_s+(long long)lay*DMODEL, ln2_b+(long long)lay*DMODEL, 0);
        run_gemm_h(2, BATCH*LSEQ, FFD, DMODEL,
                   p_x2h, DMODEL,
                   p_wf1 + (long long)lay*DMODEL*FFD, FFD,
                   nullptr, FFD, ff_b1 + (long long)lay*FFD, p_ffh);
        run_gemm_h(3, BATCH*LSEQ, DMODEL, FFD,
                   p_ffh, FFD,
                   p_wf2 + (long long)lay*FFD*DMODEL, DMODEL,
                   p_h, DMODEL, ff_b2 + (long long)lay*DMODEL);
    }

    final_kernel<<<BATCH,256>>>(fin_w, fin_b, out);
}

// round 16
// speedup vs baseline: 2.0137x; 1.0229x over previous
#include <cuda_runtime.h>
#include <cuda_bf16.h>
#include <cuda_fp16.h>
#include <math.h>
#include <stdint.h>

// ---------------- model constants ----------------
#define BATCH 16
#define LSEQ  1000
#define DMODEL 512
#define NH    8
#define DHD   64
#define NPAD  1024
#define PADL  24
#define ML    256
#define LMR   4
#define FFD   2048
#define DEPTH 6
#define KC    33
#define QSCALE 0.125f
#define BH (BATCH*NH)
#define ZKV_SCALE 16.f

// ---------------- scratch ----------------
__device__ float g_h   [BATCH*LSEQ*DMODEL];
__device__ float g_a3  [BH*ML*NPAD];
__device__ float g_a2  [BH*ML*ML];
__device__ float g_zb  [BH*ML*ML];
__device__ float g_zb2 [BH*ML*ML];
__device__ float g_pb  [BH*ML*ML];
__device__ float g_tb  [BH*ML*ML];
__device__ float g_tb2 [BH*ML*ML];
__device__ float g_kvb [BH*ML*DHD];
__device__ int   g_red [2];
// fp16 activations / weights
__device__ __half g_qh  [BH*NPAD*DHD];
__device__ __half g_kh  [BH*NPAD*DHD];
__device__ __half g_vh  [BH*NPAD*DHD];
__device__ __half g_qlh [BH*ML*DHD];
__device__ __half g_klh [BH*ML*DHD];
__device__ __half g_a1h [BH*NPAD*ML];
__device__ __half g_a3h [BH*ML*NPAD];
__device__ __half g_zkvh[BH*ML*DHD];
__device__ __half g_xh  [BATCH*NPAD*DMODEL];
__device__ __half g_x2h [BATCH*LSEQ*DMODEL];
__device__ __half g_ffh [BATCH*LSEQ*FFD];
__device__ __half g_yh  [BATCH*NPAD*DMODEL];
__device__ __half g_wqkv[DEPTH*DMODEL*3*DMODEL];
__device__ __half g_wout[DEPTH*DMODEL*DMODEL];
__device__ __half g_wf1 [DEPTH*DMODEL*FFD];
__device__ __half g_wf2 [DEPTH*FFD*DMODEL];
// bf16 shadows for pinv
__device__ __nv_bfloat16 g_a2h [BH*ML*ML];
__device__ __nv_bfloat16 g_zh  [BH*ML*ML];
__device__ __nv_bfloat16 g_zh2 [BH*ML*ML];
__device__ __nv_bfloat16 g_ph  [BH*ML*ML];
__device__ __nv_bfloat16 g_th  [BH*ML*ML];
__device__ __nv_bfloat16 g_t2h [BH*ML*ML];

// ---------------- reductions ----------------
__device__ __forceinline__ float warpSum(float v){
    #pragma unroll
    for (int o=16;o;o>>=1) v += __shfl_xor_sync(0xffffffffu, v, o);
    return v;
}
__device__ __forceinline__ float warpMax(float v){
    #pragma unroll
    for (int o=16;o;o>>=1) v = fmaxf(v, __shfl_xor_sync(0xffffffffu, v, o));
    return v;
}
__device__ __forceinline__ float blockSumN(float v, float* sh, int nw){
    int w = threadIdx.x>>5, l = threadIdx.x&31;
    v = warpSum(v);
    if (l==0) sh[w] = v;
    __syncthreads();
    if (w==0){
        float x = (l < nw) ? sh[l] : 0.f;
        x = warpSum(x);
        if (l==0) sh[0] = x;
    }
    __syncthreads();
    float r = sh[0];
    __syncthreads();
    return r;
}
__device__ __forceinline__ float blockMaxN(float v, float* sh, int nw){
    int w = threadIdx.x>>5, l = threadIdx.x&31;
    v = warpMax(v);
    if (l==0) sh[w] = v;
    __syncthreads();
    if (w==0){
        float x = (l < nw) ? sh[l] : -3.4e38f;
        x = warpMax(x);
        if (l==0) sh[0] = x;
    }
    __syncthreads();
    float r = sh[0];
    __syncthreads();
    return r;
}

// ---------------- mma / cp.async / ldmatrix helpers ----------------
__device__ __forceinline__ void mma_tf32(float c[4],
    unsigned a0, unsigned a1, unsigned a2, unsigned a3,
    unsigned b0, unsigned b1)
{
    asm volatile(
        "mma.sync.aligned.m16n8k8.row.col.f32.tf32.tf32.f32 "
        "{%0,%1,%2,%3}, {%4,%5,%6,%7}, {%8,%9}, {%0,%1,%2,%3};"
        : "+f"(c[0]), "+f"(c[1]), "+f"(c[2]), "+f"(c[3])
        : "r"(a0), "r"(a1), "r"(a2), "r"(a3), "r"(b0), "r"(b1));
}
__device__ __forceinline__ void mma_bf16(float c[4],
    unsigned a0, unsigned a1, unsigned a2, unsigned a3,
    unsigned b0, unsigned b1)
{
    asm volatile(
        "mma.sync.aligned.m16n8k16.row.col.f32.bf16.bf16.f32 "
        "{%0,%1,%2,%3}, {%4,%5,%6,%7}, {%8,%9}, {%0,%1,%2,%3};"
        : "+f"(c[0]), "+f"(c[1]), "+f"(c[2]), "+f"(c[3])
        : "r"(a0), "r"(a1), "r"(a2), "r"(a3), "r"(b0), "r"(b1));
}
__device__ __forceinline__ void mma_f16(float c[4],
    unsigned a0, unsigned a1, unsigned a2, unsigned a3,
    unsigned b0, unsigned b1)
{
    asm volatile(
        "mma.sync.aligned.m16n8k16.row.col.f32.f16.f16.f32 "
        "{%0,%1,%2,%3}, {%4,%5,%6,%7}, {%8,%9}, {%0,%1,%2,%3};"
        : "+f"(c[0]), "+f"(c[1]), "+f"(c[2]), "+f"(c[3])
        : "r"(a0), "r"(a1), "r"(a2), "r"(a3), "r"(b0), "r"(b1));
}
__device__ __forceinline__ void cp16(unsigned saddr, const void* gptr){
    asm volatile("cp.async.cg.shared.global [%0], [%1], 16;\n"
                 :: "r"(saddr), "l"(gptr));
}
__device__ __forceinline__ void cp_commit(){
    asm volatile("cp.async.commit_group;\n");
}
template<int N>
__device__ __forceinline__ void cp_wait(){
    asm volatile("cp.async.wait_group %0;\n" :: "n"(N));
}
__device__ __forceinline__ void ldsm4(unsigned &r0, unsigned &r1,
                                      unsigned &r2, unsigned &r3,
                                      unsigned addr){
    asm volatile("ldmatrix.sync.aligned.m8n8.x4.shared.b16 {%0,%1,%2,%3}, [%4];"
        : "=r"(r0), "=r"(r1), "=r"(r2), "=r"(r3) : "r"(addr));
}
__device__ __forceinline__ void ldsm4t(unsigned &r0, unsigned &r1,
                                       unsigned &r2, unsigned &r3,
                                       unsigned addr){
    asm volatile("ldmatrix.sync.aligned.m8n8.x4.trans.shared.b16 {%0,%1,%2,%3}, [%4];"
        : "=r"(r0), "=r"(r1), "=r"(r2), "=r"(r3) : "r"(addr));
}

// ---------------- common tile constants ----------------
#define AS_STRIDE 20
#define AS_ST     (128*AS_STRIDE)
#define NSTAGE 3
#define ASH 40
#define AH_ST (128*ASH)
#define BSH 264
#define BH_ST (32*BSH)
#define SMEM_BF_BYTES (NSTAGE*(AH_ST + BH_ST)*2)
#define HS_B_ST (256*ASH)
#define SMEM_HS_BYTES (NSTAGE*(AH_ST + HS_B_ST)*2)
#define BS0_STRIDE 264
#define BS_TF_ST  (16*BS0_STRIDE)
#define SMEM_TC_BYTES (NSTAGE*(AS_ST + BS_TF_ST)*4)
#define BS64_STRIDE 72
#define BS64_ST     (16*BS64_STRIDE)
#define SMEM_TC64_BYTES (NSTAGE*(AS_ST + BS64_ST)*4)
#define H64_B_ST (32*72)
#define SMEM_H64_BYTES (NSTAGE*(AH_ST + H64_B_ST)*2)

// == TF32 tensor GEMM (pinv polish): 256 thr, CTA 128x256, TB0, LDSM ======
template<int EPI>
__global__ void __launch_bounds__(256,1) gemm_tc_kernel(
    int Ki,
    const float* __restrict__ A, int lda, long long sA,
    const float* __restrict__ Bm, int ldb, long long sB,
    float* __restrict__ C, int ldc, long long sC,
    float alpha, float* __restrict__ C2)
{
    extern __shared__ unsigned sm[];
    unsigned* As = sm;
    unsigned* Bs = sm + NSTAGE*AS_ST;
    const unsigned As_base = (unsigned)__cvta_generic_to_shared(As);
    const unsigned Bs_base = (unsigned)__cvta_generic_to_shared(Bs);

    const int bz = blockIdx.z;
    A  += (long long)bz*sA;
    Bm += (long long)bz*sB;
    C  += (long long)bz*sC;
    if (EPI==6) C2 += (long long)bz*sC;

    const int row0 = blockIdx.y*128;
    const int col0 = blockIdx.x*256;
    const int tid = threadIdx.x;
    const int warp = tid>>5, lane = tid&31;
    const int wm = warp & 1, wn = warp >> 1;
    const int g = lane>>2, qc = lane&3;

    const int a_r  = tid>>1;
    const int a_c2 = (tid&1)<<1;

    auto issue = [&](int kt, int st){
        unsigned abase = As_base + (unsigned)(st*AS_ST)*4u;
        #pragma unroll
        for (int i=0;i<2;i++)
            cp16(abase + (unsigned)(a_r*AS_STRIDE + (a_c2+i)*4)*4u,
                 A + (long long)(row0 + a_r)*lda + kt + (a_c2+i)*4);
        unsigned bbase = Bs_base + (unsigned)(st*BS_TF_ST)*4u;
        #pragma unroll
        for (int i=0;i<4;i++){
            int fidx = tid + i*256;
            int bk = fidx>>6, bn4 = (fidx&63)<<2;
            cp16(bbase + (unsigned)(bk*BS0_STRIDE + bn4)*4u,
                 Bm + (long long)(kt + bk)*ldb + col0 + bn4);
        }
    };

    float acc[4][8][4];
    #pragma unroll
    for (int mt=0;mt<4;mt++)
        #pragma unroll
        for (int nt=0;nt<8;nt++)
            #pragma unroll
            for (int i=0;i<4;i++) acc[mt][nt][i]=0.f;

    const int nk = Ki >> 4;
    issue(0, 0);  cp_commit();
    issue(16, 1); cp_commit();

    const int lane8 = lane & 7;
    const int a_lrow = wm*64 + lane8 + ((lane>>3)&1)*8;
    const int a_lw   = ((lane>>4)&1)*4;
    const int b0_frag_off = qc*BS0_STRIDE + wn*64 + g;

    for (int t = 0; t < nk; ++t){
        cp_wait<1>();
        __syncthreads();
        const int rb = t % NSTAGE;
        if (t+2 < nk) issue((t+2)<<4, (t+2)%NSTAGE);
        cp_commit();

        const unsigned a_stage = As_base + (unsigned)(rb*AS_ST)*4u;

        #pragma unroll
        for (int grp=0; grp<2; grp++){
            const int koff = grp*8;
            unsigned af[4][4], bf[8][2];
            #pragma unroll
            for (int mt=0;mt<4;mt++)
                ldsm4(af[mt][0], af[mt][1], af[mt][2], af[mt][3],
                      a_stage + (unsigned)(((a_lrow + mt*16)*AS_STRIDE) + a_lw + koff)*4u);
            const unsigned* Bb = Bs + rb*BS_TF_ST + b0_frag_off + koff*BS0_STRIDE;
            #pragma unroll
            for (int nt=0;nt<8;nt++){
                bf[nt][0] = Bb[nt*8];
                bf[nt][1] = Bb[4*BS0_STRIDE + nt*8];
            }
            #pragma unroll
            for (int mt=0;mt<4;mt++)
                #pragma unroll
                for (int nt=0;nt<8;nt++)
                    mma_tf32(acc[mt][nt], af[mt][0],af[mt][1],af[mt][2],af[mt][3],
                             bf[nt][0],bf[nt][1]);
        }
    }

    #pragma unroll
    for (int mt=0;mt<4;mt++){
        #pragma unroll
        for (int half=0; half<2; half++){
            int r = row0 + wm*64 + mt*16 + g + half*8;
            #pragma unroll
            for (int nt=0;nt<8;nt++){
                int cc = col0 + wn*64 + nt*8 + 2*qc;
                float v0 = acc[mt][nt][2*half+0];
                float v1 = acc[mt][nt][2*half+1];
                if (EPI==0){
                    float2 o = {alpha*v0, alpha*v1};
                    *(float2*)&C[(long long)r*ldc + cc] = o;
                } else if (EPI==5){
                    float2 o = {(r==cc ? alpha : 0.f) - v0, (r==cc+1 ? alpha : 0.f) - v1};
                    *(float2*)&C[(long long)r*ldc + cc] = o;
                } else if (EPI==6){
                    float2 o = {v0, v1};
                    *(float2*)&C[(long long)r*ldc + cc] = o;
                    float2 o2 = {(r==cc ? alpha : 0.f) - v0, (r==cc+1 ? alpha : 0.f) - v1};
                    *(float2*)&C2[(long long)r*ldc + cc] = o2;
                }
            }
        }
    }
}

// ==== BF16 batched GEMM for pinv ==========================================
template<int EPI>
__global__ void __launch_bounds__(256,1) gemm_bf16_kernel(
    const __nv_bfloat16* __restrict__ A,
    const __nv_bfloat16* __restrict__ Bm,
    __nv_bfloat16* __restrict__ Cb,
    __nv_bfloat16* __restrict__ C2b,
    float* __restrict__ Cf,
    float alpha)
{
    extern __shared__ __nv_bfloat16 smh[];
    const unsigned As_base = (unsigned)__cvta_generic_to_shared(smh);
    const unsigned Bs_base = As_base + NSTAGE*AH_ST*2u;

    const long long boff = (long long)blockIdx.z * (ML*ML);
    A  += boff; Bm += boff;

    const int row0 = blockIdx.y*128;
    const int tid = threadIdx.x;
    const int warp = tid>>5, lane = tid&31;
    const int wm = warp & 1, wn = warp >> 1;
    const int g = lane>>2, qc = lane&3;

    auto issue = [&](int kt, int st){
        unsigned abase = As_base + (unsigned)(st*AH_ST)*2u;
        #pragma unroll
        for (int i=0;i<2;i++){
            int r = tid>>1, ch = ((tid&1)<<1) + i;
            cp16(abase + (unsigned)(r*ASH + ch*8)*2u,
                 A + (long long)(row0 + r)*ML + kt + ch*8);
        }
        unsigned bbase = Bs_base + (unsigned)(st*BH_ST)*2u;
        #pragma unroll
        for (int i=0;i<4;i++){
            int fidx = tid + i*256;
            int r = fidx>>5, ch = fidx&31;
            cp16(bbase + (unsigned)(r*BSH + ch*8)*2u,
                 Bm + (long long)(kt + r)*ML + ch*8);
        }
    };

    float acc[4][8][4];
    #pragma unroll
    for (int mt=0;mt<4;mt++)
        #pragma unroll
        for (int nt=0;nt<8;nt++)
            #pragma unroll
            for (int i=0;i<4;i++) acc[mt][nt][i]=0.f;

    const int nk = ML >> 5;
    issue(0, 0);  cp_commit();
    issue(32, 1); cp_commit();

    const int lane8 = lane & 7;
    const int a_row = wm*64 + lane8 + ((lane>>3)&1)*8;
    const int a_col = ((lane>>4)&1)*8;
    const int b_row = lane8 + ((lane>>3)&1)*8;
    const int b_col = ((lane>>4)&1)*8;

    for (int t = 0; t < nk; ++t){
        cp_wait<1>();
        __syncthreads();
        const int rb = t % NSTAGE;
        if (t+2 < nk) issue((t+2)<<5, (t+2)%NSTAGE);
        cp_commit();

        const unsigned a_st = As_base + (unsigned)(rb*AH_ST)*2u;
        const unsigned b_st = Bs_base + (unsigned)(rb*BH_ST)*2u;

        #pragma unroll
        for (int kk=0; kk<2; kk++){
            const int k0 = kk*16;
            unsigned af[4][4], bf[8][2];
            #pragma unroll
            for (int mt=0;mt<4;mt++)
                ldsm4(af[mt][0], af[mt][1], af[mt][2], af[mt][3],
                      a_st + (unsigned)((a_row + mt*16)*ASH + k0 + a_col)*2u);
            #pragma unroll
            for (int np=0;np<4;np++)
                ldsm4t(bf[2*np][0], bf[2*np][1], bf[2*np+1][0], bf[2*np+1][1],
                       b_st + (unsigned)((k0 + b_row)*BSH + wn*64 + np*16 + b_col)*2u);
            #pragma unroll
            for (int mt=0;mt<4;mt++)
                #pragma unroll
                for (int nt=0;nt<8;nt++)
                    mma_bf16(acc[mt][nt], af[mt][0],af[mt][1],af[mt][2],af[mt][3],
                             bf[nt][0],bf[nt][1]);
        }
    }

    #pragma unroll
    for (int mt=0;mt<4;mt++){
        #pragma unroll
        for (int half=0; half<2; half++){
            int r = row0 + wm*64 + mt*16 + g + half*8;
            #pragma unroll
            for (int nt=0;nt<8;nt++){
                int cc = wn*64 + nt*8 + 2*qc;
                float v0 = acc[mt][nt][2*half+0];
                float v1 = acc[mt][nt][2*half+1];
                long long idx = boff + (long long)r*ML + cc;
                if (EPI==0){
                    __nv_bfloat162 pk;
                    pk.x = __float2bfloat16(alpha*v0);
                    pk.y = __float2bfloat16(alpha*v1);
                    *(__nv_bfloat162*)&Cb[idx] = pk;
                } else if (EPI==1){
                    float2 o = {alpha*v0, alpha*v1};
                    *(float2*)&Cf[idx] = o;
                } else if (EPI==5){
                    __nv_bfloat162 pk;
                    pk.x = __float2bfloat16((r==cc   ? alpha : 0.f) - v0);
                    pk.y = __float2bfloat16((r==cc+1 ? alpha : 0.f) - v1);
                    *(__nv_bfloat162*)&Cb[idx] = pk;
                } else if (EPI==6){
                    __nv_bfloat162 pk;
                    pk.x = __float2bfloat16(v0);
                    pk.y = __float2bfloat16(v1);
                    *(__nv_bfloat162*)&Cb[idx] = pk;
                    __nv_bfloat162 pk2;
                    pk2.x = __float2bfloat16((r==cc   ? alpha : 0.f) - v0);
                    pk2.y = __float2bfloat16((r==cc+1 ? alpha : 0.f) - v1);
                    *(__nv_bfloat162*)&C2b[idx] = pk2;
                }
            }
        }
    }
}

// ==== FP16 general GEMM (big mats): CTA 128x256, K-tile 32, TB0 ===========
// EPI 7: qkv split -> fp16 q(Ch,*QSCALE), k(Ch2), v(Ch3).
// EPI 4: pad-residual into C. EPI 2: gelu->Ch. EPI 3: C += val+bias.
template<int EPI>
__global__ void __launch_bounds__(256,1) gemm_h_kernel(
    int Ki,
    const __half* __restrict__ A, int lda,
    const __half* __restrict__ Bm, int ldb,
    float* __restrict__ C, int ldc,
    float alpha, const float* __restrict__ bias,
    __half* __restrict__ Ch, __half* __restrict__ Ch2, __half* __restrict__ Ch3)
{
    extern __shared__ __half smhh[];
    const unsigned As_base = (unsigned)__cvta_generic_to_shared(smhh);
    const unsigned Bs_base = As_base + NSTAGE*AH_ST*2u;

    const int row0 = blockIdx.y*128;
    const int col0 = blockIdx.x*256;
    const int tid = threadIdx.x;
    const int warp = tid>>5, lane = tid&31;
    const int wm = warp & 1, wn = warp >> 1;
    const int g = lane>>2, qc = lane&3;

    auto issue = [&](int kt, int st){
        unsigned abase = As_base + (unsigned)(st*AH_ST)*2u;
        #pragma unroll
        for (int i=0;i<2;i++){
            int r = tid>>1, ch = ((tid&1)<<1) + i;
            cp16(abase + (unsigned)(r*ASH + ch*8)*2u,
                 A + (long long)(row0 + r)*lda + kt + ch*8);
        }
        unsigned bbase = Bs_base + (unsigned)(st*BH_ST)*2u;
        #pragma unroll
        for (int i=0;i<4;i++){
            int fidx = tid + i*256;
            int r = fidx>>5, ch = fidx&31;
            cp16(bbase + (unsigned)(r*BSH + ch*8)*2u,
                 Bm + (long long)(kt + r)*ldb + col0 + ch*8);
        }
    };

    float acc[4][8][4];
    #pragma unroll
    for (int mt=0;mt<4;mt++)
        #pragma unroll
        for (int nt=0;nt<8;nt++)
            #pragma unroll
            for (int i=0;i<4;i++) acc[mt][nt][i]=0.f;

    const int nk = Ki >> 5;
    issue(0, 0);  cp_commit();
    issue(32, 1); cp_commit();

    const int lane8 = lane & 7;
    const int a_row = wm*64 + lane8 + ((lane>>3)&1)*8;
    const int a_col = ((lane>>4)&1)*8;
    const int b_row = lane8 + ((lane>>3)&1)*8;
    const int b_col = ((lane>>4)&1)*8;

    for (int t = 0; t < nk; ++t){
        cp_wait<1>();
        __syncthreads();
        const int rb = t % NSTAGE;
        if (t+2 < nk) issue((t+2)<<5, (t+2)%NSTAGE);
        cp_commit();

        const unsigned a_st = As_base + (unsigned)(rb*AH_ST)*2u;
        const unsigned b_st = Bs_base + (unsigned)(rb*BH_ST)*2u;

        #pragma unroll
        for (int kk=0; kk<2; kk++){
            const int k0 = kk*16;
            unsigned af[4][4], bf[8][2];
            #pragma unroll
            for (int mt=0;mt<4;mt++)
                ldsm4(af[mt][0], af[mt][1], af[mt][2], af[mt][3],
                      a_st + (unsigned)((a_row + mt*16)*ASH + k0 + a_col)*2u);
            #pragma unroll
            for (int np=0;np<4;np++)
                ldsm4t(bf[2*np][0], bf[2*np][1], bf[2*np+1][0], bf[2*np+1][1],
                       b_st + (unsigned)((k0 + b_row)*BSH + wn*64 + np*16 + b_col)*2u);
            #pragma unroll
            for (int mt=0;mt<4;mt++)
                #pragma unroll
                for (int nt=0;nt<8;nt++)
                    mma_f16(acc[mt][nt], af[mt][0],af[mt][1],af[mt][2],af[mt][3],
                            bf[nt][0],bf[nt][1]);
        }
    }

    #pragma unroll
    for (int mt=0;mt<4;mt++){
        #pragma unroll
        for (int half=0; half<2; half++){
            int r = row0 + wm*64 + mt*16 + g + half*8;
            #pragma unroll
            for (int nt=0;nt<8;nt++){
                int cc = col0 + wn*64 + nt*8 + 2*qc;
                float v0 = acc[mt][nt][2*half+0];
                float v1 = acc[mt][nt][2*half+1];
                if (EPI==7){
                    int b = r >> 10, n = r & 1023;
                    int which = cc >> 9;
                    int hd = cc & 511;
                    long long idx = ((((long long)b*NH + (hd>>6))*NPAD) + n)*DHD + (hd&63);
                    if (which==0){
                        *(__half2*)&Ch[idx] = __floats2half2_rn(v0*QSCALE, v1*QSCALE);
                    } else if (which==1){
                        *(__half2*)&Ch2[idx] = __floats2half2_rn(v0, v1);
                    } else {
                        *(__half2*)&Ch3[idx] = __floats2half2_rn(v0, v1);
                    }
                } else if (EPI==4){
                    int bb = r / NPAD, nl = r % NPAD;
                    if (nl >= PADL){
                        long long orow = (long long)bb*LSEQ + (nl - PADL);
                        float2 o = *(float2*)&C[orow*ldc + cc];
                        o.x += v0 + bias[cc];
                        o.y += v1 + bias[cc+1];
                        *(float2*)&C[orow*ldc + cc] = o;
                    }
                } else if (EPI==2){
                    float x0 = v0 + bias[cc], x1 = v1 + bias[cc+1];
                    float g0 = 0.5f*x0*(1.f+erff(x0*0.70710678118654752f));
                    float g1 = 0.5f*x1*(1.f+erff(x1*0.70710678118654752f));
                    *(__half2*)&Ch[(long long)r*ldc + cc] = __floats2half2_rn(g0, g1);
                } else if (EPI==3){
                    float2 o = *(float2*)&C[(long long)r*ldc + cc];
                    o.x += v0 + bias[cc];
                    o.y += v1 + bias[cc+1];
                    *(float2*)&C[(long long)r*ldc + cc] = o;
                }
            }
        }
    }
}

// ==== FP16 TB1 score GEMM: CTA 128x256, B is NxK rm, K<=64, batched =======
template<int EPI>
__global__ void __launch_bounds__(256,1) gemm_hs_kernel(
    int Ki,
    const __half* __restrict__ A, int lda, long long sA,
    const __half* __restrict__ Bm, int ldb, long long sB,
    float* __restrict__ C, int ldc, long long sC,
    __half* __restrict__ Chh)
{
    extern __shared__ __half smhh[];
    const unsigned As_base = (unsigned)__cvta_generic_to_shared(smhh);
    const unsigned Bs_base = As_base + NSTAGE*AH_ST*2u;

    const int bz = blockIdx.z;
    A  += (long long)bz*sA;
    Bm += (long long)bz*sB;
    if (EPI==0 || EPI==9) C += (long long)bz*sC;
    else Chh += (long long)bz*sC;

    const int row0 = blockIdx.y*128;
    const int col0 = blockIdx.x*256;
    const int tid = threadIdx.x;
    const int warp = tid>>5, lane = tid&31;
    const int wm = warp & 1, wn = warp >> 1;
    const int g = lane>>2, qc = lane&3;

    auto issue = [&](int kt, int st){
        unsigned abase = As_base + (unsigned)(st*AH_ST)*2u;
        #pragma unroll
        for (int i=0;i<2;i++){
            int r = tid>>1, ch = ((tid&1)<<1) + i;
            cp16(abase + (unsigned)(r*ASH + ch*8)*2u,
                 A + (long long)(row0 + r)*lda + kt + ch*8);
        }
        unsigned bbase = Bs_base + (unsigned)(st*HS_B_ST)*2u;
        #pragma unroll
        for (int i=0;i<4;i++){
            int fidx = tid + i*256;
            int r = fidx>>2, ch = fidx&3;
            cp16(bbase + (unsigned)(r*ASH + ch*8)*2u,
                 Bm + (long long)(col0 + r)*ldb + kt + ch*8);
        }
    };

    float acc[4][8][4];
    #pragma unroll
    for (int mt=0;mt<4;mt++)
        #pragma unroll
        for (int nt=0;nt<8;nt++)
            #pragma unroll
            for (int i=0;i<4;i++) acc[mt][nt][i]=0.f;

    const int nk = Ki >> 5;
    issue(0, 0);  cp_commit();
    if (nk > 1){ issue(32, 1); cp_commit(); }
    else cp_commit();

    const int lane8 = lane & 7;
    const int a_row = wm*64 + lane8 + ((lane>>3)&1)*8;
    const int a_col = ((lane>>4)&1)*8;
    const int b_rowm = lane8 + ((lane>>4)&1)*8;
    const int b_colm = ((lane>>3)&1)*8;

    for (int t = 0; t < nk; ++t){
        cp_wait<1>();
        __syncthreads();
        const int rb = t % NSTAGE;
        if (t+2 < nk) issue((t+2)<<5, (t+2)%NSTAGE);
        cp_commit();

        const unsigned a_st = As_base + (unsigned)(rb*AH_ST)*2u;
        const unsigned b_st = Bs_base + (unsigned)(rb*HS_B_ST)*2u;

        #pragma unroll
        for (int kk=0; kk<2; kk++){
            const int k0 = kk*16;
            unsigned af[4][4], bf[8][2];
            #pragma unroll
            for (int mt=0;mt<4;mt++)
                ldsm4(af[mt][0], af[mt][1], af[mt][2], af[mt][3],
                      a_st + (unsigned)((a_row + mt*16)*ASH + k0 + a_col)*2u);
            #pragma unroll
            for (int np=0;np<4;np++)
                ldsm4(bf[2*np][0], bf[2*np][1], bf[2*np+1][0], bf[2*np+1][1],
                      b_st + (unsigned)((wn*64 + np*16 + b_rowm)*ASH + k0 + b_colm)*2u);
            #pragma unroll
            for (int mt=0;mt<4;mt++)
                #pragma unroll
                for (int nt=0;nt<8;nt++)
                    mma_f16(acc[mt][nt], af[mt][0],af[mt][1],af[mt][2],af[mt][3],
                            bf[nt][0],bf[nt][1]);
        }
    }

    if (EPI==8 || EPI==9){
        __syncthreads();
        float* redmax = (float*)smhh;
        float* redsum = (float*)smhh + 512;
        float rm[4][2];
        #pragma unroll
        for (int mt=0;mt<4;mt++){
            #pragma unroll
            for (int half=0; half<2; half++){
                float m = -3.4e38f;
                #pragma unroll
                for (int nt=0;nt<8;nt++){
                    m = fmaxf(m, acc[mt][nt][2*half]);
                    m = fmaxf(m, acc[mt][nt][2*half+1]);
                }
                m = fmaxf(m, __shfl_xor_sync(0xffffffffu, m, 1));
                m = fmaxf(m, __shfl_xor_sync(0xffffffffu, m, 2));
                rm[mt][half] = m;
            }
        }
        if (qc==0){
            #pragma unroll
            for (int mt=0;mt<4;mt++)
                #pragma unroll
                for (int half=0; half<2; half++){
                    int rl = wm*64 + mt*16 + g + half*8;
                    redmax[rl*4 + wn] = rm[mt][half];
                }
        }
        __syncthreads();
        float inv[4][2];
        #pragma unroll
        for (int mt=0;mt<4;mt++){
            #pragma unroll
            for (int half=0; half<2; half++){
                int rl = wm*64 + mt*16 + g + half*8;
                float m = fmaxf(fmaxf(redmax[rl*4+0], redmax[rl*4+1]),
                                fmaxf(redmax[rl*4+2], redmax[rl*4+3]));
                float s = 0.f;
                #pragma unroll
                for (int nt=0;nt<8;nt++){
                    float e0 = expf(acc[mt][nt][2*half]   - m);
                    float e1 = expf(acc[mt][nt][2*half+1] - m);
                    acc[mt][nt][2*half]   = e0;
                    acc[mt][nt][2*half+1] = e1;
                    s += e0 + e1;
                }
                s += __shfl_xor_sync(0xffffffffu, s, 1);
                s += __shfl_xor_sync(0xffffffffu, s, 2);
                if (qc==0) redsum[rl*4 + wn] = s;
                inv[mt][half] = 0.f;
            }
        }
        __syncthreads();
        #pragma unroll
        for (int mt=0;mt<4;mt++)
            #pragma unroll
            for (int half=0; half<2; half++){
                int rl = wm*64 + mt*16 + g + half*8;
                float s = redsum[rl*4+0] + redsum[rl*4+1] + redsum[rl*4+2] + redsum[rl*4+3];
                inv[mt][half] = 1.f / s;
            }
        #pragma unroll
        for (int mt=0;mt<4;mt++){
            #pragma unroll
            for (int half=0; half<2; half++){
                int r = row0 + wm*64 + mt*16 + g + half*8;
                #pragma unroll
                for (int nt=0;nt<8;nt++){
                    int cc = wn*64 + nt*8 + 2*qc;
                    float o0 = acc[mt][nt][2*half]*inv[mt][half];
                    float o1 = acc[mt][nt][2*half+1]*inv[mt][half];
                    if (EPI==8)
                        *(__half2*)&Chh[(long long)r*ldc + cc] = __floats2half2_rn(o0, o1);
                    else {
                        float2 o = {o0, o1};
                        *(float2*)&C[(long long)r*ldc + cc] = o;
                    }
                }
            }
        }
        return;
    }

    #pragma unroll
    for (int mt=0;mt<4;mt++){
        #pragma unroll
        for (int half=0; half<2; half++){
            int r = row0 + wm*64 + mt*16 + g + half*8;
            #pragma unroll
            for (int nt=0;nt<8;nt++){
                int cc = col0 + wn*64 + nt*8 + 2*qc;
                float2 o = {acc[mt][nt][2*half], acc[mt][nt][2*half+1]};
                *(float2*)&C[(long long)r*ldc + cc] = o;
            }
        }
    }
}

// ==== FP16 N=64 GEMM: CTA 128x64, 128 thr, K-tile 32 ======================
// EPI 0: C = val (fp32, for kv).   EPI 1: ao + fused conv(vh) -> fp16 Y.
template<int EPI>
__global__ void __launch_bounds__(128) gemm_h64_kernel(
    int Ki,
    const __half* __restrict__ A, int lda, long long sA,
    const __half* __restrict__ Bm, long long sB,
    float* __restrict__ C, long long sC,
    const __half* __restrict__ Vg, const float* __restrict__ cw,
    __half* __restrict__ Y)
{
    extern __shared__ __half smhh[];
    const unsigned As_base = (unsigned)__cvta_generic_to_shared(smhh);
    const unsigned Bs_base = As_base + NSTAGE*AH_ST*2u;
    __shared__ float ws[KC];

    const int bz = blockIdx.z;
    A  += (long long)bz*sA;
    Bm += (long long)bz*sB;
    if (EPI==0) C += (long long)bz*sC;

    const int row0 = blockIdx.y*128;
    const int tid = threadIdx.x;
    const int warp = tid>>5, lane = tid&31;
    const int wm = warp & 1, wn = warp >> 1;
    const int g = lane>>2, qc = lane&3;

    if (EPI==1 && tid < KC) ws[tid] = cw[(bz % NH)*KC + tid];

    auto issue = [&](int kt, int st){
        unsigned abase = As_base + (unsigned)(st*AH_ST)*2u;
        #pragma unroll
        for (int i=0;i<4;i++){
            int fidx = tid + i*128;
            int r = fidx>>2, ch = fidx&3;
            cp16(abase + (unsigned)(r*ASH + ch*8)*2u,
                 A + (long long)(row0 + r)*lda + kt + ch*8);
        }
        unsigned bbase = Bs_base + (unsigned)(st*H64_B_ST)*2u;
        #pragma unroll
        for (int i=0;i<2;i++){
            int fidx = tid + i*128;
            int r = fidx>>3, ch = fidx&7;
            cp16(bbase + (unsigned)(r*72 + ch*8)*2u,
                 Bm + (long long)(kt + r)*DHD + ch*8);
        }
    };

    float acc[4][4][4];
    #pragma unroll
    for (int mt=0;mt<4;mt++)
        #pragma unroll
        for (int nt=0;nt<4;nt++)
            #pragma unroll
            for (int i=0;i<4;i++) acc[mt][nt][i]=0.f;

    const int nk = Ki >> 5;
    issue(0, 0);  cp_commit();
    issue(32, 1); cp_commit();

    const int lane8 = lane & 7;
    const int a_row = wm*64 + lane8 + ((lane>>3)&1)*8;
    const int a_col = ((lane>>4)&1)*8;
    const int b_row = lane8 + ((lane>>3)&1)*8;
    const int b_col = ((lane>>4)&1)*8;

    for (int t = 0; t < nk; ++t){
        cp_wait<1>();
        __syncthreads();
        const int rb = t % NSTAGE;
        if (t+2 < nk) issue((t+2)<<5, (t+2)%NSTAGE);
        cp_commit();

        const unsigned a_st = As_base + (unsigned)(rb*AH_ST)*2u;
        const unsigned b_st = Bs_base + (unsigned)(rb*H64_B_ST)*2u;

        #pragma unroll
        for (int kk=0; kk<2; kk++){
            const int k0 = kk*16;
            unsigned af[4][4], bf[4][2];
            #pragma unroll
            for (int mt=0;mt<4;mt++)
                ldsm4(af[mt][0], af[mt][1], af[mt][2], af[mt][3],
                      a_st + (unsigned)((a_row + mt*16)*ASH + k0 + a_col)*2u);
            #pragma unroll
            for (int np=0;np<2;np++)
                ldsm4t(bf[2*np][0], bf[2*np][1], bf[2*np+1][0], bf[2*np+1][1],
                       b_st + (unsigned)((k0 + b_row)*72 + wn*32 + np*16 + b_col)*2u);
            #pragma unroll
            for (int mt=0;mt<4;mt++)
                #pragma unroll
                for (int nt=0;nt<4;nt++)
                    mma_f16(acc[mt][nt], af[mt][0],af[mt][1],af[mt][2],af[mt][3],
                            bf[nt][0],bf[nt][1]);
        }
    }

    if (EPI==0){
        #pragma unroll
        for (int mt=0;mt<4;mt++){
            #pragma unroll
            for (int half=0; half<2; half++){
                int r = row0 + wm*64 + mt*16 + g + half*8;
                #pragma unroll
                for (int nt=0;nt<4;nt++){
                    int cc = wn*32 + nt*8 + 2*qc;
                    float2 o = {acc[mt][nt][2*half], acc[mt][nt][2*half+1]};
                    *(float2*)&C[(long long)r*DHD + cc] = o;
                }
            }
        }
        return;
    }

    const int h = bz % NH, b = bz / NH;
    const __half* vp = Vg + (long long)bz*NPAD*DHD;
    #pragma unroll
    for (int mt=0;mt<4;mt++){
        #pragma unroll
        for (int half=0; half<2; half++){
            int n = row0 + wm*64 + mt*16 + g + half*8;
            int k0 = (16-n > 0) ? (16-n) : 0;
            int k1 = (NPAD+16-n < KC) ? (NPAD+16-n) : KC;
            #pragma unroll
            for (int nt=0;nt<4;nt++){
                int cc = wn*32 + nt*8 + 2*qc;
                float s0 = acc[mt][nt][2*half+0] * ZKV_SCALE;
                float s1 = acc[mt][nt][2*half+1] * ZKV_SCALE;
                for (int kk=k0; kk<k1; kk++){
                    __half2 vv = *(const __half2*)&vp[(long long)(n+kk-16)*DHD + cc];
                    s0 = fmaf(__half2float(vv.x), ws[kk], s0);
                    s1 = fmaf(__half2float(vv.y), ws[kk], s1);
                }
                *(__half2*)&Y[((long long)b*NPAD + n)*DMODEL + h*DHD + cc] = __floats2half2_rn(s0, s1);
            }
        }
    }
}

// ==== TF32 tensor GEMM N=64 (zkv): 128 thr, CTA 128x64 ====================
// EPI 2: Ch = half(val / ZKV_SCALE).
__global__ void __launch_bounds__(128) gemm_tc64_kernel(
    int Ki,
    const float* __restrict__ A, int lda, long long sA,
    const float* __restrict__ Bm, int ldb, long long sB,
    long long sC, __half* __restrict__ Ch)
{
    extern __shared__ unsigned sm[];
    unsigned* As = sm;
    unsigned* Bs = sm + NSTAGE*AS_ST;
    const unsigned As_base = (unsigned)__cvta_generic_to_shared(As);
    const unsigned Bs_base = (unsigned)__cvta_generic_to_shared(Bs);

    const int bz = blockIdx.z;
    A  += (long long)bz*sA;
    Bm += (long long)bz*sB;
    Ch += (long long)bz*sC;

    const int row0 = blockIdx.y*128;
    const int tid = threadIdx.x;
    const int warp = tid>>5, lane = tid&31;
    const int wm = warp & 1, wn = warp >> 1;
    const int g = lane>>2, qc = lane&3;

    auto issue = [&](int kt, int st){
        unsigned abase = As_base + (unsigned)(st*AS_ST)*4u;
        #pragma unroll
        for (int i=0;i<4;i++){
            int fidx = tid + i*128;
            int a_r = fidx>>2, a_c4 = (fidx&3)<<2;
            cp16(abase + (unsigned)(a_r*AS_STRIDE + a_c4)*4u,
                 A + (long long)(row0 + a_r)*lda + kt + a_c4);
        }
        unsigned bbase = Bs_base + (unsigned)(st*BS64_ST)*4u;
        #pragma unroll
        for (int i=0;i<2;i++){
            int fidx = tid + i*128;
            int bk = fidx>>4, bn4 = (fidx&15)<<2;
            cp16(bbase + (unsigned)(bk*BS64_STRIDE + bn4)*4u,
                 Bm + (long long)(kt + bk)*ldb + bn4);
        }
    };

    float acc[4][4][4];
    #pragma unroll
    for (int mt=0;mt<4;mt++)
        #pragma unroll
        for (int nt=0;nt<4;nt++)
            #pragma unroll
            for (int i=0;i<4;i++) acc[mt][nt][i]=0.f;

    const int nk = Ki >> 4;
    issue(0, 0);  cp_commit();
    issue(16, 1); cp_commit();

    const int lane8 = lane & 7;
    const int a_lrow = wm*64 + lane8 + ((lane>>3)&1)*8;
    const int a_lw   = ((lane>>4)&1)*4;
    const int b_frag_off = qc*BS64_STRIDE + wn*32 + g;

    for (int t = 0; t < nk; ++t){
        cp_wait<1>();
        __syncthreads();
        const int rb = t % NSTAGE;
        if (t+2 < nk) issue((t+2)<<4, (t+2)%NSTAGE);
        cp_commit();

        const unsigned a_stage = As_base + (unsigned)(rb*AS_ST)*4u;

        #pragma unroll
        for (int grp=0; grp<2; grp++){
            const int koff = grp*8;
            unsigned af[4][4], bf[4][2];
            #pragma unroll
            for (int mt=0;mt<4;mt++)
                ldsm4(af[mt][0], af[mt][1], af[mt][2], af[mt][3],
                      a_stage + (unsigned)(((a_lrow + mt*16)*AS_STRIDE) + a_lw + koff)*4u);
            const unsigned* Bb = Bs + rb*BS64_ST + b_frag_off + koff*BS64_STRIDE;
            #pragma unroll
            for (int nt=0;nt<4;nt++){
                bf[nt][0] = Bb[nt*8];
                bf[nt][1] = Bb[4*BS64_STRIDE + nt*8];
            }
            #pragma unroll
            for (int mt=0;mt<4;mt++)
                #pragma unroll
                for (int nt=0;nt<4;nt++)
                    mma_tf32(acc[mt][nt], af[mt][0],af[mt][1],af[mt][2],af[mt][3],
                             bf[nt][0],bf[nt][1]);
        }
    }

    #pragma unroll
    for (int mt=0;mt<4;mt++){
        #pragma unroll
        for (int half=0; half<2; half++){
            int r = row0 + wm*64 + mt*16 + g + half*8;
            #pragma unroll
            for (int nt=0;nt<4;nt++){
                int cc = wn*32 + nt*8 + 2*qc;
                *(__half2*)&Ch[(long long)r*DHD + cc] =
                    __floats2half2_rn(acc[mt][nt][2*half]*(1.f/ZKV_SCALE),
                                      acc[mt][nt][2*half+1]*(1.f/ZKV_SCALE));
            }
        }
    }
}

// ---------------- elementwise / small kernels ----------------
__global__ void embed_kernel(const int* __restrict__ x,
                             const float* __restrict__ emb,
                             const float* __restrict__ pos){
    long long idx = (long long)blockIdx.x*blockDim.x + threadIdx.x;
    if (idx >= (long long)BATCH*LSEQ*DMODEL) return;
    int d = (int)(idx % DMODEL);
    long long bl = idx / DMODEL;
    int l = (int)(bl % LSEQ);
    int tok = x[bl];
    g_h[idx] = emb[(long long)tok*DMODEL + d] + pos[(long long)l*DMODEL + d];
}

__global__ void zero_pad_kernel(){
    int idx = blockIdx.x*blockDim.x + threadIdx.x;
    if (idx >= BATCH*PADL*DMODEL) return;
    int d  = idx % DMODEL;
    int bp = idx / DMODEL;
    int b  = bp / PADL, p = bp % PADL;
    g_xh[((long long)b*NPAD + p)*DMODEL + d] = __float2half(0.f);
}

__global__ void cvtw_kernel(const float* __restrict__ src, __half* __restrict__ dst, long long n){
    long long idx = (long long)blockIdx.x*blockDim.x + threadIdx.x;
    if (idx < n) dst[idx] = __float2half(src[idx]);
}

__global__ void ln_kernel(const float* __restrict__ in, __half* __restrict__ out,
                          const float* __restrict__ gm, const float* __restrict__ bt,
                          int padmode){
    __shared__ float sh[8];
    int r = blockIdx.x;
    int t = threadIdx.x;
    const float* p = in + (long long)r*DMODEL;
    float a  = p[t];
    float b2 = p[t+256];
    float s  = blockSumN(a+b2, sh, 8);
    float mu = s * (1.f/512.f);
    float da = a - mu, db = b2 - mu;
    float v  = blockSumN(da*da + db*db, sh, 8) * (1.f/512.f);
    float rstd = rsqrtf(v + 1e-5f);
    long long orow = padmode ? ((long long)(r/LSEQ)*NPAD + PADL + (r%LSEQ)) : (long long)r;
    __half* q = out + orow*DMODEL;
    q[t]     = __float2half(da*rstd*gm[t]     + bt[t]);
    q[t+256] = __float2half(db*rstd*gm[t+256] + bt[t+256]);
}

__global__ void landmark_kernel(){
    long long idx = (long long)blockIdx.x*blockDim.x + threadIdx.x;
    if (idx >= (long long)BH*ML*DHD) return;
    int d = (int)(idx & 63);
    long long r = idx >> 6;
    int m  = (int)(r % ML);
    int bh = (int)(r / ML);
    long long base = ((long long)bh*NPAD + (long long)m*LMR)*DHD + d;
    float sq = 0.f, sk = 0.f;
    #pragma unroll
    for (int j=0;j<LMR;j++){
        sq += __half2float(g_qh[base + (long long)j*DHD]);
        sk += __half2float(g_kh[base + (long long)j*DHD]);
    }
    g_qlh[idx] = __float2half(sq * 0.25f);
    g_klh[idx] = __float2half(sk * 0.25f);
}

// softmax: fp32 in -> fp16 out
__global__ void softmax_h_kernel(const float* __restrict__ X, __half* __restrict__ O, int cols){
    __shared__ float sh[4];
    long long row = blockIdx.x;
    const float* p = X + row*(long long)cols;
    __half* q = O + row*(long long)cols;
    int t = threadIdx.x;
    int cnt = cols >> 7;
    float v[8];
    float mx = -3.4e38f;
    #pragma unroll
    for (int i=0;i<8;i++) if (i<cnt){ v[i]=p[t + (i<<7)]; mx = fmaxf(mx, v[i]); }
    mx = blockMaxN(mx, sh, 4);
    float s = 0.f;
    #pragma unroll
    for (int i=0;i<8;i++) if (i<cnt){ v[i]=expf(v[i]-mx); s += v[i]; }
    s = blockSumN(s, sh, 4);
    float inv = 1.f/s;
    #pragma unroll
    for (int i=0;i<8;i++) if (i<cnt) q[t + (i<<7)] = __float2half(v[i]*inv);
}

__global__ void red_init_kernel(){ g_red[0]=0; g_red[1]=0; }

__global__ void colsum_kernel(){
    __shared__ float sh[8];
    int bz = blockIdx.x;
    const float* p = g_a2 + (long long)bz*ML*ML;
    int c = threadIdx.x;
    float s = 0.f;
    for (int r=0;r<ML;r++) s += fabsf(p[(long long)r*ML + c]);
    float m = blockMaxN(s, sh, 8);
    if (threadIdx.x==0) atomicMax(&g_red[0], __float_as_int(m));
}
__global__ void rowsum_kernel(){
    __shared__ float sh[8];
    int bz = blockIdx.x;
    const float* p = g_a2 + (long long)bz*ML*ML;
    int w = threadIdx.x>>5, l = threadIdx.x&31;
    float m = -3.4e38f;
    for (int r=w; r<ML; r+=8){
        float s = 0.f;
        for (int c=l; c<ML; c+=32) s += fabsf(p[(long long)r*ML + c]);
        s = warpSum(s);
        m = fmaxf(m, s);
    }
    m = blockMaxN(m, sh, 8);
    if (threadIdx.x==0) atomicMax(&g_red[1], __float_as_int(m));
}
__global__ void zinit_kernel(){
    __shared__ float tile[32][33];
    int bz = blockIdx.z;
    int i0 = blockIdx.x*32;
    int j0 = blockIdx.y*32;
    const long long base = (long long)bz*ML*ML;
    float c = __int_as_float(g_red[0]) * __int_as_float(g_red[1]);
    float invc = 1.f/c;
    #pragma unroll
    for (int k=0;k<4;k++){
        int j = j0 + threadIdx.y + k*8;
        float v = g_a2[base + (long long)j*ML + i0 + threadIdx.x];
        tile[threadIdx.y + k*8][threadIdx.x] = v;
        g_a2h[base + (long long)j*ML + i0 + threadIdx.x] = __float2bfloat16(v);
    }
    __syncthreads();
    #pragma unroll
    for (int k=0;k<4;k++){
        int i = i0 + threadIdx.y + k*8;
        float v = tile[threadIdx.x][threadIdx.y + k*8] * invc;
        long long idx = base + (long long)i*ML + j0 + threadIdx.x;
        g_zb[idx] = v;
        g_zh[idx] = __float2bfloat16(v);
    }
}

__global__ void final_kernel(const float* __restrict__ fw,
                             const float* __restrict__ fb,
                             float* __restrict__ out){
    __shared__ float sh[8];
    int b = blockIdx.x;
    int t = threadIdx.x;
    const float* hp = g_h + (long long)b*LSEQ*DMODEL;
    float s = 0.f;
    for (long long i=t; i<(long long)LSEQ*DMODEL; i+=256)
        s = fmaf(hp[i], fw[i], s);
    s = blockSumN(s, sh, 8);
    if (t==0) out[b] = s + fb[0];
}

// ---------------- host-side dispatch ----------------
static void run_gemm(int epi, int Mi, int Ni, int Ki,
                     const float* A, int lda, long long sA,
                     const float* Bm, int ldb, long long sB,
                     float* C, int ldc, long long sC,
                     int batch, float alpha, float* C2 = nullptr)
{
    dim3 g(Ni/256, Mi/128, batch), t(256);
    size_t sh = SMEM_TC_BYTES;
    switch (epi) {
        case 0: gemm_tc_kernel<0><<<g,t,sh>>>(Ki,A,lda,sA,Bm,ldb,sB,C,ldc,sC,alpha,C2); break;
        case 5: gemm_tc_kernel<5><<<g,t,sh>>>(Ki,A,lda,sA,Bm,ldb,sB,C,ldc,sC,alpha,C2); break;
        case 6: gemm_tc_kernel<6><<<g,t,sh>>>(Ki,A,lda,sA,Bm,ldb,sB,C,ldc,sC,alpha,C2); break;
    }
}

static void run_gemm_h(int epi, int Mi, int Ni, int Ki,
                       const __half* A, int lda,
                       const __half* Bm, int ldb,
                       float* C, int ldc,
                       const float* bias,
                       __half* Ch = nullptr, __half* Ch2 = nullptr, __half* Ch3 = nullptr)
{
    dim3 g(Ni/256, Mi/128, 1), t(256);
    size_t sh = SMEM_BF_BYTES;
    switch (epi) {
        case 2: gemm_h_kernel<2><<<g,t,sh>>>(Ki,A,lda,Bm,ldb,C,ldc,1.f,bias,Ch,Ch2,Ch3); break;
        case 3: gemm_h_kernel<3><<<g,t,sh>>>(Ki,A,lda,Bm,ldb,C,ldc,1.f,bias,Ch,Ch2,Ch3); break;
        case 4: gemm_h_kernel<4><<<g,t,sh>>>(Ki,A,lda,Bm,ldb,C,ldc,1.f,bias,Ch,Ch2,Ch3); break;
        case 7: gemm_h_kernel<7><<<g,t,sh>>>(Ki,A,lda,Bm,ldb,C,ldc,1.f,bias,Ch,Ch2,Ch3); break;
    }
}

static void run_gemm_hs(int epi, int Mi, int Ni, int Ki,
                        const __half* A, int lda, long long sA,
                        const __half* Bm, int ldb, long long sB,
                        float* C, int ldc, long long sC, int batch,
                        __half* Chh = nullptr)
{
    dim3 g(Ni/256, Mi/128, batch), t(256);
    size_t sh = SMEM_HS_BYTES;
    switch (epi) {
        case 0: gemm_hs_kernel<0><<<g,t,sh>>>(Ki,A,lda,sA,Bm,ldb,sB,C,ldc,sC,Chh); break;
        case 8: gemm_hs_kernel<8><<<g,t,sh>>>(Ki,A,lda,sA,Bm,ldb,sB,C,ldc,sC,Chh); break;
        case 9: gemm_hs_kernel<9><<<g,t,sh>>>(Ki,A,lda,sA,Bm,ldb,sB,C,ldc,sC,Chh); break;
    }
}

static void run_gemm_bf16(int epi,
                          const __nv_bfloat16* A, const __nv_bfloat16* Bm,
                          __nv_bfloat16* Cb, __nv_bfloat16* C2b, float* Cf,
                          float alpha)
{
    dim3 g(1, ML/128, BH), t(256);
    size_t sh = SMEM_BF_BYTES;
    switch (epi) {
        case 0: gemm_bf16_kernel<0><<<g,t,sh>>>(A,Bm,Cb,C2b,Cf,alpha); break;
        case 1: gemm_bf16_kernel<1><<<g,t,sh>>>(A,Bm,Cb,C2b,Cf,alpha); break;
        case 5: gemm_bf16_kernel<5><<<g,t,sh>>>(A,Bm,Cb,C2b,Cf,alpha); break;
        case 6: gemm_bf16_kernel<6><<<g,t,sh>>>(A,Bm,Cb,C2b,Cf,alpha); break;
    }
}

static void setup_tc_attrs(){
    cudaFuncSetAttribute(gemm_tc_kernel<0>, cudaFuncAttributeMaxDynamicSharedMemorySize, SMEM_TC_BYTES);
    cudaFuncSetAttribute(gemm_tc_kernel<5>, cudaFuncAttributeMaxDynamicSharedMemorySize, SMEM_TC_BYTES);
    cudaFuncSetAttribute(gemm_tc_kernel<6>, cudaFuncAttributeMaxDynamicSharedMemorySize, SMEM_TC_BYTES);
    cudaFuncSetAttribute(gemm_tc64_kernel, cudaFuncAttributeMaxDynamicSharedMemorySize, SMEM_TC64_BYTES);
    cudaFuncSetAttribute(gemm_bf16_kernel<0>, cudaFuncAttributeMaxDynamicSharedMemorySize, SMEM_BF_BYTES);
    cudaFuncSetAttribute(gemm_bf16_kernel<1>, cudaFuncAttributeMaxDynamicSharedMemorySize, SMEM_BF_BYTES);
    cudaFuncSetAttribute(gemm_bf16_kernel<5>, cudaFuncAttributeMaxDynamicSharedMemorySize, SMEM_BF_BYTES);
    cudaFuncSetAttribute(gemm_bf16_kernel<6>, cudaFuncAttributeMaxDynamicSharedMemorySize, SMEM_BF_BYTES);
    cudaFuncSetAttribute(gemm_h_kernel<2>, cudaFuncAttributeMaxDynamicSharedMemorySize, SMEM_BF_BYTES);
    cudaFuncSetAttribute(gemm_h_kernel<3>, cudaFuncAttributeMaxDynamicSharedMemorySize, SMEM_BF_BYTES);
    cudaFuncSetAttribute(gemm_h_kernel<4>, cudaFuncAttributeMaxDynamicSharedMemorySize, SMEM_BF_BYTES);
    cudaFuncSetAttribute(gemm_h_kernel<7>, cudaFuncAttributeMaxDynamicSharedMemorySize, SMEM_BF_BYTES);
    cudaFuncSetAttribute(gemm_hs_kernel<0>, cudaFuncAttributeMaxDynamicSharedMemorySize, SMEM_HS_BYTES);
    cudaFuncSetAttribute(gemm_hs_kernel<8>, cudaFuncAttributeMaxDynamicSharedMemorySize, SMEM_HS_BYTES);
    cudaFuncSetAttribute(gemm_hs_kernel<9>, cudaFuncAttributeMaxDynamicSharedMemorySize, SMEM_HS_BYTES);
    cudaFuncSetAttribute(gemm_h64_kernel<0>, cudaFuncAttributeMaxDynamicSharedMemorySize, SMEM_H64_BYTES);
    cudaFuncSetAttribute(gemm_h64_kernel<1>, cudaFuncAttributeMaxDynamicSharedMemorySize, SMEM_H64_BYTES);
}

extern "C" void kernel_launch(void* const* d_in, const int* in_sizes, int n_in,
                              void* d_out, int out_size)
{
    (void)in_sizes; (void)n_in; (void)out_size;
    const int*   x       = (const int*)  d_in[0];
    const float* enc_emb = (const float*)d_in[1];
    const float* pos_emb = (const float*)d_in[2];
    const float* ln1_s   = (const float*)d_in[3];
    const float* ln1_b   = (const float*)d_in[4];
    const float* qkv_w   = (const float*)d_in[5];
    const float* aout_w  = (const float*)d_in[6];
    const float* aout_b  = (const float*)d_in[7];
    const float* conv_k  = (const float*)d_in[8];
    const float* ln2_s   = (const float*)d_in[9];
    const float* ln2_b   = (const float*)d_in[10];
    const float* ff_w1   = (const float*)d_in[11];
    const float* ff_b1   = (const float*)d_in[12];
    const float* ff_w2   = (const float*)d_in[13];
    const float* ff_b2   = (const float*)d_in[14];
    const float* fin_w   = (const float*)d_in[15];
    const float* fin_b   = (const float*)d_in[16];
    float* out = (float*)d_out;

    setup_tc_attrs();

    float *p_h,*p_a3,*p_a2,*p_z,*p_z2,*p_p,*p_t,*p_t2,*p_kv;
    __half *p_qh,*p_kh,*p_vh,*p_qlh,*p_klh,*p_a1h,*p_a3h,*p_zkvh;
    __half *p_xh,*p_x2h,*p_ffh,*p_yh,*p_wqkv,*p_wout,*p_wf1,*p_wf2;
    __nv_bfloat16 *p_a2h,*p_zh,*p_zh2,*p_ph,*p_th,*p_t2h;
    cudaGetSymbolAddress((void**)&p_h,  g_h);
    cudaGetSymbolAddress((void**)&p_a3, g_a3);
    cudaGetSymbolAddress((void**)&p_a2, g_a2);
    cudaGetSymbolAddress((void**)&p_z,  g_zb);
    cudaGetSymbolAddress((void**)&p_z2, g_zb2);
    cudaGetSymbolAddress((void**)&p_p,  g_pb);
    cudaGetSymbolAddress((void**)&p_t,  g_tb);
    cudaGetSymbolAddress((void**)&p_t2, g_tb2);
    cudaGetSymbolAddress((void**)&p_kv, g_kvb);
    cudaGetSymbolAddress((void**)&p_qh,  g_qh);
    cudaGetSymbolAddress((void**)&p_kh,  g_kh);
    cudaGetSymbolAddress((void**)&p_vh,  g_vh);
    cudaGetSymbolAddress((void**)&p_qlh, g_qlh);
    cudaGetSymbolAddress((void**)&p_klh, g_klh);
    cudaGetSymbolAddress((void**)&p_a1h, g_a1h);
    cudaGetSymbolAddress((void**)&p_a3h, g_a3h);
    cudaGetSymbolAddress((void**)&p_zkvh,g_zkvh);
    cudaGetSymbolAddress((void**)&p_xh,  g_xh);
    cudaGetSymbolAddress((void**)&p_x2h, g_x2h);
    cudaGetSymbolAddress((void**)&p_ffh, g_ffh);
    cudaGetSymbolAddress((void**)&p_yh,  g_yh);
    cudaGetSymbolAddress((void**)&p_wqkv,g_wqkv);
    cudaGetSymbolAddress((void**)&p_wout,g_wout);
    cudaGetSymbolAddress((void**)&p_wf1, g_wf1);
    cudaGetSymbolAddress((void**)&p_wf2, g_wf2);
    cudaGetSymbolAddress((void**)&p_a2h, g_a2h);
    cudaGetSymbolAddress((void**)&p_zh,  g_zh);
    cudaGetSymbolAddress((void**)&p_zh2, g_zh2);
    cudaGetSymbolAddress((void**)&p_ph,  g_ph);
    cudaGetSymbolAddress((void**)&p_th,  g_th);
    cudaGetSymbolAddress((void**)&p_t2h, g_t2h);

    const long long MM  = (long long)ML*ML;
    const long long NM  = (long long)NPAD*ML;
    const long long ND  = (long long)NPAD*DHD;
    const long long MD  = (long long)ML*DHD;

    {
        long long n1 = (long long)DEPTH*DMODEL*3*DMODEL;
        long long n2 = (long long)DEPTH*DMODEL*DMODEL;
        long long n3 = (long long)DEPTH*DMODEL*FFD;
        long long n4 = (long long)DEPTH*FFD*DMODEL;
        cvtw_kernel<<<(unsigned)((n1+255)/256),256>>>(qkv_w, p_wqkv, n1);
        cvtw_kernel<<<(unsigned)((n2+255)/256),256>>>(aout_w, p_wout, n2);
        cvtw_kernel<<<(unsigned)((n3+255)/256),256>>>(ff_w1, p_wf1, n3);
        cvtw_kernel<<<(unsigned)((n4+255)/256),256>>>(ff_w2, p_wf2, n4);
    }

    {
        long long tot = (long long)BATCH*LSEQ*DMODEL;
        embed_kernel<<<(unsigned)((tot+255)/256),256>>>(x, enc_emb, pos_emb);
        int tot2 = BATCH*PADL*DMODEL;
        zero_pad_kernel<<<(tot2+255)/256,256>>>();
    }

    for (int lay=0; lay<DEPTH; lay++){
        ln_kernel<<<BATCH*LSEQ,256>>>(p_h, p_xh, ln1_s+(long long)lay*DMODEL, ln1_b+(long long)lay*DMODEL, 1);
        // QKV [fp16, fused split: fp16 q/k/v]
        run_gemm_h(7, BATCH*NPAD, 3*DMODEL, DMODEL,
                   p_xh, DMODEL,
                   p_wqkv + (long long)lay*DMODEL*3*DMODEL, 3*DMODEL,
                   nullptr, 3*DMODEL, nullptr, p_qh, p_kh, p_vh);
        {
            long long tot2 = (long long)BH*ML*DHD;
            landmark_kernel<<<(unsigned)((tot2+255)/256),256>>>();
        }
        // attn1 = softmax(q @ kl^T)  [fp16 TB1, fused softmax -> fp16]
        run_gemm_hs(8, NPAD, ML, DHD, p_qh, DHD, ND, p_klh, DHD, MD, nullptr, ML, NM, BH, p_a1h);
        // attn2 = softmax(ql @ kl^T)  [fp16 TB1, fused softmax -> fp32]
        run_gemm_hs(9, ML, ML, DHD, p_qlh, DHD, MD, p_klh, DHD, MD, p_a2, ML, MM, BH);
        // attn3 = ql @ k^T  [fp16 TB1 -> fp32] + softmax -> fp16 a3h
        run_gemm_hs(0, ML, NPAD, DHD, p_qlh, DHD, MD, p_kh, DHD, ND, p_a3, NPAD, (long long)ML*NPAD, BH);
        softmax_h_kernel<<<BH*ML,128>>>(p_a3, p_a3h, NPAD);

        // ---- pinv: 5 bf16 quintic iterations + 1 tf32 quintic polish ----
        red_init_kernel<<<1,1>>>();
        colsum_kernel<<<BH,256>>>();
        rowsum_kernel<<<BH,256>>>();
        {
            dim3 gz(ML/32, ML/32, BH), tz(32, 8);
            zinit_kernel<<<gz, tz>>>();
        }
        __nv_bfloat16* zhc = p_zh; __nv_bfloat16* zhn = p_zh2;
        for (int it=0; it<5; it++){
            run_gemm_bf16(6, p_a2h, zhc, p_ph, p_th, nullptr, 7.f);
            run_gemm_bf16(5, p_ph, p_th,  p_t2h, nullptr, nullptr, 15.f);
            run_gemm_bf16(5, p_ph, p_t2h, p_th,  nullptr, nullptr, 13.f);
            if (it < 4){
                run_gemm_bf16(0, zhc, p_th, zhn, nullptr, nullptr, 0.25f);
                __nv_bfloat16* tmp = zhc; zhc = zhn; zhn = tmp;
            } else {
                run_gemm_bf16(1, zhc, p_th, nullptr, nullptr, p_z, 0.25f);
            }
        }
        run_gemm(6, ML, ML, ML, p_a2, ML, MM, p_z, ML, MM, p_p, ML, MM, BH, 7.f, p_t);
        run_gemm(5, ML, ML, ML, p_p, ML, MM, p_t, ML, MM, p_t2, ML, MM, BH, 15.f);
        run_gemm(5, ML, ML, ML, p_p, ML, MM, p_t2, ML, MM, p_t, ML, MM, BH, 13.f);
        run_gemm(0, ML, ML, ML, p_z, ML, MM, p_t, ML, MM, p_z2, ML, MM, BH, 0.25f);
        float* zc = p_z2;

        // kv = a3h @ vh  [fp16 N=64 -> fp32]
        {
            dim3 g(1, ML/128, BH), t(128);
            gemm_h64_kernel<0><<<g,t,SMEM_H64_BYTES>>>(NPAD, p_a3h, NPAD, (long long)ML*NPAD,
                                                       p_vh, ND, p_kv, MD,
                                                       nullptr, nullptr, nullptr);
        }
        // zkv = Z @ kv  [tf32 N=64 -> fp16/16]
        {
            dim3 g(1, ML/128, BH), t(128);
            gemm_tc64_kernel<<<g,t,SMEM_TC64_BYTES>>>(ML, zc, ML, MM, p_kv, DHD, MD, MD, p_zkvh);
        }
        // ao = a1h @ zkvh*16 + conv(vh) -> fp16 y  [fp16 N=64, fused]
        {
            dim3 g(1, NPAD/128, BH), t(128);
            gemm_h64_kernel<1><<<g,t,SMEM_H64_BYTES>>>(ML, p_a1h, ML, NM, p_zkvh, MD,
                                                       nullptr, 0,
                                                       p_vh, conv_k + (long long)lay*NH*KC, p_yh);
        }
        // out projection + residual [fp16]
        run_gemm_h(4, BATCH*NPAD, DMODEL, DMODEL,
                   p_yh, DMODEL,
                   p_wout + (long long)lay*DMODEL*DMODEL, DMODEL,
                   p_h, DMODEL, aout_b + (long long)lay*DMODEL);

        // ---- FFN [fp16] ----
        ln_kernel<<<BATCH*LSEQ,256>>>(p_h, p_x2h, ln2_s+(long long)lay*DMODEL, ln2_b+(long long)lay*DMODEL, 0);
        run_gemm_h(2, BATCH*LSEQ, FFD, DMODEL,
                   p_x2h, DMODEL,
                   p_wf1 + (long long)lay*DMODEL*FFD, FFD,
                   nullptr, FFD, ff_b1 + (long long)lay*FFD, p_ffh);
        run_gemm_h(3, BATCH*LSEQ, DMODEL, FFD,
                   p_ffh, FFD,
                   p_wf2 + (long long)lay*FFD*DMODEL, DMODEL,
                   p_h, DMODEL, ff_b2 + (long long)lay*DMODEL);
    }

    final_kernel<<<BATCH,256>>>(fin_w, fin_b, out);
}